// round 1
// baseline (speedup 1.0000x reference)
#include <cuda_runtime.h>
#include <math.h>

// ---------------------------------------------------------------------------
// Problem constants
// ---------------------------------------------------------------------------
#define BATCH 512
// conv1: in 4x84x84 -> 32x20x20 (8x8 stride4)
// conv2: 32x20x20 -> 64x9x9 (4x4 stride2)
// conv3: 64x9x9 -> 64x7x7 (3x3 stride1), flatten 3136
#define A1_PER_OBS (512*32*20*20)   // 6,553,600
#define A2_PER_OBS (512*64*9*9)     // 2,654,208
#define FEAT_PER_OBS (512*3136)     // 1,605,632

#define CONV1_SMEM ((28224 + 8192) * 4)      // 145,664 B
#define CONV2_SMEM ((12800 + 32768) * 4)     // 182,272 B
#define CONV3_SMEM ((5184 + 36864) * 4)      // 168,192 B

// ---------------------------------------------------------------------------
// Device scratch (static device globals: allowed, no runtime allocation)
// ---------------------------------------------------------------------------
__device__ __align__(128) float g_a1[2 * A1_PER_OBS];
__device__ __align__(128) float g_a2[2 * A2_PER_OBS];
__device__ __align__(128) float g_feat[2 * FEAT_PER_OBS];   // [1024][3136]
__device__ __align__(128) float g_f[1024 * 256];            // fc out (relu)
__device__ __align__(128) float g_h1[1024 * 256];           // relu(f@e1w+e1b)
__device__ __align__(128) float g_phi[1024 * 64];           // h1@e2w+e2b
__device__ __align__(128) float g_hp[512 * 256];            // relu(f_next@pw1+pb1)
__device__ __align__(128) float g_cy[512];
__device__ __align__(128) float g_lse[512];
__device__ __align__(128) float g_diag[512];
__device__ __align__(128) float g_part[4 * 1024 * 256];     // split-K partials

// ---------------------------------------------------------------------------
// conv1: 4ch 84x84 -> 32ch 20x20, k=8, s=4, + relu
// one block per image; stage image (28224f) + weights (8192f) in smem.
// tiles: 8 oc-groups(4) x 20 oy x 5 ox-groups(4) = 800 tiles
// ---------------------------------------------------------------------------
__global__ void conv1_kernel(const float* __restrict__ in,
                             const float* __restrict__ w,
                             const float* __restrict__ bias,
                             float* __restrict__ out) {
    extern __shared__ float sm[];
    float* simg = sm;           // 28224
    float* sw   = sm + 28224;   // 8192
    const int b = blockIdx.x;
    const float* img = in + (size_t)b * 28224;
    for (int i = threadIdx.x; i < 28224; i += blockDim.x) simg[i] = img[i];
    for (int i = threadIdx.x; i < 8192;  i += blockDim.x) sw[i]   = w[i];
    __syncthreads();

    for (int t = threadIdx.x; t < 800; t += blockDim.x) {
        const int ox0 = (t % 5) * 4;
        const int oy  = (t / 5) % 20;
        const int oc0 = (t / 100) * 4;
        float acc[4][4];
        #pragma unroll
        for (int o = 0; o < 4; o++) {
            float bv = bias[oc0 + o];
            acc[o][0] = bv; acc[o][1] = bv; acc[o][2] = bv; acc[o][3] = bv;
        }
        for (int ic = 0; ic < 4; ic++) {
            #pragma unroll
            for (int ky = 0; ky < 8; ky++) {
                const float* srow = simg + ic * 7056 + (oy * 4 + ky) * 84 + ox0 * 4;
                const float* wrow = sw + oc0 * 256 + ic * 64 + ky * 8;
                #pragma unroll
                for (int kx = 0; kx < 8; kx++) {
                    const float i0 = srow[kx], i1 = srow[kx + 4];
                    const float i2 = srow[kx + 8], i3 = srow[kx + 12];
                    #pragma unroll
                    for (int o = 0; o < 4; o++) {
                        const float wv = wrow[o * 256 + kx];
                        acc[o][0] = fmaf(wv, i0, acc[o][0]);
                        acc[o][1] = fmaf(wv, i1, acc[o][1]);
                        acc[o][2] = fmaf(wv, i2, acc[o][2]);
                        acc[o][3] = fmaf(wv, i3, acc[o][3]);
                    }
                }
            }
        }
        #pragma unroll
        for (int o = 0; o < 4; o++) {
            float* orow = out + (((size_t)b * 32 + oc0 + o) * 20 + oy) * 20 + ox0;
            #pragma unroll
            for (int j = 0; j < 4; j++) orow[j] = fmaxf(acc[o][j], 0.0f);
        }
    }
}

// ---------------------------------------------------------------------------
// conv2: 32ch 20x20 -> 64ch 9x9, k=4, s=2, + relu
// one block per image; stage input (12800f) + weights (32768f).
// tiles: 16 oc-groups(4) x 9 oy x 2 ox-halves = 288
// ---------------------------------------------------------------------------
__global__ void conv2_kernel(const float* __restrict__ in,
                             const float* __restrict__ w,
                             const float* __restrict__ bias,
                             float* __restrict__ out) {
    extern __shared__ float sm[];
    float* sin = sm;            // 12800
    float* sw  = sm + 12800;    // 32768
    const int b = blockIdx.x;
    const float* ib = in + (size_t)b * 12800;
    for (int i = threadIdx.x; i < 12800; i += blockDim.x) sin[i] = ib[i];
    for (int i = threadIdx.x; i < 32768; i += blockDim.x) sw[i]  = w[i];
    __syncthreads();

    for (int t = threadIdx.x; t < 288; t += blockDim.x) {
        const int half = t & 1;
        const int oy   = (t >> 1) % 9;
        const int oc0  = (t / 18) * 4;
        const int ox0  = half ? 5 : 0;
        const int nx   = half ? 4 : 5;
        float acc[4][5];
        #pragma unroll
        for (int o = 0; o < 4; o++) {
            float bv = bias[oc0 + o];
            #pragma unroll
            for (int j = 0; j < 5; j++) acc[o][j] = bv;
        }
        for (int ic = 0; ic < 32; ic++) {
            #pragma unroll
            for (int ky = 0; ky < 4; ky++) {
                const float* srow = sin + ic * 400 + (oy * 2 + ky) * 20 + ox0 * 2;
                const float* wrow = sw + (oc0 * 32 + ic) * 16 + ky * 4;
                #pragma unroll
                for (int kx = 0; kx < 4; kx++) {
                    float iv[5];
                    #pragma unroll
                    for (int j = 0; j < 5; j++) iv[j] = srow[2 * j + kx];
                    #pragma unroll
                    for (int o = 0; o < 4; o++) {
                        const float wv = wrow[o * 512 + kx];
                        #pragma unroll
                        for (int j = 0; j < 5; j++)
                            acc[o][j] = fmaf(wv, iv[j], acc[o][j]);
                    }
                }
            }
        }
        #pragma unroll
        for (int o = 0; o < 4; o++) {
            float* orow = out + (((size_t)b * 64 + oc0 + o) * 9 + oy) * 9 + ox0;
            for (int j = 0; j < nx; j++) orow[j] = fmaxf(acc[o][j], 0.0f);
        }
    }
}

// ---------------------------------------------------------------------------
// conv3: 64ch 9x9 -> 64ch 7x7, k=3, s=1, + relu, written flattened [b][3136]
// one block (224 threads) per image; tiles: 32 oc-groups(2) x 7 oy = 224
// ---------------------------------------------------------------------------
__global__ void conv3_kernel(const float* __restrict__ in,
                             const float* __restrict__ w,
                             const float* __restrict__ bias,
                             float* __restrict__ out) {
    extern __shared__ float sm[];
    float* sin = sm;           // 5184
    float* sw  = sm + 5184;    // 36864
    const int b = blockIdx.x;
    const float* ib = in + (size_t)b * 5184;
    for (int i = threadIdx.x; i < 5184; i += blockDim.x) sin[i] = ib[i];
    for (int i = threadIdx.x; i < 36864; i += blockDim.x) sw[i] = w[i];
    __syncthreads();

    const int t   = threadIdx.x;   // 224 tiles exactly
    const int oy  = t % 7;
    const int oc0 = (t / 7) * 2;
    float acc[2][7];
    {
        float b0 = bias[oc0], b1 = bias[oc0 + 1];
        #pragma unroll
        for (int j = 0; j < 7; j++) { acc[0][j] = b0; acc[1][j] = b1; }
    }
    for (int ic = 0; ic < 64; ic++) {
        #pragma unroll
        for (int ky = 0; ky < 3; ky++) {
            const float* srow = sin + ic * 81 + (oy + ky) * 9;
            float r[9];
            #pragma unroll
            for (int x = 0; x < 9; x++) r[x] = srow[x];
            const float* wr = sw + oc0 * 576 + ic * 9 + ky * 3;
            #pragma unroll
            for (int kx = 0; kx < 3; kx++) {
                const float w0 = wr[kx], w1 = wr[576 + kx];
                #pragma unroll
                for (int j = 0; j < 7; j++) {
                    acc[0][j] = fmaf(w0, r[j + kx], acc[0][j]);
                    acc[1][j] = fmaf(w1, r[j + kx], acc[1][j]);
                }
            }
        }
    }
    #pragma unroll
    for (int o = 0; o < 2; o++) {
        float* orow = out + (size_t)b * 3136 + (oc0 + o) * 49 + oy * 7;
        #pragma unroll
        for (int j = 0; j < 7; j++) orow[j] = fmaxf(acc[o][j], 0.0f);
    }
}

// ---------------------------------------------------------------------------
// Tiled fp32 GEMM with split-K. C_part[z] = A[:, kz] @ W[kz, :]
// BM=BN=64, BK=16, 256 threads, 4x4 micro-tile. Requires M%64==0, N%64==0,
// K%16==0, kChunk%16==0.
// ---------------------------------------------------------------------------
__global__ void gemm_part_kernel(const float* __restrict__ A,
                                 const float* __restrict__ W,
                                 float* __restrict__ Cp,
                                 int M, int N, int K, int kChunk) {
    __shared__ float sA[16][68];
    __shared__ float sW[16][68];
    const int m0 = blockIdx.x * 64;
    const int n0 = blockIdx.y * 64;
    const int z  = blockIdx.z;
    int k0beg = z * kChunk;
    int k0end = k0beg + kChunk; if (k0end > K) k0end = K;
    const int tid = threadIdx.x;
    const int tx = tid & 15, ty = tid >> 4;
    float acc[4][4] = {};

    for (int k0 = k0beg; k0 < k0end; k0 += 16) {
        {   // A tile: 64m x 16k, thread loads float4 along k
            const int mm = tid >> 2;
            const int kk = (tid & 3) * 4;
            const float4 av = *(const float4*)(A + (size_t)(m0 + mm) * K + k0 + kk);
            sA[kk + 0][mm] = av.x; sA[kk + 1][mm] = av.y;
            sA[kk + 2][mm] = av.z; sA[kk + 3][mm] = av.w;
        }
        {   // W tile: 16k x 64n
            const int kk = tid >> 4;
            const int nn = (tid & 15) * 4;
            const float4 wv = *(const float4*)(W + (size_t)(k0 + kk) * N + n0 + nn);
            *(float4*)&sW[kk][nn] = wv;
        }
        __syncthreads();
        #pragma unroll
        for (int kk = 0; kk < 16; kk++) {
            const float4 av = *(const float4*)&sA[kk][ty * 4];
            const float4 wv = *(const float4*)&sW[kk][tx * 4];
            const float a[4] = {av.x, av.y, av.z, av.w};
            const float w[4] = {wv.x, wv.y, wv.z, wv.w};
            #pragma unroll
            for (int i = 0; i < 4; i++)
                #pragma unroll
                for (int j = 0; j < 4; j++)
                    acc[i][j] = fmaf(a[i], w[j], acc[i][j]);
        }
        __syncthreads();
    }
    float* cb = Cp + (size_t)z * M * N;
    #pragma unroll
    for (int i = 0; i < 4; i++)
        #pragma unroll
        for (int j = 0; j < 4; j++)
            cb[(size_t)(m0 + ty * 4 + i) * N + n0 + tx * 4 + j] = acc[i][j];
}

__global__ void combine_kernel(const float* __restrict__ Cp,
                               const float* __restrict__ bias,
                               float* __restrict__ C,
                               int MN, int N, int nsplit, int doRelu) {
    const int idx = blockIdx.x * blockDim.x + threadIdx.x;
    if (idx >= MN) return;
    float s = bias[idx % N];
    for (int z = 0; z < nsplit; z++) s += Cp[(size_t)z * MN + idx];
    if (doRelu) s = fmaxf(s, 0.0f);
    C[idx] = s;
}

// ---------------------------------------------------------------------------
// c_y[b] = hp[b,:] . pw2 + pb2   (one warp per row)
// ---------------------------------------------------------------------------
__global__ void cy_kernel(const float* __restrict__ hp,
                          const float* __restrict__ pw2,
                          const float* __restrict__ pb2,
                          float* __restrict__ cy) {
    const int gw = (blockIdx.x * blockDim.x + threadIdx.x) >> 5;
    const int lane = threadIdx.x & 31;
    if (gw >= 512) return;
    float s = 0.0f;
    for (int k = lane; k < 256; k += 32) s = fmaf(hp[(size_t)gw * 256 + k], pw2[k], s);
    #pragma unroll
    for (int off = 16; off > 0; off >>= 1) s += __shfl_xor_sync(0xffffffffu, s, off);
    if (lane == 0) cy[gw] = s + pb2[0];
}

// ---------------------------------------------------------------------------
// Per-row i: logits[i,j] = cy[j] - mrn(phi_x[i], phi_y[j]); write lse_i, diag_i
// ---------------------------------------------------------------------------
__global__ void logits_kernel(const float* __restrict__ phi,
                              const float* __restrict__ cy,
                              float* __restrict__ lse,
                              float* __restrict__ diag) {
    const int i = blockIdx.x;
    __shared__ float sx[64];
    __shared__ float red[256];
    __shared__ float sdiag;
    const int tid = threadIdx.x;
    if (tid < 64) sx[tid] = phi[(size_t)i * 64 + tid];
    __syncthreads();

    float lg[2];
    #pragma unroll
    for (int r = 0; r < 2; r++) {
        const int j = tid + r * 256;
        const float* y = phi + (size_t)(512 + j) * 64;
        float mx = 0.0f;
        #pragma unroll
        for (int k = 0; k < 32; k++) {
            float d = sx[k] - y[k];
            mx = fmaxf(mx, fmaxf(d, 0.0f));
        }
        float ss = 0.0f;
        #pragma unroll
        for (int k = 32; k < 64; k++) {
            float d = sx[k] - y[k];
            ss = fmaf(d, d, ss);
        }
        lg[r] = cy[j] - (mx + sqrtf(ss + 1e-8f));
        if (j == i) sdiag = lg[r];
    }
    // row max
    red[tid] = fmaxf(lg[0], lg[1]);
    __syncthreads();
    for (int s = 128; s > 0; s >>= 1) {
        if (tid < s) red[tid] = fmaxf(red[tid], red[tid + s]);
        __syncthreads();
    }
    const float rowmax = red[0];
    __syncthreads();
    red[tid] = expf(lg[0] - rowmax) + expf(lg[1] - rowmax);
    __syncthreads();
    for (int s = 128; s > 0; s >>= 1) {
        if (tid < s) red[tid] += red[tid + s];
        __syncthreads();
    }
    if (tid == 0) {
        lse[i] = rowmax + logf(red[0]);
        diag[i] = sdiag;
    }
}

// loss = mean(lse - diag) + 0.1 * mean((lse + 1e-6)^2)
__global__ void loss_kernel(const float* __restrict__ lse,
                            const float* __restrict__ diag,
                            float* __restrict__ out) {
    __shared__ float r1[256], r2[256];
    const int tid = threadIdx.x;
    float s1 = 0.0f, s2 = 0.0f;
    for (int i = tid; i < 512; i += 256) {
        const float l = lse[i];
        s1 += l - diag[i];
        const float u = l + 1e-6f;
        s2 = fmaf(u, u, s2);
    }
    r1[tid] = s1; r2[tid] = s2;
    __syncthreads();
    for (int s = 128; s > 0; s >>= 1) {
        if (tid < s) { r1[tid] += r1[tid + s]; r2[tid] += r2[tid + s]; }
        __syncthreads();
    }
    if (tid == 0)
        out[0] = r1[0] * (1.0f / 512.0f) + 0.1f * r2[0] * (1.0f / 512.0f);
}

// ---------------------------------------------------------------------------
// Host launcher
// ---------------------------------------------------------------------------
extern "C" void kernel_launch(void* const* d_in, const int* in_sizes, int n_in,
                              void* d_out, int out_size) {
    const float* curr = (const float*)d_in[0];
    const float* next = (const float*)d_in[1];
    const float* c1w = (const float*)d_in[2];
    const float* c1b = (const float*)d_in[3];
    const float* c2w = (const float*)d_in[4];
    const float* c2b = (const float*)d_in[5];
    const float* c3w = (const float*)d_in[6];
    const float* c3b = (const float*)d_in[7];
    const float* fcw = (const float*)d_in[8];
    const float* fcb = (const float*)d_in[9];
    const float* e1w = (const float*)d_in[10];
    const float* e1b = (const float*)d_in[11];
    const float* e2w = (const float*)d_in[12];
    const float* e2b = (const float*)d_in[13];
    const float* pw1 = (const float*)d_in[14];
    const float* pb1 = (const float*)d_in[15];
    const float* pw2 = (const float*)d_in[16];
    const float* pb2 = (const float*)d_in[17];

    float *p_a1, *p_a2, *p_feat, *p_f, *p_h1, *p_phi, *p_hp, *p_cy, *p_lse, *p_diag, *p_part;
    cudaGetSymbolAddress((void**)&p_a1, g_a1);
    cudaGetSymbolAddress((void**)&p_a2, g_a2);
    cudaGetSymbolAddress((void**)&p_feat, g_feat);
    cudaGetSymbolAddress((void**)&p_f, g_f);
    cudaGetSymbolAddress((void**)&p_h1, g_h1);
    cudaGetSymbolAddress((void**)&p_phi, g_phi);
    cudaGetSymbolAddress((void**)&p_hp, g_hp);
    cudaGetSymbolAddress((void**)&p_cy, g_cy);
    cudaGetSymbolAddress((void**)&p_lse, g_lse);
    cudaGetSymbolAddress((void**)&p_diag, g_diag);
    cudaGetSymbolAddress((void**)&p_part, g_part);

    cudaFuncSetAttribute(conv1_kernel, cudaFuncAttributeMaxDynamicSharedMemorySize, CONV1_SMEM);
    cudaFuncSetAttribute(conv2_kernel, cudaFuncAttributeMaxDynamicSharedMemorySize, CONV2_SMEM);
    cudaFuncSetAttribute(conv3_kernel, cudaFuncAttributeMaxDynamicSharedMemorySize, CONV3_SMEM);

    const float* obs[2] = {curr, next};
    for (int o = 0; o < 2; o++) {
        conv1_kernel<<<BATCH, 256, CONV1_SMEM>>>(obs[o], c1w, c1b,
                                                 p_a1 + (size_t)o * A1_PER_OBS);
        conv2_kernel<<<BATCH, 256, CONV2_SMEM>>>(p_a1 + (size_t)o * A1_PER_OBS, c2w, c2b,
                                                 p_a2 + (size_t)o * A2_PER_OBS);
        conv3_kernel<<<BATCH, 224, CONV3_SMEM>>>(p_a2 + (size_t)o * A2_PER_OBS, c3w, c3b,
                                                 p_feat + (size_t)o * FEAT_PER_OBS);
    }

    // fc: [1024,3136] @ [3136,256] + bias, relu; split-K 4
    gemm_part_kernel<<<dim3(16, 4, 4), 256>>>(p_feat, fcw, p_part, 1024, 256, 3136, 784);
    combine_kernel<<<(1024 * 256 + 255) / 256, 256>>>(p_part, fcb, p_f, 1024 * 256, 256, 4, 1);

    // h1 = relu(f @ e1w + e1b)
    gemm_part_kernel<<<dim3(16, 4, 1), 256>>>(p_f, e1w, p_part, 1024, 256, 256, 256);
    combine_kernel<<<(1024 * 256 + 255) / 256, 256>>>(p_part, e1b, p_h1, 1024 * 256, 256, 1, 1);

    // phi = h1 @ e2w + e2b (no relu)
    gemm_part_kernel<<<dim3(16, 1, 1), 256>>>(p_h1, e2w, p_part, 1024, 64, 256, 256);
    combine_kernel<<<(1024 * 64 + 255) / 256, 256>>>(p_part, e2b, p_phi, 1024 * 64, 64, 1, 0);

    // hp = relu(f_next @ pw1 + pb1)
    gemm_part_kernel<<<dim3(8, 4, 1), 256>>>(p_f + (size_t)512 * 256, pw1, p_part, 512, 256, 256, 256);
    combine_kernel<<<(512 * 256 + 255) / 256, 256>>>(p_part, pb1, p_hp, 512 * 256, 256, 1, 1);

    // c_y
    cy_kernel<<<64, 256>>>(p_hp, pw2, pb2, p_cy);

    // pairwise logits -> per-row lse + diag
    logits_kernel<<<512, 256>>>(p_phi, p_cy, p_lse, p_diag);

    // final scalar
    loss_kernel<<<1, 256>>>(p_lse, p_diag, (float*)d_out);
}

// round 2
// speedup vs baseline: 1.3681x; 1.3681x over previous
#include <cuda_runtime.h>
#include <math.h>

#define NIMG 1024

__device__ __align__(128) float g_w1t[8192];     // [256][32]
__device__ __align__(128) float g_w2t[32768];    // [512][64]
__device__ __align__(128) float g_w3t[36864];    // [576][64]
__device__ __align__(128) float g_a1[(size_t)NIMG*32*20*20];
__device__ __align__(128) float g_a2[(size_t)NIMG*64*9*9];
__device__ __align__(128) float g_feat[(size_t)NIMG*3136];
__device__ __align__(128) float g_f[NIMG*256];
__device__ __align__(128) float g_h1[NIMG*256];
__device__ __align__(128) float g_phi[NIMG*64];
__device__ __align__(128) float g_hp[512*256];
__device__ __align__(128) float g_cy[512];
__device__ __align__(128) float g_lse[512];
__device__ __align__(128) float g_diag[512];
__device__ __align__(128) float g_part[8*1024*256];

// ---------------------------------------------------------------------------
// weight transpose: wt[k][oc] = w[oc][k]
// ---------------------------------------------------------------------------
__global__ void transpose_kernel(const float* __restrict__ w,
                                 float* __restrict__ wt, int OC, int K) {
    int i = blockIdx.x * 256 + threadIdx.x;
    if (i < OC * K) {
        int k = i / OC, oc = i % OC;
        wt[i] = w[oc * K + k];
    }
}

// ---------------------------------------------------------------------------
// conv1: 4ch 84x84 -> 32ch 20x20, k=8 s4, relu.
// grid (1024 img, 4 oy-groups of 5), 256 thr, smem 65KB -> 3 blocks/SM.
// tile = 4oc x 4ox; tile order: ocg fastest (warp-broadcast image loads).
// ---------------------------------------------------------------------------
__global__ void conv1_kernel(const float* __restrict__ curr,
                             const float* __restrict__ next,
                             const float* __restrict__ wt,
                             const float* __restrict__ bias,
                             float* __restrict__ out) {
    extern __shared__ float sm[];
    float* simg = sm;          // 4 * 24 * 84 = 8064
    float* sw   = sm + 8064;   // 8192
    __shared__ float sb[32];
    const int img = blockIdx.x;
    const int oy0 = blockIdx.y * 5;
    const int iy0 = oy0 * 4;
    const float* in = (img < 512) ? curr + (size_t)img * 28224
                                  : next + (size_t)(img - 512) * 28224;
    for (int i = threadIdx.x; i < 2016; i += 256) {
        int e = i * 4;
        int ic = e / 2016, rem = e % 2016;
        *(float4*)&simg[e] = *(const float4*)&in[ic * 7056 + iy0 * 84 + rem];
    }
    for (int i = threadIdx.x; i < 2048; i += 256)
        *(float4*)&sw[i * 4] = *(const float4*)&wt[i * 4];
    if (threadIdx.x < 32) sb[threadIdx.x] = bias[threadIdx.x];
    __syncthreads();

    const int t = threadIdx.x;
    if (t < 200) {
        const int ocg = t & 7;
        const int oxg = (t >> 3) % 5;
        const int oyl = t / 40;
        const int oc0 = ocg * 4, ox0 = oxg * 4;
        float acc[4][4];
        #pragma unroll
        for (int o = 0; o < 4; o++) {
            float bv = sb[oc0 + o];
            #pragma unroll
            for (int j = 0; j < 4; j++) acc[o][j] = bv;
        }
        #pragma unroll
        for (int ic = 0; ic < 4; ic++) {
            #pragma unroll
            for (int ky = 0; ky < 8; ky++) {
                const float* base = simg + ic * 2016 + (oyl * 4 + ky) * 84 + ox0 * 4;
                float r[20];
                #pragma unroll
                for (int q = 0; q < 5; q++)
                    *(float4*)&r[q * 4] = *(const float4*)&base[q * 4];
                const float* wb = sw + ((ic * 8 + ky) * 8) * 32 + oc0;
                #pragma unroll
                for (int kx = 0; kx < 8; kx++) {
                    float4 wv = *(const float4*)&wb[kx * 32];
                    #pragma unroll
                    for (int j = 0; j < 4; j++) {
                        const float iv = r[4 * j + kx];
                        acc[0][j] = fmaf(wv.x, iv, acc[0][j]);
                        acc[1][j] = fmaf(wv.y, iv, acc[1][j]);
                        acc[2][j] = fmaf(wv.z, iv, acc[2][j]);
                        acc[3][j] = fmaf(wv.w, iv, acc[3][j]);
                    }
                }
            }
        }
        #pragma unroll
        for (int o = 0; o < 4; o++) {
            float4 v = make_float4(fmaxf(acc[o][0], 0.f), fmaxf(acc[o][1], 0.f),
                                   fmaxf(acc[o][2], 0.f), fmaxf(acc[o][3], 0.f));
            *(float4*)&out[((size_t)img * 32 + oc0 + o) * 400 + (oy0 + oyl) * 20 + ox0] = v;
        }
    }
}

// ---------------------------------------------------------------------------
// conv2: 32ch 20x20 -> 64ch 9x9, k=4 s2, relu.
// grid (1024 img, 4 oc-quarters of 16), 96 thr, smem 82KB -> 2 blocks/SM.
// tile = 4oc x (5|4)ox; ocg fastest.
// ---------------------------------------------------------------------------
template<int NX, int SH>
__device__ __forceinline__ void conv2_tile(const float* __restrict__ sin,
                                           const float* __restrict__ sw,
                                           const float* __restrict__ sb,
                                           float* __restrict__ outbase,
                                           int ocl, int oy, int foff, int ox0) {
    float acc[4][NX];
    #pragma unroll
    for (int o = 0; o < 4; o++) {
        float bv = sb[ocl + o];
        #pragma unroll
        for (int j = 0; j < NX; j++) acc[o][j] = bv;
    }
    for (int ic = 0; ic < 32; ic++) {
        #pragma unroll
        for (int ky = 0; ky < 4; ky++) {
            const float* base = sin + ic * 400 + (oy * 2 + ky) * 20 + foff;
            float r[12];
            #pragma unroll
            for (int q = 0; q < 3; q++)
                *(float4*)&r[q * 4] = *(const float4*)&base[q * 4];
            const float* wb = sw + ((ic * 4 + ky) * 4) * 16 + ocl;
            #pragma unroll
            for (int kx = 0; kx < 4; kx++) {
                float4 wv = *(const float4*)&wb[kx * 16];
                #pragma unroll
                for (int j = 0; j < NX; j++) {
                    const float iv = r[SH + 2 * j + kx];
                    acc[0][j] = fmaf(wv.x, iv, acc[0][j]);
                    acc[1][j] = fmaf(wv.y, iv, acc[1][j]);
                    acc[2][j] = fmaf(wv.z, iv, acc[2][j]);
                    acc[3][j] = fmaf(wv.w, iv, acc[3][j]);
                }
            }
        }
    }
    #pragma unroll
    for (int o = 0; o < 4; o++) {
        float* orow = outbase + (size_t)(ocl + o) * 81 + oy * 9 + ox0;
        #pragma unroll
        for (int j = 0; j < NX; j++) orow[j] = fmaxf(acc[o][j], 0.0f);
    }
}

__global__ void conv2_kernel(const float* __restrict__ a1,
                             const float* __restrict__ w2t,
                             const float* __restrict__ bias,
                             float* __restrict__ out) {
    extern __shared__ float sm[];
    float* sin = sm;           // 12800
    float* sw  = sm + 12800;   // 8192
    __shared__ float sb[16];
    const int img = blockIdx.x;
    const int oc0 = blockIdx.y * 16;
    const float* in = a1 + (size_t)img * 12800;
    for (int i = threadIdx.x; i < 3200; i += blockDim.x)
        *(float4*)&sin[i * 4] = *(const float4*)&in[i * 4];
    for (int i = threadIdx.x; i < 2048; i += blockDim.x) {
        int e = i * 4;
        int kk = e >> 4, j = e & 15;
        *(float4*)&sw[e] = *(const float4*)&w2t[kk * 64 + oc0 + j];
    }
    if (threadIdx.x < 16) sb[threadIdx.x] = bias[oc0 + threadIdx.x];
    __syncthreads();
    const int t = threadIdx.x;
    if (t < 72) {
        const int ocl = (t & 3) * 4;
        const int rest = t >> 2;
        const int oy = rest % 9;
        const int half = rest / 9;
        float* outbase = out + ((size_t)img * 64 + oc0) * 81;
        if (half == 0) conv2_tile<5, 0>(sin, sw, sb, outbase, ocl, oy, 0, 0);
        else           conv2_tile<4, 2>(sin, sw, sb, outbase, ocl, oy, 8, 5);
    }
}

// ---------------------------------------------------------------------------
// conv3: 64ch 9x9 -> 64ch 7x7, k=3 s1, relu, flattened output [img][3136].
// grid (1024 img, 2 oc-halves of 32), 128 thr, smem 101KB -> 2 blocks/SM.
// tile = 2oc x 7ox (full row); ocg fastest.
// ---------------------------------------------------------------------------
__global__ void conv3_kernel(const float* __restrict__ a2,
                             const float* __restrict__ w3t,
                             const float* __restrict__ bias,
                             float* __restrict__ feat) {
    extern __shared__ float sm[];
    float* sin = sm;           // 64 * 108 (rows padded 9->12)
    float* sw  = sm + 6912;    // 576 * 32
    __shared__ float sb[32];
    const int img = blockIdx.x;
    const int oc0 = blockIdx.y * 32;
    const float* in = a2 + (size_t)img * 5184;
    for (int i = threadIdx.x; i < 5184; i += blockDim.x) {
        int ic = i / 81, rem = i % 81;
        sin[ic * 108 + (rem / 9) * 12 + rem % 9] = in[i];
    }
    for (int i = threadIdx.x; i < 4608; i += blockDim.x) {
        int e = i * 4;
        int kk = e >> 5, j = e & 31;
        *(float4*)&sw[e] = *(const float4*)&w3t[kk * 64 + oc0 + j];
    }
    if (threadIdx.x < 32) sb[threadIdx.x] = bias[oc0 + threadIdx.x];
    __syncthreads();
    const int t = threadIdx.x;
    if (t < 112) {
        const int ocl = (t & 15) * 2;
        const int oy  = t >> 4;
        float acc[2][7];
        {
            float b0 = sb[ocl], b1 = sb[ocl + 1];
            #pragma unroll
            for (int j = 0; j < 7; j++) { acc[0][j] = b0; acc[1][j] = b1; }
        }
        for (int ic = 0; ic < 64; ic++) {
            #pragma unroll
            for (int ky = 0; ky < 3; ky++) {
                const float* base = sin + ic * 108 + (oy + ky) * 12;
                float r[12];
                #pragma unroll
                for (int q = 0; q < 3; q++)
                    *(float4*)&r[q * 4] = *(const float4*)&base[q * 4];
                const float* wb = sw + ((ic * 3 + ky) * 3) * 32 + ocl;
                #pragma unroll
                for (int kx = 0; kx < 3; kx++) {
                    float2 wv = *(const float2*)&wb[kx * 32];
                    #pragma unroll
                    for (int j = 0; j < 7; j++) {
                        acc[0][j] = fmaf(wv.x, r[j + kx], acc[0][j]);
                        acc[1][j] = fmaf(wv.y, r[j + kx], acc[1][j]);
                    }
                }
            }
        }
        float* ob = feat + (size_t)img * 3136 + (oc0 + ocl) * 49 + oy * 7;
        #pragma unroll
        for (int j = 0; j < 7; j++) {
            ob[j]      = fmaxf(acc[0][j], 0.0f);
            ob[49 + j] = fmaxf(acc[1][j], 0.0f);
        }
    }
}

// ---------------------------------------------------------------------------
// Tiled fp32 GEMMs (BM=BN=64, BK=16, 256 thr, 4x4 micro-tile)
// ---------------------------------------------------------------------------
__global__ void gemm_part_kernel(const float* __restrict__ A,
                                 const float* __restrict__ W,
                                 float* __restrict__ Cp,
                                 int M, int N, int K, int kChunk) {
    __shared__ float sA[16][68];
    __shared__ float sW[16][68];
    const int m0 = blockIdx.x * 64;
    const int n0 = blockIdx.y * 64;
    const int z  = blockIdx.z;
    int k0beg = z * kChunk;
    int k0end = k0beg + kChunk; if (k0end > K) k0end = K;
    const int tid = threadIdx.x;
    const int tx = tid & 15, ty = tid >> 4;
    float acc[4][4] = {};
    for (int k0 = k0beg; k0 < k0end; k0 += 16) {
        {
            const int mm = tid >> 2;
            const int kk = (tid & 3) * 4;
            const float4 av = *(const float4*)(A + (size_t)(m0 + mm) * K + k0 + kk);
            sA[kk + 0][mm] = av.x; sA[kk + 1][mm] = av.y;
            sA[kk + 2][mm] = av.z; sA[kk + 3][mm] = av.w;
        }
        {
            const int kk = tid >> 4;
            const int nn = (tid & 15) * 4;
            *(float4*)&sW[kk][nn] = *(const float4*)(W + (size_t)(k0 + kk) * N + n0 + nn);
        }
        __syncthreads();
        #pragma unroll
        for (int kk = 0; kk < 16; kk++) {
            const float4 av = *(const float4*)&sA[kk][ty * 4];
            const float4 wv = *(const float4*)&sW[kk][tx * 4];
            const float a[4] = {av.x, av.y, av.z, av.w};
            const float w[4] = {wv.x, wv.y, wv.z, wv.w};
            #pragma unroll
            for (int i = 0; i < 4; i++)
                #pragma unroll
                for (int j = 0; j < 4; j++)
                    acc[i][j] = fmaf(a[i], w[j], acc[i][j]);
        }
        __syncthreads();
    }
    float* cb = Cp + (size_t)z * M * N;
    #pragma unroll
    for (int i = 0; i < 4; i++)
        #pragma unroll
        for (int j = 0; j < 4; j++)
            cb[(size_t)(m0 + ty * 4 + i) * N + n0 + tx * 4 + j] = acc[i][j];
}

__global__ void combine_kernel(const float* __restrict__ Cp,
                               const float* __restrict__ bias,
                               float* __restrict__ C,
                               int MN, int N, int nsplit, int doRelu) {
    const int idx = blockIdx.x * blockDim.x + threadIdx.x;
    if (idx >= MN) return;
    float s = bias[idx % N];
    for (int z = 0; z < nsplit; z++) s += Cp[(size_t)z * MN + idx];
    if (doRelu) s = fmaxf(s, 0.0f);
    C[idx] = s;
}

// GEMM with fused bias (+optional relu), no split-K
__global__ void gemm_ep_kernel(const float* __restrict__ A,
                               const float* __restrict__ W,
                               const float* __restrict__ bias,
                               float* __restrict__ C,
                               int M, int N, int K, int doRelu) {
    __shared__ float sA[16][68];
    __shared__ float sW[16][68];
    const int m0 = blockIdx.x * 64;
    const int n0 = blockIdx.y * 64;
    const int tid = threadIdx.x;
    const int tx = tid & 15, ty = tid >> 4;
    float acc[4][4] = {};
    for (int k0 = 0; k0 < K; k0 += 16) {
        {
            const int mm = tid >> 2;
            const int kk = (tid & 3) * 4;
            const float4 av = *(const float4*)(A + (size_t)(m0 + mm) * K + k0 + kk);
            sA[kk + 0][mm] = av.x; sA[kk + 1][mm] = av.y;
            sA[kk + 2][mm] = av.z; sA[kk + 3][mm] = av.w;
        }
        {
            const int kk = tid >> 4;
            const int nn = (tid & 15) * 4;
            *(float4*)&sW[kk][nn] = *(const float4*)(W + (size_t)(k0 + kk) * N + n0 + nn);
        }
        __syncthreads();
        #pragma unroll
        for (int kk = 0; kk < 16; kk++) {
            const float4 av = *(const float4*)&sA[kk][ty * 4];
            const float4 wv = *(const float4*)&sW[kk][tx * 4];
            const float a[4] = {av.x, av.y, av.z, av.w};
            const float w[4] = {wv.x, wv.y, wv.z, wv.w};
            #pragma unroll
            for (int i = 0; i < 4; i++)
                #pragma unroll
                for (int j = 0; j < 4; j++)
                    acc[i][j] = fmaf(a[i], w[j], acc[i][j]);
        }
        __syncthreads();
    }
    #pragma unroll
    for (int i = 0; i < 4; i++)
        #pragma unroll
        for (int j = 0; j < 4; j++) {
            float v = acc[i][j] + bias[n0 + tx * 4 + j];
            if (doRelu) v = fmaxf(v, 0.0f);
            C[(size_t)(m0 + ty * 4 + i) * N + n0 + tx * 4 + j] = v;
        }
}

// ---------------------------------------------------------------------------
// c_y[b] = hp[b,:] . pw2 + pb2
// ---------------------------------------------------------------------------
__global__ void cy_kernel(const float* __restrict__ hp,
                          const float* __restrict__ pw2,
                          const float* __restrict__ pb2,
                          float* __restrict__ cy) {
    const int gw = (blockIdx.x * blockDim.x + threadIdx.x) >> 5;
    const int lane = threadIdx.x & 31;
    if (gw >= 512) return;
    float s = 0.0f;
    for (int k = lane; k < 256; k += 32) s = fmaf(hp[(size_t)gw * 256 + k], pw2[k], s);
    #pragma unroll
    for (int off = 16; off > 0; off >>= 1) s += __shfl_xor_sync(0xffffffffu, s, off);
    if (lane == 0) cy[gw] = s + pb2[0];
}

// ---------------------------------------------------------------------------
// row i: logits[i,j] = cy[j] - mrn(phi_x[i], phi_y[j]) -> lse_i, diag_i
// ---------------------------------------------------------------------------
__global__ void logits_kernel(const float* __restrict__ phi,
                              const float* __restrict__ cy,
                              float* __restrict__ lse,
                              float* __restrict__ diag) {
    const int i = blockIdx.x;
    __shared__ float sx[64];
    __shared__ float red[256];
    __shared__ float sdiag;
    const int tid = threadIdx.x;
    if (tid < 64) sx[tid] = phi[(size_t)i * 64 + tid];
    __syncthreads();
    float lg[2];
    #pragma unroll
    for (int r = 0; r < 2; r++) {
        const int j = tid + r * 256;
        const float* y = phi + (size_t)(512 + j) * 64;
        float mx = 0.0f;
        #pragma unroll
        for (int k = 0; k < 32; k++) {
            float d = sx[k] - y[k];
            mx = fmaxf(mx, fmaxf(d, 0.0f));
        }
        float ss = 0.0f;
        #pragma unroll
        for (int k = 32; k < 64; k++) {
            float d = sx[k] - y[k];
            ss = fmaf(d, d, ss);
        }
        lg[r] = cy[j] - (mx + sqrtf(ss + 1e-8f));
        if (j == i) sdiag = lg[r];
    }
    red[tid] = fmaxf(lg[0], lg[1]);
    __syncthreads();
    for (int s = 128; s > 0; s >>= 1) {
        if (tid < s) red[tid] = fmaxf(red[tid], red[tid + s]);
        __syncthreads();
    }
    const float rowmax = red[0];
    __syncthreads();
    red[tid] = expf(lg[0] - rowmax) + expf(lg[1] - rowmax);
    __syncthreads();
    for (int s = 128; s > 0; s >>= 1) {
        if (tid < s) red[tid] += red[tid + s];
        __syncthreads();
    }
    if (tid == 0) {
        lse[i] = rowmax + logf(red[0]);
        diag[i] = sdiag;
    }
}

__global__ void loss_kernel(const float* __restrict__ lse,
                            const float* __restrict__ diag,
                            float* __restrict__ out) {
    __shared__ float r1[256], r2[256];
    const int tid = threadIdx.x;
    float s1 = 0.0f, s2 = 0.0f;
    for (int i = tid; i < 512; i += 256) {
        const float l = lse[i];
        s1 += l - diag[i];
        const float u = l + 1e-6f;
        s2 = fmaf(u, u, s2);
    }
    r1[tid] = s1; r2[tid] = s2;
    __syncthreads();
    for (int s = 128; s > 0; s >>= 1) {
        if (tid < s) { r1[tid] += r1[tid + s]; r2[tid] += r2[tid + s]; }
        __syncthreads();
    }
    if (tid == 0)
        out[0] = r1[0] * (1.0f / 512.0f) + 0.1f * r2[0] * (1.0f / 512.0f);
}

// ---------------------------------------------------------------------------
// Host launcher
// ---------------------------------------------------------------------------
extern "C" void kernel_launch(void* const* d_in, const int* in_sizes, int n_in,
                              void* d_out, int out_size) {
    const float* curr = (const float*)d_in[0];
    const float* next = (const float*)d_in[1];
    const float* c1w = (const float*)d_in[2];
    const float* c1b = (const float*)d_in[3];
    const float* c2w = (const float*)d_in[4];
    const float* c2b = (const float*)d_in[5];
    const float* c3w = (const float*)d_in[6];
    const float* c3b = (const float*)d_in[7];
    const float* fcw = (const float*)d_in[8];
    const float* fcb = (const float*)d_in[9];
    const float* e1w = (const float*)d_in[10];
    const float* e1b = (const float*)d_in[11];
    const float* e2w = (const float*)d_in[12];
    const float* e2b = (const float*)d_in[13];
    const float* pw1 = (const float*)d_in[14];
    const float* pb1 = (const float*)d_in[15];
    const float* pw2 = (const float*)d_in[16];
    const float* pb2 = (const float*)d_in[17];

    float *p_w1t, *p_w2t, *p_w3t, *p_a1, *p_a2, *p_feat, *p_f, *p_h1, *p_phi,
          *p_hp, *p_cy, *p_lse, *p_diag, *p_part;
    cudaGetSymbolAddress((void**)&p_w1t, g_w1t);
    cudaGetSymbolAddress((void**)&p_w2t, g_w2t);
    cudaGetSymbolAddress((void**)&p_w3t, g_w3t);
    cudaGetSymbolAddress((void**)&p_a1, g_a1);
    cudaGetSymbolAddress((void**)&p_a2, g_a2);
    cudaGetSymbolAddress((void**)&p_feat, g_feat);
    cudaGetSymbolAddress((void**)&p_f, g_f);
    cudaGetSymbolAddress((void**)&p_h1, g_h1);
    cudaGetSymbolAddress((void**)&p_phi, g_phi);
    cudaGetSymbolAddress((void**)&p_hp, g_hp);
    cudaGetSymbolAddress((void**)&p_cy, g_cy);
    cudaGetSymbolAddress((void**)&p_lse, g_lse);
    cudaGetSymbolAddress((void**)&p_diag, g_diag);
    cudaGetSymbolAddress((void**)&p_part, g_part);

    const int SM1 = (8064 + 8192) * 4;
    const int SM2 = (12800 + 8192) * 4;
    const int SM3 = (6912 + 18432) * 4;
    cudaFuncSetAttribute(conv1_kernel, cudaFuncAttributeMaxDynamicSharedMemorySize, SM1);
    cudaFuncSetAttribute(conv2_kernel, cudaFuncAttributeMaxDynamicSharedMemorySize, SM2);
    cudaFuncSetAttribute(conv3_kernel, cudaFuncAttributeMaxDynamicSharedMemorySize, SM3);

    // weight transposes
    transpose_kernel<<<32, 256>>>(c1w, p_w1t, 32, 256);
    transpose_kernel<<<128, 256>>>(c2w, p_w2t, 64, 512);
    transpose_kernel<<<144, 256>>>(c3w, p_w3t, 64, 576);

    // convs over both observations (img 0..511 curr, 512..1023 next)
    conv1_kernel<<<dim3(NIMG, 4), 256, SM1>>>(curr, next, p_w1t, c1b, p_a1);
    conv2_kernel<<<dim3(NIMG, 4), 96, SM2>>>(p_a1, p_w2t, c2b, p_a2);
    conv3_kernel<<<dim3(NIMG, 2), 128, SM3>>>(p_a2, p_w3t, c3b, p_feat);

    // fc: [1024,3136]@[3136,256]+b, relu; split-K 8 (kChunk 400)
    gemm_part_kernel<<<dim3(16, 4, 8), 256>>>(p_feat, fcw, p_part, 1024, 256, 3136, 400);
    combine_kernel<<<(1024 * 256 + 255) / 256, 256>>>(p_part, fcb, p_f, 1024 * 256, 256, 8, 1);

    // heads (fused bias/relu epilogue)
    gemm_ep_kernel<<<dim3(16, 4), 256>>>(p_f, e1w, e1b, p_h1, 1024, 256, 256, 1);
    gemm_ep_kernel<<<dim3(16, 1), 256>>>(p_h1, e2w, e2b, p_phi, 1024, 64, 256, 0);
    gemm_ep_kernel<<<dim3(8, 4), 256>>>(p_f + (size_t)512 * 256, pw1, pb1, p_hp, 512, 256, 256, 1);

    cy_kernel<<<64, 256>>>(p_hp, pw2, pb2, p_cy);
    logits_kernel<<<512, 256>>>(p_phi, p_cy, p_lse, p_diag);
    loss_kernel<<<1, 256>>>(p_lse, p_diag, (float*)d_out);
}

// round 3
// speedup vs baseline: 2.4303x; 1.7764x over previous
#include <cuda_runtime.h>
#include <math.h>

#define NIMG 1024

// ---------------------------------------------------------------------------
// scratch
// ---------------------------------------------------------------------------
__device__ __align__(128) float g_w1f[8192];                  // conv1 frag weights (tf32)
__device__ __align__(128) float g_w2f[32768];                 // conv2
__device__ __align__(128) float g_w3f[36864];                 // conv3
__device__ __align__(128) float g_a1[(size_t)NIMG*32*400];    // conv1 out NCHW
__device__ __align__(128) float g_a2n[(size_t)NIMG*81*64];    // conv2 out NHWC
__device__ __align__(128) float g_feat[(size_t)NIMG*3136];    // conv3 out, flat (oc*49+px)
__device__ __align__(128) float g_f[NIMG*256];
__device__ __align__(128) float g_h1[NIMG*256];
__device__ __align__(128) float g_phi[NIMG*64];
__device__ __align__(128) float g_hp[512*256];
__device__ __align__(128) float g_cy[512];
__device__ __align__(128) float g_lse[512];
__device__ __align__(128) float g_diag[512];
__device__ __align__(128) float g_part[8*1024*256];

// ---------------------------------------------------------------------------
// tf32 helpers
// ---------------------------------------------------------------------------
__device__ __forceinline__ unsigned f2tf(float f) {
    unsigned u;
    asm("cvt.rna.tf32.f32 %0, %1;" : "=r"(u) : "f"(f));
    return u;
}
__device__ __forceinline__ void mma8(float* d, const unsigned* a, const unsigned* b) {
    asm volatile(
        "mma.sync.aligned.m16n8k8.row.col.f32.tf32.tf32.f32 "
        "{%0,%1,%2,%3}, {%4,%5,%6,%7}, {%8,%9}, {%0,%1,%2,%3};\n"
        : "+f"(d[0]), "+f"(d[1]), "+f"(d[2]), "+f"(d[3])
        : "r"(a[0]), "r"(a[1]), "r"(a[2]), "r"(a[3]), "r"(b[0]), "r"(b[1]));
}

// ---------------------------------------------------------------------------
// weight prep: frag layout wf[(chunk*NT + nt)*64 + lane*2 + s] =
//   tf32( W[k = chunk*8 + s*4 + lane%4][n = nt*8 + lane/4] )
// ---------------------------------------------------------------------------
__global__ void prep1(const float* __restrict__ w, float* __restrict__ wf) {
    int i = blockIdx.x * 256 + threadIdx.x;
    if (i >= 8192) return;
    int s = i & 1, lane = (i >> 1) & 31;
    int cn = i >> 6, nt = cn & 3, chunk = cn >> 2;
    int k = chunk * 8 + s * 4 + (lane & 3);
    int n = nt * 8 + (lane >> 2);
    int ic = k >> 6, ky = (k >> 3) & 7, kx = k & 7;
    wf[i] = __uint_as_float(f2tf(w[((n * 4 + ic) * 8 + ky) * 8 + kx]));
}
__global__ void prep2(const float* __restrict__ w, float* __restrict__ wf) {
    int i = blockIdx.x * 256 + threadIdx.x;
    if (i >= 32768) return;
    int s = i & 1, lane = (i >> 1) & 31;
    int cn = i >> 6, nt = cn & 7, chunk = cn >> 3;
    int k = chunk * 8 + s * 4 + (lane & 3);
    int n = nt * 8 + (lane >> 2);
    int ic = k >> 4, ky = (k >> 2) & 3, kx = k & 3;
    wf[i] = __uint_as_float(f2tf(w[((n * 32 + ic) * 4 + ky) * 4 + kx]));
}
__global__ void prep3(const float* __restrict__ w, float* __restrict__ wf) {
    int i = blockIdx.x * 256 + threadIdx.x;
    if (i >= 36864) return;
    int s = i & 1, lane = (i >> 1) & 31;
    int cn = i >> 6, nt = cn & 7, chunk = cn >> 3;
    int p = chunk >> 3, icc = chunk & 7;
    int ic = icc * 8 + s * 4 + (lane & 3);
    int n = nt * 8 + (lane >> 2);
    int ky = p / 3, kx = p % 3;
    wf[i] = __uint_as_float(f2tf(w[((n * 64 + ic) * 3 + ky) * 3 + kx]));
}

// ---------------------------------------------------------------------------
// conv1 (tf32 mma): 4ch 84x84 -> 32ch 20x20, k8 s4, relu. NCHW out.
// grid (1024, 5 oy-groups of 4), 160 thr (5 warps = 5 m16-tiles of M=80).
// K = 256 (32 chunks of 8: chunk = ic*8+ky, col = kx). N = 32 (4 n-tiles).
// ---------------------------------------------------------------------------
__global__ void conv1_mma(const float* __restrict__ curr,
                          const float* __restrict__ next,
                          const float* __restrict__ wf,
                          const float* __restrict__ bias,
                          float* __restrict__ out) {
    extern __shared__ float sm[];
    float* simg = sm;         // 4ch * 20rows * 84 = 6720
    float* swf  = sm + 6720;  // 8192
    const int img = blockIdx.x, oyg = blockIdx.y;
    const float* in = (img < 512) ? curr + (size_t)img * 28224
                                  : next + (size_t)(img - 512) * 28224;
    const int iy0 = oyg * 16;
    for (int i = threadIdx.x; i < 1680; i += 160) {
        int e = i * 4, ic = e / 1680, rem = e % 1680;
        *(float4*)&simg[e] = *(const float4*)&in[ic * 7056 + iy0 * 84 + rem];
    }
    for (int i = threadIdx.x; i < 2048; i += 160)
        *(float4*)&swf[i * 4] = *(const float4*)&wf[i * 4];
    __syncthreads();

    const int lane = threadIdx.x & 31, wid = threadIdx.x >> 5;
    const int r0 = wid * 16 + (lane >> 2), r1 = r0 + 8;
    const int ab0 = (r0 / 20) * 336 + (r0 % 20) * 4 + (lane & 3);
    const int ab1 = (r1 / 20) * 336 + (r1 % 20) * 4 + (lane & 3);

    float acc[4][4];
    #pragma unroll
    for (int nt = 0; nt < 4; nt++) {
        int oc = nt * 8 + (lane & 3) * 2;
        float b0 = bias[oc], b1 = bias[oc + 1];
        acc[nt][0] = b0; acc[nt][1] = b1; acc[nt][2] = b0; acc[nt][3] = b1;
    }
    #pragma unroll
    for (int ic = 0; ic < 4; ic++) {
        #pragma unroll
        for (int ky = 0; ky < 8; ky++) {
            const int base = ic * 1680 + ky * 84;
            unsigned a[4];
            a[0] = f2tf(simg[base + ab0]);
            a[1] = f2tf(simg[base + ab1]);
            a[2] = f2tf(simg[base + ab0 + 4]);
            a[3] = f2tf(simg[base + ab1 + 4]);
            const float* wb = swf + (ic * 8 + ky) * 256 + lane * 2;
            #pragma unroll
            for (int nt = 0; nt < 4; nt++) {
                float2 bv = *(const float2*)&wb[nt * 64];
                unsigned b[2] = {__float_as_uint(bv.x), __float_as_uint(bv.y)};
                mma8(acc[nt], a, b);
            }
        }
    }
    const size_t ob = (size_t)img * 12800 + oyg * 80;
    #pragma unroll
    for (int nt = 0; nt < 4; nt++) {
        int oc = nt * 8 + (lane & 3) * 2;
        float* p0 = out + ob + (size_t)oc * 400;
        p0[r0]       = fmaxf(acc[nt][0], 0.0f);
        p0[400 + r0] = fmaxf(acc[nt][1], 0.0f);
        p0[r1]       = fmaxf(acc[nt][2], 0.0f);
        p0[400 + r1] = fmaxf(acc[nt][3], 0.0f);
    }
}

// ---------------------------------------------------------------------------
// conv2 (tf32 mma): 32ch 20x20 -> 64ch 9x9, k4 s2, relu. NHWC out.
// grid (1024, 4 oc-quarters of 16), 192 thr (6 warps = 6 m16-tiles, M=81).
// K = 512 (64 chunks: chunk = ic*2+h; cols 0-3: ky=2h,kx=c; 4-7: ky=2h+1).
// ---------------------------------------------------------------------------
__global__ void conv2_mma(const float* __restrict__ a1,
                          const float* __restrict__ wf,
                          const float* __restrict__ bias,
                          float* __restrict__ out) {
    extern __shared__ float sm[];
    float* sin = sm;           // 12800
    float* swf = sm + 12800;   // 8192 (quarter)
    const int img = blockIdx.x, q = blockIdx.y;
    const float* ib = a1 + (size_t)img * 12800;
    for (int i = threadIdx.x; i < 3200; i += 192)
        *(float4*)&sin[i * 4] = *(const float4*)&ib[i * 4];
    for (int i = threadIdx.x; i < 2048; i += 192) {
        int e = i * 4;
        int cn = e >> 6, off = e & 63;
        int chunk = cn >> 1, ntl = cn & 1;
        *(float4*)&swf[e] = *(const float4*)&wf[((chunk * 8) + (q * 2 + ntl)) * 64 + off];
    }
    __syncthreads();

    const int lane = threadIdx.x & 31, wid = threadIdx.x >> 5;
    const int r0 = wid * 16 + (lane >> 2), r1 = r0 + 8;
    const int p0 = (r0 < 81) ? r0 : 80, p1 = (r1 < 81) ? r1 : 80;
    const int t0 = (p0 / 9) * 40 + (p0 % 9) * 2 + (lane & 3);
    const int t1 = (p1 / 9) * 40 + (p1 % 9) * 2 + (lane & 3);

    float acc[2][4];
    #pragma unroll
    for (int nt = 0; nt < 2; nt++) {
        int oc = q * 16 + nt * 8 + (lane & 3) * 2;
        float b0 = bias[oc], b1 = bias[oc + 1];
        acc[nt][0] = b0; acc[nt][1] = b1; acc[nt][2] = b0; acc[nt][3] = b1;
    }
    for (int ic = 0; ic < 32; ic++) {
        #pragma unroll
        for (int h = 0; h < 2; h++) {
            const int base = ic * 400 + h * 40;
            unsigned a[4];
            a[0] = f2tf(sin[base + t0]);
            a[1] = f2tf(sin[base + t1]);
            a[2] = f2tf(sin[base + 20 + t0]);
            a[3] = f2tf(sin[base + 20 + t1]);
            const float* wb = swf + (ic * 2 + h) * 128 + lane * 2;
            #pragma unroll
            for (int nt = 0; nt < 2; nt++) {
                float2 bv = *(const float2*)&wb[nt * 64];
                unsigned b[2] = {__float_as_uint(bv.x), __float_as_uint(bv.y)};
                mma8(acc[nt], a, b);
            }
        }
    }
    #pragma unroll
    for (int nt = 0; nt < 2; nt++) {
        int oc = q * 16 + nt * 8 + (lane & 3) * 2;
        if (r0 < 81)
            *(float2*)&out[((size_t)img * 81 + r0) * 64 + oc] =
                make_float2(fmaxf(acc[nt][0], 0.0f), fmaxf(acc[nt][1], 0.0f));
        if (r1 < 81)
            *(float2*)&out[((size_t)img * 81 + r1) * 64 + oc] =
                make_float2(fmaxf(acc[nt][2], 0.0f), fmaxf(acc[nt][3], 0.0f));
    }
}

// ---------------------------------------------------------------------------
// conv3 (tf32 mma): 64ch 9x9 -> 64ch 7x7, k3 s1, relu. Flat out (oc*49+px).
// 2 images per block (M = 98, 7 m16-tiles), grid (512, 4 oc-quarters of 16),
// 224 thr. K decomposed: 9 spatial positions x 8 ic-chunks = 72 chunks.
// Input NHWC, smem rows padded 64->68 for conflict-free ic loads.
// ---------------------------------------------------------------------------
__global__ void conv3_mma(const float* __restrict__ a2n,
                          const float* __restrict__ wf,
                          const float* __restrict__ bias,
                          float* __restrict__ feat) {
    extern __shared__ float sm[];
    float* sin = sm;            // 2 * 81 * 68 = 11016
    float* swf = sm + 11016;    // 72*2*64 = 9216 (quarter)
    const int q = blockIdx.y;
    const int imgb = blockIdx.x * 2;
    for (int j = threadIdx.x; j < 2592; j += 224) {
        int im = j / 1296, rj = j % 1296;
        int px = rj / 16, off = (rj % 16) * 4;
        *(float4*)&sin[im * 5508 + px * 68 + off] =
            *(const float4*)&a2n[((size_t)(imgb + im) * 81 + px) * 64 + off];
    }
    for (int i = threadIdx.x; i < 2304; i += 224) {
        int e = i * 4;
        int cn = e >> 6, off = e & 63;
        int chunk = cn >> 1, ntl = cn & 1;
        *(float4*)&swf[e] = *(const float4*)&wf[((chunk * 8) + (q * 2 + ntl)) * 64 + off];
    }
    __syncthreads();

    const int lane = threadIdx.x & 31, wid = threadIdx.x >> 5;
    const int r0 = wid * 16 + (lane >> 2), r1 = r0 + 8;
    const int g0 = (r0 < 98) ? r0 : 97, g1 = (r1 < 98) ? r1 : 97;
    const int im0 = g0 / 49, lp0 = g0 % 49;
    const int im1 = g1 / 49, lp1 = g1 % 49;
    const int A0 = im0 * 5508 + ((lp0 / 7) * 9 + lp0 % 7) * 68 + (lane & 3);
    const int A1 = im1 * 5508 + ((lp1 / 7) * 9 + lp1 % 7) * 68 + (lane & 3);

    float acc[2][4];
    #pragma unroll
    for (int nt = 0; nt < 2; nt++) {
        int oc = q * 16 + nt * 8 + (lane & 3) * 2;
        float b0 = bias[oc], b1 = bias[oc + 1];
        acc[nt][0] = b0; acc[nt][1] = b1; acc[nt][2] = b0; acc[nt][3] = b1;
    }
    #pragma unroll
    for (int p = 0; p < 9; p++) {
        const int rowoff = ((p / 3) * 9 + (p % 3)) * 68;
        #pragma unroll
        for (int icc = 0; icc < 8; icc++) {
            unsigned a[4];
            a[0] = f2tf(sin[A0 + rowoff + icc * 8]);
            a[1] = f2tf(sin[A1 + rowoff + icc * 8]);
            a[2] = f2tf(sin[A0 + rowoff + icc * 8 + 4]);
            a[3] = f2tf(sin[A1 + rowoff + icc * 8 + 4]);
            const float* wb = swf + (p * 8 + icc) * 128 + lane * 2;
            #pragma unroll
            for (int nt = 0; nt < 2; nt++) {
                float2 bv = *(const float2*)&wb[nt * 64];
                unsigned b[2] = {__float_as_uint(bv.x), __float_as_uint(bv.y)};
                mma8(acc[nt], a, b);
            }
        }
    }
    #pragma unroll
    for (int nt = 0; nt < 2; nt++) {
        int oc = q * 16 + nt * 8 + (lane & 3) * 2;
        if (r0 < 98) {
            float* fb = feat + (size_t)(imgb + im0) * 3136 + oc * 49 + lp0;
            fb[0]  = fmaxf(acc[nt][0], 0.0f);
            fb[49] = fmaxf(acc[nt][1], 0.0f);
        }
        if (r1 < 98) {
            float* fb = feat + (size_t)(imgb + im1) * 3136 + oc * 49 + lp1;
            fb[0]  = fmaxf(acc[nt][2], 0.0f);
            fb[49] = fmaxf(acc[nt][3], 0.0f);
        }
    }
}

// ---------------------------------------------------------------------------
// fp32 tiled GEMMs (fc split-K + heads) — unchanged from round 2
// ---------------------------------------------------------------------------
__global__ void gemm_part_kernel(const float* __restrict__ A,
                                 const float* __restrict__ W,
                                 float* __restrict__ Cp,
                                 int M, int N, int K, int kChunk) {
    __shared__ float sA[16][68];
    __shared__ float sW[16][68];
    const int m0 = blockIdx.x * 64;
    const int n0 = blockIdx.y * 64;
    const int z  = blockIdx.z;
    int k0beg = z * kChunk;
    int k0end = k0beg + kChunk; if (k0end > K) k0end = K;
    const int tid = threadIdx.x;
    const int tx = tid & 15, ty = tid >> 4;
    float acc[4][4] = {};
    for (int k0 = k0beg; k0 < k0end; k0 += 16) {
        {
            const int mm = tid >> 2;
            const int kk = (tid & 3) * 4;
            const float4 av = *(const float4*)(A + (size_t)(m0 + mm) * K + k0 + kk);
            sA[kk + 0][mm] = av.x; sA[kk + 1][mm] = av.y;
            sA[kk + 2][mm] = av.z; sA[kk + 3][mm] = av.w;
        }
        {
            const int kk = tid >> 4;
            const int nn = (tid & 15) * 4;
            *(float4*)&sW[kk][nn] = *(const float4*)(W + (size_t)(k0 + kk) * N + n0 + nn);
        }
        __syncthreads();
        #pragma unroll
        for (int kk = 0; kk < 16; kk++) {
            const float4 av = *(const float4*)&sA[kk][ty * 4];
            const float4 wv = *(const float4*)&sW[kk][tx * 4];
            const float a[4] = {av.x, av.y, av.z, av.w};
            const float w[4] = {wv.x, wv.y, wv.z, wv.w};
            #pragma unroll
            for (int i = 0; i < 4; i++)
                #pragma unroll
                for (int j = 0; j < 4; j++)
                    acc[i][j] = fmaf(a[i], w[j], acc[i][j]);
        }
        __syncthreads();
    }
    float* cb = Cp + (size_t)z * M * N;
    #pragma unroll
    for (int i = 0; i < 4; i++)
        #pragma unroll
        for (int j = 0; j < 4; j++)
            cb[(size_t)(m0 + ty * 4 + i) * N + n0 + tx * 4 + j] = acc[i][j];
}

__global__ void combine_kernel(const float* __restrict__ Cp,
                               const float* __restrict__ bias,
                               float* __restrict__ C,
                               int MN, int N, int nsplit, int doRelu) {
    const int idx = blockIdx.x * blockDim.x + threadIdx.x;
    if (idx >= MN) return;
    float s = bias[idx % N];
    for (int z = 0; z < nsplit; z++) s += Cp[(size_t)z * MN + idx];
    if (doRelu) s = fmaxf(s, 0.0f);
    C[idx] = s;
}

__global__ void gemm_ep_kernel(const float* __restrict__ A,
                               const float* __restrict__ W,
                               const float* __restrict__ bias,
                               float* __restrict__ C,
                               int M, int N, int K, int doRelu) {
    __shared__ float sA[16][68];
    __shared__ float sW[16][68];
    const int m0 = blockIdx.x * 64;
    const int n0 = blockIdx.y * 64;
    const int tid = threadIdx.x;
    const int tx = tid & 15, ty = tid >> 4;
    float acc[4][4] = {};
    for (int k0 = 0; k0 < K; k0 += 16) {
        {
            const int mm = tid >> 2;
            const int kk = (tid & 3) * 4;
            const float4 av = *(const float4*)(A + (size_t)(m0 + mm) * K + k0 + kk);
            sA[kk + 0][mm] = av.x; sA[kk + 1][mm] = av.y;
            sA[kk + 2][mm] = av.z; sA[kk + 3][mm] = av.w;
        }
        {
            const int kk = tid >> 4;
            const int nn = (tid & 15) * 4;
            *(float4*)&sW[kk][nn] = *(const float4*)(W + (size_t)(k0 + kk) * N + n0 + nn);
        }
        __syncthreads();
        #pragma unroll
        for (int kk = 0; kk < 16; kk++) {
            const float4 av = *(const float4*)&sA[kk][ty * 4];
            const float4 wv = *(const float4*)&sW[kk][tx * 4];
            const float a[4] = {av.x, av.y, av.z, av.w};
            const float w[4] = {wv.x, wv.y, wv.z, wv.w};
            #pragma unroll
            for (int i = 0; i < 4; i++)
                #pragma unroll
                for (int j = 0; j < 4; j++)
                    acc[i][j] = fmaf(a[i], w[j], acc[i][j]);
        }
        __syncthreads();
    }
    #pragma unroll
    for (int i = 0; i < 4; i++)
        #pragma unroll
        for (int j = 0; j < 4; j++) {
            float v = acc[i][j] + bias[n0 + tx * 4 + j];
            if (doRelu) v = fmaxf(v, 0.0f);
            C[(size_t)(m0 + ty * 4 + i) * N + n0 + tx * 4 + j] = v;
        }
}

// ---------------------------------------------------------------------------
// c_y / logits / loss (unchanged)
// ---------------------------------------------------------------------------
__global__ void cy_kernel(const float* __restrict__ hp,
                          const float* __restrict__ pw2,
                          const float* __restrict__ pb2,
                          float* __restrict__ cy) {
    const int gw = (blockIdx.x * blockDim.x + threadIdx.x) >> 5;
    const int lane = threadIdx.x & 31;
    if (gw >= 512) return;
    float s = 0.0f;
    for (int k = lane; k < 256; k += 32) s = fmaf(hp[(size_t)gw * 256 + k], pw2[k], s);
    #pragma unroll
    for (int off = 16; off > 0; off >>= 1) s += __shfl_xor_sync(0xffffffffu, s, off);
    if (lane == 0) cy[gw] = s + pb2[0];
}

__global__ void logits_kernel(const float* __restrict__ phi,
                              const float* __restrict__ cy,
                              float* __restrict__ lse,
                              float* __restrict__ diag) {
    const int i = blockIdx.x;
    __shared__ float sx[64];
    __shared__ float red[256];
    __shared__ float sdiag;
    const int tid = threadIdx.x;
    if (tid < 64) sx[tid] = phi[(size_t)i * 64 + tid];
    __syncthreads();
    float lg[2];
    #pragma unroll
    for (int r = 0; r < 2; r++) {
        const int j = tid + r * 256;
        const float* y = phi + (size_t)(512 + j) * 64;
        float mx = 0.0f;
        #pragma unroll
        for (int k = 0; k < 32; k++) {
            float d = sx[k] - y[k];
            mx = fmaxf(mx, fmaxf(d, 0.0f));
        }
        float ss = 0.0f;
        #pragma unroll
        for (int k = 32; k < 64; k++) {
            float d = sx[k] - y[k];
            ss = fmaf(d, d, ss);
        }
        lg[r] = cy[j] - (mx + sqrtf(ss + 1e-8f));
        if (j == i) sdiag = lg[r];
    }
    red[tid] = fmaxf(lg[0], lg[1]);
    __syncthreads();
    for (int s = 128; s > 0; s >>= 1) {
        if (tid < s) red[tid] = fmaxf(red[tid], red[tid + s]);
        __syncthreads();
    }
    const float rowmax = red[0];
    __syncthreads();
    red[tid] = expf(lg[0] - rowmax) + expf(lg[1] - rowmax);
    __syncthreads();
    for (int s = 128; s > 0; s >>= 1) {
        if (tid < s) red[tid] += red[tid + s];
        __syncthreads();
    }
    if (tid == 0) {
        lse[i] = rowmax + logf(red[0]);
        diag[i] = sdiag;
    }
}

__global__ void loss_kernel(const float* __restrict__ lse,
                            const float* __restrict__ diag,
                            float* __restrict__ out) {
    __shared__ float r1[256], r2[256];
    const int tid = threadIdx.x;
    float s1 = 0.0f, s2 = 0.0f;
    for (int i = tid; i < 512; i += 256) {
        const float l = lse[i];
        s1 += l - diag[i];
        const float u = l + 1e-6f;
        s2 = fmaf(u, u, s2);
    }
    r1[tid] = s1; r2[tid] = s2;
    __syncthreads();
    for (int s = 128; s > 0; s >>= 1) {
        if (tid < s) { r1[tid] += r1[tid + s]; r2[tid] += r2[tid + s]; }
        __syncthreads();
    }
    if (tid == 0)
        out[0] = r1[0] * (1.0f / 512.0f) + 0.1f * r2[0] * (1.0f / 512.0f);
}

// ---------------------------------------------------------------------------
// Host launcher
// ---------------------------------------------------------------------------
extern "C" void kernel_launch(void* const* d_in, const int* in_sizes, int n_in,
                              void* d_out, int out_size) {
    const float* curr = (const float*)d_in[0];
    const float* next = (const float*)d_in[1];
    const float* c1w = (const float*)d_in[2];
    const float* c1b = (const float*)d_in[3];
    const float* c2w = (const float*)d_in[4];
    const float* c2b = (const float*)d_in[5];
    const float* c3w = (const float*)d_in[6];
    const float* c3b = (const float*)d_in[7];
    const float* fcw = (const float*)d_in[8];
    const float* fcb = (const float*)d_in[9];
    const float* e1w = (const float*)d_in[10];
    const float* e1b = (const float*)d_in[11];
    const float* e2w = (const float*)d_in[12];
    const float* e2b = (const float*)d_in[13];
    const float* pw1 = (const float*)d_in[14];
    const float* pb1 = (const float*)d_in[15];
    const float* pw2 = (const float*)d_in[16];
    const float* pb2 = (const float*)d_in[17];

    float *p_w1f, *p_w2f, *p_w3f, *p_a1, *p_a2n, *p_feat, *p_f, *p_h1, *p_phi,
          *p_hp, *p_cy, *p_lse, *p_diag, *p_part;
    cudaGetSymbolAddress((void**)&p_w1f, g_w1f);
    cudaGetSymbolAddress((void**)&p_w2f, g_w2f);
    cudaGetSymbolAddress((void**)&p_w3f, g_w3f);
    cudaGetSymbolAddress((void**)&p_a1, g_a1);
    cudaGetSymbolAddress((void**)&p_a2n, g_a2n);
    cudaGetSymbolAddress((void**)&p_feat, g_feat);
    cudaGetSymbolAddress((void**)&p_f, g_f);
    cudaGetSymbolAddress((void**)&p_h1, g_h1);
    cudaGetSymbolAddress((void**)&p_phi, g_phi);
    cudaGetSymbolAddress((void**)&p_hp, g_hp);
    cudaGetSymbolAddress((void**)&p_cy, g_cy);
    cudaGetSymbolAddress((void**)&p_lse, g_lse);
    cudaGetSymbolAddress((void**)&p_diag, g_diag);
    cudaGetSymbolAddress((void**)&p_part, g_part);

    const int SM1 = (6720 + 8192) * 4;     // 59,648
    const int SM2 = (12800 + 8192) * 4;    // 83,968
    const int SM3 = (11016 + 9216) * 4;    // 80,928
    cudaFuncSetAttribute(conv1_mma, cudaFuncAttributeMaxDynamicSharedMemorySize, SM1);
    cudaFuncSetAttribute(conv2_mma, cudaFuncAttributeMaxDynamicSharedMemorySize, SM2);
    cudaFuncSetAttribute(conv3_mma, cudaFuncAttributeMaxDynamicSharedMemorySize, SM3);

    prep1<<<32, 256>>>(c1w, p_w1f);
    prep2<<<128, 256>>>(c2w, p_w2f);
    prep3<<<144, 256>>>(c3w, p_w3f);

    conv1_mma<<<dim3(NIMG, 5), 160, SM1>>>(curr, next, p_w1f, c1b, p_a1);
    conv2_mma<<<dim3(NIMG, 4), 192, SM2>>>(p_a1, p_w2f, c2b, p_a2n);
    conv3_mma<<<dim3(NIMG / 2, 4), 224, SM3>>>(p_a2n, p_w3f, c3b, p_feat);

    // fc: [1024,3136]@[3136,256]+b, relu; split-K 8
    gemm_part_kernel<<<dim3(16, 4, 8), 256>>>(p_feat, fcw, p_part, 1024, 256, 3136, 400);
    combine_kernel<<<(1024 * 256 + 255) / 256, 256>>>(p_part, fcb, p_f, 1024 * 256, 256, 8, 1);

    // heads
    gemm_ep_kernel<<<dim3(16, 4), 256>>>(p_f, e1w, e1b, p_h1, 1024, 256, 256, 1);
    gemm_ep_kernel<<<dim3(16, 1), 256>>>(p_h1, e2w, e2b, p_phi, 1024, 64, 256, 0);
    gemm_ep_kernel<<<dim3(8, 4), 256>>>(p_f + (size_t)512 * 256, pw1, pb1, p_hp, 512, 256, 256, 1);

    cy_kernel<<<64, 256>>>(p_hp, pw2, pb2, p_cy);
    logits_kernel<<<512, 256>>>(p_phi, p_cy, p_lse, p_diag);
    loss_kernel<<<1, 256>>>(p_lse, p_diag, (float*)d_out);
}

// round 4
// speedup vs baseline: 4.3888x; 1.8059x over previous
#include <cuda_runtime.h>
#include <cuda_bf16.h>
#include <math.h>

#define NIMG 1024
typedef unsigned int u32;

// ---------------------------------------------------------------------------
// scratch
// ---------------------------------------------------------------------------
__device__ __align__(128) u32 g_w1f[16 * 4 * 64];        // 4096 conv1 frags
__device__ __align__(128) u32 g_w2f[32 * 8 * 64];        // 16384 conv2
__device__ __align__(128) u32 g_w3f[36 * 8 * 64];        // 18432 conv3
__device__ __align__(128) u32 g_wfc[196 * 32 * 64];      // 401408 fc
__device__ __align__(128) __nv_bfloat16 g_a1[(size_t)NIMG * 12800];   // conv1 out NCHW
__device__ __align__(128) __nv_bfloat16 g_a2n[(size_t)NIMG * 81 * 64]; // conv2 out NHWC
__device__ __align__(128) __nv_bfloat16 g_feat[(size_t)NIMG * 3136];  // conv3 out flat
__device__ __align__(128) float g_f[NIMG * 256];
__device__ __align__(128) float g_h1[NIMG * 256];
__device__ __align__(128) float g_phi[NIMG * 64];
__device__ __align__(128) float g_hp[512 * 256];
__device__ __align__(128) float g_cy[512];
__device__ __align__(128) float g_lse[512];
__device__ __align__(128) float g_diag[512];
__device__ __align__(128) float g_part[4 * 1024 * 256];

// ---------------------------------------------------------------------------
// helpers
// ---------------------------------------------------------------------------
__device__ __forceinline__ u32 packbf(float lo, float hi) {
    __nv_bfloat162 h = __float22bfloat162_rn(make_float2(lo, hi));
    return *reinterpret_cast<u32*>(&h);
}
__device__ __forceinline__ void mmabf(float* d, const u32* a, const u32* b) {
    asm volatile(
        "mma.sync.aligned.m16n8k16.row.col.f32.bf16.bf16.f32 "
        "{%0,%1,%2,%3},{%4,%5,%6,%7},{%8,%9},{%0,%1,%2,%3};\n"
        : "+f"(d[0]), "+f"(d[1]), "+f"(d[2]), "+f"(d[3])
        : "r"(a[0]), "r"(a[1]), "r"(a[2]), "r"(a[3]), "r"(b[0]), "r"(b[1]));
}

// ---------------------------------------------------------------------------
// weight prep: frag layout wf[(c*NT+nt)*64 + lane*2 + s] = bf16x2 of
//   W[k = c*16 + s*8 + 2*(lane&3) (+1)][n = nt*8 + lane/4]
// ---------------------------------------------------------------------------
__global__ void prep1(const float* __restrict__ w, u32* __restrict__ wf) {
    int i = blockIdx.x * 256 + threadIdx.x;
    if (i >= 4096) return;
    int s = i & 1, lane = (i >> 1) & 31;
    int cn = i >> 6, nt = cn & 3, c = cn >> 2;
    int t = lane & 3, g = lane >> 2;
    int n = nt * 8 + g;
    int ic = c >> 2, ky = (c & 3) * 2 + s, kx = 2 * t;
    const float* base = w + ((n * 4 + ic) * 8 + ky) * 8 + kx;
    wf[i] = packbf(base[0], base[1]);
}
__global__ void prep2(const float* __restrict__ w, u32* __restrict__ wf) {
    int i = blockIdx.x * 256 + threadIdx.x;
    if (i >= 16384) return;
    int s = i & 1, lane = (i >> 1) & 31;
    int cn = i >> 6, nt = cn & 7, ic = cn >> 3;
    int t = lane & 3, g = lane >> 2;
    int n = nt * 8 + g;
    int ky = s * 2 + (t >> 1), kx = (t & 1) * 2;
    const float* base = w + ((n * 32 + ic) * 4 + ky) * 4 + kx;
    wf[i] = packbf(base[0], base[1]);
}
__global__ void prep3(const float* __restrict__ w, u32* __restrict__ wf) {
    int i = blockIdx.x * 256 + threadIdx.x;
    if (i >= 18432) return;
    int s = i & 1, lane = (i >> 1) & 31;
    int cn = i >> 6, nt = cn & 7, c = cn >> 3;
    int t = lane & 3, g = lane >> 2;
    int n = nt * 8 + g;
    int p = c >> 2, icc = c & 3;
    int ic = icc * 16 + s * 8 + 2 * t;
    int ky = p / 3, kx = p % 3;
    float lo = w[((n * 64 + ic) * 3 + ky) * 3 + kx];
    float hi = w[((n * 64 + ic + 1) * 3 + ky) * 3 + kx];
    wf[i] = packbf(lo, hi);
}
__global__ void prepfc(const float* __restrict__ w, u32* __restrict__ wf) {
    int i = blockIdx.x * 256 + threadIdx.x;
    if (i >= 401408) return;
    int s = i & 1, lane = (i >> 1) & 31;
    int cn = i >> 6, nt = cn & 31, c = cn >> 5;
    int t = lane & 3, g = lane >> 2;
    int n = nt * 8 + g;
    int k0 = c * 16 + s * 8 + 2 * t;
    wf[i] = packbf(w[(size_t)k0 * 256 + n], w[(size_t)(k0 + 1) * 256 + n]);
}

// ---------------------------------------------------------------------------
// conv1 (bf16 mma): 4ch 84x84 -> 32ch 20x20, k8 s4, relu. bf16 NCHW out.
// grid (1024, 5), 160 thr. K=256 = 16 chunks (c: ic=c>>2, ky pair=(c&3)*2).
// ---------------------------------------------------------------------------
__global__ void conv1_mma(const float* __restrict__ curr,
                          const float* __restrict__ next,
                          const u32* __restrict__ wfu,
                          const float* __restrict__ bias,
                          __nv_bfloat16* __restrict__ out) {
    extern __shared__ char smc[];
    __nv_bfloat16* simg = (__nv_bfloat16*)smc;     // 6720 bf16
    u32* swf = (u32*)(smc + 13440);                 // 4096 u32
    const int img = blockIdx.x, oyg = blockIdx.y;
    const int iy0 = oyg * 16;
    const float* in = (img < 512) ? curr + (size_t)img * 28224
                                  : next + (size_t)(img - 512) * 28224;
    for (int i = threadIdx.x; i < 1680; i += 160) {
        int e = i * 4, ic = e / 1680, rem = e % 1680;
        float4 v = *(const float4*)&in[ic * 7056 + iy0 * 84 + rem];
        u32* d = (u32*)&simg[e];
        d[0] = packbf(v.x, v.y);
        d[1] = packbf(v.z, v.w);
    }
    for (int i = threadIdx.x; i < 1024; i += 160)
        ((uint4*)swf)[i] = ((const uint4*)wfu)[i];
    __syncthreads();

    const int lane = threadIdx.x & 31, wid = threadIdx.x >> 5;
    const int t = lane & 3;
    const int r0 = wid * 16 + (lane >> 2), r1 = r0 + 8;
    const int base0 = (r0 / 20) * 336 + (r0 % 20) * 4 + 2 * t;
    const int base1 = (r1 / 20) * 336 + (r1 % 20) * 4 + 2 * t;

    float acc[4][4];
    #pragma unroll
    for (int nt = 0; nt < 4; nt++) {
        int oc = nt * 8 + t * 2;
        float b0 = bias[oc], b1 = bias[oc + 1];
        acc[nt][0] = b0; acc[nt][1] = b1; acc[nt][2] = b0; acc[nt][3] = b1;
    }
    #pragma unroll
    for (int c = 0; c < 16; c++) {
        const int o = (c >> 2) * 1680 + ((c & 3) * 2) * 84;
        u32 a[4];
        a[0] = *(const u32*)&simg[o + base0];
        a[1] = *(const u32*)&simg[o + base1];
        a[2] = *(const u32*)&simg[o + 84 + base0];
        a[3] = *(const u32*)&simg[o + 84 + base1];
        const u32* wb = swf + c * 256 + lane * 2;
        #pragma unroll
        for (int nt = 0; nt < 4; nt++) {
            uint2 bv = *(const uint2*)&wb[nt * 64];
            u32 b[2] = {bv.x, bv.y};
            mmabf(acc[nt], a, b);
        }
    }
    __nv_bfloat16* ob = out + (size_t)img * 12800 + oyg * 80;
    #pragma unroll
    for (int nt = 0; nt < 4; nt++) {
        int oc = nt * 8 + t * 2;
        __nv_bfloat16* p0 = ob + (size_t)oc * 400;
        p0[r0]       = __float2bfloat16(fmaxf(acc[nt][0], 0.0f));
        p0[400 + r0] = __float2bfloat16(fmaxf(acc[nt][1], 0.0f));
        p0[r1]       = __float2bfloat16(fmaxf(acc[nt][2], 0.0f));
        p0[400 + r1] = __float2bfloat16(fmaxf(acc[nt][3], 0.0f));
    }
}

// ---------------------------------------------------------------------------
// conv2 (bf16 mma): 32ch 20x20 -> 64ch 9x9, k4 s2, relu. bf16 NHWC out.
// grid (1024, 4 oc-quarters), 192 thr. K=512 = 32 chunks (c = ic).
// ---------------------------------------------------------------------------
__global__ void conv2_mma(const __nv_bfloat16* __restrict__ a1,
                          const u32* __restrict__ wfu,
                          const float* __restrict__ bias,
                          __nv_bfloat16* __restrict__ out) {
    extern __shared__ char smc[];
    __nv_bfloat16* sin = (__nv_bfloat16*)smc;      // 12800 bf16
    u32* swf = (u32*)(smc + 25600);                 // 4096 u32
    const int img = blockIdx.x, q = blockIdx.y;
    const uint4* src = (const uint4*)(a1 + (size_t)img * 12800);
    for (int i = threadIdx.x; i < 1600; i += 192)
        ((uint4*)sin)[i] = src[i];
    for (int i = threadIdx.x; i < 1024; i += 192) {
        int cn = i >> 4, c = cn >> 1, ntl = cn & 1;
        ((uint4*)swf)[i] = *(const uint4*)&wfu[(c * 8 + q * 2 + ntl) * 64 + (i & 15) * 4];
    }
    __syncthreads();

    const int lane = threadIdx.x & 31, wid = threadIdx.x >> 5;
    const int t = lane & 3;
    const int r0 = wid * 16 + (lane >> 2), r1 = r0 + 8;
    const int p0 = (r0 < 81) ? r0 : 80, p1 = (r1 < 81) ? r1 : 80;
    const int toff = (t >> 1) * 20 + (t & 1) * 2;
    const int A0 = (p0 / 9) * 40 + (p0 % 9) * 2 + toff;
    const int A1 = (p1 / 9) * 40 + (p1 % 9) * 2 + toff;

    float acc[2][4];
    #pragma unroll
    for (int nt = 0; nt < 2; nt++) {
        int oc = q * 16 + nt * 8 + t * 2;
        float b0 = bias[oc], b1 = bias[oc + 1];
        acc[nt][0] = b0; acc[nt][1] = b1; acc[nt][2] = b0; acc[nt][3] = b1;
    }
    #pragma unroll 4
    for (int ic = 0; ic < 32; ic++) {
        u32 a[4];
        a[0] = *(const u32*)&sin[ic * 400 + A0];
        a[1] = *(const u32*)&sin[ic * 400 + A1];
        a[2] = *(const u32*)&sin[ic * 400 + 40 + A0];
        a[3] = *(const u32*)&sin[ic * 400 + 40 + A1];
        const u32* wb = swf + ic * 128 + lane * 2;
        #pragma unroll
        for (int nt = 0; nt < 2; nt++) {
            uint2 bv = *(const uint2*)&wb[nt * 64];
            u32 b[2] = {bv.x, bv.y};
            mmabf(acc[nt], a, b);
        }
    }
    #pragma unroll
    for (int nt = 0; nt < 2; nt++) {
        int oc = q * 16 + nt * 8 + t * 2;
        if (r0 < 81)
            *(u32*)&out[((size_t)img * 81 + r0) * 64 + oc] =
                packbf(fmaxf(acc[nt][0], 0.0f), fmaxf(acc[nt][1], 0.0f));
        if (r1 < 81)
            *(u32*)&out[((size_t)img * 81 + r1) * 64 + oc] =
                packbf(fmaxf(acc[nt][2], 0.0f), fmaxf(acc[nt][3], 0.0f));
    }
}

// ---------------------------------------------------------------------------
// conv3 (bf16 mma): 64ch 9x9 -> 64ch 7x7, k3 s1, relu. bf16 flat out.
// 2 img/block (M=98), grid (512, 4 oc-quarters), 224 thr.
// K=576 = 36 chunks (c = p*4 + icc). smem px rows padded 64->72.
// ---------------------------------------------------------------------------
__global__ void conv3_mma(const __nv_bfloat16* __restrict__ a2n,
                          const u32* __restrict__ wfu,
                          const float* __restrict__ bias,
                          __nv_bfloat16* __restrict__ feat) {
    extern __shared__ char smc[];
    __nv_bfloat16* sin = (__nv_bfloat16*)smc;      // 2*81*72 = 11664 bf16
    u32* swf = (u32*)(smc + 23328);                 // 4608 u32
    const int q = blockIdx.y;
    const int imgb = blockIdx.x * 2;
    for (int i = threadIdx.x; i < 1296; i += 224) {
        int im = i / 648, r = i % 648;
        int px = r >> 3, qq = r & 7;
        *((uint4*)&sin[im * 5832 + px * 72]       + qq) =
        *((const uint4*)&a2n[((size_t)(imgb + im) * 81 + px) * 64] + qq);
    }
    for (int i = threadIdx.x; i < 1152; i += 224) {
        int cn = i >> 4, c = cn >> 1, ntl = cn & 1;
        ((uint4*)swf)[i] = *(const uint4*)&wfu[(c * 8 + q * 2 + ntl) * 64 + (i & 15) * 4];
    }
    __syncthreads();

    const int lane = threadIdx.x & 31, wid = threadIdx.x >> 5;
    const int t = lane & 3;
    const int r0 = wid * 16 + (lane >> 2), r1 = r0 + 8;
    const int g0 = (r0 < 98) ? r0 : 97, g1 = (r1 < 98) ? r1 : 97;
    const int im0 = g0 / 49, lp0 = g0 % 49;
    const int im1 = g1 / 49, lp1 = g1 % 49;
    const int A0 = im0 * 5832 + ((lp0 / 7) * 9 + lp0 % 7) * 72 + 2 * t;
    const int A1 = im1 * 5832 + ((lp1 / 7) * 9 + lp1 % 7) * 72 + 2 * t;

    float acc[2][4];
    #pragma unroll
    for (int nt = 0; nt < 2; nt++) {
        int oc = q * 16 + nt * 8 + t * 2;
        float b0 = bias[oc], b1 = bias[oc + 1];
        acc[nt][0] = b0; acc[nt][1] = b1; acc[nt][2] = b0; acc[nt][3] = b1;
    }
    #pragma unroll
    for (int p = 0; p < 9; p++) {
        const int rowoff = ((p / 3) * 9 + (p % 3)) * 72;
        #pragma unroll
        for (int icc = 0; icc < 4; icc++) {
            u32 a[4];
            a[0] = *(const u32*)&sin[A0 + rowoff + icc * 16];
            a[1] = *(const u32*)&sin[A1 + rowoff + icc * 16];
            a[2] = *(const u32*)&sin[A0 + rowoff + icc * 16 + 8];
            a[3] = *(const u32*)&sin[A1 + rowoff + icc * 16 + 8];
            const u32* wb = swf + (p * 4 + icc) * 128 + lane * 2;
            #pragma unroll
            for (int nt = 0; nt < 2; nt++) {
                uint2 bv = *(const uint2*)&wb[nt * 64];
                u32 b[2] = {bv.x, bv.y};
                mmabf(acc[nt], a, b);
            }
        }
    }
    #pragma unroll
    for (int nt = 0; nt < 2; nt++) {
        int oc = q * 16 + nt * 8 + t * 2;
        if (r0 < 98) {
            __nv_bfloat16* fb = feat + (size_t)(imgb + im0) * 3136 + oc * 49 + lp0;
            fb[0]  = __float2bfloat16(fmaxf(acc[nt][0], 0.0f));
            fb[49] = __float2bfloat16(fmaxf(acc[nt][1], 0.0f));
        }
        if (r1 < 98) {
            __nv_bfloat16* fb = feat + (size_t)(imgb + im1) * 3136 + oc * 49 + lp1;
            fb[0]  = __float2bfloat16(fmaxf(acc[nt][2], 0.0f));
            fb[49] = __float2bfloat16(fmaxf(acc[nt][3], 0.0f));
        }
    }
}

// ---------------------------------------------------------------------------
// FC (bf16 mma): [1024,3136] @ [3136,256], split-K 4 -> fp32 partials.
// grid (8 mb, 4 nb, 4 z), 256 thr (8 m-warps), BM=128, BN=64.
// Stage 7 chunks (112 k) per iter, 7 iters. sA rows padded 112->120.
// ---------------------------------------------------------------------------
__global__ void fc_mma(const __nv_bfloat16* __restrict__ feat,
                       const u32* __restrict__ wfu,
                       float* __restrict__ part) {
    extern __shared__ char smc[];
    __nv_bfloat16* sA = (__nv_bfloat16*)smc;       // 128*120 bf16 = 30720B
    u32* sB = (u32*)(smc + 30720);                  // 3584 u32
    const int mb = blockIdx.x, nb = blockIdx.y, z = blockIdx.z;
    const int m0b = mb * 128;
    const int lane = threadIdx.x & 31, wid = threadIdx.x >> 5;
    const int t = lane & 3, g = lane >> 2;

    float acc[8][4] = {};
    for (int it = 0; it < 7; it++) {
        const int kbase = z * 784 + it * 112;
        const int cbase = z * 49 + it * 7;
        __syncthreads();
        for (int i = threadIdx.x; i < 1792; i += 256) {
            int row = i / 14, seg = i % 14;
            *(uint4*)&sA[row * 120 + seg * 8] =
                *(const uint4*)&feat[(size_t)(m0b + row) * 3136 + kbase + seg * 8];
        }
        for (int i = threadIdx.x; i < 896; i += 256) {
            int cn = i >> 4, c_l = cn >> 3, ntl = cn & 7;
            ((uint4*)sB)[i] =
                *(const uint4*)&wfu[((size_t)(cbase + c_l) * 32 + nb * 8 + ntl) * 64 + (i & 15) * 4];
        }
        __syncthreads();
        #pragma unroll
        for (int c_l = 0; c_l < 7; c_l++) {
            const int ra = (wid * 16 + g) * 120 + c_l * 16 + 2 * t;
            u32 a[4];
            a[0] = *(const u32*)&sA[ra];
            a[1] = *(const u32*)&sA[ra + 8 * 120];
            a[2] = *(const u32*)&sA[ra + 8];
            a[3] = *(const u32*)&sA[ra + 8 * 120 + 8];
            const u32* wb = sB + c_l * 512 + lane * 2;
            #pragma unroll
            for (int nt = 0; nt < 8; nt++) {
                uint2 bv = *(const uint2*)&wb[nt * 64];
                u32 b[2] = {bv.x, bv.y};
                mmabf(acc[nt], a, b);
            }
        }
    }
    float* pb = part + (size_t)z * 262144;
    const int mr0 = m0b + wid * 16 + g, mr1 = mr0 + 8;
    #pragma unroll
    for (int nt = 0; nt < 8; nt++) {
        int col = nb * 64 + nt * 8 + 2 * t;
        *(float2*)&pb[(size_t)mr0 * 256 + col] = make_float2(acc[nt][0], acc[nt][1]);
        *(float2*)&pb[(size_t)mr1 * 256 + col] = make_float2(acc[nt][2], acc[nt][3]);
    }
}

__global__ void combine_kernel(const float* __restrict__ Cp,
                               const float* __restrict__ bias,
                               float* __restrict__ C,
                               int MN, int N, int nsplit, int doRelu) {
    const int idx = blockIdx.x * blockDim.x + threadIdx.x;
    if (idx >= MN) return;
    float s = bias[idx % N];
    for (int z = 0; z < nsplit; z++) s += Cp[(size_t)z * MN + idx];
    if (doRelu) s = fmaxf(s, 0.0f);
    C[idx] = s;
}

// ---------------------------------------------------------------------------
// fp32 head GEMM (fused bias/relu) — unchanged
// ---------------------------------------------------------------------------
__global__ void gemm_ep_kernel(const float* __restrict__ A,
                               const float* __restrict__ W,
                               const float* __restrict__ bias,
                               float* __restrict__ C,
                               int M, int N, int K, int doRelu) {
    __shared__ float sA[16][68];
    __shared__ float sW[16][68];
    const int m0 = blockIdx.x * 64;
    const int n0 = blockIdx.y * 64;
    const int tid = threadIdx.x;
    const int tx = tid & 15, ty = tid >> 4;
    float acc[4][4] = {};
    for (int k0 = 0; k0 < K; k0 += 16) {
        {
            const int mm = tid >> 2;
            const int kk = (tid & 3) * 4;
            const float4 av = *(const float4*)(A + (size_t)(m0 + mm) * K + k0 + kk);
            sA[kk + 0][mm] = av.x; sA[kk + 1][mm] = av.y;
            sA[kk + 2][mm] = av.z; sA[kk + 3][mm] = av.w;
        }
        {
            const int kk = tid >> 4;
            const int nn = (tid & 15) * 4;
            *(float4*)&sW[kk][nn] = *(const float4*)(W + (size_t)(k0 + kk) * N + n0 + nn);
        }
        __syncthreads();
        #pragma unroll
        for (int kk = 0; kk < 16; kk++) {
            const float4 av = *(const float4*)&sA[kk][ty * 4];
            const float4 wv = *(const float4*)&sW[kk][tx * 4];
            const float a[4] = {av.x, av.y, av.z, av.w};
            const float w[4] = {wv.x, wv.y, wv.z, wv.w};
            #pragma unroll
            for (int i = 0; i < 4; i++)
                #pragma unroll
                for (int j = 0; j < 4; j++)
                    acc[i][j] = fmaf(a[i], w[j], acc[i][j]);
        }
        __syncthreads();
    }
    #pragma unroll
    for (int i = 0; i < 4; i++)
        #pragma unroll
        for (int j = 0; j < 4; j++) {
            float v = acc[i][j] + bias[n0 + tx * 4 + j];
            if (doRelu) v = fmaxf(v, 0.0f);
            C[(size_t)(m0 + ty * 4 + i) * N + n0 + tx * 4 + j] = v;
        }
}

// ---------------------------------------------------------------------------
// c_y / logits / loss
// ---------------------------------------------------------------------------
__global__ void cy_kernel(const float* __restrict__ hp,
                          const float* __restrict__ pw2,
                          const float* __restrict__ pb2,
                          float* __restrict__ cy) {
    const int gw = (blockIdx.x * blockDim.x + threadIdx.x) >> 5;
    const int lane = threadIdx.x & 31;
    if (gw >= 512) return;
    float s = 0.0f;
    for (int k = lane; k < 256; k += 32) s = fmaf(hp[(size_t)gw * 256 + k], pw2[k], s);
    #pragma unroll
    for (int off = 16; off > 0; off >>= 1) s += __shfl_xor_sync(0xffffffffu, s, off);
    if (lane == 0) cy[gw] = s + pb2[0];
}

__global__ void logits_kernel(const float* __restrict__ phi,
                              const float* __restrict__ cy,
                              float* __restrict__ lse,
                              float* __restrict__ diag) {
    const int i = blockIdx.x;
    __shared__ float sx[64];
    __shared__ float red[256];
    __shared__ float sdiag;
    const int tid = threadIdx.x;
    if (tid < 64) sx[tid] = phi[(size_t)i * 64 + tid];
    __syncthreads();
    float lg[2];
    #pragma unroll
    for (int r = 0; r < 2; r++) {
        const int j = tid + r * 256;
        const float* y = phi + (size_t)(512 + j) * 64;
        float mx = 0.0f;
        #pragma unroll
        for (int k = 0; k < 32; k++) {
            float d = sx[k] - y[k];
            mx = fmaxf(mx, fmaxf(d, 0.0f));
        }
        float ss = 0.0f;
        #pragma unroll
        for (int k = 32; k < 64; k++) {
            float d = sx[k] - y[k];
            ss = fmaf(d, d, ss);
        }
        lg[r] = cy[j] - (mx + sqrtf(ss + 1e-8f));
        if (j == i) sdiag = lg[r];
    }
    red[tid] = fmaxf(lg[0], lg[1]);
    __syncthreads();
    for (int s = 128; s > 0; s >>= 1) {
        if (tid < s) red[tid] = fmaxf(red[tid], red[tid + s]);
        __syncthreads();
    }
    const float rowmax = red[0];
    __syncthreads();
    red[tid] = expf(lg[0] - rowmax) + expf(lg[1] - rowmax);
    __syncthreads();
    for (int s = 128; s > 0; s >>= 1) {
        if (tid < s) red[tid] += red[tid + s];
        __syncthreads();
    }
    if (tid == 0) {
        lse[i] = rowmax + logf(red[0]);
        diag[i] = sdiag;
    }
}

__global__ void loss_kernel(const float* __restrict__ lse,
                            const float* __restrict__ diag,
                            float* __restrict__ out) {
    __shared__ float r1[256], r2[256];
    const int tid = threadIdx.x;
    float s1 = 0.0f, s2 = 0.0f;
    for (int i = tid; i < 512; i += 256) {
        const float l = lse[i];
        s1 += l - diag[i];
        const float u = l + 1e-6f;
        s2 = fmaf(u, u, s2);
    }
    r1[tid] = s1; r2[tid] = s2;
    __syncthreads();
    for (int s = 128; s > 0; s >>= 1) {
        if (tid < s) { r1[tid] += r1[tid + s]; r2[tid] += r2[tid + s]; }
        __syncthreads();
    }
    if (tid == 0)
        out[0] = r1[0] * (1.0f / 512.0f) + 0.1f * r2[0] * (1.0f / 512.0f);
}

// ---------------------------------------------------------------------------
// Host launcher
// ---------------------------------------------------------------------------
extern "C" void kernel_launch(void* const* d_in, const int* in_sizes, int n_in,
                              void* d_out, int out_size) {
    const float* curr = (const float*)d_in[0];
    const float* next = (const float*)d_in[1];
    const float* c1w = (const float*)d_in[2];
    const float* c1b = (const float*)d_in[3];
    const float* c2w = (const float*)d_in[4];
    const float* c2b = (const float*)d_in[5];
    const float* c3w = (const float*)d_in[6];
    const float* c3b = (const float*)d_in[7];
    const float* fcw = (const float*)d_in[8];
    const float* fcb = (const float*)d_in[9];
    const float* e1w = (const float*)d_in[10];
    const float* e1b = (const float*)d_in[11];
    const float* e2w = (const float*)d_in[12];
    const float* e2b = (const float*)d_in[13];
    const float* pw1 = (const float*)d_in[14];
    const float* pb1 = (const float*)d_in[15];
    const float* pw2 = (const float*)d_in[16];
    const float* pb2 = (const float*)d_in[17];

    u32 *p_w1f, *p_w2f, *p_w3f, *p_wfc;
    __nv_bfloat16 *p_a1, *p_a2n, *p_feat;
    float *p_f, *p_h1, *p_phi, *p_hp, *p_cy, *p_lse, *p_diag, *p_part;
    cudaGetSymbolAddress((void**)&p_w1f, g_w1f);
    cudaGetSymbolAddress((void**)&p_w2f, g_w2f);
    cudaGetSymbolAddress((void**)&p_w3f, g_w3f);
    cudaGetSymbolAddress((void**)&p_wfc, g_wfc);
    cudaGetSymbolAddress((void**)&p_a1, g_a1);
    cudaGetSymbolAddress((void**)&p_a2n, g_a2n);
    cudaGetSymbolAddress((void**)&p_feat, g_feat);
    cudaGetSymbolAddress((void**)&p_f, g_f);
    cudaGetSymbolAddress((void**)&p_h1, g_h1);
    cudaGetSymbolAddress((void**)&p_phi, g_phi);
    cudaGetSymbolAddress((void**)&p_hp, g_hp);
    cudaGetSymbolAddress((void**)&p_cy, g_cy);
    cudaGetSymbolAddress((void**)&p_lse, g_lse);
    cudaGetSymbolAddress((void**)&p_diag, g_diag);
    cudaGetSymbolAddress((void**)&p_part, g_part);

    const int SM1 = 13440 + 4096 * 4;    // 29824
    const int SM2 = 25600 + 4096 * 4;    // 41984
    const int SM3 = 23328 + 4608 * 4;    // 41760
    const int SMF = 30720 + 3584 * 4;    // 45056
    cudaFuncSetAttribute(conv1_mma, cudaFuncAttributeMaxDynamicSharedMemorySize, SM1);
    cudaFuncSetAttribute(conv2_mma, cudaFuncAttributeMaxDynamicSharedMemorySize, SM2);
    cudaFuncSetAttribute(conv3_mma, cudaFuncAttributeMaxDynamicSharedMemorySize, SM3);
    cudaFuncSetAttribute(fc_mma, cudaFuncAttributeMaxDynamicSharedMemorySize, SMF);

    prep1<<<16, 256>>>(c1w, p_w1f);
    prep2<<<64, 256>>>(c2w, p_w2f);
    prep3<<<72, 256>>>(c3w, p_w3f);
    prepfc<<<1568, 256>>>(fcw, p_wfc);

    conv1_mma<<<dim3(NIMG, 5), 160, SM1>>>(curr, next, p_w1f, c1b, p_a1);
    conv2_mma<<<dim3(NIMG, 4), 192, SM2>>>(p_a1, p_w2f, c2b, p_a2n);
    conv3_mma<<<dim3(NIMG / 2, 4), 224, SM3>>>(p_a2n, p_w3f, c3b, p_feat);

    fc_mma<<<dim3(8, 4, 4), 256, SMF>>>(p_feat, p_wfc, p_part);
    combine_kernel<<<1024, 256>>>(p_part, fcb, p_f, 1024 * 256, 256, 4, 1);

    gemm_ep_kernel<<<dim3(16, 4), 256>>>(p_f, e1w, e1b, p_h1, 1024, 256, 256, 1);
    gemm_ep_kernel<<<dim3(16, 1), 256>>>(p_h1, e2w, e2b, p_phi, 1024, 64, 256, 0);
    gemm_ep_kernel<<<dim3(8, 4), 256>>>(p_f + (size_t)512 * 256, pw1, pb1, p_hp, 512, 256, 256, 1);

    cy_kernel<<<64, 256>>>(p_hp, pw2, pb2, p_cy);
    logits_kernel<<<512, 256>>>(p_phi, p_cy, p_lse, p_diag);
    loss_kernel<<<1, 256>>>(p_lse, p_diag, (float*)d_out);
}

// round 5
// speedup vs baseline: 4.6970x; 1.0702x over previous
#include <cuda_runtime.h>
#include <cuda_bf16.h>
#include <math.h>

#define NIMG 1024
typedef unsigned int u32;

// ---------------------------------------------------------------------------
// scratch
// ---------------------------------------------------------------------------
__device__ __align__(128) u32 g_w1f[16 * 4 * 64];        // conv1 frags
__device__ __align__(128) u32 g_w2f[32 * 8 * 64];        // conv2
__device__ __align__(128) u32 g_w3f[36 * 8 * 64];        // conv3
__device__ __align__(128) u32 g_wfc[196 * 32 * 64];      // fc
__device__ __align__(128) u32 g_we1[16 * 32 * 64];       // e1w frags
__device__ __align__(128) u32 g_we2[16 * 8 * 64];        // e2w frags
__device__ __align__(128) u32 g_wp1[16 * 32 * 64];       // pw1 frags
__device__ __align__(128) __nv_bfloat16 g_a1[(size_t)NIMG * 12800];
__device__ __align__(128) __nv_bfloat16 g_a2n[(size_t)NIMG * 81 * 64];
__device__ __align__(128) __nv_bfloat16 g_feat[(size_t)NIMG * 3136];
__device__ __align__(128) float g_f[NIMG * 256];
__device__ __align__(128) float g_h1[NIMG * 256];
__device__ __align__(128) float g_phi[NIMG * 64];
__device__ __align__(128) float g_hp[512 * 256];
__device__ __align__(128) float g_cy[512];
__device__ __align__(128) float g_lse[512];
__device__ __align__(128) float g_diag[512];
__device__ __align__(128) float g_part[4 * 1024 * 256];

// ---------------------------------------------------------------------------
// helpers
// ---------------------------------------------------------------------------
__device__ __forceinline__ u32 packbf(float lo, float hi) {
    __nv_bfloat162 h = __float22bfloat162_rn(make_float2(lo, hi));
    return *reinterpret_cast<u32*>(&h);
}
__device__ __forceinline__ void mmabf(float* d, const u32* a, const u32* b) {
    asm volatile(
        "mma.sync.aligned.m16n8k16.row.col.f32.bf16.bf16.f32 "
        "{%0,%1,%2,%3},{%4,%5,%6,%7},{%8,%9},{%0,%1,%2,%3};\n"
        : "+f"(d[0]), "+f"(d[1]), "+f"(d[2]), "+f"(d[3])
        : "r"(a[0]), "r"(a[1]), "r"(a[2]), "r"(a[3]), "r"(b[0]), "r"(b[1]));
}

// ---------------------------------------------------------------------------
// weight prep: frag layout wf[(c*NT+nt)*64 + lane*2 + s] = bf16x2 of
//   W[k = c*16 + s*8 + 2*(lane&3) (+1)][n = nt*8 + lane/4]
// ---------------------------------------------------------------------------
__global__ void prep1(const float* __restrict__ w, u32* __restrict__ wf) {
    int i = blockIdx.x * 256 + threadIdx.x;
    if (i >= 4096) return;
    int s = i & 1, lane = (i >> 1) & 31;
    int cn = i >> 6, nt = cn & 3, c = cn >> 2;
    int t = lane & 3, g = lane >> 2;
    int n = nt * 8 + g;
    int ic = c >> 2, ky = (c & 3) * 2 + s, kx = 2 * t;
    const float* base = w + ((n * 4 + ic) * 8 + ky) * 8 + kx;
    wf[i] = packbf(base[0], base[1]);
}
__global__ void prep2(const float* __restrict__ w, u32* __restrict__ wf) {
    int i = blockIdx.x * 256 + threadIdx.x;
    if (i >= 16384) return;
    int s = i & 1, lane = (i >> 1) & 31;
    int cn = i >> 6, nt = cn & 7, ic = cn >> 3;
    int t = lane & 3, g = lane >> 2;
    int n = nt * 8 + g;
    int ky = s * 2 + (t >> 1), kx = (t & 1) * 2;
    const float* base = w + ((n * 32 + ic) * 4 + ky) * 4 + kx;
    wf[i] = packbf(base[0], base[1]);
}
__global__ void prep3(const float* __restrict__ w, u32* __restrict__ wf) {
    int i = blockIdx.x * 256 + threadIdx.x;
    if (i >= 18432) return;
    int s = i & 1, lane = (i >> 1) & 31;
    int cn = i >> 6, nt = cn & 7, c = cn >> 3;
    int t = lane & 3, g = lane >> 2;
    int n = nt * 8 + g;
    int p = c >> 2, icc = c & 3;
    int ic = icc * 16 + s * 8 + 2 * t;
    int ky = p / 3, kx = p % 3;
    float lo = w[((n * 64 + ic) * 3 + ky) * 3 + kx];
    float hi = w[((n * 64 + ic + 1) * 3 + ky) * 3 + kx];
    wf[i] = packbf(lo, hi);
}
__global__ void prepfc(const float* __restrict__ w, u32* __restrict__ wf) {
    int i = blockIdx.x * 256 + threadIdx.x;
    if (i >= 401408) return;
    int s = i & 1, lane = (i >> 1) & 31;
    int cn = i >> 6, nt = cn & 31, c = cn >> 5;
    int t = lane & 3, g = lane >> 2;
    int n = nt * 8 + g;
    int k0 = c * 16 + s * 8 + 2 * t;
    wf[i] = packbf(w[(size_t)k0 * 256 + n], w[(size_t)(k0 + 1) * 256 + n]);
}
// generic head weight prep: K=256 (16 chunks), N = NTg*8
__global__ void prephead(const float* __restrict__ w, u32* __restrict__ wf,
                         int NTg, int total) {
    int i = blockIdx.x * 256 + threadIdx.x;
    if (i >= total) return;
    int s = i & 1, lane = (i >> 1) & 31;
    int cn = i >> 6;
    int nt = cn % NTg, c = cn / NTg;
    int t = lane & 3, g = lane >> 2;
    int n = nt * 8 + g;
    int k0 = c * 16 + s * 8 + 2 * t;
    int N = NTg * 8;
    wf[i] = packbf(w[(size_t)k0 * N + n], w[(size_t)(k0 + 1) * N + n]);
}

// ---------------------------------------------------------------------------
// conv1: 2 images/block. grid (512 pairs, 5 oy-groups), 320 thr (10 warps:
// warps 0-4 -> curr image, 5-9 -> next image). bf16 NCHW out.
// ---------------------------------------------------------------------------
__global__ void conv1_mma(const float* __restrict__ curr,
                          const float* __restrict__ next,
                          const u32* __restrict__ wfu,
                          const float* __restrict__ bias,
                          __nv_bfloat16* __restrict__ out) {
    extern __shared__ char smc[];
    __nv_bfloat16* simg = (__nv_bfloat16*)smc;     // 2*6720 bf16 = 26880B
    u32* swf = (u32*)(smc + 26880);                 // 4096 u32
    const int p = blockIdx.x, oyg = blockIdx.y;
    const int iy0 = oyg * 16;
    const float* in0 = curr + (size_t)p * 28224;
    const float* in1 = next + (size_t)p * 28224;
    for (int i = threadIdx.x; i < 3360; i += 320) {
        int e = i * 4;
        int im = e / 6720, e2 = e % 6720;
        int ic = e2 / 1680, rem = e2 % 1680;
        const float* src = im ? in1 : in0;
        float4 v = *(const float4*)&src[ic * 7056 + iy0 * 84 + rem];
        u32* d = (u32*)&simg[e];
        d[0] = packbf(v.x, v.y);
        d[1] = packbf(v.z, v.w);
    }
    for (int i = threadIdx.x; i < 1024; i += 320)
        ((uint4*)swf)[i] = ((const uint4*)wfu)[i];
    __syncthreads();

    const int lane = threadIdx.x & 31, wid = threadIdx.x >> 5;
    const int t = lane & 3;
    const int imsel = (wid >= 5) ? 1 : 0;
    const int wl = imsel ? wid - 5 : wid;
    const int r0 = wl * 16 + (lane >> 2), r1 = r0 + 8;
    const int ib = imsel * 6720;
    const int base0 = ib + (r0 / 20) * 336 + (r0 % 20) * 4 + 2 * t;
    const int base1 = ib + (r1 / 20) * 336 + (r1 % 20) * 4 + 2 * t;

    float acc[4][4];
    #pragma unroll
    for (int nt = 0; nt < 4; nt++) {
        int oc = nt * 8 + t * 2;
        float b0 = bias[oc], b1 = bias[oc + 1];
        acc[nt][0] = b0; acc[nt][1] = b1; acc[nt][2] = b0; acc[nt][3] = b1;
    }
    #pragma unroll
    for (int c = 0; c < 16; c++) {
        const int o = (c >> 2) * 1680 + ((c & 3) * 2) * 84;
        u32 a[4];
        a[0] = *(const u32*)&simg[o + base0];
        a[1] = *(const u32*)&simg[o + base1];
        a[2] = *(const u32*)&simg[o + 84 + base0];
        a[3] = *(const u32*)&simg[o + 84 + base1];
        const u32* wb = swf + c * 256 + lane * 2;
        #pragma unroll
        for (int nt = 0; nt < 4; nt++) {
            uint2 bv = *(const uint2*)&wb[nt * 64];
            u32 b[2] = {bv.x, bv.y};
            mmabf(acc[nt], a, b);
        }
    }
    const int img = p + imsel * 512;
    __nv_bfloat16* ob = out + (size_t)img * 12800 + oyg * 80;
    #pragma unroll
    for (int nt = 0; nt < 4; nt++) {
        int oc = nt * 8 + t * 2;
        __nv_bfloat16* p0 = ob + (size_t)oc * 400;
        p0[r0]       = __float2bfloat16(fmaxf(acc[nt][0], 0.0f));
        p0[400 + r0] = __float2bfloat16(fmaxf(acc[nt][1], 0.0f));
        p0[r1]       = __float2bfloat16(fmaxf(acc[nt][2], 0.0f));
        p0[400 + r1] = __float2bfloat16(fmaxf(acc[nt][3], 0.0f));
    }
}

// ---------------------------------------------------------------------------
// conv2: 2 images/block. grid (512 pairs, 4 oc-quarters), 352 thr (11 warps,
// M = 162 pixels over both images). bf16 NHWC out.
// ---------------------------------------------------------------------------
__global__ void conv2_mma(const __nv_bfloat16* __restrict__ a1,
                          const u32* __restrict__ wfu,
                          const float* __restrict__ bias,
                          __nv_bfloat16* __restrict__ out) {
    extern __shared__ char smc[];
    __nv_bfloat16* sin = (__nv_bfloat16*)smc;      // 2*12800 bf16 = 51200B
    u32* swf = (u32*)(smc + 51200);                 // 4096 u32
    const int p = blockIdx.x, q = blockIdx.y;
    const uint4* src = (const uint4*)(a1 + (size_t)p * 25600);
    for (int i = threadIdx.x; i < 3200; i += 352)
        ((uint4*)sin)[i] = src[i];
    for (int i = threadIdx.x; i < 1024; i += 352) {
        int cn = i >> 4, c = cn >> 1, ntl = cn & 1;
        ((uint4*)swf)[i] = *(const uint4*)&wfu[(c * 8 + q * 2 + ntl) * 64 + (i & 15) * 4];
    }
    __syncthreads();

    const int lane = threadIdx.x & 31, wid = threadIdx.x >> 5;
    const int t = lane & 3;
    const int r0 = wid * 16 + (lane >> 2), r1 = r0 + 8;
    const int gg0 = (r0 < 162) ? r0 : 161, gg1 = (r1 < 162) ? r1 : 161;
    const int im0 = gg0 / 81, px0 = gg0 % 81;
    const int im1 = gg1 / 81, px1 = gg1 % 81;
    const int toff = (t >> 1) * 20 + (t & 1) * 2;
    const int A0 = im0 * 12800 + (px0 / 9) * 40 + (px0 % 9) * 2 + toff;
    const int A1 = im1 * 12800 + (px1 / 9) * 40 + (px1 % 9) * 2 + toff;

    float acc[2][4];
    #pragma unroll
    for (int nt = 0; nt < 2; nt++) {
        int oc = q * 16 + nt * 8 + t * 2;
        float b0 = bias[oc], b1 = bias[oc + 1];
        acc[nt][0] = b0; acc[nt][1] = b1; acc[nt][2] = b0; acc[nt][3] = b1;
    }
    #pragma unroll 4
    for (int ic = 0; ic < 32; ic++) {
        u32 a[4];
        a[0] = *(const u32*)&sin[ic * 400 + A0];
        a[1] = *(const u32*)&sin[ic * 400 + A1];
        a[2] = *(const u32*)&sin[ic * 400 + 40 + A0];
        a[3] = *(const u32*)&sin[ic * 400 + 40 + A1];
        const u32* wb = swf + ic * 128 + lane * 2;
        #pragma unroll
        for (int nt = 0; nt < 2; nt++) {
            uint2 bv = *(const uint2*)&wb[nt * 64];
            u32 b[2] = {bv.x, bv.y};
            mmabf(acc[nt], a, b);
        }
    }
    #pragma unroll
    for (int nt = 0; nt < 2; nt++) {
        int oc = q * 16 + nt * 8 + t * 2;
        if (r0 < 162)
            *(u32*)&out[((size_t)(p * 2 + im0) * 81 + px0) * 64 + oc] =
                packbf(fmaxf(acc[nt][0], 0.0f), fmaxf(acc[nt][1], 0.0f));
        if (r1 < 162)
            *(u32*)&out[((size_t)(p * 2 + im1) * 81 + px1) * 64 + oc] =
                packbf(fmaxf(acc[nt][2], 0.0f), fmaxf(acc[nt][3], 0.0f));
    }
}

// ---------------------------------------------------------------------------
// conv3: 2 img/block (M=98), grid (512, 4 oc-quarters), 224 thr.
// ---------------------------------------------------------------------------
__global__ void conv3_mma(const __nv_bfloat16* __restrict__ a2n,
                          const u32* __restrict__ wfu,
                          const float* __restrict__ bias,
                          __nv_bfloat16* __restrict__ feat) {
    extern __shared__ char smc[];
    __nv_bfloat16* sin = (__nv_bfloat16*)smc;      // 2*81*72 bf16
    u32* swf = (u32*)(smc + 23328);                 // 4608 u32
    const int q = blockIdx.y;
    const int imgb = blockIdx.x * 2;
    for (int i = threadIdx.x; i < 1296; i += 224) {
        int im = i / 648, r = i % 648;
        int px = r >> 3, qq = r & 7;
        *((uint4*)&sin[im * 5832 + px * 72]       + qq) =
        *((const uint4*)&a2n[((size_t)(imgb + im) * 81 + px) * 64] + qq);
    }
    for (int i = threadIdx.x; i < 1152; i += 224) {
        int cn = i >> 4, c = cn >> 1, ntl = cn & 1;
        ((uint4*)swf)[i] = *(const uint4*)&wfu[(c * 8 + q * 2 + ntl) * 64 + (i & 15) * 4];
    }
    __syncthreads();

    const int lane = threadIdx.x & 31, wid = threadIdx.x >> 5;
    const int t = lane & 3;
    const int r0 = wid * 16 + (lane >> 2), r1 = r0 + 8;
    const int g0 = (r0 < 98) ? r0 : 97, g1 = (r1 < 98) ? r1 : 97;
    const int im0 = g0 / 49, lp0 = g0 % 49;
    const int im1 = g1 / 49, lp1 = g1 % 49;
    const int A0 = im0 * 5832 + ((lp0 / 7) * 9 + lp0 % 7) * 72 + 2 * t;
    const int A1 = im1 * 5832 + ((lp1 / 7) * 9 + lp1 % 7) * 72 + 2 * t;

    float acc[2][4];
    #pragma unroll
    for (int nt = 0; nt < 2; nt++) {
        int oc = q * 16 + nt * 8 + t * 2;
        float b0 = bias[oc], b1 = bias[oc + 1];
        acc[nt][0] = b0; acc[nt][1] = b1; acc[nt][2] = b0; acc[nt][3] = b1;
    }
    #pragma unroll
    for (int p = 0; p < 9; p++) {
        const int rowoff = ((p / 3) * 9 + (p % 3)) * 72;
        #pragma unroll
        for (int icc = 0; icc < 4; icc++) {
            u32 a[4];
            a[0] = *(const u32*)&sin[A0 + rowoff + icc * 16];
            a[1] = *(const u32*)&sin[A1 + rowoff + icc * 16];
            a[2] = *(const u32*)&sin[A0 + rowoff + icc * 16 + 8];
            a[3] = *(const u32*)&sin[A1 + rowoff + icc * 16 + 8];
            const u32* wb = swf + (p * 4 + icc) * 128 + lane * 2;
            #pragma unroll
            for (int nt = 0; nt < 2; nt++) {
                uint2 bv = *(const uint2*)&wb[nt * 64];
                u32 b[2] = {bv.x, bv.y};
                mmabf(acc[nt], a, b);
            }
        }
    }
    #pragma unroll
    for (int nt = 0; nt < 2; nt++) {
        int oc = q * 16 + nt * 8 + t * 2;
        if (r0 < 98) {
            __nv_bfloat16* fb = feat + (size_t)(imgb + im0) * 3136 + oc * 49 + lp0;
            fb[0]  = __float2bfloat16(fmaxf(acc[nt][0], 0.0f));
            fb[49] = __float2bfloat16(fmaxf(acc[nt][1], 0.0f));
        }
        if (r1 < 98) {
            __nv_bfloat16* fb = feat + (size_t)(imgb + im1) * 3136 + oc * 49 + lp1;
            fb[0]  = __float2bfloat16(fmaxf(acc[nt][2], 0.0f));
            fb[49] = __float2bfloat16(fmaxf(acc[nt][3], 0.0f));
        }
    }
}

// ---------------------------------------------------------------------------
// FC (bf16 mma): [1024,3136]@[3136,256], split-K 4 -> fp32 partials.
// ---------------------------------------------------------------------------
__global__ void fc_mma(const __nv_bfloat16* __restrict__ feat,
                       const u32* __restrict__ wfu,
                       float* __restrict__ part) {
    extern __shared__ char smc[];
    __nv_bfloat16* sA = (__nv_bfloat16*)smc;       // 128*120 bf16
    u32* sB = (u32*)(smc + 30720);                  // 3584 u32
    const int mb = blockIdx.x, nb = blockIdx.y, z = blockIdx.z;
    const int m0b = mb * 128;
    const int lane = threadIdx.x & 31, wid = threadIdx.x >> 5;
    const int t = lane & 3, g = lane >> 2;

    float acc[8][4] = {};
    for (int it = 0; it < 7; it++) {
        const int kbase = z * 784 + it * 112;
        const int cbase = z * 49 + it * 7;
        __syncthreads();
        for (int i = threadIdx.x; i < 1792; i += 256) {
            int row = i / 14, seg = i % 14;
            *(uint4*)&sA[row * 120 + seg * 8] =
                *(const uint4*)&feat[(size_t)(m0b + row) * 3136 + kbase + seg * 8];
        }
        for (int i = threadIdx.x; i < 896; i += 256) {
            int cn = i >> 4, c_l = cn >> 3, ntl = cn & 7;
            ((uint4*)sB)[i] =
                *(const uint4*)&wfu[((size_t)(cbase + c_l) * 32 + nb * 8 + ntl) * 64 + (i & 15) * 4];
        }
        __syncthreads();
        #pragma unroll
        for (int c_l = 0; c_l < 7; c_l++) {
            const int ra = (wid * 16 + g) * 120 + c_l * 16 + 2 * t;
            u32 a[4];
            a[0] = *(const u32*)&sA[ra];
            a[1] = *(const u32*)&sA[ra + 8 * 120];
            a[2] = *(const u32*)&sA[ra + 8];
            a[3] = *(const u32*)&sA[ra + 8 * 120 + 8];
            const u32* wb = sB + c_l * 512 + lane * 2;
            #pragma unroll
            for (int nt = 0; nt < 8; nt++) {
                uint2 bv = *(const uint2*)&wb[nt * 64];
                u32 b[2] = {bv.x, bv.y};
                mmabf(acc[nt], a, b);
            }
        }
    }
    float* pb = part + (size_t)z * 262144;
    const int mr0 = m0b + wid * 16 + g, mr1 = mr0 + 8;
    #pragma unroll
    for (int nt = 0; nt < 8; nt++) {
        int col = nb * 64 + nt * 8 + 2 * t;
        *(float2*)&pb[(size_t)mr0 * 256 + col] = make_float2(acc[nt][0], acc[nt][1]);
        *(float2*)&pb[(size_t)mr1 * 256 + col] = make_float2(acc[nt][2], acc[nt][3]);
    }
}

__global__ void combine_kernel(const float* __restrict__ Cp,
                               const float* __restrict__ bias,
                               float* __restrict__ C,
                               int MN, int N, int nsplit, int doRelu) {
    const int idx = blockIdx.x * blockDim.x + threadIdx.x;
    if (idx >= MN) return;
    float s = bias[idx % N];
    for (int z = 0; z < nsplit; z++) s += Cp[(size_t)z * MN + idx];
    if (doRelu) s = fmaxf(s, 0.0f);
    C[idx] = s;
}

// ---------------------------------------------------------------------------
// head GEMM (bf16 mma): C[M,N] = relu?(A[M,256] @ W[256,N] + b).
// A fp32 (converted during staging). grid (M/128, N/64), 256 thr.
// ---------------------------------------------------------------------------
__global__ void head_mma(const float* __restrict__ A,
                         const u32* __restrict__ wfu,
                         const float* __restrict__ bias,
                         float* __restrict__ C,
                         int NTg, int doRelu) {
    extern __shared__ char smc[];
    __nv_bfloat16* sA = (__nv_bfloat16*)smc;       // 128*136 bf16 = 34816B
    u32* sB = (u32*)(smc + 34816);                  // 4096 u32
    const int mb = blockIdx.x, nb = blockIdx.y;
    const int m0b = mb * 128;
    const int N = NTg * 8;
    const int lane = threadIdx.x & 31, wid = threadIdx.x >> 5;
    const int t = lane & 3, g = lane >> 2;

    float acc[8][4] = {};
    #pragma unroll
    for (int it = 0; it < 2; it++) {
        const int kbase = it * 128;
        __syncthreads();
        for (int i = threadIdx.x; i < 4096; i += 256) {
            int row = i >> 5, seg = i & 31;
            float4 v = *(const float4*)&A[(size_t)(m0b + row) * 256 + kbase + seg * 4];
            u32* d = (u32*)&sA[row * 136 + seg * 4];
            d[0] = packbf(v.x, v.y);
            d[1] = packbf(v.z, v.w);
        }
        for (int i = threadIdx.x; i < 1024; i += 256) {
            int cn = i >> 4, c_l = cn >> 3, ntl = cn & 7;
            ((uint4*)sB)[i] =
                *(const uint4*)&wfu[(((it * 8 + c_l) * NTg) + nb * 8 + ntl) * 64 + (i & 15) * 4];
        }
        __syncthreads();
        #pragma unroll
        for (int c_l = 0; c_l < 8; c_l++) {
            const int ra = (wid * 16 + g) * 136 + c_l * 16 + 2 * t;
            u32 a[4];
            a[0] = *(const u32*)&sA[ra];
            a[1] = *(const u32*)&sA[ra + 8 * 136];
            a[2] = *(const u32*)&sA[ra + 8];
            a[3] = *(const u32*)&sA[ra + 8 * 136 + 8];
            const u32* wb = sB + c_l * 512 + lane * 2;
            #pragma unroll
            for (int nt = 0; nt < 8; nt++) {
                uint2 bv = *(const uint2*)&wb[nt * 64];
                u32 b[2] = {bv.x, bv.y};
                mmabf(acc[nt], a, b);
            }
        }
    }
    const int mr0 = m0b + wid * 16 + g, mr1 = mr0 + 8;
    #pragma unroll
    for (int nt = 0; nt < 8; nt++) {
        int col = nb * 64 + nt * 8 + 2 * t;
        float b0 = bias[col], b1 = bias[col + 1];
        float v00 = acc[nt][0] + b0, v01 = acc[nt][1] + b1;
        float v10 = acc[nt][2] + b0, v11 = acc[nt][3] + b1;
        if (doRelu) {
            v00 = fmaxf(v00, 0.0f); v01 = fmaxf(v01, 0.0f);
            v10 = fmaxf(v10, 0.0f); v11 = fmaxf(v11, 0.0f);
        }
        *(float2*)&C[(size_t)mr0 * N + col] = make_float2(v00, v01);
        *(float2*)&C[(size_t)mr1 * N + col] = make_float2(v10, v11);
    }
}

// ---------------------------------------------------------------------------
// c_y / logits / loss
// ---------------------------------------------------------------------------
__global__ void cy_kernel(const float* __restrict__ hp,
                          const float* __restrict__ pw2,
                          const float* __restrict__ pb2,
                          float* __restrict__ cy) {
    const int gw = (blockIdx.x * blockDim.x + threadIdx.x) >> 5;
    const int lane = threadIdx.x & 31;
    if (gw >= 512) return;
    float s = 0.0f;
    for (int k = lane; k < 256; k += 32) s = fmaf(hp[(size_t)gw * 256 + k], pw2[k], s);
    #pragma unroll
    for (int off = 16; off > 0; off >>= 1) s += __shfl_xor_sync(0xffffffffu, s, off);
    if (lane == 0) cy[gw] = s + pb2[0];
}

__global__ void logits_kernel(const float* __restrict__ phi,
                              const float* __restrict__ cy,
                              float* __restrict__ lse,
                              float* __restrict__ diag) {
    const int i = blockIdx.x;
    __shared__ float sx[64];
    __shared__ float red[256];
    __shared__ float sdiag;
    const int tid = threadIdx.x;
    if (tid < 64) sx[tid] = phi[(size_t)i * 64 + tid];
    __syncthreads();
    float lg[2];
    #pragma unroll
    for (int r = 0; r < 2; r++) {
        const int j = tid + r * 256;
        const float* y = phi + (size_t)(512 + j) * 64;
        float mx = 0.0f;
        #pragma unroll
        for (int k = 0; k < 32; k++) {
            float d = sx[k] - y[k];
            mx = fmaxf(mx, fmaxf(d, 0.0f));
        }
        float ss = 0.0f;
        #pragma unroll
        for (int k = 32; k < 64; k++) {
            float d = sx[k] - y[k];
            ss = fmaf(d, d, ss);
        }
        lg[r] = cy[j] - (mx + sqrtf(ss + 1e-8f));
        if (j == i) sdiag = lg[r];
    }
    red[tid] = fmaxf(lg[0], lg[1]);
    __syncthreads();
    for (int s = 128; s > 0; s >>= 1) {
        if (tid < s) red[tid] = fmaxf(red[tid], red[tid + s]);
        __syncthreads();
    }
    const float rowmax = red[0];
    __syncthreads();
    red[tid] = expf(lg[0] - rowmax) + expf(lg[1] - rowmax);
    __syncthreads();
    for (int s = 128; s > 0; s >>= 1) {
        if (tid < s) red[tid] += red[tid + s];
        __syncthreads();
    }
    if (tid == 0) {
        lse[i] = rowmax + logf(red[0]);
        diag[i] = sdiag;
    }
}

__global__ void loss_kernel(const float* __restrict__ lse,
                            const float* __restrict__ diag,
                            float* __restrict__ out) {
    __shared__ float r1[256], r2[256];
    const int tid = threadIdx.x;
    float s1 = 0.0f, s2 = 0.0f;
    for (int i = tid; i < 512; i += 256) {
        const float l = lse[i];
        s1 += l - diag[i];
        const float u = l + 1e-6f;
        s2 = fmaf(u, u, s2);
    }
    r1[tid] = s1; r2[tid] = s2;
    __syncthreads();
    for (int s = 128; s > 0; s >>= 1) {
        if (tid < s) { r1[tid] += r1[tid + s]; r2[tid] += r2[tid + s]; }
        __syncthreads();
    }
    if (tid == 0)
        out[0] = r1[0] * (1.0f / 512.0f) + 0.1f * r2[0] * (1.0f / 512.0f);
}

// ---------------------------------------------------------------------------
// Host launcher
// ---------------------------------------------------------------------------
extern "C" void kernel_launch(void* const* d_in, const int* in_sizes, int n_in,
                              void* d_out, int out_size) {
    const float* curr = (const float*)d_in[0];
    const float* next = (const float*)d_in[1];
    const float* c1w = (const float*)d_in[2];
    const float* c1b = (const float*)d_in[3];
    const float* c2w = (const float*)d_in[4];
    const float* c2b = (const float*)d_in[5];
    const float* c3w = (const float*)d_in[6];
    const float* c3b = (const float*)d_in[7];
    const float* fcw = (const float*)d_in[8];
    const float* fcb = (const float*)d_in[9];
    const float* e1w = (const float*)d_in[10];
    const float* e1b = (const float*)d_in[11];
    const float* e2w = (const float*)d_in[12];
    const float* e2b = (const float*)d_in[13];
    const float* pw1 = (const float*)d_in[14];
    const float* pb1 = (const float*)d_in[15];
    const float* pw2 = (const float*)d_in[16];
    const float* pb2 = (const float*)d_in[17];

    u32 *p_w1f, *p_w2f, *p_w3f, *p_wfc, *p_we1, *p_we2, *p_wp1;
    __nv_bfloat16 *p_a1, *p_a2n, *p_feat;
    float *p_f, *p_h1, *p_phi, *p_hp, *p_cy, *p_lse, *p_diag, *p_part;
    cudaGetSymbolAddress((void**)&p_w1f, g_w1f);
    cudaGetSymbolAddress((void**)&p_w2f, g_w2f);
    cudaGetSymbolAddress((void**)&p_w3f, g_w3f);
    cudaGetSymbolAddress((void**)&p_wfc, g_wfc);
    cudaGetSymbolAddress((void**)&p_we1, g_we1);
    cudaGetSymbolAddress((void**)&p_we2, g_we2);
    cudaGetSymbolAddress((void**)&p_wp1, g_wp1);
    cudaGetSymbolAddress((void**)&p_a1, g_a1);
    cudaGetSymbolAddress((void**)&p_a2n, g_a2n);
    cudaGetSymbolAddress((void**)&p_feat, g_feat);
    cudaGetSymbolAddress((void**)&p_f, g_f);
    cudaGetSymbolAddress((void**)&p_h1, g_h1);
    cudaGetSymbolAddress((void**)&p_phi, g_phi);
    cudaGetSymbolAddress((void**)&p_hp, g_hp);
    cudaGetSymbolAddress((void**)&p_cy, g_cy);
    cudaGetSymbolAddress((void**)&p_lse, g_lse);
    cudaGetSymbolAddress((void**)&p_diag, g_diag);
    cudaGetSymbolAddress((void**)&p_part, g_part);

    const int SM1 = 26880 + 4096 * 4;    // 43264
    const int SM2 = 51200 + 4096 * 4;    // 67584
    const int SM3 = 23328 + 4608 * 4;    // 41760
    const int SMF = 30720 + 3584 * 4;    // 45056
    const int SMH = 34816 + 4096 * 4;    // 51200
    cudaFuncSetAttribute(conv1_mma, cudaFuncAttributeMaxDynamicSharedMemorySize, SM1);
    cudaFuncSetAttribute(conv2_mma, cudaFuncAttributeMaxDynamicSharedMemorySize, SM2);
    cudaFuncSetAttribute(conv3_mma, cudaFuncAttributeMaxDynamicSharedMemorySize, SM3);
    cudaFuncSetAttribute(fc_mma, cudaFuncAttributeMaxDynamicSharedMemorySize, SMF);
    cudaFuncSetAttribute(head_mma, cudaFuncAttributeMaxDynamicSharedMemorySize, SMH);

    prep1<<<16, 256>>>(c1w, p_w1f);
    prep2<<<64, 256>>>(c2w, p_w2f);
    prep3<<<72, 256>>>(c3w, p_w3f);
    prepfc<<<1568, 256>>>(fcw, p_wfc);
    prephead<<<128, 256>>>(e1w, p_we1, 32, 32768);
    prephead<<<32, 256>>>(e2w, p_we2, 8, 8192);
    prephead<<<128, 256>>>(pw1, p_wp1, 32, 32768);

    conv1_mma<<<dim3(512, 5), 320, SM1>>>(curr, next, p_w1f, c1b, p_a1);
    conv2_mma<<<dim3(512, 4), 352, SM2>>>(p_a1, p_w2f, c2b, p_a2n);
    conv3_mma<<<dim3(512, 4), 224, SM3>>>(p_a2n, p_w3f, c3b, p_feat);

    fc_mma<<<dim3(8, 4, 4), 256, SMF>>>(p_feat, p_wfc, p_part);
    combine_kernel<<<1024, 256>>>(p_part, fcb, p_f, 1024 * 256, 256, 4, 1);

    head_mma<<<dim3(8, 4), 256, SMH>>>(p_f, p_we1, e1b, p_h1, 32, 1);
    head_mma<<<dim3(8, 1), 256, SMH>>>(p_h1, p_we2, e2b, p_phi, 8, 0);
    head_mma<<<dim3(4, 4), 256, SMH>>>(p_f + (size_t)512 * 256, p_wp1, pb1, p_hp, 32, 1);

    cy_kernel<<<64, 256>>>(p_hp, pw2, pb2, p_cy);
    logits_kernel<<<512, 256>>>(p_phi, p_cy, p_lse, p_diag);
    loss_kernel<<<1, 256>>>(p_lse, p_diag, (float*)d_out);
}

// round 6
// speedup vs baseline: 5.3552x; 1.1401x over previous
#include <cuda_runtime.h>
#include <cuda_bf16.h>
#include <math.h>

#define NIMG 1024
typedef unsigned int u32;

// ---------------------------------------------------------------------------
// scratch
// ---------------------------------------------------------------------------
__device__ __align__(128) u32 g_w1f[16 * 4 * 64];
__device__ __align__(128) u32 g_w2f[32 * 8 * 64];
__device__ __align__(128) u32 g_w3f[36 * 8 * 64];
__device__ __align__(128) u32 g_wfc[196 * 32 * 64];
__device__ __align__(128) u32 g_we1[16 * 32 * 64];
__device__ __align__(128) u32 g_we2[16 * 8 * 64];
__device__ __align__(128) u32 g_wp1[16 * 32 * 64];
__device__ __align__(128) __nv_bfloat16 g_a1[(size_t)NIMG * 12800];
__device__ __align__(128) __nv_bfloat16 g_a2n[(size_t)NIMG * 81 * 64];
__device__ __align__(128) __nv_bfloat16 g_feat[(size_t)NIMG * 3136];
__device__ __align__(128) float g_f[NIMG * 256];
__device__ __align__(128) float g_h1[NIMG * 256];
__device__ __align__(128) float g_phi[NIMG * 64];
__device__ __align__(128) float g_hp[512 * 256];
__device__ __align__(128) float g_cy[512];
__device__ __align__(128) float g_lse[512];
__device__ __align__(128) float g_diag[512];
__device__ __align__(128) float g_part[4 * 1024 * 256];

// ---------------------------------------------------------------------------
// helpers
// ---------------------------------------------------------------------------
__device__ __forceinline__ u32 packbf(float lo, float hi) {
    __nv_bfloat162 h = __float22bfloat162_rn(make_float2(lo, hi));
    return *reinterpret_cast<u32*>(&h);
}
__device__ __forceinline__ void mmabf(float* d, const u32* a, const u32* b) {
    asm volatile(
        "mma.sync.aligned.m16n8k16.row.col.f32.bf16.bf16.f32 "
        "{%0,%1,%2,%3},{%4,%5,%6,%7},{%8,%9},{%0,%1,%2,%3};\n"
        : "+f"(d[0]), "+f"(d[1]), "+f"(d[2]), "+f"(d[3])
        : "r"(a[0]), "r"(a[1]), "r"(a[2]), "r"(a[3]), "r"(b[0]), "r"(b[1]));
}

// ---------------------------------------------------------------------------
// unified weight prep (one launch). frag layout:
// wf[(c*NT+nt)*64 + lane*2 + s] = bf16x2 of W[k=c*16+s*8+2(lane&3)][n=nt*8+lane/4]
// ---------------------------------------------------------------------------
__global__ void prep_all(const float* __restrict__ c1w, const float* __restrict__ c2w,
                         const float* __restrict__ c3w, const float* __restrict__ fcw,
                         const float* __restrict__ e1w, const float* __restrict__ e2w,
                         const float* __restrict__ pw1,
                         u32* __restrict__ w1f, u32* __restrict__ w2f,
                         u32* __restrict__ w3f, u32* __restrict__ wfc,
                         u32* __restrict__ we1, u32* __restrict__ we2,
                         u32* __restrict__ wp1) {
    int gi = blockIdx.x * 256 + threadIdx.x;
    if (gi < 4096) {                               // conv1
        int i = gi;
        int s = i & 1, lane = (i >> 1) & 31;
        int cn = i >> 6, nt = cn & 3, c = cn >> 2;
        int t = lane & 3, g = lane >> 2;
        int n = nt * 8 + g;
        int ic = c >> 2, ky = (c & 3) * 2 + s, kx = 2 * t;
        const float* base = c1w + ((n * 4 + ic) * 8 + ky) * 8 + kx;
        w1f[i] = packbf(base[0], base[1]);
    } else if (gi < 20480) {                       // conv2
        int i = gi - 4096;
        int s = i & 1, lane = (i >> 1) & 31;
        int cn = i >> 6, nt = cn & 7, ic = cn >> 3;
        int t = lane & 3, g = lane >> 2;
        int n = nt * 8 + g;
        int ky = s * 2 + (t >> 1), kx = (t & 1) * 2;
        const float* base = c2w + ((n * 32 + ic) * 4 + ky) * 4 + kx;
        w2f[i] = packbf(base[0], base[1]);
    } else if (gi < 38912) {                       // conv3
        int i = gi - 20480;
        int s = i & 1, lane = (i >> 1) & 31;
        int cn = i >> 6, nt = cn & 7, c = cn >> 3;
        int t = lane & 3, g = lane >> 2;
        int n = nt * 8 + g;
        int p = c >> 2, icc = c & 3;
        int ic = icc * 16 + s * 8 + 2 * t;
        int ky = p / 3, kx = p % 3;
        float lo = c3w[((n * 64 + ic) * 3 + ky) * 3 + kx];
        float hi = c3w[((n * 64 + ic + 1) * 3 + ky) * 3 + kx];
        w3f[i] = packbf(lo, hi);
    } else if (gi < 440320) {                      // fc
        int i = gi - 38912;
        int s = i & 1, lane = (i >> 1) & 31;
        int cn = i >> 6, nt = cn & 31, c = cn >> 5;
        int t = lane & 3, g = lane >> 2;
        int n = nt * 8 + g;
        int k0 = c * 16 + s * 8 + 2 * t;
        wfc[i] = packbf(fcw[(size_t)k0 * 256 + n], fcw[(size_t)(k0 + 1) * 256 + n]);
    } else if (gi < 473088) {                      // e1 (NTg=32)
        int i = gi - 440320;
        int s = i & 1, lane = (i >> 1) & 31;
        int cn = i >> 6, nt = cn & 31, c = cn >> 5;
        int t = lane & 3, g = lane >> 2;
        int n = nt * 8 + g;
        int k0 = c * 16 + s * 8 + 2 * t;
        we1[i] = packbf(e1w[(size_t)k0 * 256 + n], e1w[(size_t)(k0 + 1) * 256 + n]);
    } else if (gi < 481280) {                      // e2 (NTg=8)
        int i = gi - 473088;
        int s = i & 1, lane = (i >> 1) & 31;
        int cn = i >> 6, nt = cn & 7, c = cn >> 3;
        int t = lane & 3, g = lane >> 2;
        int n = nt * 8 + g;
        int k0 = c * 16 + s * 8 + 2 * t;
        we2[i] = packbf(e2w[(size_t)k0 * 64 + n], e2w[(size_t)(k0 + 1) * 64 + n]);
    } else if (gi < 514048) {                      // pw1 (NTg=32)
        int i = gi - 481280;
        int s = i & 1, lane = (i >> 1) & 31;
        int cn = i >> 6, nt = cn & 31, c = cn >> 5;
        int t = lane & 3, g = lane >> 2;
        int n = nt * 8 + g;
        int k0 = c * 16 + s * 8 + 2 * t;
        wp1[i] = packbf(pw1[(size_t)k0 * 256 + n], pw1[(size_t)(k0 + 1) * 256 + n]);
    }
}

// ---------------------------------------------------------------------------
// conv1: grid (512 pairs, 5 oy-groups), 160 thr (5 warps).
// Each warp computes its 16 pixels for BOTH images (M=32/warp): per chunk
// 8 A-LDS + 4 B-LDS + 8 MMA.
// ---------------------------------------------------------------------------
__global__ void conv1_mma(const float* __restrict__ curr,
                          const float* __restrict__ next,
                          const u32* __restrict__ wfu,
                          const float* __restrict__ bias,
                          __nv_bfloat16* __restrict__ out) {
    extern __shared__ char smc[];
    __nv_bfloat16* simg = (__nv_bfloat16*)smc;     // 2*6720 bf16
    u32* swf = (u32*)(smc + 26880);                 // 4096 u32
    const int p = blockIdx.x, oyg = blockIdx.y;
    const int iy0 = oyg * 16;
    const float* in0 = curr + (size_t)p * 28224;
    const float* in1 = next + (size_t)p * 28224;
    for (int i = threadIdx.x; i < 3360; i += 160) {
        int e = i * 4;
        int im = e / 6720, e2 = e % 6720;
        int ic = e2 / 1680, rem = e2 % 1680;
        const float* src = im ? in1 : in0;
        float4 v = *(const float4*)&src[ic * 7056 + iy0 * 84 + rem];
        u32* d = (u32*)&simg[e];
        d[0] = packbf(v.x, v.y);
        d[1] = packbf(v.z, v.w);
    }
    for (int i = threadIdx.x; i < 1024; i += 160)
        ((uint4*)swf)[i] = ((const uint4*)wfu)[i];
    __syncthreads();

    const int lane = threadIdx.x & 31, wid = threadIdx.x >> 5;
    const int t = lane & 3;
    const int r0 = wid * 16 + (lane >> 2), r1 = r0 + 8;
    const int b00 = (r0 / 20) * 336 + (r0 % 20) * 4 + 2 * t;
    const int b01 = (r1 / 20) * 336 + (r1 % 20) * 4 + 2 * t;

    float acc[2][4][4];
    #pragma unroll
    for (int nt = 0; nt < 4; nt++) {
        int oc = nt * 8 + t * 2;
        float b0 = bias[oc], b1 = bias[oc + 1];
        #pragma unroll
        for (int im = 0; im < 2; im++) {
            acc[im][nt][0] = b0; acc[im][nt][1] = b1;
            acc[im][nt][2] = b0; acc[im][nt][3] = b1;
        }
    }
    #pragma unroll
    for (int c = 0; c < 16; c++) {
        const int o = (c >> 2) * 1680 + ((c & 3) * 2) * 84;
        u32 a0[4], a1[4];
        a0[0] = *(const u32*)&simg[o + b00];
        a0[1] = *(const u32*)&simg[o + b01];
        a0[2] = *(const u32*)&simg[o + 84 + b00];
        a0[3] = *(const u32*)&simg[o + 84 + b01];
        a1[0] = *(const u32*)&simg[6720 + o + b00];
        a1[1] = *(const u32*)&simg[6720 + o + b01];
        a1[2] = *(const u32*)&simg[6720 + o + 84 + b00];
        a1[3] = *(const u32*)&simg[6720 + o + 84 + b01];
        const u32* wb = swf + c * 256 + lane * 2;
        #pragma unroll
        for (int nt = 0; nt < 4; nt++) {
            uint2 bv = *(const uint2*)&wb[nt * 64];
            u32 b[2] = {bv.x, bv.y};
            mmabf(acc[0][nt], a0, b);
            mmabf(acc[1][nt], a1, b);
        }
    }
    #pragma unroll
    for (int im = 0; im < 2; im++) {
        const int img = p + im * 512;
        __nv_bfloat16* ob = out + (size_t)img * 12800 + oyg * 80;
        #pragma unroll
        for (int nt = 0; nt < 4; nt++) {
            int oc = nt * 8 + t * 2;
            __nv_bfloat16* p0 = ob + (size_t)oc * 400;
            p0[r0]       = __float2bfloat16(fmaxf(acc[im][nt][0], 0.0f));
            p0[400 + r0] = __float2bfloat16(fmaxf(acc[im][nt][1], 0.0f));
            p0[r1]       = __float2bfloat16(fmaxf(acc[im][nt][2], 0.0f));
            p0[400 + r1] = __float2bfloat16(fmaxf(acc[im][nt][3], 0.0f));
        }
    }
}

// ---------------------------------------------------------------------------
// conv2: grid (512 pairs, 2 oc-halves), 352 thr. nt=4 (N=32 per block).
// ---------------------------------------------------------------------------
__global__ void conv2_mma(const __nv_bfloat16* __restrict__ a1,
                          const u32* __restrict__ wfu,
                          const float* __restrict__ bias,
                          __nv_bfloat16* __restrict__ out) {
    extern __shared__ char smc[];
    __nv_bfloat16* sin = (__nv_bfloat16*)smc;      // 25600 bf16
    u32* swf = (u32*)(smc + 51200);                 // 8192 u32
    const int p = blockIdx.x, q = blockIdx.y;
    const uint4* src = (const uint4*)(a1 + (size_t)p * 25600);
    for (int i = threadIdx.x; i < 3200; i += 352)
        ((uint4*)sin)[i] = src[i];
    for (int i = threadIdx.x; i < 2048; i += 352) {
        int cn = i >> 4, c = cn >> 2, ntl = cn & 3;
        ((uint4*)swf)[i] = *(const uint4*)&wfu[(c * 8 + q * 4 + ntl) * 64 + (i & 15) * 4];
    }
    __syncthreads();

    const int lane = threadIdx.x & 31, wid = threadIdx.x >> 5;
    const int t = lane & 3;
    const int r0 = wid * 16 + (lane >> 2), r1 = r0 + 8;
    const int gg0 = (r0 < 162) ? r0 : 161, gg1 = (r1 < 162) ? r1 : 161;
    const int im0 = gg0 / 81, px0 = gg0 % 81;
    const int im1 = gg1 / 81, px1 = gg1 % 81;
    const int toff = (t >> 1) * 20 + (t & 1) * 2;
    const int A0 = im0 * 12800 + (px0 / 9) * 40 + (px0 % 9) * 2 + toff;
    const int A1 = im1 * 12800 + (px1 / 9) * 40 + (px1 % 9) * 2 + toff;

    float acc[4][4];
    #pragma unroll
    for (int nt = 0; nt < 4; nt++) {
        int oc = q * 32 + nt * 8 + t * 2;
        float b0 = bias[oc], b1 = bias[oc + 1];
        acc[nt][0] = b0; acc[nt][1] = b1; acc[nt][2] = b0; acc[nt][3] = b1;
    }
    #pragma unroll 4
    for (int ic = 0; ic < 32; ic++) {
        u32 a[4];
        a[0] = *(const u32*)&sin[ic * 400 + A0];
        a[1] = *(const u32*)&sin[ic * 400 + A1];
        a[2] = *(const u32*)&sin[ic * 400 + 40 + A0];
        a[3] = *(const u32*)&sin[ic * 400 + 40 + A1];
        const u32* wb = swf + ic * 256 + lane * 2;
        #pragma unroll
        for (int nt = 0; nt < 4; nt++) {
            uint2 bv = *(const uint2*)&wb[nt * 64];
            u32 b[2] = {bv.x, bv.y};
            mmabf(acc[nt], a, b);
        }
    }
    #pragma unroll
    for (int nt = 0; nt < 4; nt++) {
        int oc = q * 32 + nt * 8 + t * 2;
        if (r0 < 162)
            *(u32*)&out[((size_t)(p * 2 + im0) * 81 + px0) * 64 + oc] =
                packbf(fmaxf(acc[nt][0], 0.0f), fmaxf(acc[nt][1], 0.0f));
        if (r1 < 162)
            *(u32*)&out[((size_t)(p * 2 + im1) * 81 + px1) * 64 + oc] =
                packbf(fmaxf(acc[nt][2], 0.0f), fmaxf(acc[nt][3], 0.0f));
    }
}

// ---------------------------------------------------------------------------
// conv3: grid (512, 2 oc-halves), 224 thr. nt=4 (N=32 per block).
// ---------------------------------------------------------------------------
__global__ void conv3_mma(const __nv_bfloat16* __restrict__ a2n,
                          const u32* __restrict__ wfu,
                          const float* __restrict__ bias,
                          __nv_bfloat16* __restrict__ feat) {
    extern __shared__ char smc[];
    __nv_bfloat16* sin = (__nv_bfloat16*)smc;      // 2*81*72 bf16
    u32* swf = (u32*)(smc + 23328);                 // 9216 u32
    const int q = blockIdx.y;
    const int imgb = blockIdx.x * 2;
    for (int i = threadIdx.x; i < 1296; i += 224) {
        int im = i / 648, r = i % 648;
        int px = r >> 3, qq = r & 7;
        *((uint4*)&sin[im * 5832 + px * 72]       + qq) =
        *((const uint4*)&a2n[((size_t)(imgb + im) * 81 + px) * 64] + qq);
    }
    for (int i = threadIdx.x; i < 2304; i += 224) {
        int cn = i >> 4, c = cn >> 2, ntl = cn & 3;
        ((uint4*)swf)[i] = *(const uint4*)&wfu[(c * 8 + q * 4 + ntl) * 64 + (i & 15) * 4];
    }
    __syncthreads();

    const int lane = threadIdx.x & 31, wid = threadIdx.x >> 5;
    const int t = lane & 3;
    const int r0 = wid * 16 + (lane >> 2), r1 = r0 + 8;
    const int g0 = (r0 < 98) ? r0 : 97, g1 = (r1 < 98) ? r1 : 97;
    const int im0 = g0 / 49, lp0 = g0 % 49;
    const int im1 = g1 / 49, lp1 = g1 % 49;
    const int A0 = im0 * 5832 + ((lp0 / 7) * 9 + lp0 % 7) * 72 + 2 * t;
    const int A1 = im1 * 5832 + ((lp1 / 7) * 9 + lp1 % 7) * 72 + 2 * t;

    float acc[4][4];
    #pragma unroll
    for (int nt = 0; nt < 4; nt++) {
        int oc = q * 32 + nt * 8 + t * 2;
        float b0 = bias[oc], b1 = bias[oc + 1];
        acc[nt][0] = b0; acc[nt][1] = b1; acc[nt][2] = b0; acc[nt][3] = b1;
    }
    #pragma unroll
    for (int p = 0; p < 9; p++) {
        const int rowoff = ((p / 3) * 9 + (p % 3)) * 72;
        #pragma unroll
        for (int icc = 0; icc < 4; icc++) {
            u32 a[4];
            a[0] = *(const u32*)&sin[A0 + rowoff + icc * 16];
            a[1] = *(const u32*)&sin[A1 + rowoff + icc * 16];
            a[2] = *(const u32*)&sin[A0 + rowoff + icc * 16 + 8];
            a[3] = *(const u32*)&sin[A1 + rowoff + icc * 16 + 8];
            const u32* wb = swf + (p * 4 + icc) * 256 + lane * 2;
            #pragma unroll
            for (int nt = 0; nt < 4; nt++) {
                uint2 bv = *(const uint2*)&wb[nt * 64];
                u32 b[2] = {bv.x, bv.y};
                mmabf(acc[nt], a, b);
            }
        }
    }
    #pragma unroll
    for (int nt = 0; nt < 4; nt++) {
        int oc = q * 32 + nt * 8 + t * 2;
        if (r0 < 98) {
            __nv_bfloat16* fb = feat + (size_t)(imgb + im0) * 3136 + oc * 49 + lp0;
            fb[0]  = __float2bfloat16(fmaxf(acc[nt][0], 0.0f));
            fb[49] = __float2bfloat16(fmaxf(acc[nt][1], 0.0f));
        }
        if (r1 < 98) {
            __nv_bfloat16* fb = feat + (size_t)(imgb + im1) * 3136 + oc * 49 + lp1;
            fb[0]  = __float2bfloat16(fmaxf(acc[nt][2], 0.0f));
            fb[49] = __float2bfloat16(fmaxf(acc[nt][3], 0.0f));
        }
    }
}

// ---------------------------------------------------------------------------
// FC (bf16 mma): [1024,3136]@[3136,256], split-K 4 -> fp32 partials.
// ---------------------------------------------------------------------------
__global__ void fc_mma(const __nv_bfloat16* __restrict__ feat,
                       const u32* __restrict__ wfu,
                       float* __restrict__ part) {
    extern __shared__ char smc[];
    __nv_bfloat16* sA = (__nv_bfloat16*)smc;       // 128*120 bf16
    u32* sB = (u32*)(smc + 30720);                  // 3584 u32
    const int mb = blockIdx.x, nb = blockIdx.y, z = blockIdx.z;
    const int m0b = mb * 128;
    const int lane = threadIdx.x & 31, wid = threadIdx.x >> 5;
    const int t = lane & 3, g = lane >> 2;

    float acc[8][4] = {};
    for (int it = 0; it < 7; it++) {
        const int kbase = z * 784 + it * 112;
        const int cbase = z * 49 + it * 7;
        __syncthreads();
        for (int i = threadIdx.x; i < 1792; i += 256) {
            int row = i / 14, seg = i % 14;
            *(uint4*)&sA[row * 120 + seg * 8] =
                *(const uint4*)&feat[(size_t)(m0b + row) * 3136 + kbase + seg * 8];
        }
        for (int i = threadIdx.x; i < 896; i += 256) {
            int cn = i >> 4, c_l = cn >> 3, ntl = cn & 7;
            ((uint4*)sB)[i] =
                *(const uint4*)&wfu[((size_t)(cbase + c_l) * 32 + nb * 8 + ntl) * 64 + (i & 15) * 4];
        }
        __syncthreads();
        #pragma unroll
        for (int c_l = 0; c_l < 7; c_l++) {
            const int ra = (wid * 16 + g) * 120 + c_l * 16 + 2 * t;
            u32 a[4];
            a[0] = *(const u32*)&sA[ra];
            a[1] = *(const u32*)&sA[ra + 8 * 120];
            a[2] = *(const u32*)&sA[ra + 8];
            a[3] = *(const u32*)&sA[ra + 8 * 120 + 8];
            const u32* wb = sB + c_l * 512 + lane * 2;
            #pragma unroll
            for (int nt = 0; nt < 8; nt++) {
                uint2 bv = *(const uint2*)&wb[nt * 64];
                u32 b[2] = {bv.x, bv.y};
                mmabf(acc[nt], a, b);
            }
        }
    }
    float* pb = part + (size_t)z * 262144;
    const int mr0 = m0b + wid * 16 + g, mr1 = mr0 + 8;
    #pragma unroll
    for (int nt = 0; nt < 8; nt++) {
        int col = nb * 64 + nt * 8 + 2 * t;
        *(float2*)&pb[(size_t)mr0 * 256 + col] = make_float2(acc[nt][0], acc[nt][1]);
        *(float2*)&pb[(size_t)mr1 * 256 + col] = make_float2(acc[nt][2], acc[nt][3]);
    }
}

__global__ void combine_kernel(const float* __restrict__ Cp,
                               const float* __restrict__ bias,
                               float* __restrict__ C,
                               int MN, int N, int nsplit, int doRelu) {
    const int idx = blockIdx.x * blockDim.x + threadIdx.x;
    if (idx >= MN) return;
    float s = bias[idx % N];
    for (int z = 0; z < nsplit; z++) s += Cp[(size_t)z * MN + idx];
    if (doRelu) s = fmaxf(s, 0.0f);
    C[idx] = s;
}

// ---------------------------------------------------------------------------
// head GEMM body (bf16 mma): C[:,N] = relu?(A[:,256] @ W + b), one 128x64 tile.
// ---------------------------------------------------------------------------
__device__ void head_body(const float* __restrict__ A,
                          const u32* __restrict__ wfu,
                          const float* __restrict__ bias,
                          float* __restrict__ C,
                          int NTg, int doRelu, int mb, int nb) {
    extern __shared__ char smc[];
    __nv_bfloat16* sA = (__nv_bfloat16*)smc;       // 128*136 bf16
    u32* sB = (u32*)(smc + 34816);                  // 4096 u32
    const int m0b = mb * 128;
    const int N = NTg * 8;
    const int lane = threadIdx.x & 31, wid = threadIdx.x >> 5;
    const int t = lane & 3, g = lane >> 2;

    float acc[8][4] = {};
    #pragma unroll
    for (int it = 0; it < 2; it++) {
        const int kbase = it * 128;
        __syncthreads();
        for (int i = threadIdx.x; i < 4096; i += 256) {
            int row = i >> 5, seg = i & 31;
            float4 v = *(const float4*)&A[(size_t)(m0b + row) * 256 + kbase + seg * 4];
            u32* d = (u32*)&sA[row * 136 + seg * 4];
            d[0] = packbf(v.x, v.y);
            d[1] = packbf(v.z, v.w);
        }
        for (int i = threadIdx.x; i < 1024; i += 256) {
            int cn = i >> 4, c_l = cn >> 3, ntl = cn & 7;
            ((uint4*)sB)[i] =
                *(const uint4*)&wfu[(((it * 8 + c_l) * NTg) + nb * 8 + ntl) * 64 + (i & 15) * 4];
        }
        __syncthreads();
        #pragma unroll
        for (int c_l = 0; c_l < 8; c_l++) {
            const int ra = (wid * 16 + g) * 136 + c_l * 16 + 2 * t;
            u32 a[4];
            a[0] = *(const u32*)&sA[ra];
            a[1] = *(const u32*)&sA[ra + 8 * 136];
            a[2] = *(const u32*)&sA[ra + 8];
            a[3] = *(const u32*)&sA[ra + 8 * 136 + 8];
            const u32* wb = sB + c_l * 512 + lane * 2;
            #pragma unroll
            for (int nt = 0; nt < 8; nt++) {
                uint2 bv = *(const uint2*)&wb[nt * 64];
                u32 b[2] = {bv.x, bv.y};
                mmabf(acc[nt], a, b);
            }
        }
    }
    const int mr0 = m0b + wid * 16 + g, mr1 = mr0 + 8;
    #pragma unroll
    for (int nt = 0; nt < 8; nt++) {
        int col = nb * 64 + nt * 8 + 2 * t;
        float b0 = bias[col], b1 = bias[col + 1];
        float v00 = acc[nt][0] + b0, v01 = acc[nt][1] + b1;
        float v10 = acc[nt][2] + b0, v11 = acc[nt][3] + b1;
        if (doRelu) {
            v00 = fmaxf(v00, 0.0f); v01 = fmaxf(v01, 0.0f);
            v10 = fmaxf(v10, 0.0f); v11 = fmaxf(v11, 0.0f);
        }
        *(float2*)&C[(size_t)mr0 * N + col] = make_float2(v00, v01);
        *(float2*)&C[(size_t)mr1 * N + col] = make_float2(v10, v11);
    }
}

// headA: blocks 0-31 -> h1 = relu(f@e1w+e1b); blocks 32-47 -> hp = relu(f_next@pw1+pb1)
__global__ void headA(const float* __restrict__ f,
                      const u32* __restrict__ we1, const float* __restrict__ e1b,
                      float* __restrict__ h1,
                      const u32* __restrict__ wp1, const float* __restrict__ pb1,
                      float* __restrict__ hp) {
    int bid = blockIdx.x;
    if (bid < 32) head_body(f, we1, e1b, h1, 32, 1, bid >> 2, bid & 3);
    else {
        bid -= 32;
        head_body(f + (size_t)512 * 256, wp1, pb1, hp, 32, 1, bid >> 2, bid & 3);
    }
}

// headB: blocks 0-7 -> phi = h1@e2w+e2b; blocks 8-71 -> c_y = hp.pw2+pb2
__global__ void headB(const float* __restrict__ h1,
                      const u32* __restrict__ we2, const float* __restrict__ e2b,
                      float* __restrict__ phi,
                      const float* __restrict__ hp,
                      const float* __restrict__ pw2, const float* __restrict__ pb2,
                      float* __restrict__ cy) {
    int bid = blockIdx.x;
    if (bid < 8) {
        head_body(h1, we2, e2b, phi, 8, 0, bid, 0);
    } else {
        const int gw = (bid - 8) * 8 + (threadIdx.x >> 5);
        const int lane = threadIdx.x & 31;
        float s = 0.0f;
        for (int k = lane; k < 256; k += 32)
            s = fmaf(hp[(size_t)gw * 256 + k], pw2[k], s);
        #pragma unroll
        for (int off = 16; off > 0; off >>= 1) s += __shfl_xor_sync(0xffffffffu, s, off);
        if (lane == 0) cy[gw] = s + pb2[0];
    }
}

// ---------------------------------------------------------------------------
// logits / loss
// ---------------------------------------------------------------------------
__global__ void logits_kernel(const float* __restrict__ phi,
                              const float* __restrict__ cy,
                              float* __restrict__ lse,
                              float* __restrict__ diag) {
    const int i = blockIdx.x;
    __shared__ float sx[64];
    __shared__ float red[256];
    __shared__ float sdiag;
    const int tid = threadIdx.x;
    if (tid < 64) sx[tid] = phi[(size_t)i * 64 + tid];
    __syncthreads();
    float lg[2];
    #pragma unroll
    for (int r = 0; r < 2; r++) {
        const int j = tid + r * 256;
        const float* y = phi + (size_t)(512 + j) * 64;
        float mx = 0.0f;
        #pragma unroll
        for (int k = 0; k < 32; k++) {
            float d = sx[k] - y[k];
            mx = fmaxf(mx, fmaxf(d, 0.0f));
        }
        float ss = 0.0f;
        #pragma unroll
        for (int k = 32; k < 64; k++) {
            float d = sx[k] - y[k];
            ss = fmaf(d, d, ss);
        }
        lg[r] = cy[j] - (mx + sqrtf(ss + 1e-8f));
        if (j == i) sdiag = lg[r];
    }
    red[tid] = fmaxf(lg[0], lg[1]);
    __syncthreads();
    for (int s = 128; s > 0; s >>= 1) {
        if (tid < s) red[tid] = fmaxf(red[tid], red[tid + s]);
        __syncthreads();
    }
    const float rowmax = red[0];
    __syncthreads();
    red[tid] = expf(lg[0] - rowmax) + expf(lg[1] - rowmax);
    __syncthreads();
    for (int s = 128; s > 0; s >>= 1) {
        if (tid < s) red[tid] += red[tid + s];
        __syncthreads();
    }
    if (tid == 0) {
        lse[i] = rowmax + logf(red[0]);
        diag[i] = sdiag;
    }
}

__global__ void loss_kernel(const float* __restrict__ lse,
                            const float* __restrict__ diag,
                            float* __restrict__ out) {
    __shared__ float r1[256], r2[256];
    const int tid = threadIdx.x;
    float s1 = 0.0f, s2 = 0.0f;
    for (int i = tid; i < 512; i += 256) {
        const float l = lse[i];
        s1 += l - diag[i];
        const float u = l + 1e-6f;
        s2 = fmaf(u, u, s2);
    }
    r1[tid] = s1; r2[tid] = s2;
    __syncthreads();
    for (int s = 128; s > 0; s >>= 1) {
        if (tid < s) { r1[tid] += r1[tid + s]; r2[tid] += r2[tid + s]; }
        __syncthreads();
    }
    if (tid == 0)
        out[0] = r1[0] * (1.0f / 512.0f) + 0.1f * r2[0] * (1.0f / 512.0f);
}

// ---------------------------------------------------------------------------
// Host launcher
// ---------------------------------------------------------------------------
extern "C" void kernel_launch(void* const* d_in, const int* in_sizes, int n_in,
                              void* d_out, int out_size) {
    const float* curr = (const float*)d_in[0];
    const float* next = (const float*)d_in[1];
    const float* c1w = (const float*)d_in[2];
    const float* c1b = (const float*)d_in[3];
    const float* c2w = (const float*)d_in[4];
    const float* c2b = (const float*)d_in[5];
    const float* c3w = (const float*)d_in[6];
    const float* c3b = (const float*)d_in[7];
    const float* fcw = (const float*)d_in[8];
    const float* fcb = (const float*)d_in[9];
    const float* e1w = (const float*)d_in[10];
    const float* e1b = (const float*)d_in[11];
    const float* e2w = (const float*)d_in[12];
    const float* e2b = (const float*)d_in[13];
    const float* pw1 = (const float*)d_in[14];
    const float* pb1 = (const float*)d_in[15];
    const float* pw2 = (const float*)d_in[16];
    const float* pb2 = (const float*)d_in[17];

    u32 *p_w1f, *p_w2f, *p_w3f, *p_wfc, *p_we1, *p_we2, *p_wp1;
    __nv_bfloat16 *p_a1, *p_a2n, *p_feat;
    float *p_f, *p_h1, *p_phi, *p_hp, *p_cy, *p_lse, *p_diag, *p_part;
    cudaGetSymbolAddress((void**)&p_w1f, g_w1f);
    cudaGetSymbolAddress((void**)&p_w2f, g_w2f);
    cudaGetSymbolAddress((void**)&p_w3f, g_w3f);
    cudaGetSymbolAddress((void**)&p_wfc, g_wfc);
    cudaGetSymbolAddress((void**)&p_we1, g_we1);
    cudaGetSymbolAddress((void**)&p_we2, g_we2);
    cudaGetSymbolAddress((void**)&p_wp1, g_wp1);
    cudaGetSymbolAddress((void**)&p_a1, g_a1);
    cudaGetSymbolAddress((void**)&p_a2n, g_a2n);
    cudaGetSymbolAddress((void**)&p_feat, g_feat);
    cudaGetSymbolAddress((void**)&p_f, g_f);
    cudaGetSymbolAddress((void**)&p_h1, g_h1);
    cudaGetSymbolAddress((void**)&p_phi, g_phi);
    cudaGetSymbolAddress((void**)&p_hp, g_hp);
    cudaGetSymbolAddress((void**)&p_cy, g_cy);
    cudaGetSymbolAddress((void**)&p_lse, g_lse);
    cudaGetSymbolAddress((void**)&p_diag, g_diag);
    cudaGetSymbolAddress((void**)&p_part, g_part);

    const int SM1 = 26880 + 4096 * 4;    // 43264
    const int SM2 = 51200 + 8192 * 4;    // 83968
    const int SM3 = 23328 + 9216 * 4;    // 60192
    const int SMF = 30720 + 3584 * 4;    // 45056
    const int SMH = 34816 + 4096 * 4;    // 51200
    cudaFuncSetAttribute(conv1_mma, cudaFuncAttributeMaxDynamicSharedMemorySize, SM1);
    cudaFuncSetAttribute(conv2_mma, cudaFuncAttributeMaxDynamicSharedMemorySize, SM2);
    cudaFuncSetAttribute(conv3_mma, cudaFuncAttributeMaxDynamicSharedMemorySize, SM3);
    cudaFuncSetAttribute(fc_mma, cudaFuncAttributeMaxDynamicSharedMemorySize, SMF);
    cudaFuncSetAttribute(headA, cudaFuncAttributeMaxDynamicSharedMemorySize, SMH);
    cudaFuncSetAttribute(headB, cudaFuncAttributeMaxDynamicSharedMemorySize, SMH);

    prep_all<<<2008, 256>>>(c1w, c2w, c3w, fcw, e1w, e2w, pw1,
                            p_w1f, p_w2f, p_w3f, p_wfc, p_we1, p_we2, p_wp1);

    conv1_mma<<<dim3(512, 5), 160, SM1>>>(curr, next, p_w1f, c1b, p_a1);
    conv2_mma<<<dim3(512, 2), 352, SM2>>>(p_a1, p_w2f, c2b, p_a2n);
    conv3_mma<<<dim3(512, 2), 224, SM3>>>(p_a2n, p_w3f, c3b, p_feat);

    fc_mma<<<dim3(8, 4, 4), 256, SMF>>>(p_feat, p_wfc, p_part);
    combine_kernel<<<1024, 256>>>(p_part, fcb, p_f, 1024 * 256, 256, 4, 1);

    headA<<<48, 256, SMH>>>(p_f, p_we1, e1b, p_h1, p_wp1, pb1, p_hp);
    headB<<<72, 256, SMH>>>(p_h1, p_we2, e2b, p_phi, p_hp, pw2, pb2, p_cy);

    logits_kernel<<<512, 256>>>(p_phi, p_cy, p_lse, p_diag);
    loss_kernel<<<1, 256>>>(p_lse, p_diag, (float*)d_out);
}

// round 8
// speedup vs baseline: 6.0709x; 1.1336x over previous
#include <cuda_runtime.h>
#include <cuda_bf16.h>
#include <math.h>

#define NIMG 1024
typedef unsigned int u32;

// ---------------------------------------------------------------------------
// scratch
// ---------------------------------------------------------------------------
__device__ __align__(128) u32 g_w1f[16 * 4 * 64];
__device__ __align__(128) u32 g_w2f[32 * 8 * 64];
__device__ __align__(128) u32 g_w3f[36 * 8 * 64];
__device__ __align__(128) u32 g_wfc[196 * 32 * 64];
__device__ __align__(128) u32 g_we1[16 * 32 * 64];
__device__ __align__(128) u32 g_we2[16 * 8 * 64];
__device__ __align__(128) u32 g_wp1[16 * 32 * 64];
__device__ __align__(128) __nv_bfloat16 g_a1[(size_t)NIMG * 12800];
__device__ __align__(128) __nv_bfloat16 g_a2n[(size_t)NIMG * 81 * 64];
__device__ __align__(128) __nv_bfloat16 g_feat[(size_t)NIMG * 3136];
__device__ __align__(128) float g_f[NIMG * 256];
__device__ __align__(128) float g_h1[NIMG * 256];
__device__ __align__(128) float g_phi[NIMG * 64];
__device__ __align__(128) float g_hp[512 * 256];
__device__ __align__(128) float g_cy[512];
__device__ __align__(128) float g_lse[512];
__device__ __align__(128) float g_diag[512];
__device__ __align__(128) float g_part[4 * 1024 * 256];

// ---------------------------------------------------------------------------
// helpers
// ---------------------------------------------------------------------------
__device__ __forceinline__ u32 packbf(float lo, float hi) {
    __nv_bfloat162 h = __float22bfloat162_rn(make_float2(lo, hi));
    return *reinterpret_cast<u32*>(&h);
}
__device__ __forceinline__ void mmabf(float* d, const u32* a, const u32* b) {
    asm volatile(
        "mma.sync.aligned.m16n8k16.row.col.f32.bf16.bf16.f32 "
        "{%0,%1,%2,%3},{%4,%5,%6,%7},{%8,%9},{%0,%1,%2,%3};\n"
        : "+f"(d[0]), "+f"(d[1]), "+f"(d[2]), "+f"(d[3])
        : "r"(a[0]), "r"(a[1]), "r"(a[2]), "r"(a[3]), "r"(b[0]), "r"(b[1]));
}
__device__ __forceinline__ void ldsm4(u32* r, u32 addr) {
    asm volatile("ldmatrix.sync.aligned.m8n8.x4.shared.b16 {%0,%1,%2,%3}, [%4];"
                 : "=r"(r[0]), "=r"(r[1]), "=r"(r[2]), "=r"(r[3]) : "r"(addr));
}
__device__ __forceinline__ u32 smem_u32(const void* p) {
    u32 a;
    asm("{ .reg .u64 t; cvta.to.shared.u64 t, %1; cvt.u32.u64 %0, t; }"
        : "=r"(a) : "l"(p));
    return a;
}

// ---------------------------------------------------------------------------
// unified weight prep (one launch). frag layout:
// wf[(c*NT+nt)*64 + lane*2 + s] = bf16x2 of W[k=c*16+s*8+2(lane&3)][n=nt*8+lane/4]
// ---------------------------------------------------------------------------
__global__ void prep_all(const float* __restrict__ c1w, const float* __restrict__ c2w,
                         const float* __restrict__ c3w, const float* __restrict__ fcw,
                         const float* __restrict__ e1w, const float* __restrict__ e2w,
                         const float* __restrict__ pw1,
                         u32* __restrict__ w1f, u32* __restrict__ w2f,
                         u32* __restrict__ w3f, u32* __restrict__ wfc,
                         u32* __restrict__ we1, u32* __restrict__ we2,
                         u32* __restrict__ wp1) {
    int gi = blockIdx.x * 256 + threadIdx.x;
    if (gi < 4096) {                               // conv1
        int i = gi;
        int s = i & 1, lane = (i >> 1) & 31;
        int cn = i >> 6, nt = cn & 3, c = cn >> 2;
        int t = lane & 3, g = lane >> 2;
        int n = nt * 8 + g;
        int ic = c >> 2, ky = (c & 3) * 2 + s, kx = 2 * t;
        const float* base = c1w + ((n * 4 + ic) * 8 + ky) * 8 + kx;
        w1f[i] = packbf(base[0], base[1]);
    } else if (gi < 20480) {                       // conv2
        int i = gi - 4096;
        int s = i & 1, lane = (i >> 1) & 31;
        int cn = i >> 6, nt = cn & 7, ic = cn >> 3;
        int t = lane & 3, g = lane >> 2;
        int n = nt * 8 + g;
        int ky = s * 2 + (t >> 1), kx = (t & 1) * 2;
        const float* base = c2w + ((n * 32 + ic) * 4 + ky) * 4 + kx;
        w2f[i] = packbf(base[0], base[1]);
    } else if (gi < 38912) {                       // conv3
        int i = gi - 20480;
        int s = i & 1, lane = (i >> 1) & 31;
        int cn = i >> 6, nt = cn & 7, c = cn >> 3;
        int t = lane & 3, g = lane >> 2;
        int n = nt * 8 + g;
        int p = c >> 2, icc = c & 3;
        int ic = icc * 16 + s * 8 + 2 * t;
        int ky = p / 3, kx = p % 3;
        float lo = c3w[((n * 64 + ic) * 3 + ky) * 3 + kx];
        float hi = c3w[((n * 64 + ic + 1) * 3 + ky) * 3 + kx];
        w3f[i] = packbf(lo, hi);
    } else if (gi < 440320) {                      // fc
        int i = gi - 38912;
        int s = i & 1, lane = (i >> 1) & 31;
        int cn = i >> 6, nt = cn & 31, c = cn >> 5;
        int t = lane & 3, g = lane >> 2;
        int n = nt * 8 + g;
        int k0 = c * 16 + s * 8 + 2 * t;
        wfc[i] = packbf(fcw[(size_t)k0 * 256 + n], fcw[(size_t)(k0 + 1) * 256 + n]);
    } else if (gi < 473088) {                      // e1 (NTg=32)
        int i = gi - 440320;
        int s = i & 1, lane = (i >> 1) & 31;
        int cn = i >> 6, nt = cn & 31, c = cn >> 5;
        int t = lane & 3, g = lane >> 2;
        int n = nt * 8 + g;
        int k0 = c * 16 + s * 8 + 2 * t;
        we1[i] = packbf(e1w[(size_t)k0 * 256 + n], e1w[(size_t)(k0 + 1) * 256 + n]);
    } else if (gi < 481280) {                      // e2 (NTg=8)
        int i = gi - 473088;
        int s = i & 1, lane = (i >> 1) & 31;
        int cn = i >> 6, nt = cn & 7, c = cn >> 3;
        int t = lane & 3, g = lane >> 2;
        int n = nt * 8 + g;
        int k0 = c * 16 + s * 8 + 2 * t;
        we2[i] = packbf(e2w[(size_t)k0 * 64 + n], e2w[(size_t)(k0 + 1) * 64 + n]);
    } else if (gi < 514048) {                      // pw1 (NTg=32)
        int i = gi - 481280;
        int s = i & 1, lane = (i >> 1) & 31;
        int cn = i >> 6, nt = cn & 31, c = cn >> 5;
        int t = lane & 3, g = lane >> 2;
        int n = nt * 8 + g;
        int k0 = c * 16 + s * 8 + 2 * t;
        wp1[i] = packbf(pw1[(size_t)k0 * 256 + n], pw1[(size_t)(k0 + 1) * 256 + n]);
    }
}

// ---------------------------------------------------------------------------
// conv1: grid (512 pairs, 5 oy-groups), 160 thr. Scalar A loads (LDSM is
// NOT legal here: pixel rows are only 8B-aligned) + register double buffer.
// ---------------------------------------------------------------------------
__global__ void __launch_bounds__(160, 4)
conv1_mma(const float* __restrict__ curr,
          const float* __restrict__ next,
          const u32* __restrict__ wfu,
          const float* __restrict__ bias,
          __nv_bfloat16* __restrict__ out) {
    extern __shared__ char smc[];
    __nv_bfloat16* simg = (__nv_bfloat16*)smc;     // 2*6720 bf16
    u32* swf = (u32*)(smc + 26880);                 // 4096 u32
    const int p = blockIdx.x, oyg = blockIdx.y;
    const int iy0 = oyg * 16;
    const float* in0 = curr + (size_t)p * 28224;
    const float* in1 = next + (size_t)p * 28224;
    for (int i = threadIdx.x; i < 3360; i += 160) {
        int e = i * 4;
        int im = e / 6720, e2 = e % 6720;
        int ic = e2 / 1680, rem = e2 % 1680;
        const float* src = im ? in1 : in0;
        float4 v = *(const float4*)&src[ic * 7056 + iy0 * 84 + rem];
        u32* d = (u32*)&simg[e];
        d[0] = packbf(v.x, v.y);
        d[1] = packbf(v.z, v.w);
    }
    for (int i = threadIdx.x; i < 1024; i += 160)
        ((uint4*)swf)[i] = ((const uint4*)wfu)[i];
    __syncthreads();

    const int lane = threadIdx.x & 31, wid = threadIdx.x >> 5;
    const int t = lane & 3;
    const int r0 = wid * 16 + (lane >> 2), r1 = r0 + 8;
    const int b00 = (r0 / 20) * 336 + (r0 % 20) * 4 + 2 * t;
    const int b01 = (r1 / 20) * 336 + (r1 % 20) * 4 + 2 * t;

    float acc[2][4][4];
    #pragma unroll
    for (int nt = 0; nt < 4; nt++) {
        int oc = nt * 8 + t * 2;
        float b0 = bias[oc], b1 = bias[oc + 1];
        #pragma unroll
        for (int im = 0; im < 2; im++) {
            acc[im][nt][0] = b0; acc[im][nt][1] = b1;
            acc[im][nt][2] = b0; acc[im][nt][3] = b1;
        }
    }
    u32 a0[4], a1[4];
    uint2 bv[4];
    a0[0] = *(const u32*)&simg[b00];
    a0[1] = *(const u32*)&simg[b01];
    a0[2] = *(const u32*)&simg[84 + b00];
    a0[3] = *(const u32*)&simg[84 + b01];
    a1[0] = *(const u32*)&simg[6720 + b00];
    a1[1] = *(const u32*)&simg[6720 + b01];
    a1[2] = *(const u32*)&simg[6720 + 84 + b00];
    a1[3] = *(const u32*)&simg[6720 + 84 + b01];
    #pragma unroll
    for (int nt = 0; nt < 4; nt++)
        bv[nt] = *(const uint2*)&swf[nt * 64 + lane * 2];

    #pragma unroll
    for (int c = 0; c < 16; c++) {
        u32 na0[4], na1[4];
        uint2 nbv[4];
        if (c < 15) {
            const int o = ((c + 1) >> 2) * 1680 + ((c + 1) & 3) * 168;
            na0[0] = *(const u32*)&simg[o + b00];
            na0[1] = *(const u32*)&simg[o + b01];
            na0[2] = *(const u32*)&simg[o + 84 + b00];
            na0[3] = *(const u32*)&simg[o + 84 + b01];
            na1[0] = *(const u32*)&simg[6720 + o + b00];
            na1[1] = *(const u32*)&simg[6720 + o + b01];
            na1[2] = *(const u32*)&simg[6720 + o + 84 + b00];
            na1[3] = *(const u32*)&simg[6720 + o + 84 + b01];
            #pragma unroll
            for (int nt = 0; nt < 4; nt++)
                nbv[nt] = *(const uint2*)&swf[(c + 1) * 256 + nt * 64 + lane * 2];
        }
        #pragma unroll
        for (int nt = 0; nt < 4; nt++) {
            u32 b[2] = {bv[nt].x, bv[nt].y};
            mmabf(acc[0][nt], a0, b);
            mmabf(acc[1][nt], a1, b);
        }
        if (c < 15) {
            #pragma unroll
            for (int q = 0; q < 4; q++) { a0[q] = na0[q]; a1[q] = na1[q]; }
            #pragma unroll
            for (int nt = 0; nt < 4; nt++) bv[nt] = nbv[nt];
        }
    }
    #pragma unroll
    for (int im = 0; im < 2; im++) {
        const int img = p + im * 512;
        __nv_bfloat16* ob = out + (size_t)img * 12800 + oyg * 80;
        #pragma unroll
        for (int nt = 0; nt < 4; nt++) {
            int oc = nt * 8 + t * 2;
            __nv_bfloat16* p0 = ob + (size_t)oc * 400;
            p0[r0]       = __float2bfloat16(fmaxf(acc[im][nt][0], 0.0f));
            p0[400 + r0] = __float2bfloat16(fmaxf(acc[im][nt][1], 0.0f));
            p0[r1]       = __float2bfloat16(fmaxf(acc[im][nt][2], 0.0f));
            p0[400 + r1] = __float2bfloat16(fmaxf(acc[im][nt][3], 0.0f));
        }
    }
}

// ---------------------------------------------------------------------------
// conv2: grid (512 pairs, 2 oc-halves), 192 thr (6 warps x M=32). nt=4.
// Double-buffered scalar A loads.
// ---------------------------------------------------------------------------
__global__ void __launch_bounds__(192, 2)
conv2_mma(const __nv_bfloat16* __restrict__ a1,
          const u32* __restrict__ wfu,
          const float* __restrict__ bias,
          __nv_bfloat16* __restrict__ out) {
    extern __shared__ char smc[];
    __nv_bfloat16* sin = (__nv_bfloat16*)smc;      // 25600 bf16
    u32* swf = (u32*)(smc + 51200);                 // 8192 u32
    const int p = blockIdx.x, q = blockIdx.y;
    const uint4* src = (const uint4*)(a1 + (size_t)p * 25600);
    for (int i = threadIdx.x; i < 3200; i += 192)
        ((uint4*)sin)[i] = src[i];
    for (int i = threadIdx.x; i < 2048; i += 192) {
        int cn = i >> 4, c = cn >> 2, ntl = cn & 3;
        ((uint4*)swf)[i] = *(const uint4*)&wfu[(c * 8 + q * 4 + ntl) * 64 + (i & 15) * 4];
    }
    __syncthreads();

    const int lane = threadIdx.x & 31, wid = threadIdx.x >> 5;
    const int t = lane & 3;
    const int toff = (t >> 1) * 20 + (t & 1) * 2;
    const int rb = wid * 32 + (lane >> 2);
    int rr[4] = {rb, rb + 8, rb + 16, rb + 24};
    int AO[4], IM[4], PX[4];
    #pragma unroll
    for (int k = 0; k < 4; k++) {
        int gg = (rr[k] < 162) ? rr[k] : 161;
        IM[k] = gg / 81; PX[k] = gg % 81;
        AO[k] = IM[k] * 12800 + (PX[k] / 9) * 40 + (PX[k] % 9) * 2 + toff;
    }

    float acc[2][4][4];
    #pragma unroll
    for (int nt = 0; nt < 4; nt++) {
        int oc = q * 32 + nt * 8 + t * 2;
        float b0 = bias[oc], b1 = bias[oc + 1];
        #pragma unroll
        for (int G = 0; G < 2; G++) {
            acc[G][nt][0] = b0; acc[G][nt][1] = b1;
            acc[G][nt][2] = b0; acc[G][nt][3] = b1;
        }
    }

    u32 aG0[4], aG1[4];
    uint2 bv[4];
    aG0[0] = *(const u32*)&sin[AO[0]];
    aG0[1] = *(const u32*)&sin[AO[1]];
    aG0[2] = *(const u32*)&sin[40 + AO[0]];
    aG0[3] = *(const u32*)&sin[40 + AO[1]];
    aG1[0] = *(const u32*)&sin[AO[2]];
    aG1[1] = *(const u32*)&sin[AO[3]];
    aG1[2] = *(const u32*)&sin[40 + AO[2]];
    aG1[3] = *(const u32*)&sin[40 + AO[3]];
    #pragma unroll
    for (int nt = 0; nt < 4; nt++)
        bv[nt] = *(const uint2*)&swf[nt * 64 + lane * 2];

    #pragma unroll 8
    for (int ic = 0; ic < 32; ic++) {
        u32 na0[4], na1[4];
        uint2 nbv[4];
        if (ic < 31) {
            const int o = (ic + 1) * 400;
            na0[0] = *(const u32*)&sin[o + AO[0]];
            na0[1] = *(const u32*)&sin[o + AO[1]];
            na0[2] = *(const u32*)&sin[o + 40 + AO[0]];
            na0[3] = *(const u32*)&sin[o + 40 + AO[1]];
            na1[0] = *(const u32*)&sin[o + AO[2]];
            na1[1] = *(const u32*)&sin[o + AO[3]];
            na1[2] = *(const u32*)&sin[o + 40 + AO[2]];
            na1[3] = *(const u32*)&sin[o + 40 + AO[3]];
            #pragma unroll
            for (int nt = 0; nt < 4; nt++)
                nbv[nt] = *(const uint2*)&swf[(ic + 1) * 256 + nt * 64 + lane * 2];
        }
        #pragma unroll
        for (int nt = 0; nt < 4; nt++) {
            u32 b[2] = {bv[nt].x, bv[nt].y};
            mmabf(acc[0][nt], aG0, b);
            mmabf(acc[1][nt], aG1, b);
        }
        if (ic < 31) {
            #pragma unroll
            for (int k = 0; k < 4; k++) { aG0[k] = na0[k]; aG1[k] = na1[k]; }
            #pragma unroll
            for (int nt = 0; nt < 4; nt++) bv[nt] = nbv[nt];
        }
    }
    #pragma unroll
    for (int G = 0; G < 2; G++) {
        #pragma unroll
        for (int nt = 0; nt < 4; nt++) {
            int oc = q * 32 + nt * 8 + t * 2;
            const int k0 = G * 2, k1 = G * 2 + 1;
            if (rr[k0] < 162)
                *(u32*)&out[((size_t)(p * 2 + IM[k0]) * 81 + PX[k0]) * 64 + oc] =
                    packbf(fmaxf(acc[G][nt][0], 0.0f), fmaxf(acc[G][nt][1], 0.0f));
            if (rr[k1] < 162)
                *(u32*)&out[((size_t)(p * 2 + IM[k1]) * 81 + PX[k1]) * 64 + oc] =
                    packbf(fmaxf(acc[G][nt][2], 0.0f), fmaxf(acc[G][nt][3], 0.0f));
        }
    }
}

// ---------------------------------------------------------------------------
// conv3: grid (512, 2 oc-halves), 128 thr (4 warps x M=32). LDSM A + dbuf.
// (LDSM is legal here: row stride 144B and offsets icc*32+{0,16} are all
// 16B-aligned.)
// ---------------------------------------------------------------------------
__global__ void __launch_bounds__(128, 3)
conv3_mma(const __nv_bfloat16* __restrict__ a2n,
          const u32* __restrict__ wfu,
          const float* __restrict__ bias,
          __nv_bfloat16* __restrict__ feat) {
    extern __shared__ char smc[];
    __nv_bfloat16* sin = (__nv_bfloat16*)smc;      // 2*81*72 bf16
    u32* swf = (u32*)(smc + 23328);                 // 9216 u32
    const int q = blockIdx.y;
    const int imgb = blockIdx.x * 2;
    for (int i = threadIdx.x; i < 1296; i += 128) {
        int im = i / 648, r = i % 648;
        int px = r >> 3, qq = r & 7;
        *((uint4*)&sin[im * 5832 + px * 72]       + qq) =
        *((const uint4*)&a2n[((size_t)(imgb + im) * 81 + px) * 64] + qq);
    }
    for (int i = threadIdx.x; i < 2304; i += 128) {
        int cn = i >> 4, c = cn >> 2, ntl = cn & 3;
        ((uint4*)swf)[i] = *(const uint4*)&wfu[(c * 8 + q * 4 + ntl) * 64 + (i & 15) * 4];
    }
    __syncthreads();

    const int lane = threadIdx.x & 31, wid = threadIdx.x >> 5;
    const int t = lane & 3;
    const u32 sb = smem_u32(smc);
    u32 laG[2];
    #pragma unroll
    for (int G = 0; G < 2; G++) {
        int r = wid * 32 + G * 16 + (lane & 15);
        if (r > 97) r = 97;
        int im = r / 49, lp = r % 49;
        laG[G] = sb + (u32)(im * 11664 + ((lp / 7) * 9 + lp % 7) * 144)
                    + ((lane & 16) ? 16u : 0u);
    }

    float acc[2][4][4];
    #pragma unroll
    for (int nt = 0; nt < 4; nt++) {
        int oc = q * 32 + nt * 8 + t * 2;
        float b0 = bias[oc], b1 = bias[oc + 1];
        #pragma unroll
        for (int G = 0; G < 2; G++) {
            acc[G][nt][0] = b0; acc[G][nt][1] = b1;
            acc[G][nt][2] = b0; acc[G][nt][3] = b1;
        }
    }

    u32 a0[4], a1[4];
    uint2 bv[4];
    ldsm4(a0, laG[0]);
    ldsm4(a1, laG[1]);
    #pragma unroll
    for (int nt = 0; nt < 4; nt++)
        bv[nt] = *(const uint2*)&swf[nt * 64 + lane * 2];

    #pragma unroll
    for (int c = 0; c < 36; c++) {
        u32 na0[4], na1[4];
        uint2 nbv[4];
        if (c < 35) {
            const int pp = (c + 1) >> 2, icc = (c + 1) & 3;
            const u32 off = (u32)(((pp / 3) * 9 + (pp % 3)) * 144 + icc * 32);
            ldsm4(na0, laG[0] + off);
            ldsm4(na1, laG[1] + off);
            #pragma unroll
            for (int nt = 0; nt < 4; nt++)
                nbv[nt] = *(const uint2*)&swf[(c + 1) * 256 + nt * 64 + lane * 2];
        }
        #pragma unroll
        for (int nt = 0; nt < 4; nt++) {
            u32 b[2] = {bv[nt].x, bv[nt].y};
            mmabf(acc[0][nt], a0, b);
            mmabf(acc[1][nt], a1, b);
        }
        if (c < 35) {
            #pragma unroll
            for (int k = 0; k < 4; k++) { a0[k] = na0[k]; a1[k] = na1[k]; }
            #pragma unroll
            for (int nt = 0; nt < 4; nt++) bv[nt] = nbv[nt];
        }
    }
    #pragma unroll
    for (int G = 0; G < 2; G++) {
        const int r0 = wid * 32 + G * 16 + (lane >> 2), r1 = r0 + 8;
        const int g0 = (r0 < 98) ? r0 : 97, g1 = (r1 < 98) ? r1 : 97;
        const int im0 = g0 / 49, lp0 = g0 % 49;
        const int im1 = g1 / 49, lp1 = g1 % 49;
        #pragma unroll
        for (int nt = 0; nt < 4; nt++) {
            int oc = q * 32 + nt * 8 + t * 2;
            if (r0 < 98) {
                __nv_bfloat16* fb = feat + (size_t)(imgb + im0) * 3136 + oc * 49 + lp0;
                fb[0]  = __float2bfloat16(fmaxf(acc[G][nt][0], 0.0f));
                fb[49] = __float2bfloat16(fmaxf(acc[G][nt][1], 0.0f));
            }
            if (r1 < 98) {
                __nv_bfloat16* fb = feat + (size_t)(imgb + im1) * 3136 + oc * 49 + lp1;
                fb[0]  = __float2bfloat16(fmaxf(acc[G][nt][2], 0.0f));
                fb[49] = __float2bfloat16(fmaxf(acc[G][nt][3], 0.0f));
            }
        }
    }
}

// ---------------------------------------------------------------------------
// FC (bf16 mma): [1024,3136]@[3136,256], split-K 4 -> fp32 partials.
// ---------------------------------------------------------------------------
__global__ void fc_mma(const __nv_bfloat16* __restrict__ feat,
                       const u32* __restrict__ wfu,
                       float* __restrict__ part) {
    extern __shared__ char smc[];
    __nv_bfloat16* sA = (__nv_bfloat16*)smc;       // 128*120 bf16
    u32* sB = (u32*)(smc + 30720);                  // 3584 u32
    const int mb = blockIdx.x, nb = blockIdx.y, z = blockIdx.z;
    const int m0b = mb * 128;
    const int lane = threadIdx.x & 31, wid = threadIdx.x >> 5;
    const int t = lane & 3, g = lane >> 2;

    float acc[8][4] = {};
    for (int it = 0; it < 7; it++) {
        const int kbase = z * 784 + it * 112;
        const int cbase = z * 49 + it * 7;
        __syncthreads();
        for (int i = threadIdx.x; i < 1792; i += 256) {
            int row = i / 14, seg = i % 14;
            *(uint4*)&sA[row * 120 + seg * 8] =
                *(const uint4*)&feat[(size_t)(m0b + row) * 3136 + kbase + seg * 8];
        }
        for (int i = threadIdx.x; i < 896; i += 256) {
            int cn = i >> 4, c_l = cn >> 3, ntl = cn & 7;
            ((uint4*)sB)[i] =
                *(const uint4*)&wfu[((size_t)(cbase + c_l) * 32 + nb * 8 + ntl) * 64 + (i & 15) * 4];
        }
        __syncthreads();
        #pragma unroll
        for (int c_l = 0; c_l < 7; c_l++) {
            const int ra = (wid * 16 + g) * 120 + c_l * 16 + 2 * t;
            u32 a[4];
            a[0] = *(const u32*)&sA[ra];
            a[1] = *(const u32*)&sA[ra + 8 * 120];
            a[2] = *(const u32*)&sA[ra + 8];
            a[3] = *(const u32*)&sA[ra + 8 * 120 + 8];
            const u32* wb = sB + c_l * 512 + lane * 2;
            #pragma unroll
            for (int nt = 0; nt < 8; nt++) {
                uint2 bv = *(const uint2*)&wb[nt * 64];
                u32 b[2] = {bv.x, bv.y};
                mmabf(acc[nt], a, b);
            }
        }
    }
    float* pb = part + (size_t)z * 262144;
    const int mr0 = m0b + wid * 16 + g, mr1 = mr0 + 8;
    #pragma unroll
    for (int nt = 0; nt < 8; nt++) {
        int col = nb * 64 + nt * 8 + 2 * t;
        *(float2*)&pb[(size_t)mr0 * 256 + col] = make_float2(acc[nt][0], acc[nt][1]);
        *(float2*)&pb[(size_t)mr1 * 256 + col] = make_float2(acc[nt][2], acc[nt][3]);
    }
}

__global__ void combine_kernel(const float* __restrict__ Cp,
                               const float* __restrict__ bias,
                               float* __restrict__ C,
                               int MN, int N, int nsplit, int doRelu) {
    const int idx = blockIdx.x * blockDim.x + threadIdx.x;
    if (idx >= MN) return;
    float s = bias[idx % N];
    for (int z = 0; z < nsplit; z++) s += Cp[(size_t)z * MN + idx];
    if (doRelu) s = fmaxf(s, 0.0f);
    C[idx] = s;
}

// ---------------------------------------------------------------------------
// head GEMM body (bf16 mma): one 128x64 tile of relu?(A[:,256]@W+b).
// ---------------------------------------------------------------------------
__device__ void head_body(const float* __restrict__ A,
                          const u32* __restrict__ wfu,
                          const float* __restrict__ bias,
                          float* __restrict__ C,
                          int NTg, int doRelu, int mb, int nb) {
    extern __shared__ char smc[];
    __nv_bfloat16* sA = (__nv_bfloat16*)smc;       // 128*136 bf16
    u32* sB = (u32*)(smc + 34816);                  // 4096 u32
    const int m0b = mb * 128;
    const int N = NTg * 8;
    const int lane = threadIdx.x & 31, wid = threadIdx.x >> 5;
    const int t = lane & 3, g = lane >> 2;

    float acc[8][4] = {};
    #pragma unroll
    for (int it = 0; it < 2; it++) {
        const int kbase = it * 128;
        __syncthreads();
        for (int i = threadIdx.x; i < 4096; i += 256) {
            int row = i >> 5, seg = i & 31;
            float4 v = *(const float4*)&A[(size_t)(m0b + row) * 256 + kbase + seg * 4];
            u32* d = (u32*)&sA[row * 136 + seg * 4];
            d[0] = packbf(v.x, v.y);
            d[1] = packbf(v.z, v.w);
        }
        for (int i = threadIdx.x; i < 1024; i += 256) {
            int cn = i >> 4, c_l = cn >> 3, ntl = cn & 7;
            ((uint4*)sB)[i] =
                *(const uint4*)&wfu[(((it * 8 + c_l) * NTg) + nb * 8 + ntl) * 64 + (i & 15) * 4];
        }
        __syncthreads();
        #pragma unroll
        for (int c_l = 0; c_l < 8; c_l++) {
            const int ra = (wid * 16 + g) * 136 + c_l * 16 + 2 * t;
            u32 a[4];
            a[0] = *(const u32*)&sA[ra];
            a[1] = *(const u32*)&sA[ra + 8 * 136];
            a[2] = *(const u32*)&sA[ra + 8];
            a[3] = *(const u32*)&sA[ra + 8 * 136 + 8];
            const u32* wb = sB + c_l * 512 + lane * 2;
            #pragma unroll
            for (int nt = 0; nt < 8; nt++) {
                uint2 bv = *(const uint2*)&wb[nt * 64];
                u32 b[2] = {bv.x, bv.y};
                mmabf(acc[nt], a, b);
            }
        }
    }
    const int mr0 = m0b + wid * 16 + g, mr1 = mr0 + 8;
    #pragma unroll
    for (int nt = 0; nt < 8; nt++) {
        int col = nb * 64 + nt * 8 + 2 * t;
        float b0 = bias[col], b1 = bias[col + 1];
        float v00 = acc[nt][0] + b0, v01 = acc[nt][1] + b1;
        float v10 = acc[nt][2] + b0, v11 = acc[nt][3] + b1;
        if (doRelu) {
            v00 = fmaxf(v00, 0.0f); v01 = fmaxf(v01, 0.0f);
            v10 = fmaxf(v10, 0.0f); v11 = fmaxf(v11, 0.0f);
        }
        *(float2*)&C[(size_t)mr0 * N + col] = make_float2(v00, v01);
        *(float2*)&C[(size_t)mr1 * N + col] = make_float2(v10, v11);
    }
}

__global__ void headA(const float* __restrict__ f,
                      const u32* __restrict__ we1, const float* __restrict__ e1b,
                      float* __restrict__ h1,
                      const u32* __restrict__ wp1, const float* __restrict__ pb1,
                      float* __restrict__ hp) {
    int bid = blockIdx.x;
    if (bid < 32) head_body(f, we1, e1b, h1, 32, 1, bid >> 2, bid & 3);
    else {
        bid -= 32;
        head_body(f + (size_t)512 * 256, wp1, pb1, hp, 32, 1, bid >> 2, bid & 3);
    }
}

__global__ void headB(const float* __restrict__ h1,
                      const u32* __restrict__ we2, const float* __restrict__ e2b,
                      float* __restrict__ phi,
                      const float* __restrict__ hp,
                      const float* __restrict__ pw2, const float* __restrict__ pb2,
                      float* __restrict__ cy) {
    int bid = blockIdx.x;
    if (bid < 8) {
        head_body(h1, we2, e2b, phi, 8, 0, bid, 0);
    } else {
        const int gw = (bid - 8) * 8 + (threadIdx.x >> 5);
        const int lane = threadIdx.x & 31;
        float s = 0.0f;
        for (int k = lane; k < 256; k += 32)
            s = fmaf(hp[(size_t)gw * 256 + k], pw2[k], s);
        #pragma unroll
        for (int off = 16; off > 0; off >>= 1) s += __shfl_xor_sync(0xffffffffu, s, off);
        if (lane == 0) cy[gw] = s + pb2[0];
    }
}

// ---------------------------------------------------------------------------
// logits: 4 rows/block (grid 128).
// ---------------------------------------------------------------------------
__global__ void logits_kernel(const float* __restrict__ phi,
                              const float* __restrict__ cy,
                              float* __restrict__ lse,
                              float* __restrict__ diag) {
    const int i0 = blockIdx.x * 4;
    __shared__ float sx[4][64];
    __shared__ float red[256];
    __shared__ float sdiag[4];
    const int tid = threadIdx.x;
    sx[tid >> 6][tid & 63] = phi[(size_t)(i0 + (tid >> 6)) * 64 + (tid & 63)];
    __syncthreads();

    float lg[2][4];
    #pragma unroll
    for (int rep = 0; rep < 2; rep++) {
        const int j = tid + rep * 256;
        const float* y = phi + (size_t)(512 + j) * 64;
        float mx[4] = {0.f, 0.f, 0.f, 0.f}, ss[4] = {0.f, 0.f, 0.f, 0.f};
        #pragma unroll
        for (int k = 0; k < 32; k++) {
            const float yk = y[k];
            #pragma unroll
            for (int r = 0; r < 4; r++) {
                float d = sx[r][k] - yk;
                mx[r] = fmaxf(mx[r], fmaxf(d, 0.0f));
            }
        }
        #pragma unroll
        for (int k = 32; k < 64; k++) {
            const float yk = y[k];
            #pragma unroll
            for (int r = 0; r < 4; r++) {
                float d = sx[r][k] - yk;
                ss[r] = fmaf(d, d, ss[r]);
            }
        }
        const float cyj = cy[j];
        #pragma unroll
        for (int r = 0; r < 4; r++) {
            lg[rep][r] = cyj - (mx[r] + sqrtf(ss[r] + 1e-8f));
            if (j == i0 + r) sdiag[r] = lg[rep][r];
        }
    }
    #pragma unroll
    for (int r = 0; r < 4; r++) {
        __syncthreads();
        red[tid] = fmaxf(lg[0][r], lg[1][r]);
        __syncthreads();
        for (int s = 128; s > 0; s >>= 1) {
            if (tid < s) red[tid] = fmaxf(red[tid], red[tid + s]);
            __syncthreads();
        }
        const float rowmax = red[0];
        __syncthreads();
        red[tid] = expf(lg[0][r] - rowmax) + expf(lg[1][r] - rowmax);
        __syncthreads();
        for (int s = 128; s > 0; s >>= 1) {
            if (tid < s) red[tid] += red[tid + s];
            __syncthreads();
        }
        if (tid == 0) {
            lse[i0 + r] = rowmax + logf(red[0]);
            diag[i0 + r] = sdiag[r];
        }
    }
}

__global__ void loss_kernel(const float* __restrict__ lse,
                            const float* __restrict__ diag,
                            float* __restrict__ out) {
    __shared__ float r1[256], r2[256];
    const int tid = threadIdx.x;
    float s1 = 0.0f, s2 = 0.0f;
    for (int i = tid; i < 512; i += 256) {
        const float l = lse[i];
        s1 += l - diag[i];
        const float u = l + 1e-6f;
        s2 = fmaf(u, u, s2);
    }
    r1[tid] = s1; r2[tid] = s2;
    __syncthreads();
    for (int s = 128; s > 0; s >>= 1) {
        if (tid < s) { r1[tid] += r1[tid + s]; r2[tid] += r2[tid + s]; }
        __syncthreads();
    }
    if (tid == 0)
        out[0] = r1[0] * (1.0f / 512.0f) + 0.1f * r2[0] * (1.0f / 512.0f);
}

// ---------------------------------------------------------------------------
// Host launcher
// ---------------------------------------------------------------------------
extern "C" void kernel_launch(void* const* d_in, const int* in_sizes, int n_in,
                              void* d_out, int out_size) {
    const float* curr = (const float*)d_in[0];
    const float* next = (const float*)d_in[1];
    const float* c1w = (const float*)d_in[2];
    const float* c1b = (const float*)d_in[3];
    const float* c2w = (const float*)d_in[4];
    const float* c2b = (const float*)d_in[5];
    const float* c3w = (const float*)d_in[6];
    const float* c3b = (const float*)d_in[7];
    const float* fcw = (const float*)d_in[8];
    const float* fcb = (const float*)d_in[9];
    const float* e1w = (const float*)d_in[10];
    const float* e1b = (const float*)d_in[11];
    const float* e2w = (const float*)d_in[12];
    const float* e2b = (const float*)d_in[13];
    const float* pw1 = (const float*)d_in[14];
    const float* pb1 = (const float*)d_in[15];
    const float* pw2 = (const float*)d_in[16];
    const float* pb2 = (const float*)d_in[17];

    u32 *p_w1f, *p_w2f, *p_w3f, *p_wfc, *p_we1, *p_we2, *p_wp1;
    __nv_bfloat16 *p_a1, *p_a2n, *p_feat;
    float *p_f, *p_h1, *p_phi, *p_hp, *p_cy, *p_lse, *p_diag, *p_part;
    cudaGetSymbolAddress((void**)&p_w1f, g_w1f);
    cudaGetSymbolAddress((void**)&p_w2f, g_w2f);
    cudaGetSymbolAddress((void**)&p_w3f, g_w3f);
    cudaGetSymbolAddress((void**)&p_wfc, g_wfc);
    cudaGetSymbolAddress((void**)&p_we1, g_we1);
    cudaGetSymbolAddress((void**)&p_we2, g_we2);
    cudaGetSymbolAddress((void**)&p_wp1, g_wp1);
    cudaGetSymbolAddress((void**)&p_a1, g_a1);
    cudaGetSymbolAddress((void**)&p_a2n, g_a2n);
    cudaGetSymbolAddress((void**)&p_feat, g_feat);
    cudaGetSymbolAddress((void**)&p_f, g_f);
    cudaGetSymbolAddress((void**)&p_h1, g_h1);
    cudaGetSymbolAddress((void**)&p_phi, g_phi);
    cudaGetSymbolAddress((void**)&p_hp, g_hp);
    cudaGetSymbolAddress((void**)&p_cy, g_cy);
    cudaGetSymbolAddress((void**)&p_lse, g_lse);
    cudaGetSymbolAddress((void**)&p_diag, g_diag);
    cudaGetSymbolAddress((void**)&p_part, g_part);

    const int SM1 = 26880 + 4096 * 4;    // 43264
    const int SM2 = 51200 + 8192 * 4;    // 83968
    const int SM3 = 23328 + 9216 * 4;    // 60192
    const int SMF = 30720 + 3584 * 4;    // 45056
    const int SMH = 34816 + 4096 * 4;    // 51200
    cudaFuncSetAttribute(conv1_mma, cudaFuncAttributeMaxDynamicSharedMemorySize, SM1);
    cudaFuncSetAttribute(conv2_mma, cudaFuncAttributeMaxDynamicSharedMemorySize, SM2);
    cudaFuncSetAttribute(conv3_mma, cudaFuncAttributeMaxDynamicSharedMemorySize, SM3);
    cudaFuncSetAttribute(fc_mma, cudaFuncAttributeMaxDynamicSharedMemorySize, SMF);
    cudaFuncSetAttribute(headA, cudaFuncAttributeMaxDynamicSharedMemorySize, SMH);
    cudaFuncSetAttribute(headB, cudaFuncAttributeMaxDynamicSharedMemorySize, SMH);

    prep_all<<<2008, 256>>>(c1w, c2w, c3w, fcw, e1w, e2w, pw1,
                            p_w1f, p_w2f, p_w3f, p_wfc, p_we1, p_we2, p_wp1);

    conv1_mma<<<dim3(512, 5), 160, SM1>>>(curr, next, p_w1f, c1b, p_a1);
    conv2_mma<<<dim3(512, 2), 192, SM2>>>(p_a1, p_w2f, c2b, p_a2n);
    conv3_mma<<<dim3(512, 2), 128, SM3>>>(p_a2n, p_w3f, c3b, p_feat);

    fc_mma<<<dim3(8, 4, 4), 256, SMF>>>(p_feat, p_wfc, p_part);
    combine_kernel<<<1024, 256>>>(p_part, fcb, p_f, 1024 * 256, 256, 4, 1);

    headA<<<48, 256, SMH>>>(p_f, p_we1, e1b, p_h1, p_wp1, pb1, p_hp);
    headB<<<72, 256, SMH>>>(p_h1, p_we2, e2b, p_phi, p_hp, pw2, pb2, p_cy);

    logits_kernel<<<128, 256>>>(p_phi, p_cy, p_lse, p_diag);
    loss_kernel<<<1, 256>>>(p_lse, p_diag, (float*)d_out);
}

// round 9
// speedup vs baseline: 6.6647x; 1.0978x over previous
#include <cuda_runtime.h>
#include <cuda_bf16.h>
#include <math.h>

#define NIMG 1024
typedef unsigned int u32;

// ---------------------------------------------------------------------------
// scratch
// ---------------------------------------------------------------------------
__device__ __align__(128) u32 g_w1f[16 * 4 * 64];
__device__ __align__(128) u32 g_w2f[32 * 8 * 64];
__device__ __align__(128) u32 g_w3f[36 * 8 * 64];
__device__ __align__(128) u32 g_wfc[196 * 32 * 64];
__device__ __align__(128) u32 g_we1[16 * 32 * 64];
__device__ __align__(128) u32 g_we2[16 * 8 * 64];
__device__ __align__(128) u32 g_wp1[16 * 32 * 64];
__device__ __align__(128) __nv_bfloat16 g_a1[(size_t)NIMG * 12800];
__device__ __align__(128) __nv_bfloat16 g_a2n[(size_t)NIMG * 81 * 64];
__device__ __align__(128) __nv_bfloat16 g_feat[(size_t)NIMG * 3136];
__device__ __align__(128) float g_f[NIMG * 256];
__device__ __align__(128) float g_h1[NIMG * 256];
__device__ __align__(128) float g_phi[NIMG * 64];
__device__ __align__(128) float g_hp[512 * 256];
__device__ __align__(128) float g_cy[512];
__device__ __align__(128) float g_lse[512];
__device__ __align__(128) float g_diag[512];
__device__ __align__(128) float g_part[4 * 1024 * 256];

// ---------------------------------------------------------------------------
// helpers
// ---------------------------------------------------------------------------
__device__ __forceinline__ u32 packbf(float lo, float hi) {
    __nv_bfloat162 h = __float22bfloat162_rn(make_float2(lo, hi));
    return *reinterpret_cast<u32*>(&h);
}
__device__ __forceinline__ void mmabf(float* d, const u32* a, const u32* b) {
    asm volatile(
        "mma.sync.aligned.m16n8k16.row.col.f32.bf16.bf16.f32 "
        "{%0,%1,%2,%3},{%4,%5,%6,%7},{%8,%9},{%0,%1,%2,%3};\n"
        : "+f"(d[0]), "+f"(d[1]), "+f"(d[2]), "+f"(d[3])
        : "r"(a[0]), "r"(a[1]), "r"(a[2]), "r"(a[3]), "r"(b[0]), "r"(b[1]));
}
__device__ __forceinline__ void ldsm4(u32* r, u32 addr) {
    asm volatile("ldmatrix.sync.aligned.m8n8.x4.shared.b16 {%0,%1,%2,%3}, [%4];"
                 : "=r"(r[0]), "=r"(r[1]), "=r"(r[2]), "=r"(r[3]) : "r"(addr));
}
__device__ __forceinline__ u32 smem_u32(const void* p) {
    u32 a;
    asm("{ .reg .u64 t; cvta.to.shared.u64 t, %1; cvt.u32.u64 %0, t; }"
        : "=r"(a) : "l"(p));
    return a;
}

// ---------------------------------------------------------------------------
// unified weight prep (one launch). frag layout:
// wf[(c*NT+nt)*64 + lane*2 + s] = bf16x2 of W[k=c*16+s*8+2(lane&3)][n=nt*8+lane/4]
// ---------------------------------------------------------------------------
__global__ void prep_all(const float* __restrict__ c1w, const float* __restrict__ c2w,
                         const float* __restrict__ c3w, const float* __restrict__ fcw,
                         const float* __restrict__ e1w, const float* __restrict__ e2w,
                         const float* __restrict__ pw1,
                         u32* __restrict__ w1f, u32* __restrict__ w2f,
                         u32* __restrict__ w3f, u32* __restrict__ wfc,
                         u32* __restrict__ we1, u32* __restrict__ we2,
                         u32* __restrict__ wp1) {
    int gi = blockIdx.x * 256 + threadIdx.x;
    if (gi < 4096) {                               // conv1
        int i = gi;
        int s = i & 1, lane = (i >> 1) & 31;
        int cn = i >> 6, nt = cn & 3, c = cn >> 2;
        int t = lane & 3, g = lane >> 2;
        int n = nt * 8 + g;
        int ic = c >> 2, ky = (c & 3) * 2 + s, kx = 2 * t;
        const float* base = c1w + ((n * 4 + ic) * 8 + ky) * 8 + kx;
        w1f[i] = packbf(base[0], base[1]);
    } else if (gi < 20480) {                       // conv2
        int i = gi - 4096;
        int s = i & 1, lane = (i >> 1) & 31;
        int cn = i >> 6, nt = cn & 7, ic = cn >> 3;
        int t = lane & 3, g = lane >> 2;
        int n = nt * 8 + g;
        int ky = s * 2 + (t >> 1), kx = (t & 1) * 2;
        const float* base = c2w + ((n * 32 + ic) * 4 + ky) * 4 + kx;
        w2f[i] = packbf(base[0], base[1]);
    } else if (gi < 38912) {                       // conv3
        int i = gi - 20480;
        int s = i & 1, lane = (i >> 1) & 31;
        int cn = i >> 6, nt = cn & 7, c = cn >> 3;
        int t = lane & 3, g = lane >> 2;
        int n = nt * 8 + g;
        int p = c >> 2, icc = c & 3;
        int ic = icc * 16 + s * 8 + 2 * t;
        int ky = p / 3, kx = p % 3;
        float lo = c3w[((n * 64 + ic) * 3 + ky) * 3 + kx];
        float hi = c3w[((n * 64 + ic + 1) * 3 + ky) * 3 + kx];
        w3f[i] = packbf(lo, hi);
    } else if (gi < 440320) {                      // fc
        int i = gi - 38912;
        int s = i & 1, lane = (i >> 1) & 31;
        int cn = i >> 6, nt = cn & 31, c = cn >> 5;
        int t = lane & 3, g = lane >> 2;
        int n = nt * 8 + g;
        int k0 = c * 16 + s * 8 + 2 * t;
        wfc[i] = packbf(fcw[(size_t)k0 * 256 + n], fcw[(size_t)(k0 + 1) * 256 + n]);
    } else if (gi < 473088) {                      // e1 (NTg=32)
        int i = gi - 440320;
        int s = i & 1, lane = (i >> 1) & 31;
        int cn = i >> 6, nt = cn & 31, c = cn >> 5;
        int t = lane & 3, g = lane >> 2;
        int n = nt * 8 + g;
        int k0 = c * 16 + s * 8 + 2 * t;
        we1[i] = packbf(e1w[(size_t)k0 * 256 + n], e1w[(size_t)(k0 + 1) * 256 + n]);
    } else if (gi < 481280) {                      // e2 (NTg=8)
        int i = gi - 473088;
        int s = i & 1, lane = (i >> 1) & 31;
        int cn = i >> 6, nt = cn & 7, c = cn >> 3;
        int t = lane & 3, g = lane >> 2;
        int n = nt * 8 + g;
        int k0 = c * 16 + s * 8 + 2 * t;
        we2[i] = packbf(e2w[(size_t)k0 * 64 + n], e2w[(size_t)(k0 + 1) * 64 + n]);
    } else if (gi < 514048) {                      // pw1 (NTg=32)
        int i = gi - 481280;
        int s = i & 1, lane = (i >> 1) & 31;
        int cn = i >> 6, nt = cn & 31, c = cn >> 5;
        int t = lane & 3, g = lane >> 2;
        int n = nt * 8 + g;
        int k0 = c * 16 + s * 8 + 2 * t;
        wp1[i] = packbf(pw1[(size_t)k0 * 256 + n], pw1[(size_t)(k0 + 1) * 256 + n]);
    }
}

// ---------------------------------------------------------------------------
// conv1: grid (512 pairs, 5 oy-groups), 160 thr. Scalar A loads + dbuf.
// ---------------------------------------------------------------------------
__global__ void __launch_bounds__(160, 4)
conv1_mma(const float* __restrict__ curr,
          const float* __restrict__ next,
          const u32* __restrict__ wfu,
          const float* __restrict__ bias,
          __nv_bfloat16* __restrict__ out) {
    extern __shared__ char smc[];
    __nv_bfloat16* simg = (__nv_bfloat16*)smc;     // 2*6720 bf16
    u32* swf = (u32*)(smc + 26880);                 // 4096 u32
    const int p = blockIdx.x, oyg = blockIdx.y;
    const int iy0 = oyg * 16;
    const float* in0 = curr + (size_t)p * 28224;
    const float* in1 = next + (size_t)p * 28224;
    for (int i = threadIdx.x; i < 3360; i += 160) {
        int e = i * 4;
        int im = e / 6720, e2 = e % 6720;
        int ic = e2 / 1680, rem = e2 % 1680;
        const float* src = im ? in1 : in0;
        float4 v = *(const float4*)&src[ic * 7056 + iy0 * 84 + rem];
        u32* d = (u32*)&simg[e];
        d[0] = packbf(v.x, v.y);
        d[1] = packbf(v.z, v.w);
    }
    for (int i = threadIdx.x; i < 1024; i += 160)
        ((uint4*)swf)[i] = ((const uint4*)wfu)[i];
    __syncthreads();

    const int lane = threadIdx.x & 31, wid = threadIdx.x >> 5;
    const int t = lane & 3;
    const int r0 = wid * 16 + (lane >> 2), r1 = r0 + 8;
    const int b00 = (r0 / 20) * 336 + (r0 % 20) * 4 + 2 * t;
    const int b01 = (r1 / 20) * 336 + (r1 % 20) * 4 + 2 * t;

    float acc[2][4][4];
    #pragma unroll
    for (int nt = 0; nt < 4; nt++) {
        int oc = nt * 8 + t * 2;
        float b0 = bias[oc], b1 = bias[oc + 1];
        #pragma unroll
        for (int im = 0; im < 2; im++) {
            acc[im][nt][0] = b0; acc[im][nt][1] = b1;
            acc[im][nt][2] = b0; acc[im][nt][3] = b1;
        }
    }
    u32 a0[4], a1[4];
    uint2 bv[4];
    a0[0] = *(const u32*)&simg[b00];
    a0[1] = *(const u32*)&simg[b01];
    a0[2] = *(const u32*)&simg[84 + b00];
    a0[3] = *(const u32*)&simg[84 + b01];
    a1[0] = *(const u32*)&simg[6720 + b00];
    a1[1] = *(const u32*)&simg[6720 + b01];
    a1[2] = *(const u32*)&simg[6720 + 84 + b00];
    a1[3] = *(const u32*)&simg[6720 + 84 + b01];
    #pragma unroll
    for (int nt = 0; nt < 4; nt++)
        bv[nt] = *(const uint2*)&swf[nt * 64 + lane * 2];

    #pragma unroll
    for (int c = 0; c < 16; c++) {
        u32 na0[4], na1[4];
        uint2 nbv[4];
        if (c < 15) {
            const int o = ((c + 1) >> 2) * 1680 + ((c + 1) & 3) * 168;
            na0[0] = *(const u32*)&simg[o + b00];
            na0[1] = *(const u32*)&simg[o + b01];
            na0[2] = *(const u32*)&simg[o + 84 + b00];
            na0[3] = *(const u32*)&simg[o + 84 + b01];
            na1[0] = *(const u32*)&simg[6720 + o + b00];
            na1[1] = *(const u32*)&simg[6720 + o + b01];
            na1[2] = *(const u32*)&simg[6720 + o + 84 + b00];
            na1[3] = *(const u32*)&simg[6720 + o + 84 + b01];
            #pragma unroll
            for (int nt = 0; nt < 4; nt++)
                nbv[nt] = *(const uint2*)&swf[(c + 1) * 256 + nt * 64 + lane * 2];
        }
        #pragma unroll
        for (int nt = 0; nt < 4; nt++) {
            u32 b[2] = {bv[nt].x, bv[nt].y};
            mmabf(acc[0][nt], a0, b);
            mmabf(acc[1][nt], a1, b);
        }
        if (c < 15) {
            #pragma unroll
            for (int q = 0; q < 4; q++) { a0[q] = na0[q]; a1[q] = na1[q]; }
            #pragma unroll
            for (int nt = 0; nt < 4; nt++) bv[nt] = nbv[nt];
        }
    }
    #pragma unroll
    for (int im = 0; im < 2; im++) {
        const int img = p + im * 512;
        __nv_bfloat16* ob = out + (size_t)img * 12800 + oyg * 80;
        #pragma unroll
        for (int nt = 0; nt < 4; nt++) {
            int oc = nt * 8 + t * 2;
            __nv_bfloat16* p0 = ob + (size_t)oc * 400;
            p0[r0]       = __float2bfloat16(fmaxf(acc[im][nt][0], 0.0f));
            p0[400 + r0] = __float2bfloat16(fmaxf(acc[im][nt][1], 0.0f));
            p0[r1]       = __float2bfloat16(fmaxf(acc[im][nt][2], 0.0f));
            p0[400 + r1] = __float2bfloat16(fmaxf(acc[im][nt][3], 0.0f));
        }
    }
}

// ---------------------------------------------------------------------------
// conv2: grid (512 pairs, 2 oc-halves), 352 thr (11 warps, M=16/warp). nt=4.
// Double-buffered scalar A loads. 22 warps/SM.
// ---------------------------------------------------------------------------
__global__ void __launch_bounds__(352, 2)
conv2_mma(const __nv_bfloat16* __restrict__ a1,
          const u32* __restrict__ wfu,
          const float* __restrict__ bias,
          __nv_bfloat16* __restrict__ out) {
    extern __shared__ char smc[];
    __nv_bfloat16* sin = (__nv_bfloat16*)smc;      // 25600 bf16
    u32* swf = (u32*)(smc + 51200);                 // 8192 u32
    const int p = blockIdx.x, q = blockIdx.y;
    const uint4* src = (const uint4*)(a1 + (size_t)p * 25600);
    for (int i = threadIdx.x; i < 3200; i += 352)
        ((uint4*)sin)[i] = src[i];
    for (int i = threadIdx.x; i < 2048; i += 352) {
        int cn = i >> 4, c = cn >> 2, ntl = cn & 3;
        ((uint4*)swf)[i] = *(const uint4*)&wfu[(c * 8 + q * 4 + ntl) * 64 + (i & 15) * 4];
    }
    __syncthreads();

    const int lane = threadIdx.x & 31, wid = threadIdx.x >> 5;
    const int t = lane & 3;
    const int toff = (t >> 1) * 20 + (t & 1) * 2;
    const int r0 = wid * 16 + (lane >> 2), r1 = r0 + 8;
    const int gg0 = (r0 < 162) ? r0 : 161, gg1 = (r1 < 162) ? r1 : 161;
    const int im0 = gg0 / 81, px0 = gg0 % 81;
    const int im1 = gg1 / 81, px1 = gg1 % 81;
    const int A0 = im0 * 12800 + (px0 / 9) * 40 + (px0 % 9) * 2 + toff;
    const int A1 = im1 * 12800 + (px1 / 9) * 40 + (px1 % 9) * 2 + toff;

    float acc[4][4];
    #pragma unroll
    for (int nt = 0; nt < 4; nt++) {
        int oc = q * 32 + nt * 8 + t * 2;
        float b0 = bias[oc], b1 = bias[oc + 1];
        acc[nt][0] = b0; acc[nt][1] = b1; acc[nt][2] = b0; acc[nt][3] = b1;
    }

    u32 a[4];
    uint2 bv[4];
    a[0] = *(const u32*)&sin[A0];
    a[1] = *(const u32*)&sin[A1];
    a[2] = *(const u32*)&sin[40 + A0];
    a[3] = *(const u32*)&sin[40 + A1];
    #pragma unroll
    for (int nt = 0; nt < 4; nt++)
        bv[nt] = *(const uint2*)&swf[nt * 64 + lane * 2];

    #pragma unroll 8
    for (int ic = 0; ic < 32; ic++) {
        u32 na[4];
        uint2 nbv[4];
        if (ic < 31) {
            const int o = (ic + 1) * 400;
            na[0] = *(const u32*)&sin[o + A0];
            na[1] = *(const u32*)&sin[o + A1];
            na[2] = *(const u32*)&sin[o + 40 + A0];
            na[3] = *(const u32*)&sin[o + 40 + A1];
            #pragma unroll
            for (int nt = 0; nt < 4; nt++)
                nbv[nt] = *(const uint2*)&swf[(ic + 1) * 256 + nt * 64 + lane * 2];
        }
        #pragma unroll
        for (int nt = 0; nt < 4; nt++) {
            u32 b[2] = {bv[nt].x, bv[nt].y};
            mmabf(acc[nt], a, b);
        }
        if (ic < 31) {
            #pragma unroll
            for (int k = 0; k < 4; k++) a[k] = na[k];
            #pragma unroll
            for (int nt = 0; nt < 4; nt++) bv[nt] = nbv[nt];
        }
    }
    #pragma unroll
    for (int nt = 0; nt < 4; nt++) {
        int oc = q * 32 + nt * 8 + t * 2;
        if (r0 < 162)
            *(u32*)&out[((size_t)(p * 2 + im0) * 81 + px0) * 64 + oc] =
                packbf(fmaxf(acc[nt][0], 0.0f), fmaxf(acc[nt][1], 0.0f));
        if (r1 < 162)
            *(u32*)&out[((size_t)(p * 2 + im1) * 81 + px1) * 64 + oc] =
                packbf(fmaxf(acc[nt][2], 0.0f), fmaxf(acc[nt][3], 0.0f));
    }
}

// ---------------------------------------------------------------------------
// conv3: grid (512, 2 oc-halves), 224 thr (7 warps, M=16/warp). LDSM + dbuf.
// 21 warps/SM (3 blocks x 7 warps).
// ---------------------------------------------------------------------------
__global__ void __launch_bounds__(224, 3)
conv3_mma(const __nv_bfloat16* __restrict__ a2n,
          const u32* __restrict__ wfu,
          const float* __restrict__ bias,
          __nv_bfloat16* __restrict__ feat) {
    extern __shared__ char smc[];
    __nv_bfloat16* sin = (__nv_bfloat16*)smc;      // 2*81*72 bf16
    u32* swf = (u32*)(smc + 23328);                 // 9216 u32
    const int q = blockIdx.y;
    const int imgb = blockIdx.x * 2;
    for (int i = threadIdx.x; i < 1296; i += 224) {
        int im = i / 648, r = i % 648;
        int px = r >> 3, qq = r & 7;
        *((uint4*)&sin[im * 5832 + px * 72]       + qq) =
        *((const uint4*)&a2n[((size_t)(imgb + im) * 81 + px) * 64] + qq);
    }
    for (int i = threadIdx.x; i < 2304; i += 224) {
        int cn = i >> 4, c = cn >> 2, ntl = cn & 3;
        ((uint4*)swf)[i] = *(const uint4*)&wfu[(c * 8 + q * 4 + ntl) * 64 + (i & 15) * 4];
    }
    __syncthreads();

    const int lane = threadIdx.x & 31, wid = threadIdx.x >> 5;
    const int t = lane & 3;
    const u32 sb = smem_u32(smc);
    u32 la;
    {
        int r = wid * 16 + (lane & 15);
        if (r > 97) r = 97;
        int im = r / 49, lp = r % 49;
        la = sb + (u32)(im * 11664 + ((lp / 7) * 9 + lp % 7) * 144)
               + ((lane & 16) ? 16u : 0u);
    }

    float acc[4][4];
    #pragma unroll
    for (int nt = 0; nt < 4; nt++) {
        int oc = q * 32 + nt * 8 + t * 2;
        float b0 = bias[oc], b1 = bias[oc + 1];
        acc[nt][0] = b0; acc[nt][1] = b1; acc[nt][2] = b0; acc[nt][3] = b1;
    }

    u32 a[4];
    uint2 bv[4];
    ldsm4(a, la);
    #pragma unroll
    for (int nt = 0; nt < 4; nt++)
        bv[nt] = *(const uint2*)&swf[nt * 64 + lane * 2];

    #pragma unroll
    for (int c = 0; c < 36; c++) {
        u32 na[4];
        uint2 nbv[4];
        if (c < 35) {
            const int pp = (c + 1) >> 2, icc = (c + 1) & 3;
            const u32 off = (u32)(((pp / 3) * 9 + (pp % 3)) * 144 + icc * 32);
            ldsm4(na, la + off);
            #pragma unroll
            for (int nt = 0; nt < 4; nt++)
                nbv[nt] = *(const uint2*)&swf[(c + 1) * 256 + nt * 64 + lane * 2];
        }
        #pragma unroll
        for (int nt = 0; nt < 4; nt++) {
            u32 b[2] = {bv[nt].x, bv[nt].y};
            mmabf(acc[nt], a, b);
        }
        if (c < 35) {
            #pragma unroll
            for (int k = 0; k < 4; k++) a[k] = na[k];
            #pragma unroll
            for (int nt = 0; nt < 4; nt++) bv[nt] = nbv[nt];
        }
    }
    {
        const int r0 = wid * 16 + (lane >> 2), r1 = r0 + 8;
        const int g0 = (r0 < 98) ? r0 : 97, g1 = (r1 < 98) ? r1 : 97;
        const int im0 = g0 / 49, lp0 = g0 % 49;
        const int im1 = g1 / 49, lp1 = g1 % 49;
        #pragma unroll
        for (int nt = 0; nt < 4; nt++) {
            int oc = q * 32 + nt * 8 + t * 2;
            if (r0 < 98) {
                __nv_bfloat16* fb = feat + (size_t)(imgb + im0) * 3136 + oc * 49 + lp0;
                fb[0]  = __float2bfloat16(fmaxf(acc[nt][0], 0.0f));
                fb[49] = __float2bfloat16(fmaxf(acc[nt][1], 0.0f));
            }
            if (r1 < 98) {
                __nv_bfloat16* fb = feat + (size_t)(imgb + im1) * 3136 + oc * 49 + lp1;
                fb[0]  = __float2bfloat16(fmaxf(acc[nt][2], 0.0f));
                fb[49] = __float2bfloat16(fmaxf(acc[nt][3], 0.0f));
            }
        }
    }
}

// ---------------------------------------------------------------------------
// FC (bf16 mma): [1024,3136]@[3136,256], split-K 4 -> fp32 partials.
// ---------------------------------------------------------------------------
__global__ void fc_mma(const __nv_bfloat16* __restrict__ feat,
                       const u32* __restrict__ wfu,
                       float* __restrict__ part) {
    extern __shared__ char smc[];
    __nv_bfloat16* sA = (__nv_bfloat16*)smc;       // 128*120 bf16
    u32* sB = (u32*)(smc + 30720);                  // 3584 u32
    const int mb = blockIdx.x, nb = blockIdx.y, z = blockIdx.z;
    const int m0b = mb * 128;
    const int lane = threadIdx.x & 31, wid = threadIdx.x >> 5;
    const int t = lane & 3, g = lane >> 2;

    float acc[8][4] = {};
    for (int it = 0; it < 7; it++) {
        const int kbase = z * 784 + it * 112;
        const int cbase = z * 49 + it * 7;
        __syncthreads();
        for (int i = threadIdx.x; i < 1792; i += 256) {
            int row = i / 14, seg = i % 14;
            *(uint4*)&sA[row * 120 + seg * 8] =
                *(const uint4*)&feat[(size_t)(m0b + row) * 3136 + kbase + seg * 8];
        }
        for (int i = threadIdx.x; i < 896; i += 256) {
            int cn = i >> 4, c_l = cn >> 3, ntl = cn & 7;
            ((uint4*)sB)[i] =
                *(const uint4*)&wfu[((size_t)(cbase + c_l) * 32 + nb * 8 + ntl) * 64 + (i & 15) * 4];
        }
        __syncthreads();
        #pragma unroll
        for (int c_l = 0; c_l < 7; c_l++) {
            const int ra = (wid * 16 + g) * 120 + c_l * 16 + 2 * t;
            u32 a[4];
            a[0] = *(const u32*)&sA[ra];
            a[1] = *(const u32*)&sA[ra + 8 * 120];
            a[2] = *(const u32*)&sA[ra + 8];
            a[3] = *(const u32*)&sA[ra + 8 * 120 + 8];
            const u32* wb = sB + c_l * 512 + lane * 2;
            #pragma unroll
            for (int nt = 0; nt < 8; nt++) {
                uint2 bv = *(const uint2*)&wb[nt * 64];
                u32 b[2] = {bv.x, bv.y};
                mmabf(acc[nt], a, b);
            }
        }
    }
    float* pb = part + (size_t)z * 262144;
    const int mr0 = m0b + wid * 16 + g, mr1 = mr0 + 8;
    #pragma unroll
    for (int nt = 0; nt < 8; nt++) {
        int col = nb * 64 + nt * 8 + 2 * t;
        *(float2*)&pb[(size_t)mr0 * 256 + col] = make_float2(acc[nt][0], acc[nt][1]);
        *(float2*)&pb[(size_t)mr1 * 256 + col] = make_float2(acc[nt][2], acc[nt][3]);
    }
}

__global__ void combine_kernel(const float* __restrict__ Cp,
                               const float* __restrict__ bias,
                               float* __restrict__ C,
                               int MN, int N, int nsplit, int doRelu) {
    const int idx = blockIdx.x * blockDim.x + threadIdx.x;
    if (idx >= MN) return;
    float s = bias[idx % N];
    for (int z = 0; z < nsplit; z++) s += Cp[(size_t)z * MN + idx];
    if (doRelu) s = fmaxf(s, 0.0f);
    C[idx] = s;
}

// ---------------------------------------------------------------------------
// head GEMM body (bf16 mma): one 128x64 tile of relu?(A[:,256]@W+b).
// ---------------------------------------------------------------------------
__device__ void head_body(const float* __restrict__ A,
                          const u32* __restrict__ wfu,
                          const float* __restrict__ bias,
                          float* __restrict__ C,
                          int NTg, int doRelu, int mb, int nb) {
    extern __shared__ char smc[];
    __nv_bfloat16* sA = (__nv_bfloat16*)smc;       // 128*136 bf16
    u32* sB = (u32*)(smc + 34816);                  // 4096 u32
    const int m0b = mb * 128;
    const int N = NTg * 8;
    const int lane = threadIdx.x & 31, wid = threadIdx.x >> 5;
    const int t = lane & 3, g = lane >> 2;

    float acc[8][4] = {};
    #pragma unroll
    for (int it = 0; it < 2; it++) {
        const int kbase = it * 128;
        __syncthreads();
        for (int i = threadIdx.x; i < 4096; i += 256) {
            int row = i >> 5, seg = i & 31;
            float4 v = *(const float4*)&A[(size_t)(m0b + row) * 256 + kbase + seg * 4];
            u32* d = (u32*)&sA[row * 136 + seg * 4];
            d[0] = packbf(v.x, v.y);
            d[1] = packbf(v.z, v.w);
        }
        for (int i = threadIdx.x; i < 1024; i += 256) {
            int cn = i >> 4, c_l = cn >> 3, ntl = cn & 7;
            ((uint4*)sB)[i] =
                *(const uint4*)&wfu[(((it * 8 + c_l) * NTg) + nb * 8 + ntl) * 64 + (i & 15) * 4];
        }
        __syncthreads();
        #pragma unroll
        for (int c_l = 0; c_l < 8; c_l++) {
            const int ra = (wid * 16 + g) * 136 + c_l * 16 + 2 * t;
            u32 a[4];
            a[0] = *(const u32*)&sA[ra];
            a[1] = *(const u32*)&sA[ra + 8 * 136];
            a[2] = *(const u32*)&sA[ra + 8];
            a[3] = *(const u32*)&sA[ra + 8 * 136 + 8];
            const u32* wb = sB + c_l * 512 + lane * 2;
            #pragma unroll
            for (int nt = 0; nt < 8; nt++) {
                uint2 bv = *(const uint2*)&wb[nt * 64];
                u32 b[2] = {bv.x, bv.y};
                mmabf(acc[nt], a, b);
            }
        }
    }
    const int mr0 = m0b + wid * 16 + g, mr1 = mr0 + 8;
    #pragma unroll
    for (int nt = 0; nt < 8; nt++) {
        int col = nb * 64 + nt * 8 + 2 * t;
        float b0 = bias[col], b1 = bias[col + 1];
        float v00 = acc[nt][0] + b0, v01 = acc[nt][1] + b1;
        float v10 = acc[nt][2] + b0, v11 = acc[nt][3] + b1;
        if (doRelu) {
            v00 = fmaxf(v00, 0.0f); v01 = fmaxf(v01, 0.0f);
            v10 = fmaxf(v10, 0.0f); v11 = fmaxf(v11, 0.0f);
        }
        *(float2*)&C[(size_t)mr0 * N + col] = make_float2(v00, v01);
        *(float2*)&C[(size_t)mr1 * N + col] = make_float2(v10, v11);
    }
}

__global__ void headA(const float* __restrict__ f,
                      const u32* __restrict__ we1, const float* __restrict__ e1b,
                      float* __restrict__ h1,
                      const u32* __restrict__ wp1, const float* __restrict__ pb1,
                      float* __restrict__ hp) {
    int bid = blockIdx.x;
    if (bid < 32) head_body(f, we1, e1b, h1, 32, 1, bid >> 2, bid & 3);
    else {
        bid -= 32;
        head_body(f + (size_t)512 * 256, wp1, pb1, hp, 32, 1, bid >> 2, bid & 3);
    }
}

__global__ void headB(const float* __restrict__ h1,
                      const u32* __restrict__ we2, const float* __restrict__ e2b,
                      float* __restrict__ phi,
                      const float* __restrict__ hp,
                      const float* __restrict__ pw2, const float* __restrict__ pb2,
                      float* __restrict__ cy) {
    int bid = blockIdx.x;
    if (bid < 8) {
        head_body(h1, we2, e2b, phi, 8, 0, bid, 0);
    } else {
        const int gw = (bid - 8) * 8 + (threadIdx.x >> 5);
        const int lane = threadIdx.x & 31;
        float s = 0.0f;
        for (int k = lane; k < 256; k += 32)
            s = fmaf(hp[(size_t)gw * 256 + k], pw2[k], s);
        #pragma unroll
        for (int off = 16; off > 0; off >>= 1) s += __shfl_xor_sync(0xffffffffu, s, off);
        if (lane == 0) cy[gw] = s + pb2[0];
    }
}

// ---------------------------------------------------------------------------
// logits: 4 rows/block (grid 128).
// ---------------------------------------------------------------------------
__global__ void logits_kernel(const float* __restrict__ phi,
                              const float* __restrict__ cy,
                              float* __restrict__ lse,
                              float* __restrict__ diag) {
    const int i0 = blockIdx.x * 4;
    __shared__ float sx[4][64];
    __shared__ float red[256];
    __shared__ float sdiag[4];
    const int tid = threadIdx.x;
    sx[tid >> 6][tid & 63] = phi[(size_t)(i0 + (tid >> 6)) * 64 + (tid & 63)];
    __syncthreads();

    float lg[2][4];
    #pragma unroll
    for (int rep = 0; rep < 2; rep++) {
        const int j = tid + rep * 256;
        const float* y = phi + (size_t)(512 + j) * 64;
        float mx[4] = {0.f, 0.f, 0.f, 0.f}, ss[4] = {0.f, 0.f, 0.f, 0.f};
        #pragma unroll
        for (int k = 0; k < 32; k++) {
            const float yk = y[k];
            #pragma unroll
            for (int r = 0; r < 4; r++) {
                float d = sx[r][k] - yk;
                mx[r] = fmaxf(mx[r], fmaxf(d, 0.0f));
            }
        }
        #pragma unroll
        for (int k = 32; k < 64; k++) {
            const float yk = y[k];
            #pragma unroll
            for (int r = 0; r < 4; r++) {
                float d = sx[r][k] - yk;
                ss[r] = fmaf(d, d, ss[r]);
            }
        }
        const float cyj = cy[j];
        #pragma unroll
        for (int r = 0; r < 4; r++) {
            lg[rep][r] = cyj - (mx[r] + sqrtf(ss[r] + 1e-8f));
            if (j == i0 + r) sdiag[r] = lg[rep][r];
        }
    }
    #pragma unroll
    for (int r = 0; r < 4; r++) {
        __syncthreads();
        red[tid] = fmaxf(lg[0][r], lg[1][r]);
        __syncthreads();
        for (int s = 128; s > 0; s >>= 1) {
            if (tid < s) red[tid] = fmaxf(red[tid], red[tid + s]);
            __syncthreads();
        }
        const float rowmax = red[0];
        __syncthreads();
        red[tid] = expf(lg[0][r] - rowmax) + expf(lg[1][r] - rowmax);
        __syncthreads();
        for (int s = 128; s > 0; s >>= 1) {
            if (tid < s) red[tid] += red[tid + s];
            __syncthreads();
        }
        if (tid == 0) {
            lse[i0 + r] = rowmax + logf(red[0]);
            diag[i0 + r] = sdiag[r];
        }
    }
}

__global__ void loss_kernel(const float* __restrict__ lse,
                            const float* __restrict__ diag,
                            float* __restrict__ out) {
    __shared__ float r1[256], r2[256];
    const int tid = threadIdx.x;
    float s1 = 0.0f, s2 = 0.0f;
    for (int i = tid; i < 512; i += 256) {
        const float l = lse[i];
        s1 += l - diag[i];
        const float u = l + 1e-6f;
        s2 = fmaf(u, u, s2);
    }
    r1[tid] = s1; r2[tid] = s2;
    __syncthreads();
    for (int s = 128; s > 0; s >>= 1) {
        if (tid < s) { r1[tid] += r1[tid + s]; r2[tid] += r2[tid + s]; }
        __syncthreads();
    }
    if (tid == 0)
        out[0] = r1[0] * (1.0f / 512.0f) + 0.1f * r2[0] * (1.0f / 512.0f);
}

// ---------------------------------------------------------------------------
// Host launcher
// ---------------------------------------------------------------------------
extern "C" void kernel_launch(void* const* d_in, const int* in_sizes, int n_in,
                              void* d_out, int out_size) {
    const float* curr = (const float*)d_in[0];
    const float* next = (const float*)d_in[1];
    const float* c1w = (const float*)d_in[2];
    const float* c1b = (const float*)d_in[3];
    const float* c2w = (const float*)d_in[4];
    const float* c2b = (const float*)d_in[5];
    const float* c3w = (const float*)d_in[6];
    const float* c3b = (const float*)d_in[7];
    const float* fcw = (const float*)d_in[8];
    const float* fcb = (const float*)d_in[9];
    const float* e1w = (const float*)d_in[10];
    const float* e1b = (const float*)d_in[11];
    const float* e2w = (const float*)d_in[12];
    const float* e2b = (const float*)d_in[13];
    const float* pw1 = (const float*)d_in[14];
    const float* pb1 = (const float*)d_in[15];
    const float* pw2 = (const float*)d_in[16];
    const float* pb2 = (const float*)d_in[17];

    u32 *p_w1f, *p_w2f, *p_w3f, *p_wfc, *p_we1, *p_we2, *p_wp1;
    __nv_bfloat16 *p_a1, *p_a2n, *p_feat;
    float *p_f, *p_h1, *p_phi, *p_hp, *p_cy, *p_lse, *p_diag, *p_part;
    cudaGetSymbolAddress((void**)&p_w1f, g_w1f);
    cudaGetSymbolAddress((void**)&p_w2f, g_w2f);
    cudaGetSymbolAddress((void**)&p_w3f, g_w3f);
    cudaGetSymbolAddress((void**)&p_wfc, g_wfc);
    cudaGetSymbolAddress((void**)&p_we1, g_we1);
    cudaGetSymbolAddress((void**)&p_we2, g_we2);
    cudaGetSymbolAddress((void**)&p_wp1, g_wp1);
    cudaGetSymbolAddress((void**)&p_a1, g_a1);
    cudaGetSymbolAddress((void**)&p_a2n, g_a2n);
    cudaGetSymbolAddress((void**)&p_feat, g_feat);
    cudaGetSymbolAddress((void**)&p_f, g_f);
    cudaGetSymbolAddress((void**)&p_h1, g_h1);
    cudaGetSymbolAddress((void**)&p_phi, g_phi);
    cudaGetSymbolAddress((void**)&p_hp, g_hp);
    cudaGetSymbolAddress((void**)&p_cy, g_cy);
    cudaGetSymbolAddress((void**)&p_lse, g_lse);
    cudaGetSymbolAddress((void**)&p_diag, g_diag);
    cudaGetSymbolAddress((void**)&p_part, g_part);

    const int SM1 = 26880 + 4096 * 4;    // 43264
    const int SM2 = 51200 + 8192 * 4;    // 83968
    const int SM3 = 23328 + 9216 * 4;    // 60192
    const int SMF = 30720 + 3584 * 4;    // 45056
    const int SMH = 34816 + 4096 * 4;    // 51200
    cudaFuncSetAttribute(conv1_mma, cudaFuncAttributeMaxDynamicSharedMemorySize, SM1);
    cudaFuncSetAttribute(conv2_mma, cudaFuncAttributeMaxDynamicSharedMemorySize, SM2);
    cudaFuncSetAttribute(conv3_mma, cudaFuncAttributeMaxDynamicSharedMemorySize, SM3);
    cudaFuncSetAttribute(fc_mma, cudaFuncAttributeMaxDynamicSharedMemorySize, SMF);
    cudaFuncSetAttribute(headA, cudaFuncAttributeMaxDynamicSharedMemorySize, SMH);
    cudaFuncSetAttribute(headB, cudaFuncAttributeMaxDynamicSharedMemorySize, SMH);

    prep_all<<<2008, 256>>>(c1w, c2w, c3w, fcw, e1w, e2w, pw1,
                            p_w1f, p_w2f, p_w3f, p_wfc, p_we1, p_we2, p_wp1);

    conv1_mma<<<dim3(512, 5), 160, SM1>>>(curr, next, p_w1f, c1b, p_a1);
    conv2_mma<<<dim3(512, 2), 352, SM2>>>(p_a1, p_w2f, c2b, p_a2n);
    conv3_mma<<<dim3(512, 2), 224, SM3>>>(p_a2n, p_w3f, c3b, p_feat);

    fc_mma<<<dim3(8, 4, 4), 256, SMF>>>(p_feat, p_wfc, p_part);
    combine_kernel<<<1024, 256>>>(p_part, fcb, p_f, 1024 * 256, 256, 4, 1);

    headA<<<48, 256, SMH>>>(p_f, p_we1, e1b, p_h1, p_wp1, pb1, p_hp);
    headB<<<72, 256, SMH>>>(p_h1, p_we2, e2b, p_phi, p_hp, pw2, pb2, p_cy);

    logits_kernel<<<128, 256>>>(p_phi, p_cy, p_lse, p_diag);
    loss_kernel<<<1, 256>>>(p_lse, p_diag, (float*)d_out);
}

// round 10
// speedup vs baseline: 7.0289x; 1.0546x over previous
#include <cuda_runtime.h>
#include <cuda_bf16.h>
#include <math.h>

#define NIMG 1024
typedef unsigned int u32;

// ---------------------------------------------------------------------------
// scratch
// ---------------------------------------------------------------------------
__device__ __align__(128) u32 g_w1f[16 * 4 * 64];
__device__ __align__(128) u32 g_w2f[32 * 8 * 64];
__device__ __align__(128) u32 g_w3f[36 * 8 * 64];
__device__ __align__(128) u32 g_wfc[196 * 32 * 64];
__device__ __align__(128) u32 g_we1[16 * 32 * 64];
__device__ __align__(128) u32 g_we2[16 * 8 * 64];
__device__ __align__(128) u32 g_wp1[16 * 32 * 64];
__device__ __align__(128) __nv_bfloat16 g_a1[(size_t)NIMG * 12800];
__device__ __align__(128) __nv_bfloat16 g_a2n[(size_t)NIMG * 81 * 64];
__device__ __align__(128) __nv_bfloat16 g_feat[(size_t)NIMG * 3136];
__device__ __align__(128) float g_f[NIMG * 256];
__device__ __align__(128) float g_h1[NIMG * 256];
__device__ __align__(128) float g_phi[NIMG * 64];
__device__ __align__(128) float g_hp[512 * 256];
__device__ __align__(128) float g_cy[512];
__device__ __align__(128) float g_lse[512];
__device__ __align__(128) float g_diag[512];
__device__ __align__(128) float g_part[4 * 1024 * 256];

// ---------------------------------------------------------------------------
// helpers
// ---------------------------------------------------------------------------
__device__ __forceinline__ u32 packbf(float lo, float hi) {
    __nv_bfloat162 h = __float22bfloat162_rn(make_float2(lo, hi));
    return *reinterpret_cast<u32*>(&h);
}
__device__ __forceinline__ void mmabf(float* d, const u32* a, const u32* b) {
    asm volatile(
        "mma.sync.aligned.m16n8k16.row.col.f32.bf16.bf16.f32 "
        "{%0,%1,%2,%3},{%4,%5,%6,%7},{%8,%9},{%0,%1,%2,%3};\n"
        : "+f"(d[0]), "+f"(d[1]), "+f"(d[2]), "+f"(d[3])
        : "r"(a[0]), "r"(a[1]), "r"(a[2]), "r"(a[3]), "r"(b[0]), "r"(b[1]));
}
__device__ __forceinline__ void ldsm4(u32* r, u32 addr) {
    asm volatile("ldmatrix.sync.aligned.m8n8.x4.shared.b16 {%0,%1,%2,%3}, [%4];"
                 : "=r"(r[0]), "=r"(r[1]), "=r"(r[2]), "=r"(r[3]) : "r"(addr));
}
__device__ __forceinline__ u32 smem_u32(const void* p) {
    u32 a;
    asm("{ .reg .u64 t; cvta.to.shared.u64 t, %1; cvt.u32.u64 %0, t; }"
        : "=r"(a) : "l"(p));
    return a;
}

// ---------------------------------------------------------------------------
// unified weight prep (one launch). frag layout:
// wf[(c*NT+nt)*64 + lane*2 + s] = bf16x2 of W[k=c*16+s*8+2(lane&3)][n=nt*8+lane/4]
// ---------------------------------------------------------------------------
__global__ void prep_all(const float* __restrict__ c1w, const float* __restrict__ c2w,
                         const float* __restrict__ c3w, const float* __restrict__ fcw,
                         const float* __restrict__ e1w, const float* __restrict__ e2w,
                         const float* __restrict__ pw1,
                         u32* __restrict__ w1f, u32* __restrict__ w2f,
                         u32* __restrict__ w3f, u32* __restrict__ wfc,
                         u32* __restrict__ we1, u32* __restrict__ we2,
                         u32* __restrict__ wp1) {
    int gi = blockIdx.x * 256 + threadIdx.x;
    if (gi < 4096) {                               // conv1
        int i = gi;
        int s = i & 1, lane = (i >> 1) & 31;
        int cn = i >> 6, nt = cn & 3, c = cn >> 2;
        int t = lane & 3, g = lane >> 2;
        int n = nt * 8 + g;
        int ic = c >> 2, ky = (c & 3) * 2 + s, kx = 2 * t;
        const float* base = c1w + ((n * 4 + ic) * 8 + ky) * 8 + kx;
        w1f[i] = packbf(base[0], base[1]);
    } else if (gi < 20480) {                       // conv2
        int i = gi - 4096;
        int s = i & 1, lane = (i >> 1) & 31;
        int cn = i >> 6, nt = cn & 7, ic = cn >> 3;
        int t = lane & 3, g = lane >> 2;
        int n = nt * 8 + g;
        int ky = s * 2 + (t >> 1), kx = (t & 1) * 2;
        const float* base = c2w + ((n * 32 + ic) * 4 + ky) * 4 + kx;
        w2f[i] = packbf(base[0], base[1]);
    } else if (gi < 38912) {                       // conv3
        int i = gi - 20480;
        int s = i & 1, lane = (i >> 1) & 31;
        int cn = i >> 6, nt = cn & 7, c = cn >> 3;
        int t = lane & 3, g = lane >> 2;
        int n = nt * 8 + g;
        int p = c >> 2, icc = c & 3;
        int ic = icc * 16 + s * 8 + 2 * t;
        int ky = p / 3, kx = p % 3;
        float lo = c3w[((n * 64 + ic) * 3 + ky) * 3 + kx];
        float hi = c3w[((n * 64 + ic + 1) * 3 + ky) * 3 + kx];
        w3f[i] = packbf(lo, hi);
    } else if (gi < 440320) {                      // fc
        int i = gi - 38912;
        int s = i & 1, lane = (i >> 1) & 31;
        int cn = i >> 6, nt = cn & 31, c = cn >> 5;
        int t = lane & 3, g = lane >> 2;
        int n = nt * 8 + g;
        int k0 = c * 16 + s * 8 + 2 * t;
        wfc[i] = packbf(fcw[(size_t)k0 * 256 + n], fcw[(size_t)(k0 + 1) * 256 + n]);
    } else if (gi < 473088) {                      // e1 (NTg=32)
        int i = gi - 440320;
        int s = i & 1, lane = (i >> 1) & 31;
        int cn = i >> 6, nt = cn & 31, c = cn >> 5;
        int t = lane & 3, g = lane >> 2;
        int n = nt * 8 + g;
        int k0 = c * 16 + s * 8 + 2 * t;
        we1[i] = packbf(e1w[(size_t)k0 * 256 + n], e1w[(size_t)(k0 + 1) * 256 + n]);
    } else if (gi < 481280) {                      // e2 (NTg=8)
        int i = gi - 473088;
        int s = i & 1, lane = (i >> 1) & 31;
        int cn = i >> 6, nt = cn & 7, c = cn >> 3;
        int t = lane & 3, g = lane >> 2;
        int n = nt * 8 + g;
        int k0 = c * 16 + s * 8 + 2 * t;
        we2[i] = packbf(e2w[(size_t)k0 * 64 + n], e2w[(size_t)(k0 + 1) * 64 + n]);
    } else if (gi < 514048) {                      // pw1 (NTg=32)
        int i = gi - 481280;
        int s = i & 1, lane = (i >> 1) & 31;
        int cn = i >> 6, nt = cn & 31, c = cn >> 5;
        int t = lane & 3, g = lane >> 2;
        int n = nt * 8 + g;
        int k0 = c * 16 + s * 8 + 2 * t;
        wp1[i] = packbf(pw1[(size_t)k0 * 256 + n], pw1[(size_t)(k0 + 1) * 256 + n]);
    }
}

// ---------------------------------------------------------------------------
// conv1: grid (512 pairs, 5 oy-groups), 160 thr. Scalar A (smem) + B frags
// direct from gmem (L1-resident, 16KB shared by all blocks). smem 26.9KB
// -> ~7 blocks/SM (35 warps).
// ---------------------------------------------------------------------------
__global__ void __launch_bounds__(160, 7)
conv1_mma(const float* __restrict__ curr,
          const float* __restrict__ next,
          const u32* __restrict__ wfu,
          const float* __restrict__ bias,
          __nv_bfloat16* __restrict__ out) {
    extern __shared__ char smc[];
    __nv_bfloat16* simg = (__nv_bfloat16*)smc;     // 2*6720 bf16
    const int p = blockIdx.x, oyg = blockIdx.y;
    const int iy0 = oyg * 16;
    const float* in0 = curr + (size_t)p * 28224;
    const float* in1 = next + (size_t)p * 28224;
    for (int i = threadIdx.x; i < 3360; i += 160) {
        int e = i * 4;
        int im = e / 6720, e2 = e % 6720;
        int ic = e2 / 1680, rem = e2 % 1680;
        const float* src = im ? in1 : in0;
        float4 v = *(const float4*)&src[ic * 7056 + iy0 * 84 + rem];
        u32* d = (u32*)&simg[e];
        d[0] = packbf(v.x, v.y);
        d[1] = packbf(v.z, v.w);
    }
    __syncthreads();

    const int lane = threadIdx.x & 31, wid = threadIdx.x >> 5;
    const int t = lane & 3;
    const int r0 = wid * 16 + (lane >> 2), r1 = r0 + 8;
    const int b00 = (r0 / 20) * 336 + (r0 % 20) * 4 + 2 * t;
    const int b01 = (r1 / 20) * 336 + (r1 % 20) * 4 + 2 * t;
    const u32* wlane = wfu + lane * 2;

    float acc[2][4][4];
    #pragma unroll
    for (int nt = 0; nt < 4; nt++) {
        int oc = nt * 8 + t * 2;
        float b0 = bias[oc], b1 = bias[oc + 1];
        #pragma unroll
        for (int im = 0; im < 2; im++) {
            acc[im][nt][0] = b0; acc[im][nt][1] = b1;
            acc[im][nt][2] = b0; acc[im][nt][3] = b1;
        }
    }
    u32 a0[4], a1[4];
    uint2 bv[4];
    a0[0] = *(const u32*)&simg[b00];
    a0[1] = *(const u32*)&simg[b01];
    a0[2] = *(const u32*)&simg[84 + b00];
    a0[3] = *(const u32*)&simg[84 + b01];
    a1[0] = *(const u32*)&simg[6720 + b00];
    a1[1] = *(const u32*)&simg[6720 + b01];
    a1[2] = *(const u32*)&simg[6720 + 84 + b00];
    a1[3] = *(const u32*)&simg[6720 + 84 + b01];
    #pragma unroll
    for (int nt = 0; nt < 4; nt++)
        bv[nt] = *(const uint2*)&wlane[nt * 64];

    #pragma unroll
    for (int c = 0; c < 16; c++) {
        u32 na0[4], na1[4];
        uint2 nbv[4];
        if (c < 15) {
            const int o = ((c + 1) >> 2) * 1680 + ((c + 1) & 3) * 168;
            na0[0] = *(const u32*)&simg[o + b00];
            na0[1] = *(const u32*)&simg[o + b01];
            na0[2] = *(const u32*)&simg[o + 84 + b00];
            na0[3] = *(const u32*)&simg[o + 84 + b01];
            na1[0] = *(const u32*)&simg[6720 + o + b00];
            na1[1] = *(const u32*)&simg[6720 + o + b01];
            na1[2] = *(const u32*)&simg[6720 + o + 84 + b00];
            na1[3] = *(const u32*)&simg[6720 + o + 84 + b01];
            #pragma unroll
            for (int nt = 0; nt < 4; nt++)
                nbv[nt] = *(const uint2*)&wlane[((c + 1) * 4 + nt) * 64];
        }
        #pragma unroll
        for (int nt = 0; nt < 4; nt++) {
            u32 b[2] = {bv[nt].x, bv[nt].y};
            mmabf(acc[0][nt], a0, b);
            mmabf(acc[1][nt], a1, b);
        }
        if (c < 15) {
            #pragma unroll
            for (int q = 0; q < 4; q++) { a0[q] = na0[q]; a1[q] = na1[q]; }
            #pragma unroll
            for (int nt = 0; nt < 4; nt++) bv[nt] = nbv[nt];
        }
    }
    #pragma unroll
    for (int im = 0; im < 2; im++) {
        const int img = p + im * 512;
        __nv_bfloat16* ob = out + (size_t)img * 12800 + oyg * 80;
        #pragma unroll
        for (int nt = 0; nt < 4; nt++) {
            int oc = nt * 8 + t * 2;
            __nv_bfloat16* p0 = ob + (size_t)oc * 400;
            p0[r0]       = __float2bfloat16(fmaxf(acc[im][nt][0], 0.0f));
            p0[400 + r0] = __float2bfloat16(fmaxf(acc[im][nt][1], 0.0f));
            p0[r1]       = __float2bfloat16(fmaxf(acc[im][nt][2], 0.0f));
            p0[400 + r1] = __float2bfloat16(fmaxf(acc[im][nt][3], 0.0f));
        }
    }
}

// ---------------------------------------------------------------------------
// conv2: grid (512 pairs, 2 oc-halves), 352 thr. Scalar A (smem) + B frags
// direct from gmem. smem 51.2KB -> 3 blocks/SM (33 warps).
// ---------------------------------------------------------------------------
__global__ void __launch_bounds__(352, 3)
conv2_mma(const __nv_bfloat16* __restrict__ a1,
          const u32* __restrict__ wfu,
          const float* __restrict__ bias,
          __nv_bfloat16* __restrict__ out) {
    extern __shared__ char smc[];
    __nv_bfloat16* sin = (__nv_bfloat16*)smc;      // 25600 bf16
    const int p = blockIdx.x, q = blockIdx.y;
    const uint4* src = (const uint4*)(a1 + (size_t)p * 25600);
    for (int i = threadIdx.x; i < 3200; i += 352)
        ((uint4*)sin)[i] = src[i];
    __syncthreads();

    const int lane = threadIdx.x & 31, wid = threadIdx.x >> 5;
    const int t = lane & 3;
    const int toff = (t >> 1) * 20 + (t & 1) * 2;
    const int r0 = wid * 16 + (lane >> 2), r1 = r0 + 8;
    const int gg0 = (r0 < 162) ? r0 : 161, gg1 = (r1 < 162) ? r1 : 161;
    const int im0 = gg0 / 81, px0 = gg0 % 81;
    const int im1 = gg1 / 81, px1 = gg1 % 81;
    const int A0 = im0 * 12800 + (px0 / 9) * 40 + (px0 % 9) * 2 + toff;
    const int A1 = im1 * 12800 + (px1 / 9) * 40 + (px1 % 9) * 2 + toff;
    const u32* wlane = wfu + (size_t)q * 4 * 64 + lane * 2;

    float acc[4][4];
    #pragma unroll
    for (int nt = 0; nt < 4; nt++) {
        int oc = q * 32 + nt * 8 + t * 2;
        float b0 = bias[oc], b1 = bias[oc + 1];
        acc[nt][0] = b0; acc[nt][1] = b1; acc[nt][2] = b0; acc[nt][3] = b1;
    }

    u32 a[4];
    uint2 bv[4];
    a[0] = *(const u32*)&sin[A0];
    a[1] = *(const u32*)&sin[A1];
    a[2] = *(const u32*)&sin[40 + A0];
    a[3] = *(const u32*)&sin[40 + A1];
    #pragma unroll
    for (int nt = 0; nt < 4; nt++)
        bv[nt] = *(const uint2*)&wlane[nt * 64];

    #pragma unroll 8
    for (int ic = 0; ic < 32; ic++) {
        u32 na[4];
        uint2 nbv[4];
        if (ic < 31) {
            const int o = (ic + 1) * 400;
            na[0] = *(const u32*)&sin[o + A0];
            na[1] = *(const u32*)&sin[o + A1];
            na[2] = *(const u32*)&sin[o + 40 + A0];
            na[3] = *(const u32*)&sin[o + 40 + A1];
            #pragma unroll
            for (int nt = 0; nt < 4; nt++)
                nbv[nt] = *(const uint2*)&wlane[((ic + 1) * 8 + nt) * 64];
        }
        #pragma unroll
        for (int nt = 0; nt < 4; nt++) {
            u32 b[2] = {bv[nt].x, bv[nt].y};
            mmabf(acc[nt], a, b);
        }
        if (ic < 31) {
            #pragma unroll
            for (int k = 0; k < 4; k++) a[k] = na[k];
            #pragma unroll
            for (int nt = 0; nt < 4; nt++) bv[nt] = nbv[nt];
        }
    }
    #pragma unroll
    for (int nt = 0; nt < 4; nt++) {
        int oc = q * 32 + nt * 8 + t * 2;
        if (r0 < 162)
            *(u32*)&out[((size_t)(p * 2 + im0) * 81 + px0) * 64 + oc] =
                packbf(fmaxf(acc[nt][0], 0.0f), fmaxf(acc[nt][1], 0.0f));
        if (r1 < 162)
            *(u32*)&out[((size_t)(p * 2 + im1) * 81 + px1) * 64 + oc] =
                packbf(fmaxf(acc[nt][2], 0.0f), fmaxf(acc[nt][3], 0.0f));
    }
}

// ---------------------------------------------------------------------------
// conv3: grid (512, 2 oc-halves), 224 thr. LDSM A (smem) + B frags from gmem.
// smem 23.3KB -> ~5 blocks/SM (35 warps).
// ---------------------------------------------------------------------------
__global__ void __launch_bounds__(224, 5)
conv3_mma(const __nv_bfloat16* __restrict__ a2n,
          const u32* __restrict__ wfu,
          const float* __restrict__ bias,
          __nv_bfloat16* __restrict__ feat) {
    extern __shared__ char smc[];
    __nv_bfloat16* sin = (__nv_bfloat16*)smc;      // 2*81*72 bf16
    const int q = blockIdx.y;
    const int imgb = blockIdx.x * 2;
    for (int i = threadIdx.x; i < 1296; i += 224) {
        int im = i / 648, r = i % 648;
        int px = r >> 3, qq = r & 7;
        *((uint4*)&sin[im * 5832 + px * 72]       + qq) =
        *((const uint4*)&a2n[((size_t)(imgb + im) * 81 + px) * 64] + qq);
    }
    __syncthreads();

    const int lane = threadIdx.x & 31, wid = threadIdx.x >> 5;
    const int t = lane & 3;
    const u32 sb = smem_u32(smc);
    u32 la;
    {
        int r = wid * 16 + (lane & 15);
        if (r > 97) r = 97;
        int im = r / 49, lp = r % 49;
        la = sb + (u32)(im * 11664 + ((lp / 7) * 9 + lp % 7) * 144)
               + ((lane & 16) ? 16u : 0u);
    }
    const u32* wlane = wfu + (size_t)q * 4 * 64 + lane * 2;

    float acc[4][4];
    #pragma unroll
    for (int nt = 0; nt < 4; nt++) {
        int oc = q * 32 + nt * 8 + t * 2;
        float b0 = bias[oc], b1 = bias[oc + 1];
        acc[nt][0] = b0; acc[nt][1] = b1; acc[nt][2] = b0; acc[nt][3] = b1;
    }

    u32 a[4];
    uint2 bv[4];
    ldsm4(a, la);
    #pragma unroll
    for (int nt = 0; nt < 4; nt++)
        bv[nt] = *(const uint2*)&wlane[nt * 64];

    #pragma unroll
    for (int c = 0; c < 36; c++) {
        u32 na[4];
        uint2 nbv[4];
        if (c < 35) {
            const int pp = (c + 1) >> 2, icc = (c + 1) & 3;
            const u32 off = (u32)(((pp / 3) * 9 + (pp % 3)) * 144 + icc * 32);
            ldsm4(na, la + off);
            #pragma unroll
            for (int nt = 0; nt < 4; nt++)
                nbv[nt] = *(const uint2*)&wlane[((c + 1) * 8 + nt) * 64];
        }
        #pragma unroll
        for (int nt = 0; nt < 4; nt++) {
            u32 b[2] = {bv[nt].x, bv[nt].y};
            mmabf(acc[nt], a, b);
        }
        if (c < 35) {
            #pragma unroll
            for (int k = 0; k < 4; k++) a[k] = na[k];
            #pragma unroll
            for (int nt = 0; nt < 4; nt++) bv[nt] = nbv[nt];
        }
    }
    {
        const int r0 = wid * 16 + (lane >> 2), r1 = r0 + 8;
        const int g0 = (r0 < 98) ? r0 : 97, g1 = (r1 < 98) ? r1 : 97;
        const int im0 = g0 / 49, lp0 = g0 % 49;
        const int im1 = g1 / 49, lp1 = g1 % 49;
        #pragma unroll
        for (int nt = 0; nt < 4; nt++) {
            int oc = q * 32 + nt * 8 + t * 2;
            if (r0 < 98) {
                __nv_bfloat16* fb = feat + (size_t)(imgb + im0) * 3136 + oc * 49 + lp0;
                fb[0]  = __float2bfloat16(fmaxf(acc[nt][0], 0.0f));
                fb[49] = __float2bfloat16(fmaxf(acc[nt][1], 0.0f));
            }
            if (r1 < 98) {
                __nv_bfloat16* fb = feat + (size_t)(imgb + im1) * 3136 + oc * 49 + lp1;
                fb[0]  = __float2bfloat16(fmaxf(acc[nt][2], 0.0f));
                fb[49] = __float2bfloat16(fmaxf(acc[nt][3], 0.0f));
            }
        }
    }
}

// ---------------------------------------------------------------------------
// FC (bf16 mma): [1024,3136]@[3136,256], split-K 4 -> fp32 partials.
// ---------------------------------------------------------------------------
__global__ void fc_mma(const __nv_bfloat16* __restrict__ feat,
                       const u32* __restrict__ wfu,
                       float* __restrict__ part) {
    extern __shared__ char smc[];
    __nv_bfloat16* sA = (__nv_bfloat16*)smc;       // 128*120 bf16
    u32* sB = (u32*)(smc + 30720);                  // 3584 u32
    const int mb = blockIdx.x, nb = blockIdx.y, z = blockIdx.z;
    const int m0b = mb * 128;
    const int lane = threadIdx.x & 31, wid = threadIdx.x >> 5;
    const int t = lane & 3, g = lane >> 2;

    float acc[8][4] = {};
    for (int it = 0; it < 7; it++) {
        const int kbase = z * 784 + it * 112;
        const int cbase = z * 49 + it * 7;
        __syncthreads();
        for (int i = threadIdx.x; i < 1792; i += 256) {
            int row = i / 14, seg = i % 14;
            *(uint4*)&sA[row * 120 + seg * 8] =
                *(const uint4*)&feat[(size_t)(m0b + row) * 3136 + kbase + seg * 8];
        }
        for (int i = threadIdx.x; i < 896; i += 256) {
            int cn = i >> 4, c_l = cn >> 3, ntl = cn & 7;
            ((uint4*)sB)[i] =
                *(const uint4*)&wfu[((size_t)(cbase + c_l) * 32 + nb * 8 + ntl) * 64 + (i & 15) * 4];
        }
        __syncthreads();
        #pragma unroll
        for (int c_l = 0; c_l < 7; c_l++) {
            const int ra = (wid * 16 + g) * 120 + c_l * 16 + 2 * t;
            u32 a[4];
            a[0] = *(const u32*)&sA[ra];
            a[1] = *(const u32*)&sA[ra + 8 * 120];
            a[2] = *(const u32*)&sA[ra + 8];
            a[3] = *(const u32*)&sA[ra + 8 * 120 + 8];
            const u32* wb = sB + c_l * 512 + lane * 2;
            #pragma unroll
            for (int nt = 0; nt < 8; nt++) {
                uint2 bv = *(const uint2*)&wb[nt * 64];
                u32 b[2] = {bv.x, bv.y};
                mmabf(acc[nt], a, b);
            }
        }
    }
    float* pb = part + (size_t)z * 262144;
    const int mr0 = m0b + wid * 16 + g, mr1 = mr0 + 8;
    #pragma unroll
    for (int nt = 0; nt < 8; nt++) {
        int col = nb * 64 + nt * 8 + 2 * t;
        *(float2*)&pb[(size_t)mr0 * 256 + col] = make_float2(acc[nt][0], acc[nt][1]);
        *(float2*)&pb[(size_t)mr1 * 256 + col] = make_float2(acc[nt][2], acc[nt][3]);
    }
}

__global__ void combine_kernel(const float* __restrict__ Cp,
                               const float* __restrict__ bias,
                               float* __restrict__ C,
                               int MN, int N, int nsplit, int doRelu) {
    const int idx = blockIdx.x * blockDim.x + threadIdx.x;
    if (idx >= MN) return;
    float s = bias[idx % N];
    for (int z = 0; z < nsplit; z++) s += Cp[(size_t)z * MN + idx];
    if (doRelu) s = fmaxf(s, 0.0f);
    C[idx] = s;
}

// ---------------------------------------------------------------------------
// head GEMM body (bf16 mma): one 128x64 tile of relu?(A[:,256]@W+b).
// ---------------------------------------------------------------------------
__device__ void head_body(const float* __restrict__ A,
                          const u32* __restrict__ wfu,
                          const float* __restrict__ bias,
                          float* __restrict__ C,
                          int NTg, int doRelu, int mb, int nb) {
    extern __shared__ char smc[];
    __nv_bfloat16* sA = (__nv_bfloat16*)smc;       // 128*136 bf16
    u32* sB = (u32*)(smc + 34816);                  // 4096 u32
    const int m0b = mb * 128;
    const int N = NTg * 8;
    const int lane = threadIdx.x & 31, wid = threadIdx.x >> 5;
    const int t = lane & 3, g = lane >> 2;

    float acc[8][4] = {};
    #pragma unroll
    for (int it = 0; it < 2; it++) {
        const int kbase = it * 128;
        __syncthreads();
        for (int i = threadIdx.x; i < 4096; i += 256) {
            int row = i >> 5, seg = i & 31;
            float4 v = *(const float4*)&A[(size_t)(m0b + row) * 256 + kbase + seg * 4];
            u32* d = (u32*)&sA[row * 136 + seg * 4];
            d[0] = packbf(v.x, v.y);
            d[1] = packbf(v.z, v.w);
        }
        for (int i = threadIdx.x; i < 1024; i += 256) {
            int cn = i >> 4, c_l = cn >> 3, ntl = cn & 7;
            ((uint4*)sB)[i] =
                *(const uint4*)&wfu[(((it * 8 + c_l) * NTg) + nb * 8 + ntl) * 64 + (i & 15) * 4];
        }
        __syncthreads();
        #pragma unroll
        for (int c_l = 0; c_l < 8; c_l++) {
            const int ra = (wid * 16 + g) * 136 + c_l * 16 + 2 * t;
            u32 a[4];
            a[0] = *(const u32*)&sA[ra];
            a[1] = *(const u32*)&sA[ra + 8 * 136];
            a[2] = *(const u32*)&sA[ra + 8];
            a[3] = *(const u32*)&sA[ra + 8 * 136 + 8];
            const u32* wb = sB + c_l * 512 + lane * 2;
            #pragma unroll
            for (int nt = 0; nt < 8; nt++) {
                uint2 bv = *(const uint2*)&wb[nt * 64];
                u32 b[2] = {bv.x, bv.y};
                mmabf(acc[nt], a, b);
            }
        }
    }
    const int mr0 = m0b + wid * 16 + g, mr1 = mr0 + 8;
    #pragma unroll
    for (int nt = 0; nt < 8; nt++) {
        int col = nb * 64 + nt * 8 + 2 * t;
        float b0 = bias[col], b1 = bias[col + 1];
        float v00 = acc[nt][0] + b0, v01 = acc[nt][1] + b1;
        float v10 = acc[nt][2] + b0, v11 = acc[nt][3] + b1;
        if (doRelu) {
            v00 = fmaxf(v00, 0.0f); v01 = fmaxf(v01, 0.0f);
            v10 = fmaxf(v10, 0.0f); v11 = fmaxf(v11, 0.0f);
        }
        *(float2*)&C[(size_t)mr0 * N + col] = make_float2(v00, v01);
        *(float2*)&C[(size_t)mr1 * N + col] = make_float2(v10, v11);
    }
}

__global__ void headA(const float* __restrict__ f,
                      const u32* __restrict__ we1, const float* __restrict__ e1b,
                      float* __restrict__ h1,
                      const u32* __restrict__ wp1, const float* __restrict__ pb1,
                      float* __restrict__ hp) {
    int bid = blockIdx.x;
    if (bid < 32) head_body(f, we1, e1b, h1, 32, 1, bid >> 2, bid & 3);
    else {
        bid -= 32;
        head_body(f + (size_t)512 * 256, wp1, pb1, hp, 32, 1, bid >> 2, bid & 3);
    }
}

__global__ void headB(const float* __restrict__ h1,
                      const u32* __restrict__ we2, const float* __restrict__ e2b,
                      float* __restrict__ phi,
                      const float* __restrict__ hp,
                      const float* __restrict__ pw2, const float* __restrict__ pb2,
                      float* __restrict__ cy) {
    int bid = blockIdx.x;
    if (bid < 8) {
        head_body(h1, we2, e2b, phi, 8, 0, bid, 0);
    } else {
        const int gw = (bid - 8) * 8 + (threadIdx.x >> 5);
        const int lane = threadIdx.x & 31;
        float s = 0.0f;
        for (int k = lane; k < 256; k += 32)
            s = fmaf(hp[(size_t)gw * 256 + k], pw2[k], s);
        #pragma unroll
        for (int off = 16; off > 0; off >>= 1) s += __shfl_xor_sync(0xffffffffu, s, off);
        if (lane == 0) cy[gw] = s + pb2[0];
    }
}

// ---------------------------------------------------------------------------
// logits: 4 rows/block (grid 128).
// ---------------------------------------------------------------------------
__global__ void logits_kernel(const float* __restrict__ phi,
                              const float* __restrict__ cy,
                              float* __restrict__ lse,
                              float* __restrict__ diag) {
    const int i0 = blockIdx.x * 4;
    __shared__ float sx[4][64];
    __shared__ float red[256];
    __shared__ float sdiag[4];
    const int tid = threadIdx.x;
    sx[tid >> 6][tid & 63] = phi[(size_t)(i0 + (tid >> 6)) * 64 + (tid & 63)];
    __syncthreads();

    float lg[2][4];
    #pragma unroll
    for (int rep = 0; rep < 2; rep++) {
        const int j = tid + rep * 256;
        const float* y = phi + (size_t)(512 + j) * 64;
        float mx[4] = {0.f, 0.f, 0.f, 0.f}, ss[4] = {0.f, 0.f, 0.f, 0.f};
        #pragma unroll
        for (int k = 0; k < 32; k++) {
            const float yk = y[k];
            #pragma unroll
            for (int r = 0; r < 4; r++) {
                float d = sx[r][k] - yk;
                mx[r] = fmaxf(mx[r], fmaxf(d, 0.0f));
            }
        }
        #pragma unroll
        for (int k = 32; k < 64; k++) {
            const float yk = y[k];
            #pragma unroll
            for (int r = 0; r < 4; r++) {
                float d = sx[r][k] - yk;
                ss[r] = fmaf(d, d, ss[r]);
            }
        }
        const float cyj = cy[j];
        #pragma unroll
        for (int r = 0; r < 4; r++) {
            lg[rep][r] = cyj - (mx[r] + sqrtf(ss[r] + 1e-8f));
            if (j == i0 + r) sdiag[r] = lg[rep][r];
        }
    }
    #pragma unroll
    for (int r = 0; r < 4; r++) {
        __syncthreads();
        red[tid] = fmaxf(lg[0][r], lg[1][r]);
        __syncthreads();
        for (int s = 128; s > 0; s >>= 1) {
            if (tid < s) red[tid] = fmaxf(red[tid], red[tid + s]);
            __syncthreads();
        }
        const float rowmax = red[0];
        __syncthreads();
        red[tid] = expf(lg[0][r] - rowmax) + expf(lg[1][r] - rowmax);
        __syncthreads();
        for (int s = 128; s > 0; s >>= 1) {
            if (tid < s) red[tid] += red[tid + s];
            __syncthreads();
        }
        if (tid == 0) {
            lse[i0 + r] = rowmax + logf(red[0]);
            diag[i0 + r] = sdiag[r];
        }
    }
}

__global__ void loss_kernel(const float* __restrict__ lse,
                            const float* __restrict__ diag,
                            float* __restrict__ out) {
    __shared__ float r1[256], r2[256];
    const int tid = threadIdx.x;
    float s1 = 0.0f, s2 = 0.0f;
    for (int i = tid; i < 512; i += 256) {
        const float l = lse[i];
        s1 += l - diag[i];
        const float u = l + 1e-6f;
        s2 = fmaf(u, u, s2);
    }
    r1[tid] = s1; r2[tid] = s2;
    __syncthreads();
    for (int s = 128; s > 0; s >>= 1) {
        if (tid < s) { r1[tid] += r1[tid + s]; r2[tid] += r2[tid + s]; }
        __syncthreads();
    }
    if (tid == 0)
        out[0] = r1[0] * (1.0f / 512.0f) + 0.1f * r2[0] * (1.0f / 512.0f);
}

// ---------------------------------------------------------------------------
// Host launcher
// ---------------------------------------------------------------------------
extern "C" void kernel_launch(void* const* d_in, const int* in_sizes, int n_in,
                              void* d_out, int out_size) {
    const float* curr = (const float*)d_in[0];
    const float* next = (const float*)d_in[1];
    const float* c1w = (const float*)d_in[2];
    const float* c1b = (const float*)d_in[3];
    const float* c2w = (const float*)d_in[4];
    const float* c2b = (const float*)d_in[5];
    const float* c3w = (const float*)d_in[6];
    const float* c3b = (const float*)d_in[7];
    const float* fcw = (const float*)d_in[8];
    const float* fcb = (const float*)d_in[9];
    const float* e1w = (const float*)d_in[10];
    const float* e1b = (const float*)d_in[11];
    const float* e2w = (const float*)d_in[12];
    const float* e2b = (const float*)d_in[13];
    const float* pw1 = (const float*)d_in[14];
    const float* pb1 = (const float*)d_in[15];
    const float* pw2 = (const float*)d_in[16];
    const float* pb2 = (const float*)d_in[17];

    u32 *p_w1f, *p_w2f, *p_w3f, *p_wfc, *p_we1, *p_we2, *p_wp1;
    __nv_bfloat16 *p_a1, *p_a2n, *p_feat;
    float *p_f, *p_h1, *p_phi, *p_hp, *p_cy, *p_lse, *p_diag, *p_part;
    cudaGetSymbolAddress((void**)&p_w1f, g_w1f);
    cudaGetSymbolAddress((void**)&p_w2f, g_w2f);
    cudaGetSymbolAddress((void**)&p_w3f, g_w3f);
    cudaGetSymbolAddress((void**)&p_wfc, g_wfc);
    cudaGetSymbolAddress((void**)&p_we1, g_we1);
    cudaGetSymbolAddress((void**)&p_we2, g_we2);
    cudaGetSymbolAddress((void**)&p_wp1, g_wp1);
    cudaGetSymbolAddress((void**)&p_a1, g_a1);
    cudaGetSymbolAddress((void**)&p_a2n, g_a2n);
    cudaGetSymbolAddress((void**)&p_feat, g_feat);
    cudaGetSymbolAddress((void**)&p_f, g_f);
    cudaGetSymbolAddress((void**)&p_h1, g_h1);
    cudaGetSymbolAddress((void**)&p_phi, g_phi);
    cudaGetSymbolAddress((void**)&p_hp, g_hp);
    cudaGetSymbolAddress((void**)&p_cy, g_cy);
    cudaGetSymbolAddress((void**)&p_lse, g_lse);
    cudaGetSymbolAddress((void**)&p_diag, g_diag);
    cudaGetSymbolAddress((void**)&p_part, g_part);

    const int SM1 = 26880;               // conv1: image only
    const int SM2 = 51200;               // conv2: input only
    const int SM3 = 23328;               // conv3: input only
    const int SMF = 30720 + 3584 * 4;    // 45056
    const int SMH = 34816 + 4096 * 4;    // 51200
    cudaFuncSetAttribute(conv1_mma, cudaFuncAttributeMaxDynamicSharedMemorySize, SM1);
    cudaFuncSetAttribute(conv2_mma, cudaFuncAttributeMaxDynamicSharedMemorySize, SM2);
    cudaFuncSetAttribute(conv3_mma, cudaFuncAttributeMaxDynamicSharedMemorySize, SM3);
    cudaFuncSetAttribute(fc_mma, cudaFuncAttributeMaxDynamicSharedMemorySize, SMF);
    cudaFuncSetAttribute(headA, cudaFuncAttributeMaxDynamicSharedMemorySize, SMH);
    cudaFuncSetAttribute(headB, cudaFuncAttributeMaxDynamicSharedMemorySize, SMH);

    prep_all<<<2008, 256>>>(c1w, c2w, c3w, fcw, e1w, e2w, pw1,
                            p_w1f, p_w2f, p_w3f, p_wfc, p_we1, p_we2, p_wp1);

    conv1_mma<<<dim3(512, 5), 160, SM1>>>(curr, next, p_w1f, c1b, p_a1);
    conv2_mma<<<dim3(512, 2), 352, SM2>>>(p_a1, p_w2f, c2b, p_a2n);
    conv3_mma<<<dim3(512, 2), 224, SM3>>>(p_a2n, p_w3f, c3b, p_feat);

    fc_mma<<<dim3(8, 4, 4), 256, SMF>>>(p_feat, p_wfc, p_part);
    combine_kernel<<<1024, 256>>>(p_part, fcb, p_f, 1024 * 256, 256, 4, 1);

    headA<<<48, 256, SMH>>>(p_f, p_we1, e1b, p_h1, p_wp1, pb1, p_hp);
    headB<<<72, 256, SMH>>>(p_h1, p_we2, e2b, p_phi, p_hp, pw2, pb2, p_cy);

    logits_kernel<<<128, 256>>>(p_phi, p_cy, p_lse, p_diag);
    loss_kernel<<<1, 256>>>(p_lse, p_diag, (float*)d_out);
}

// round 11
// speedup vs baseline: 7.0630x; 1.0049x over previous
#include <cuda_runtime.h>
#include <cuda_bf16.h>
#include <math.h>

#define NIMG 1024
typedef unsigned int u32;

// ---------------------------------------------------------------------------
// scratch
// ---------------------------------------------------------------------------
__device__ __align__(128) u32 g_w1f[16 * 4 * 64];
__device__ __align__(128) u32 g_w2f[32 * 8 * 64];
__device__ __align__(128) u32 g_w3f[36 * 8 * 64];
__device__ __align__(128) u32 g_wfc[196 * 32 * 64];
__device__ __align__(128) u32 g_we1[16 * 32 * 64];
__device__ __align__(128) u32 g_we2[16 * 8 * 64];
__device__ __align__(128) u32 g_wp1[16 * 32 * 64];
__device__ __align__(128) __nv_bfloat16 g_a1[(size_t)NIMG * 12800];
__device__ __align__(128) __nv_bfloat16 g_a2n[(size_t)NIMG * 81 * 64];
__device__ __align__(128) __nv_bfloat16 g_feat[(size_t)NIMG * 3136];
__device__ __align__(128) float g_f[NIMG * 256];
__device__ __align__(128) float g_h1[NIMG * 256];
__device__ __align__(128) float g_phi[NIMG * 64];
__device__ __align__(128) float g_hp[512 * 256];
__device__ __align__(128) float g_cy[512];
__device__ __align__(128) float g_lse[512];
__device__ __align__(128) float g_diag[512];
__device__ __align__(128) float g_part[4 * 1024 * 256];
__device__ int g_done = 0;   // logits completion counter (self-resetting)

// ---------------------------------------------------------------------------
// helpers
// ---------------------------------------------------------------------------
__device__ __forceinline__ u32 packbf(float lo, float hi) {
    __nv_bfloat162 h = __float22bfloat162_rn(make_float2(lo, hi));
    return *reinterpret_cast<u32*>(&h);
}
__device__ __forceinline__ void mmabf(float* d, const u32* a, const u32* b) {
    asm volatile(
        "mma.sync.aligned.m16n8k16.row.col.f32.bf16.bf16.f32 "
        "{%0,%1,%2,%3},{%4,%5,%6,%7},{%8,%9},{%0,%1,%2,%3};\n"
        : "+f"(d[0]), "+f"(d[1]), "+f"(d[2]), "+f"(d[3])
        : "r"(a[0]), "r"(a[1]), "r"(a[2]), "r"(a[3]), "r"(b[0]), "r"(b[1]));
}
__device__ __forceinline__ void ldsm4(u32* r, u32 addr) {
    asm volatile("ldmatrix.sync.aligned.m8n8.x4.shared.b16 {%0,%1,%2,%3}, [%4];"
                 : "=r"(r[0]), "=r"(r[1]), "=r"(r[2]), "=r"(r[3]) : "r"(addr));
}
__device__ __forceinline__ u32 smem_u32(const void* p) {
    u32 a;
    asm("{ .reg .u64 t; cvta.to.shared.u64 t, %1; cvt.u32.u64 %0, t; }"
        : "=r"(a) : "l"(p));
    return a;
}

// ---------------------------------------------------------------------------
// unified weight prep (one launch). frag layout:
// wf[(c*NT+nt)*64 + lane*2 + s] = bf16x2 of W[k=c*16+s*8+2(lane&3)][n=nt*8+lane/4]
// ---------------------------------------------------------------------------
__global__ void prep_all(const float* __restrict__ c1w, const float* __restrict__ c2w,
                         const float* __restrict__ c3w, const float* __restrict__ fcw,
                         const float* __restrict__ e1w, const float* __restrict__ e2w,
                         const float* __restrict__ pw1,
                         u32* __restrict__ w1f, u32* __restrict__ w2f,
                         u32* __restrict__ w3f, u32* __restrict__ wfc,
                         u32* __restrict__ we1, u32* __restrict__ we2,
                         u32* __restrict__ wp1) {
    int gi = blockIdx.x * 256 + threadIdx.x;
    if (gi < 4096) {                               // conv1
        int i = gi;
        int s = i & 1, lane = (i >> 1) & 31;
        int cn = i >> 6, nt = cn & 3, c = cn >> 2;
        int t = lane & 3, g = lane >> 2;
        int n = nt * 8 + g;
        int ic = c >> 2, ky = (c & 3) * 2 + s, kx = 2 * t;
        const float* base = c1w + ((n * 4 + ic) * 8 + ky) * 8 + kx;
        w1f[i] = packbf(base[0], base[1]);
    } else if (gi < 20480) {                       // conv2
        int i = gi - 4096;
        int s = i & 1, lane = (i >> 1) & 31;
        int cn = i >> 6, nt = cn & 7, ic = cn >> 3;
        int t = lane & 3, g = lane >> 2;
        int n = nt * 8 + g;
        int ky = s * 2 + (t >> 1), kx = (t & 1) * 2;
        const float* base = c2w + ((n * 32 + ic) * 4 + ky) * 4 + kx;
        w2f[i] = packbf(base[0], base[1]);
    } else if (gi < 38912) {                       // conv3
        int i = gi - 20480;
        int s = i & 1, lane = (i >> 1) & 31;
        int cn = i >> 6, nt = cn & 7, c = cn >> 3;
        int t = lane & 3, g = lane >> 2;
        int n = nt * 8 + g;
        int p = c >> 2, icc = c & 3;
        int ic = icc * 16 + s * 8 + 2 * t;
        int ky = p / 3, kx = p % 3;
        float lo = c3w[((n * 64 + ic) * 3 + ky) * 3 + kx];
        float hi = c3w[((n * 64 + ic + 1) * 3 + ky) * 3 + kx];
        w3f[i] = packbf(lo, hi);
    } else if (gi < 440320) {                      // fc
        int i = gi - 38912;
        int s = i & 1, lane = (i >> 1) & 31;
        int cn = i >> 6, nt = cn & 31, c = cn >> 5;
        int t = lane & 3, g = lane >> 2;
        int n = nt * 8 + g;
        int k0 = c * 16 + s * 8 + 2 * t;
        wfc[i] = packbf(fcw[(size_t)k0 * 256 + n], fcw[(size_t)(k0 + 1) * 256 + n]);
    } else if (gi < 473088) {                      // e1 (NTg=32)
        int i = gi - 440320;
        int s = i & 1, lane = (i >> 1) & 31;
        int cn = i >> 6, nt = cn & 31, c = cn >> 5;
        int t = lane & 3, g = lane >> 2;
        int n = nt * 8 + g;
        int k0 = c * 16 + s * 8 + 2 * t;
        we1[i] = packbf(e1w[(size_t)k0 * 256 + n], e1w[(size_t)(k0 + 1) * 256 + n]);
    } else if (gi < 481280) {                      // e2 (NTg=8)
        int i = gi - 473088;
        int s = i & 1, lane = (i >> 1) & 31;
        int cn = i >> 6, nt = cn & 7, c = cn >> 3;
        int t = lane & 3, g = lane >> 2;
        int n = nt * 8 + g;
        int k0 = c * 16 + s * 8 + 2 * t;
        we2[i] = packbf(e2w[(size_t)k0 * 64 + n], e2w[(size_t)(k0 + 1) * 64 + n]);
    } else if (gi < 514048) {                      // pw1 (NTg=32)
        int i = gi - 481280;
        int s = i & 1, lane = (i >> 1) & 31;
        int cn = i >> 6, nt = cn & 31, c = cn >> 5;
        int t = lane & 3, g = lane >> 2;
        int n = nt * 8 + g;
        int k0 = c * 16 + s * 8 + 2 * t;
        wp1[i] = packbf(pw1[(size_t)k0 * 256 + n], pw1[(size_t)(k0 + 1) * 256 + n]);
    }
}

// ---------------------------------------------------------------------------
// conv1: grid (512 pairs, 5 oy-groups), 160 thr. Scalar A (smem) + B frags
// direct from gmem. ~7 blocks/SM (35 warps).
// ---------------------------------------------------------------------------
__global__ void __launch_bounds__(160, 7)
conv1_mma(const float* __restrict__ curr,
          const float* __restrict__ next,
          const u32* __restrict__ wfu,
          const float* __restrict__ bias,
          __nv_bfloat16* __restrict__ out) {
    extern __shared__ char smc[];
    __nv_bfloat16* simg = (__nv_bfloat16*)smc;     // 2*6720 bf16
    const int p = blockIdx.x, oyg = blockIdx.y;
    const int iy0 = oyg * 16;
    const float* in0 = curr + (size_t)p * 28224;
    const float* in1 = next + (size_t)p * 28224;
    for (int i = threadIdx.x; i < 3360; i += 160) {
        int e = i * 4;
        int im = e / 6720, e2 = e % 6720;
        int ic = e2 / 1680, rem = e2 % 1680;
        const float* src = im ? in1 : in0;
        float4 v = *(const float4*)&src[ic * 7056 + iy0 * 84 + rem];
        u32* d = (u32*)&simg[e];
        d[0] = packbf(v.x, v.y);
        d[1] = packbf(v.z, v.w);
    }
    __syncthreads();

    const int lane = threadIdx.x & 31, wid = threadIdx.x >> 5;
    const int t = lane & 3;
    const int r0 = wid * 16 + (lane >> 2), r1 = r0 + 8;
    const int b00 = (r0 / 20) * 336 + (r0 % 20) * 4 + 2 * t;
    const int b01 = (r1 / 20) * 336 + (r1 % 20) * 4 + 2 * t;
    const u32* wlane = wfu + lane * 2;

    float acc[2][4][4];
    #pragma unroll
    for (int nt = 0; nt < 4; nt++) {
        int oc = nt * 8 + t * 2;
        float b0 = bias[oc], b1 = bias[oc + 1];
        #pragma unroll
        for (int im = 0; im < 2; im++) {
            acc[im][nt][0] = b0; acc[im][nt][1] = b1;
            acc[im][nt][2] = b0; acc[im][nt][3] = b1;
        }
    }
    u32 a0[4], a1[4];
    uint2 bv[4];
    a0[0] = *(const u32*)&simg[b00];
    a0[1] = *(const u32*)&simg[b01];
    a0[2] = *(const u32*)&simg[84 + b00];
    a0[3] = *(const u32*)&simg[84 + b01];
    a1[0] = *(const u32*)&simg[6720 + b00];
    a1[1] = *(const u32*)&simg[6720 + b01];
    a1[2] = *(const u32*)&simg[6720 + 84 + b00];
    a1[3] = *(const u32*)&simg[6720 + 84 + b01];
    #pragma unroll
    for (int nt = 0; nt < 4; nt++)
        bv[nt] = *(const uint2*)&wlane[nt * 64];

    #pragma unroll
    for (int c = 0; c < 16; c++) {
        u32 na0[4], na1[4];
        uint2 nbv[4];
        if (c < 15) {
            const int o = ((c + 1) >> 2) * 1680 + ((c + 1) & 3) * 168;
            na0[0] = *(const u32*)&simg[o + b00];
            na0[1] = *(const u32*)&simg[o + b01];
            na0[2] = *(const u32*)&simg[o + 84 + b00];
            na0[3] = *(const u32*)&simg[o + 84 + b01];
            na1[0] = *(const u32*)&simg[6720 + o + b00];
            na1[1] = *(const u32*)&simg[6720 + o + b01];
            na1[2] = *(const u32*)&simg[6720 + o + 84 + b00];
            na1[3] = *(const u32*)&simg[6720 + o + 84 + b01];
            #pragma unroll
            for (int nt = 0; nt < 4; nt++)
                nbv[nt] = *(const uint2*)&wlane[((c + 1) * 4 + nt) * 64];
        }
        #pragma unroll
        for (int nt = 0; nt < 4; nt++) {
            u32 b[2] = {bv[nt].x, bv[nt].y};
            mmabf(acc[0][nt], a0, b);
            mmabf(acc[1][nt], a1, b);
        }
        if (c < 15) {
            #pragma unroll
            for (int q = 0; q < 4; q++) { a0[q] = na0[q]; a1[q] = na1[q]; }
            #pragma unroll
            for (int nt = 0; nt < 4; nt++) bv[nt] = nbv[nt];
        }
    }
    #pragma unroll
    for (int im = 0; im < 2; im++) {
        const int img = p + im * 512;
        __nv_bfloat16* ob = out + (size_t)img * 12800 + oyg * 80;
        #pragma unroll
        for (int nt = 0; nt < 4; nt++) {
            int oc = nt * 8 + t * 2;
            __nv_bfloat16* p0 = ob + (size_t)oc * 400;
            p0[r0]       = __float2bfloat16(fmaxf(acc[im][nt][0], 0.0f));
            p0[400 + r0] = __float2bfloat16(fmaxf(acc[im][nt][1], 0.0f));
            p0[r1]       = __float2bfloat16(fmaxf(acc[im][nt][2], 0.0f));
            p0[400 + r1] = __float2bfloat16(fmaxf(acc[im][nt][3], 0.0f));
        }
    }
}

// ---------------------------------------------------------------------------
// conv2: grid (512 pairs, 2 oc-halves), 352 thr. Scalar A (smem) + B frags
// from gmem. 3 blocks/SM (33 warps).
// ---------------------------------------------------------------------------
__global__ void __launch_bounds__(352, 3)
conv2_mma(const __nv_bfloat16* __restrict__ a1,
          const u32* __restrict__ wfu,
          const float* __restrict__ bias,
          __nv_bfloat16* __restrict__ out) {
    extern __shared__ char smc[];
    __nv_bfloat16* sin = (__nv_bfloat16*)smc;      // 25600 bf16
    const int p = blockIdx.x, q = blockIdx.y;
    const uint4* src = (const uint4*)(a1 + (size_t)p * 25600);
    for (int i = threadIdx.x; i < 3200; i += 352)
        ((uint4*)sin)[i] = src[i];
    __syncthreads();

    const int lane = threadIdx.x & 31, wid = threadIdx.x >> 5;
    const int t = lane & 3;
    const int toff = (t >> 1) * 20 + (t & 1) * 2;
    const int r0 = wid * 16 + (lane >> 2), r1 = r0 + 8;
    const int gg0 = (r0 < 162) ? r0 : 161, gg1 = (r1 < 162) ? r1 : 161;
    const int im0 = gg0 / 81, px0 = gg0 % 81;
    const int im1 = gg1 / 81, px1 = gg1 % 81;
    const int A0 = im0 * 12800 + (px0 / 9) * 40 + (px0 % 9) * 2 + toff;
    const int A1 = im1 * 12800 + (px1 / 9) * 40 + (px1 % 9) * 2 + toff;
    const u32* wlane = wfu + (size_t)q * 4 * 64 + lane * 2;

    float acc[4][4];
    #pragma unroll
    for (int nt = 0; nt < 4; nt++) {
        int oc = q * 32 + nt * 8 + t * 2;
        float b0 = bias[oc], b1 = bias[oc + 1];
        acc[nt][0] = b0; acc[nt][1] = b1; acc[nt][2] = b0; acc[nt][3] = b1;
    }

    u32 a[4];
    uint2 bv[4];
    a[0] = *(const u32*)&sin[A0];
    a[1] = *(const u32*)&sin[A1];
    a[2] = *(const u32*)&sin[40 + A0];
    a[3] = *(const u32*)&sin[40 + A1];
    #pragma unroll
    for (int nt = 0; nt < 4; nt++)
        bv[nt] = *(const uint2*)&wlane[nt * 64];

    #pragma unroll 8
    for (int ic = 0; ic < 32; ic++) {
        u32 na[4];
        uint2 nbv[4];
        if (ic < 31) {
            const int o = (ic + 1) * 400;
            na[0] = *(const u32*)&sin[o + A0];
            na[1] = *(const u32*)&sin[o + A1];
            na[2] = *(const u32*)&sin[o + 40 + A0];
            na[3] = *(const u32*)&sin[o + 40 + A1];
            #pragma unroll
            for (int nt = 0; nt < 4; nt++)
                nbv[nt] = *(const uint2*)&wlane[((ic + 1) * 8 + nt) * 64];
        }
        #pragma unroll
        for (int nt = 0; nt < 4; nt++) {
            u32 b[2] = {bv[nt].x, bv[nt].y};
            mmabf(acc[nt], a, b);
        }
        if (ic < 31) {
            #pragma unroll
            for (int k = 0; k < 4; k++) a[k] = na[k];
            #pragma unroll
            for (int nt = 0; nt < 4; nt++) bv[nt] = nbv[nt];
        }
    }
    #pragma unroll
    for (int nt = 0; nt < 4; nt++) {
        int oc = q * 32 + nt * 8 + t * 2;
        if (r0 < 162)
            *(u32*)&out[((size_t)(p * 2 + im0) * 81 + px0) * 64 + oc] =
                packbf(fmaxf(acc[nt][0], 0.0f), fmaxf(acc[nt][1], 0.0f));
        if (r1 < 162)
            *(u32*)&out[((size_t)(p * 2 + im1) * 81 + px1) * 64 + oc] =
                packbf(fmaxf(acc[nt][2], 0.0f), fmaxf(acc[nt][3], 0.0f));
    }
}

// ---------------------------------------------------------------------------
// conv3: grid (512, 2 oc-halves), 128 thr (4 warps, M=32/warp). LDSM A x2
// groups sharing B frags (halves B L1 traffic per MMA). 5 blocks/SM.
// ---------------------------------------------------------------------------
__global__ void __launch_bounds__(128, 5)
conv3_mma(const __nv_bfloat16* __restrict__ a2n,
          const u32* __restrict__ wfu,
          const float* __restrict__ bias,
          __nv_bfloat16* __restrict__ feat) {
    extern __shared__ char smc[];
    __nv_bfloat16* sin = (__nv_bfloat16*)smc;      // 2*81*72 bf16
    const int q = blockIdx.y;
    const int imgb = blockIdx.x * 2;
    for (int i = threadIdx.x; i < 1296; i += 128) {
        int im = i / 648, r = i % 648;
        int px = r >> 3, qq = r & 7;
        *((uint4*)&sin[im * 5832 + px * 72]       + qq) =
        *((const uint4*)&a2n[((size_t)(imgb + im) * 81 + px) * 64] + qq);
    }
    __syncthreads();

    const int lane = threadIdx.x & 31, wid = threadIdx.x >> 5;
    const int t = lane & 3;
    const u32 sb = smem_u32(smc);
    u32 laG[2];
    #pragma unroll
    for (int G = 0; G < 2; G++) {
        int r = wid * 32 + G * 16 + (lane & 15);
        if (r > 97) r = 97;
        int im = r / 49, lp = r % 49;
        laG[G] = sb + (u32)(im * 11664 + ((lp / 7) * 9 + lp % 7) * 144)
                    + ((lane & 16) ? 16u : 0u);
    }
    const u32* wlane = wfu + (size_t)q * 4 * 64 + lane * 2;

    float acc[2][4][4];
    #pragma unroll
    for (int nt = 0; nt < 4; nt++) {
        int oc = q * 32 + nt * 8 + t * 2;
        float b0 = bias[oc], b1 = bias[oc + 1];
        #pragma unroll
        for (int G = 0; G < 2; G++) {
            acc[G][nt][0] = b0; acc[G][nt][1] = b1;
            acc[G][nt][2] = b0; acc[G][nt][3] = b1;
        }
    }

    u32 a0[4], a1[4];
    uint2 bv[4];
    ldsm4(a0, laG[0]);
    ldsm4(a1, laG[1]);
    #pragma unroll
    for (int nt = 0; nt < 4; nt++)
        bv[nt] = *(const uint2*)&wlane[nt * 64];

    #pragma unroll
    for (int c = 0; c < 36; c++) {
        u32 na0[4], na1[4];
        uint2 nbv[4];
        if (c < 35) {
            const int pp = (c + 1) >> 2, icc = (c + 1) & 3;
            const u32 off = (u32)(((pp / 3) * 9 + (pp % 3)) * 144 + icc * 32);
            ldsm4(na0, laG[0] + off);
            ldsm4(na1, laG[1] + off);
            #pragma unroll
            for (int nt = 0; nt < 4; nt++)
                nbv[nt] = *(const uint2*)&wlane[((c + 1) * 8 + nt) * 64];
        }
        #pragma unroll
        for (int nt = 0; nt < 4; nt++) {
            u32 b[2] = {bv[nt].x, bv[nt].y};
            mmabf(acc[0][nt], a0, b);
            mmabf(acc[1][nt], a1, b);
        }
        if (c < 35) {
            #pragma unroll
            for (int k = 0; k < 4; k++) { a0[k] = na0[k]; a1[k] = na1[k]; }
            #pragma unroll
            for (int nt = 0; nt < 4; nt++) bv[nt] = nbv[nt];
        }
    }
    #pragma unroll
    for (int G = 0; G < 2; G++) {
        const int r0 = wid * 32 + G * 16 + (lane >> 2), r1 = r0 + 8;
        const int g0 = (r0 < 98) ? r0 : 97, g1 = (r1 < 98) ? r1 : 97;
        const int im0 = g0 / 49, lp0 = g0 % 49;
        const int im1 = g1 / 49, lp1 = g1 % 49;
        #pragma unroll
        for (int nt = 0; nt < 4; nt++) {
            int oc = q * 32 + nt * 8 + t * 2;
            if (r0 < 98) {
                __nv_bfloat16* fb = feat + (size_t)(imgb + im0) * 3136 + oc * 49 + lp0;
                fb[0]  = __float2bfloat16(fmaxf(acc[G][nt][0], 0.0f));
                fb[49] = __float2bfloat16(fmaxf(acc[G][nt][1], 0.0f));
            }
            if (r1 < 98) {
                __nv_bfloat16* fb = feat + (size_t)(imgb + im1) * 3136 + oc * 49 + lp1;
                fb[0]  = __float2bfloat16(fmaxf(acc[G][nt][2], 0.0f));
                fb[49] = __float2bfloat16(fmaxf(acc[G][nt][3], 0.0f));
            }
        }
    }
}

// ---------------------------------------------------------------------------
// FC (bf16 mma): [1024,3136]@[3136,256], split-K 4 -> fp32 partials.
// ---------------------------------------------------------------------------
__global__ void fc_mma(const __nv_bfloat16* __restrict__ feat,
                       const u32* __restrict__ wfu,
                       float* __restrict__ part) {
    extern __shared__ char smc[];
    __nv_bfloat16* sA = (__nv_bfloat16*)smc;       // 128*120 bf16
    u32* sB = (u32*)(smc + 30720);                  // 3584 u32
    const int mb = blockIdx.x, nb = blockIdx.y, z = blockIdx.z;
    const int m0b = mb * 128;
    const int lane = threadIdx.x & 31, wid = threadIdx.x >> 5;
    const int t = lane & 3, g = lane >> 2;

    float acc[8][4] = {};
    for (int it = 0; it < 7; it++) {
        const int kbase = z * 784 + it * 112;
        const int cbase = z * 49 + it * 7;
        __syncthreads();
        for (int i = threadIdx.x; i < 1792; i += 256) {
            int row = i / 14, seg = i % 14;
            *(uint4*)&sA[row * 120 + seg * 8] =
                *(const uint4*)&feat[(size_t)(m0b + row) * 3136 + kbase + seg * 8];
        }
        for (int i = threadIdx.x; i < 896; i += 256) {
            int cn = i >> 4, c_l = cn >> 3, ntl = cn & 7;
            ((uint4*)sB)[i] =
                *(const uint4*)&wfu[((size_t)(cbase + c_l) * 32 + nb * 8 + ntl) * 64 + (i & 15) * 4];
        }
        __syncthreads();
        #pragma unroll
        for (int c_l = 0; c_l < 7; c_l++) {
            const int ra = (wid * 16 + g) * 120 + c_l * 16 + 2 * t;
            u32 a[4];
            a[0] = *(const u32*)&sA[ra];
            a[1] = *(const u32*)&sA[ra + 8 * 120];
            a[2] = *(const u32*)&sA[ra + 8];
            a[3] = *(const u32*)&sA[ra + 8 * 120 + 8];
            const u32* wb = sB + c_l * 512 + lane * 2;
            #pragma unroll
            for (int nt = 0; nt < 8; nt++) {
                uint2 bv = *(const uint2*)&wb[nt * 64];
                u32 b[2] = {bv.x, bv.y};
                mmabf(acc[nt], a, b);
            }
        }
    }
    float* pb = part + (size_t)z * 262144;
    const int mr0 = m0b + wid * 16 + g, mr1 = mr0 + 8;
    #pragma unroll
    for (int nt = 0; nt < 8; nt++) {
        int col = nb * 64 + nt * 8 + 2 * t;
        *(float2*)&pb[(size_t)mr0 * 256 + col] = make_float2(acc[nt][0], acc[nt][1]);
        *(float2*)&pb[(size_t)mr1 * 256 + col] = make_float2(acc[nt][2], acc[nt][3]);
    }
}

__global__ void combine_kernel(const float* __restrict__ Cp,
                               const float* __restrict__ bias,
                               float* __restrict__ C,
                               int MN, int N, int nsplit, int doRelu) {
    const int idx = blockIdx.x * blockDim.x + threadIdx.x;
    if (idx >= MN) return;
    float s = bias[idx % N];
    for (int z = 0; z < nsplit; z++) s += Cp[(size_t)z * MN + idx];
    if (doRelu) s = fmaxf(s, 0.0f);
    C[idx] = s;
}

// ---------------------------------------------------------------------------
// head GEMM body (bf16 mma): one 128x64 tile of relu?(A[:,256]@W+b).
// ---------------------------------------------------------------------------
__device__ void head_body(const float* __restrict__ A,
                          const u32* __restrict__ wfu,
                          const float* __restrict__ bias,
                          float* __restrict__ C,
                          int NTg, int doRelu, int mb, int nb) {
    extern __shared__ char smc[];
    __nv_bfloat16* sA = (__nv_bfloat16*)smc;       // 128*136 bf16
    u32* sB = (u32*)(smc + 34816);                  // 4096 u32
    const int m0b = mb * 128;
    const int N = NTg * 8;
    const int lane = threadIdx.x & 31, wid = threadIdx.x >> 5;
    const int t = lane & 3, g = lane >> 2;

    float acc[8][4] = {};
    #pragma unroll
    for (int it = 0; it < 2; it++) {
        const int kbase = it * 128;
        __syncthreads();
        for (int i = threadIdx.x; i < 4096; i += 256) {
            int row = i >> 5, seg = i & 31;
            float4 v = *(const float4*)&A[(size_t)(m0b + row) * 256 + kbase + seg * 4];
            u32* d = (u32*)&sA[row * 136 + seg * 4];
            d[0] = packbf(v.x, v.y);
            d[1] = packbf(v.z, v.w);
        }
        for (int i = threadIdx.x; i < 1024; i += 256) {
            int cn = i >> 4, c_l = cn >> 3, ntl = cn & 7;
            ((uint4*)sB)[i] =
                *(const uint4*)&wfu[(((it * 8 + c_l) * NTg) + nb * 8 + ntl) * 64 + (i & 15) * 4];
        }
        __syncthreads();
        #pragma unroll
        for (int c_l = 0; c_l < 8; c_l++) {
            const int ra = (wid * 16 + g) * 136 + c_l * 16 + 2 * t;
            u32 a[4];
            a[0] = *(const u32*)&sA[ra];
            a[1] = *(const u32*)&sA[ra + 8 * 136];
            a[2] = *(const u32*)&sA[ra + 8];
            a[3] = *(const u32*)&sA[ra + 8 * 136 + 8];
            const u32* wb = sB + c_l * 512 + lane * 2;
            #pragma unroll
            for (int nt = 0; nt < 8; nt++) {
                uint2 bv = *(const uint2*)&wb[nt * 64];
                u32 b[2] = {bv.x, bv.y};
                mmabf(acc[nt], a, b);
            }
        }
    }
    const int mr0 = m0b + wid * 16 + g, mr1 = mr0 + 8;
    #pragma unroll
    for (int nt = 0; nt < 8; nt++) {
        int col = nb * 64 + nt * 8 + 2 * t;
        float b0 = bias[col], b1 = bias[col + 1];
        float v00 = acc[nt][0] + b0, v01 = acc[nt][1] + b1;
        float v10 = acc[nt][2] + b0, v11 = acc[nt][3] + b1;
        if (doRelu) {
            v00 = fmaxf(v00, 0.0f); v01 = fmaxf(v01, 0.0f);
            v10 = fmaxf(v10, 0.0f); v11 = fmaxf(v11, 0.0f);
        }
        *(float2*)&C[(size_t)mr0 * N + col] = make_float2(v00, v01);
        *(float2*)&C[(size_t)mr1 * N + col] = make_float2(v10, v11);
    }
}

__global__ void headA(const float* __restrict__ f,
                      const u32* __restrict__ we1, const float* __restrict__ e1b,
                      float* __restrict__ h1,
                      const u32* __restrict__ wp1, const float* __restrict__ pb1,
                      float* __restrict__ hp) {
    int bid = blockIdx.x;
    if (bid < 32) head_body(f, we1, e1b, h1, 32, 1, bid >> 2, bid & 3);
    else {
        bid -= 32;
        head_body(f + (size_t)512 * 256, wp1, pb1, hp, 32, 1, bid >> 2, bid & 3);
    }
}

__global__ void headB(const float* __restrict__ h1,
                      const u32* __restrict__ we2, const float* __restrict__ e2b,
                      float* __restrict__ phi,
                      const float* __restrict__ hp,
                      const float* __restrict__ pw2, const float* __restrict__ pb2,
                      float* __restrict__ cy) {
    int bid = blockIdx.x;
    if (bid < 8) {
        head_body(h1, we2, e2b, phi, 8, 0, bid, 0);
    } else {
        const int gw = (bid - 8) * 8 + (threadIdx.x >> 5);
        const int lane = threadIdx.x & 31;
        float s = 0.0f;
        for (int k = lane; k < 256; k += 32)
            s = fmaf(hp[(size_t)gw * 256 + k], pw2[k], s);
        #pragma unroll
        for (int off = 16; off > 0; off >>= 1) s += __shfl_xor_sync(0xffffffffu, s, off);
        if (lane == 0) cy[gw] = s + pb2[0];
    }
}

// ---------------------------------------------------------------------------
// logits: 4 rows/block (grid 128) + fused final loss (last block).
// ---------------------------------------------------------------------------
__global__ void logits_kernel(const float* __restrict__ phi,
                              const float* __restrict__ cy,
                              float* __restrict__ lse,
                              float* __restrict__ diag,
                              float* __restrict__ out) {
    const int i0 = blockIdx.x * 4;
    __shared__ float sx[4][64];
    __shared__ float red[256];
    __shared__ float red2[256];
    __shared__ float sdiag[4];
    __shared__ int isLast;
    const int tid = threadIdx.x;
    sx[tid >> 6][tid & 63] = phi[(size_t)(i0 + (tid >> 6)) * 64 + (tid & 63)];
    __syncthreads();

    float lg[2][4];
    #pragma unroll
    for (int rep = 0; rep < 2; rep++) {
        const int j = tid + rep * 256;
        const float* y = phi + (size_t)(512 + j) * 64;
        float mx[4] = {0.f, 0.f, 0.f, 0.f}, ss[4] = {0.f, 0.f, 0.f, 0.f};
        #pragma unroll
        for (int k = 0; k < 32; k++) {
            const float yk = y[k];
            #pragma unroll
            for (int r = 0; r < 4; r++) {
                float d = sx[r][k] - yk;
                mx[r] = fmaxf(mx[r], fmaxf(d, 0.0f));
            }
        }
        #pragma unroll
        for (int k = 32; k < 64; k++) {
            const float yk = y[k];
            #pragma unroll
            for (int r = 0; r < 4; r++) {
                float d = sx[r][k] - yk;
                ss[r] = fmaf(d, d, ss[r]);
            }
        }
        const float cyj = cy[j];
        #pragma unroll
        for (int r = 0; r < 4; r++) {
            lg[rep][r] = cyj - (mx[r] + sqrtf(ss[r] + 1e-8f));
            if (j == i0 + r) sdiag[r] = lg[rep][r];
        }
    }
    #pragma unroll
    for (int r = 0; r < 4; r++) {
        __syncthreads();
        red[tid] = fmaxf(lg[0][r], lg[1][r]);
        __syncthreads();
        for (int s = 128; s > 0; s >>= 1) {
            if (tid < s) red[tid] = fmaxf(red[tid], red[tid + s]);
            __syncthreads();
        }
        const float rowmax = red[0];
        __syncthreads();
        red[tid] = expf(lg[0][r] - rowmax) + expf(lg[1][r] - rowmax);
        __syncthreads();
        for (int s = 128; s > 0; s >>= 1) {
            if (tid < s) red[tid] += red[tid + s];
            __syncthreads();
        }
        if (tid == 0) {
            lse[i0 + r] = rowmax + logf(red[0]);
            diag[i0 + r] = sdiag[r];
        }
    }

    // fused loss: last block to finish reduces lse/diag -> scalar.
    __threadfence();
    if (tid == 0) isLast = (atomicAdd(&g_done, 1) == 127) ? 1 : 0;
    __syncthreads();
    if (isLast) {
        __threadfence();
        float s1 = 0.0f, s2 = 0.0f;
        for (int i = tid; i < 512; i += 256) {
            const float l = lse[i];
            s1 += l - diag[i];
            const float u = l + 1e-6f;
            s2 = fmaf(u, u, s2);
        }
        red[tid] = s1; red2[tid] = s2;
        __syncthreads();
        for (int s = 128; s > 0; s >>= 1) {
            if (tid < s) { red[tid] += red[tid + s]; red2[tid] += red2[tid + s]; }
            __syncthreads();
        }
        if (tid == 0) {
            out[0] = red[0] * (1.0f / 512.0f) + 0.1f * red2[0] * (1.0f / 512.0f);
            g_done = 0;   // reset for next graph replay
        }
    }
}

// ---------------------------------------------------------------------------
// Host launcher
// ---------------------------------------------------------------------------
extern "C" void kernel_launch(void* const* d_in, const int* in_sizes, int n_in,
                              void* d_out, int out_size) {
    const float* curr = (const float*)d_in[0];
    const float* next = (const float*)d_in[1];
    const float* c1w = (const float*)d_in[2];
    const float* c1b = (const float*)d_in[3];
    const float* c2w = (const float*)d_in[4];
    const float* c2b = (const float*)d_in[5];
    const float* c3w = (const float*)d_in[6];
    const float* c3b = (const float*)d_in[7];
    const float* fcw = (const float*)d_in[8];
    const float* fcb = (const float*)d_in[9];
    const float* e1w = (const float*)d_in[10];
    const float* e1b = (const float*)d_in[11];
    const float* e2w = (const float*)d_in[12];
    const float* e2b = (const float*)d_in[13];
    const float* pw1 = (const float*)d_in[14];
    const float* pb1 = (const float*)d_in[15];
    const float* pw2 = (const float*)d_in[16];
    const float* pb2 = (const float*)d_in[17];

    u32 *p_w1f, *p_w2f, *p_w3f, *p_wfc, *p_we1, *p_we2, *p_wp1;
    __nv_bfloat16 *p_a1, *p_a2n, *p_feat;
    float *p_f, *p_h1, *p_phi, *p_hp, *p_cy, *p_lse, *p_diag, *p_part;
    cudaGetSymbolAddress((void**)&p_w1f, g_w1f);
    cudaGetSymbolAddress((void**)&p_w2f, g_w2f);
    cudaGetSymbolAddress((void**)&p_w3f, g_w3f);
    cudaGetSymbolAddress((void**)&p_wfc, g_wfc);
    cudaGetSymbolAddress((void**)&p_we1, g_we1);
    cudaGetSymbolAddress((void**)&p_we2, g_we2);
    cudaGetSymbolAddress((void**)&p_wp1, g_wp1);
    cudaGetSymbolAddress((void**)&p_a1, g_a1);
    cudaGetSymbolAddress((void**)&p_a2n, g_a2n);
    cudaGetSymbolAddress((void**)&p_feat, g_feat);
    cudaGetSymbolAddress((void**)&p_f, g_f);
    cudaGetSymbolAddress((void**)&p_h1, g_h1);
    cudaGetSymbolAddress((void**)&p_phi, g_phi);
    cudaGetSymbolAddress((void**)&p_hp, g_hp);
    cudaGetSymbolAddress((void**)&p_cy, g_cy);
    cudaGetSymbolAddress((void**)&p_lse, g_lse);
    cudaGetSymbolAddress((void**)&p_diag, g_diag);
    cudaGetSymbolAddress((void**)&p_part, g_part);

    const int SM1 = 26880;
    const int SM2 = 51200;
    const int SM3 = 23328;
    const int SMF = 30720 + 3584 * 4;
    const int SMH = 34816 + 4096 * 4;
    cudaFuncSetAttribute(conv1_mma, cudaFuncAttributeMaxDynamicSharedMemorySize, SM1);
    cudaFuncSetAttribute(conv2_mma, cudaFuncAttributeMaxDynamicSharedMemorySize, SM2);
    cudaFuncSetAttribute(conv3_mma, cudaFuncAttributeMaxDynamicSharedMemorySize, SM3);
    cudaFuncSetAttribute(fc_mma, cudaFuncAttributeMaxDynamicSharedMemorySize, SMF);
    cudaFuncSetAttribute(headA, cudaFuncAttributeMaxDynamicSharedMemorySize, SMH);
    cudaFuncSetAttribute(headB, cudaFuncAttributeMaxDynamicSharedMemorySize, SMH);

    prep_all<<<2008, 256>>>(c1w, c2w, c3w, fcw, e1w, e2w, pw1,
                            p_w1f, p_w2f, p_w3f, p_wfc, p_we1, p_we2, p_wp1);

    conv1_mma<<<dim3(512, 5), 160, SM1>>>(curr, next, p_w1f, c1b, p_a1);
    conv2_mma<<<dim3(512, 2), 352, SM2>>>(p_a1, p_w2f, c2b, p_a2n);
    conv3_mma<<<dim3(512, 2), 128, SM3>>>(p_a2n, p_w3f, c3b, p_feat);

    fc_mma<<<dim3(8, 4, 4), 256, SMF>>>(p_feat, p_wfc, p_part);
    combine_kernel<<<1024, 256>>>(p_part, fcb, p_f, 1024 * 256, 256, 4, 1);

    headA<<<48, 256, SMH>>>(p_f, p_we1, e1b, p_h1, p_wp1, pb1, p_hp);
    headB<<<72, 256, SMH>>>(p_h1, p_we2, e2b, p_phi, p_hp, pw2, pb2, p_cy);

    logits_kernel<<<128, 256>>>(p_phi, p_cy, p_lse, p_diag, (float*)d_out);
}

// round 12
// speedup vs baseline: 7.8261x; 1.1080x over previous
#include <cuda_runtime.h>
#include <cuda_bf16.h>
#include <math.h>

#define NIMG 1024
typedef unsigned int u32;

// ---------------------------------------------------------------------------
// scratch
// ---------------------------------------------------------------------------
__device__ __align__(128) u32 g_w1f[16 * 4 * 64];
__device__ __align__(128) u32 g_w2f[32 * 8 * 64];
__device__ __align__(128) u32 g_w3f[36 * 8 * 64];
__device__ __align__(128) u32 g_wfc[196 * 32 * 64];
__device__ __align__(128) u32 g_we1[16 * 32 * 64];
__device__ __align__(128) u32 g_we2[16 * 8 * 64];
__device__ __align__(128) u32 g_wp1[16 * 32 * 64];
__device__ __align__(128) __nv_bfloat16 g_a1[(size_t)NIMG * 12800];
__device__ __align__(128) __nv_bfloat16 g_a2n[(size_t)NIMG * 81 * 64];
__device__ __align__(128) __nv_bfloat16 g_feat[(size_t)NIMG * 3136];
__device__ __align__(128) float g_h1[NIMG * 256];
__device__ __align__(128) float g_phi[NIMG * 64];
__device__ __align__(128) float g_hp[512 * 256];
__device__ __align__(128) float g_cy[512];
__device__ __align__(128) float g_lse[512];
__device__ __align__(128) float g_diag[512];
__device__ __align__(128) float g_part[4 * 1024 * 256];
__device__ int g_done = 0;   // logits completion counter (self-resetting)

// ---------------------------------------------------------------------------
// helpers
// ---------------------------------------------------------------------------
__device__ __forceinline__ u32 packbf(float lo, float hi) {
    __nv_bfloat162 h = __float22bfloat162_rn(make_float2(lo, hi));
    return *reinterpret_cast<u32*>(&h);
}
__device__ __forceinline__ void mmabf(float* d, const u32* a, const u32* b) {
    asm volatile(
        "mma.sync.aligned.m16n8k16.row.col.f32.bf16.bf16.f32 "
        "{%0,%1,%2,%3},{%4,%5,%6,%7},{%8,%9},{%0,%1,%2,%3};\n"
        : "+f"(d[0]), "+f"(d[1]), "+f"(d[2]), "+f"(d[3])
        : "r"(a[0]), "r"(a[1]), "r"(a[2]), "r"(a[3]), "r"(b[0]), "r"(b[1]));
}
__device__ __forceinline__ void ldsm4(u32* r, u32 addr) {
    asm volatile("ldmatrix.sync.aligned.m8n8.x4.shared.b16 {%0,%1,%2,%3}, [%4];"
                 : "=r"(r[0]), "=r"(r[1]), "=r"(r[2]), "=r"(r[3]) : "r"(addr));
}
__device__ __forceinline__ u32 smem_u32(const void* p) {
    u32 a;
    asm("{ .reg .u64 t; cvta.to.shared.u64 t, %1; cvt.u32.u64 %0, t; }"
        : "=r"(a) : "l"(p));
    return a;
}
__device__ __forceinline__ void cpa16(u32 saddr, const void* g) {
    asm volatile("cp.async.ca.shared.global [%0], [%1], 16;"
                 :: "r"(saddr), "l"(g));
}
__device__ __forceinline__ void cpa_commit() {
    asm volatile("cp.async.commit_group;");
}
template<int N> __device__ __forceinline__ void cpa_wait() {
    asm volatile("cp.async.wait_group %0;" :: "n"(N));
}

// ---------------------------------------------------------------------------
// unified weight prep. blocks 0..439: scalar paths (conv1/2/3, e1, e2, pw1).
// blocks 440..537: smem-tiled fcw frag prep (coalesced).
// frag layout: wf[(c*NT+nt)*64 + lane*2 + s] =
//   bf16x2 of W[k=c*16+s*8+2(lane&3)][n=nt*8+lane/4]
// ---------------------------------------------------------------------------
__global__ void prep_all(const float* __restrict__ c1w, const float* __restrict__ c2w,
                         const float* __restrict__ c3w, const float* __restrict__ fcw,
                         const float* __restrict__ e1w, const float* __restrict__ e2w,
                         const float* __restrict__ pw1,
                         u32* __restrict__ w1f, u32* __restrict__ w2f,
                         u32* __restrict__ w3f, u32* __restrict__ wfc,
                         u32* __restrict__ we1, u32* __restrict__ we2,
                         u32* __restrict__ wp1) {
    __shared__ float S[32 * 257];
    const int b = blockIdx.x;
    if (b < 440) {
        int gi = b * 256 + threadIdx.x;
        if (gi < 4096) {                               // conv1
            int i = gi;
            int s = i & 1, lane = (i >> 1) & 31;
            int cn = i >> 6, nt = cn & 3, c = cn >> 2;
            int t = lane & 3, g = lane >> 2;
            int n = nt * 8 + g;
            int ic = c >> 2, ky = (c & 3) * 2 + s, kx = 2 * t;
            const float* base = c1w + ((n * 4 + ic) * 8 + ky) * 8 + kx;
            w1f[i] = packbf(base[0], base[1]);
        } else if (gi < 20480) {                       // conv2
            int i = gi - 4096;
            int s = i & 1, lane = (i >> 1) & 31;
            int cn = i >> 6, nt = cn & 7, ic = cn >> 3;
            int t = lane & 3, g = lane >> 2;
            int n = nt * 8 + g;
            int ky = s * 2 + (t >> 1), kx = (t & 1) * 2;
            const float* base = c2w + ((n * 32 + ic) * 4 + ky) * 4 + kx;
            w2f[i] = packbf(base[0], base[1]);
        } else if (gi < 38912) {                       // conv3
            int i = gi - 20480;
            int s = i & 1, lane = (i >> 1) & 31;
            int cn = i >> 6, nt = cn & 7, c = cn >> 3;
            int t = lane & 3, g = lane >> 2;
            int n = nt * 8 + g;
            int p = c >> 2, icc = c & 3;
            int ic = icc * 16 + s * 8 + 2 * t;
            int ky = p / 3, kx = p % 3;
            float lo = c3w[((n * 64 + ic) * 3 + ky) * 3 + kx];
            float hi = c3w[((n * 64 + ic + 1) * 3 + ky) * 3 + kx];
            w3f[i] = packbf(lo, hi);
        } else if (gi < 71680) {                       // e1 (NTg=32)
            int i = gi - 38912;
            int s = i & 1, lane = (i >> 1) & 31;
            int cn = i >> 6, nt = cn & 31, c = cn >> 5;
            int t = lane & 3, g = lane >> 2;
            int n = nt * 8 + g;
            int k0 = c * 16 + s * 8 + 2 * t;
            we1[i] = packbf(e1w[(size_t)k0 * 256 + n], e1w[(size_t)(k0 + 1) * 256 + n]);
        } else if (gi < 79872) {                       // e2 (NTg=8)
            int i = gi - 71680;
            int s = i & 1, lane = (i >> 1) & 31;
            int cn = i >> 6, nt = cn & 7, c = cn >> 3;
            int t = lane & 3, g = lane >> 2;
            int n = nt * 8 + g;
            int k0 = c * 16 + s * 8 + 2 * t;
            we2[i] = packbf(e2w[(size_t)k0 * 64 + n], e2w[(size_t)(k0 + 1) * 64 + n]);
        } else if (gi < 112640) {                      // pw1 (NTg=32)
            int i = gi - 79872;
            int s = i & 1, lane = (i >> 1) & 31;
            int cn = i >> 6, nt = cn & 31, c = cn >> 5;
            int t = lane & 3, g = lane >> 2;
            int n = nt * 8 + g;
            int k0 = c * 16 + s * 8 + 2 * t;
            wp1[i] = packbf(pw1[(size_t)k0 * 256 + n], pw1[(size_t)(k0 + 1) * 256 + n]);
        }
    } else {
        // fcw tiled: block bb handles chunks {2bb, 2bb+1} (32 k-rows, all 256 n)
        const int bb = b - 440;
        const int kb = bb * 32;
        for (int j = threadIdx.x; j < 2048; j += 256) {
            int krel = j >> 6, n4 = (j & 63) * 4;
            float4 v = *(const float4*)&fcw[(size_t)(kb + krel) * 256 + n4];
            float* row = S + krel * 257 + n4;
            row[0] = v.x; row[1] = v.y; row[2] = v.z; row[3] = v.w;
        }
        __syncthreads();
        for (int j = threadIdx.x; j < 4096; j += 256) {
            int s = j & 1, lane = (j >> 1) & 31;
            int nt = (j >> 6) & 31, cl = j >> 11;
            int t = lane & 3, g = lane >> 2;
            int krel = cl * 16 + s * 8 + 2 * t;
            int n = nt * 8 + g;
            wfc[((size_t)(2 * bb + cl) * 32 + nt) * 64 + lane * 2 + s] =
                packbf(S[krel * 257 + n], S[(krel + 1) * 257 + n]);
        }
    }
}

// ---------------------------------------------------------------------------
// conv1: grid (512 pairs, 5 oy-groups), 160 thr. Scalar A (smem) + B frags
// direct from gmem. ~7 blocks/SM.
// ---------------------------------------------------------------------------
__global__ void __launch_bounds__(160, 7)
conv1_mma(const float* __restrict__ curr,
          const float* __restrict__ next,
          const u32* __restrict__ wfu,
          const float* __restrict__ bias,
          __nv_bfloat16* __restrict__ out) {
    extern __shared__ char smc[];
    __nv_bfloat16* simg = (__nv_bfloat16*)smc;     // 2*6720 bf16
    const int p = blockIdx.x, oyg = blockIdx.y;
    const int iy0 = oyg * 16;
    const float* in0 = curr + (size_t)p * 28224;
    const float* in1 = next + (size_t)p * 28224;
    for (int i = threadIdx.x; i < 3360; i += 160) {
        int e = i * 4;
        int im = e / 6720, e2 = e % 6720;
        int ic = e2 / 1680, rem = e2 % 1680;
        const float* src = im ? in1 : in0;
        float4 v = *(const float4*)&src[ic * 7056 + iy0 * 84 + rem];
        u32* d = (u32*)&simg[e];
        d[0] = packbf(v.x, v.y);
        d[1] = packbf(v.z, v.w);
    }
    __syncthreads();

    const int lane = threadIdx.x & 31, wid = threadIdx.x >> 5;
    const int t = lane & 3;
    const int r0 = wid * 16 + (lane >> 2), r1 = r0 + 8;
    const int b00 = (r0 / 20) * 336 + (r0 % 20) * 4 + 2 * t;
    const int b01 = (r1 / 20) * 336 + (r1 % 20) * 4 + 2 * t;
    const u32* wlane = wfu + lane * 2;

    float acc[2][4][4];
    #pragma unroll
    for (int nt = 0; nt < 4; nt++) {
        int oc = nt * 8 + t * 2;
        float b0 = bias[oc], b1 = bias[oc + 1];
        #pragma unroll
        for (int im = 0; im < 2; im++) {
            acc[im][nt][0] = b0; acc[im][nt][1] = b1;
            acc[im][nt][2] = b0; acc[im][nt][3] = b1;
        }
    }
    u32 a0[4], a1[4];
    uint2 bv[4];
    a0[0] = *(const u32*)&simg[b00];
    a0[1] = *(const u32*)&simg[b01];
    a0[2] = *(const u32*)&simg[84 + b00];
    a0[3] = *(const u32*)&simg[84 + b01];
    a1[0] = *(const u32*)&simg[6720 + b00];
    a1[1] = *(const u32*)&simg[6720 + b01];
    a1[2] = *(const u32*)&simg[6720 + 84 + b00];
    a1[3] = *(const u32*)&simg[6720 + 84 + b01];
    #pragma unroll
    for (int nt = 0; nt < 4; nt++)
        bv[nt] = *(const uint2*)&wlane[nt * 64];

    #pragma unroll
    for (int c = 0; c < 16; c++) {
        u32 na0[4], na1[4];
        uint2 nbv[4];
        if (c < 15) {
            const int o = ((c + 1) >> 2) * 1680 + ((c + 1) & 3) * 168;
            na0[0] = *(const u32*)&simg[o + b00];
            na0[1] = *(const u32*)&simg[o + b01];
            na0[2] = *(const u32*)&simg[o + 84 + b00];
            na0[3] = *(const u32*)&simg[o + 84 + b01];
            na1[0] = *(const u32*)&simg[6720 + o + b00];
            na1[1] = *(const u32*)&simg[6720 + o + b01];
            na1[2] = *(const u32*)&simg[6720 + o + 84 + b00];
            na1[3] = *(const u32*)&simg[6720 + o + 84 + b01];
            #pragma unroll
            for (int nt = 0; nt < 4; nt++)
                nbv[nt] = *(const uint2*)&wlane[((c + 1) * 4 + nt) * 64];
        }
        #pragma unroll
        for (int nt = 0; nt < 4; nt++) {
            u32 b[2] = {bv[nt].x, bv[nt].y};
            mmabf(acc[0][nt], a0, b);
            mmabf(acc[1][nt], a1, b);
        }
        if (c < 15) {
            #pragma unroll
            for (int q = 0; q < 4; q++) { a0[q] = na0[q]; a1[q] = na1[q]; }
            #pragma unroll
            for (int nt = 0; nt < 4; nt++) bv[nt] = nbv[nt];
        }
    }
    #pragma unroll
    for (int im = 0; im < 2; im++) {
        const int img = p + im * 512;
        __nv_bfloat16* ob = out + (size_t)img * 12800 + oyg * 80;
        #pragma unroll
        for (int nt = 0; nt < 4; nt++) {
            int oc = nt * 8 + t * 2;
            __nv_bfloat16* p0 = ob + (size_t)oc * 400;
            p0[r0]       = __float2bfloat16(fmaxf(acc[im][nt][0], 0.0f));
            p0[400 + r0] = __float2bfloat16(fmaxf(acc[im][nt][1], 0.0f));
            p0[r1]       = __float2bfloat16(fmaxf(acc[im][nt][2], 0.0f));
            p0[400 + r1] = __float2bfloat16(fmaxf(acc[im][nt][3], 0.0f));
        }
    }
}

// ---------------------------------------------------------------------------
// conv2: grid (512 pairs, 2 oc-halves), 352 thr. Scalar A (smem) + B frags
// from gmem. 3 blocks/SM.
// ---------------------------------------------------------------------------
__global__ void __launch_bounds__(352, 3)
conv2_mma(const __nv_bfloat16* __restrict__ a1,
          const u32* __restrict__ wfu,
          const float* __restrict__ bias,
          __nv_bfloat16* __restrict__ out) {
    extern __shared__ char smc[];
    __nv_bfloat16* sin = (__nv_bfloat16*)smc;      // 25600 bf16
    const int p = blockIdx.x, q = blockIdx.y;
    const uint4* src = (const uint4*)(a1 + (size_t)p * 25600);
    for (int i = threadIdx.x; i < 3200; i += 352)
        ((uint4*)sin)[i] = src[i];
    __syncthreads();

    const int lane = threadIdx.x & 31, wid = threadIdx.x >> 5;
    const int t = lane & 3;
    const int toff = (t >> 1) * 20 + (t & 1) * 2;
    const int r0 = wid * 16 + (lane >> 2), r1 = r0 + 8;
    const int gg0 = (r0 < 162) ? r0 : 161, gg1 = (r1 < 162) ? r1 : 161;
    const int im0 = gg0 / 81, px0 = gg0 % 81;
    const int im1 = gg1 / 81, px1 = gg1 % 81;
    const int A0 = im0 * 12800 + (px0 / 9) * 40 + (px0 % 9) * 2 + toff;
    const int A1 = im1 * 12800 + (px1 / 9) * 40 + (px1 % 9) * 2 + toff;
    const u32* wlane = wfu + (size_t)q * 4 * 64 + lane * 2;

    float acc[4][4];
    #pragma unroll
    for (int nt = 0; nt < 4; nt++) {
        int oc = q * 32 + nt * 8 + t * 2;
        float b0 = bias[oc], b1 = bias[oc + 1];
        acc[nt][0] = b0; acc[nt][1] = b1; acc[nt][2] = b0; acc[nt][3] = b1;
    }

    u32 a[4];
    uint2 bv[4];
    a[0] = *(const u32*)&sin[A0];
    a[1] = *(const u32*)&sin[A1];
    a[2] = *(const u32*)&sin[40 + A0];
    a[3] = *(const u32*)&sin[40 + A1];
    #pragma unroll
    for (int nt = 0; nt < 4; nt++)
        bv[nt] = *(const uint2*)&wlane[nt * 64];

    #pragma unroll 8
    for (int ic = 0; ic < 32; ic++) {
        u32 na[4];
        uint2 nbv[4];
        if (ic < 31) {
            const int o = (ic + 1) * 400;
            na[0] = *(const u32*)&sin[o + A0];
            na[1] = *(const u32*)&sin[o + A1];
            na[2] = *(const u32*)&sin[o + 40 + A0];
            na[3] = *(const u32*)&sin[o + 40 + A1];
            #pragma unroll
            for (int nt = 0; nt < 4; nt++)
                nbv[nt] = *(const uint2*)&wlane[((ic + 1) * 8 + nt) * 64];
        }
        #pragma unroll
        for (int nt = 0; nt < 4; nt++) {
            u32 b[2] = {bv[nt].x, bv[nt].y};
            mmabf(acc[nt], a, b);
        }
        if (ic < 31) {
            #pragma unroll
            for (int k = 0; k < 4; k++) a[k] = na[k];
            #pragma unroll
            for (int nt = 0; nt < 4; nt++) bv[nt] = nbv[nt];
        }
    }
    #pragma unroll
    for (int nt = 0; nt < 4; nt++) {
        int oc = q * 32 + nt * 8 + t * 2;
        if (r0 < 162)
            *(u32*)&out[((size_t)(p * 2 + im0) * 81 + px0) * 64 + oc] =
                packbf(fmaxf(acc[nt][0], 0.0f), fmaxf(acc[nt][1], 0.0f));
        if (r1 < 162)
            *(u32*)&out[((size_t)(p * 2 + im1) * 81 + px1) * 64 + oc] =
                packbf(fmaxf(acc[nt][2], 0.0f), fmaxf(acc[nt][3], 0.0f));
    }
}

// ---------------------------------------------------------------------------
// conv3: grid (512, 2 oc-halves), 128 thr (4 warps, M=32/warp). LDSM A x2
// groups sharing B frags. 5 blocks/SM target.
// ---------------------------------------------------------------------------
__global__ void __launch_bounds__(128, 5)
conv3_mma(const __nv_bfloat16* __restrict__ a2n,
          const u32* __restrict__ wfu,
          const float* __restrict__ bias,
          __nv_bfloat16* __restrict__ feat) {
    extern __shared__ char smc[];
    __nv_bfloat16* sin = (__nv_bfloat16*)smc;      // 2*81*72 bf16
    const int q = blockIdx.y;
    const int imgb = blockIdx.x * 2;
    for (int i = threadIdx.x; i < 1296; i += 128) {
        int im = i / 648, r = i % 648;
        int px = r >> 3, qq = r & 7;
        *((uint4*)&sin[im * 5832 + px * 72]       + qq) =
        *((const uint4*)&a2n[((size_t)(imgb + im) * 81 + px) * 64] + qq);
    }
    __syncthreads();

    const int lane = threadIdx.x & 31, wid = threadIdx.x >> 5;
    const int t = lane & 3;
    const u32 sb = smem_u32(smc);
    u32 laG[2];
    #pragma unroll
    for (int G = 0; G < 2; G++) {
        int r = wid * 32 + G * 16 + (lane & 15);
        if (r > 97) r = 97;
        int im = r / 49, lp = r % 49;
        laG[G] = sb + (u32)(im * 11664 + ((lp / 7) * 9 + lp % 7) * 144)
                    + ((lane & 16) ? 16u : 0u);
    }
    const u32* wlane = wfu + (size_t)q * 4 * 64 + lane * 2;

    float acc[2][4][4];
    #pragma unroll
    for (int nt = 0; nt < 4; nt++) {
        int oc = q * 32 + nt * 8 + t * 2;
        float b0 = bias[oc], b1 = bias[oc + 1];
        #pragma unroll
        for (int G = 0; G < 2; G++) {
            acc[G][nt][0] = b0; acc[G][nt][1] = b1;
            acc[G][nt][2] = b0; acc[G][nt][3] = b1;
        }
    }

    u32 a0[4], a1[4];
    uint2 bv[4];
    ldsm4(a0, laG[0]);
    ldsm4(a1, laG[1]);
    #pragma unroll
    for (int nt = 0; nt < 4; nt++)
        bv[nt] = *(const uint2*)&wlane[nt * 64];

    #pragma unroll
    for (int c = 0; c < 36; c++) {
        u32 na0[4], na1[4];
        uint2 nbv[4];
        if (c < 35) {
            const int pp = (c + 1) >> 2, icc = (c + 1) & 3;
            const u32 off = (u32)(((pp / 3) * 9 + (pp % 3)) * 144 + icc * 32);
            ldsm4(na0, laG[0] + off);
            ldsm4(na1, laG[1] + off);
            #pragma unroll
            for (int nt = 0; nt < 4; nt++)
                nbv[nt] = *(const uint2*)&wlane[((c + 1) * 8 + nt) * 64];
        }
        #pragma unroll
        for (int nt = 0; nt < 4; nt++) {
            u32 b[2] = {bv[nt].x, bv[nt].y};
            mmabf(acc[0][nt], a0, b);
            mmabf(acc[1][nt], a1, b);
        }
        if (c < 35) {
            #pragma unroll
            for (int k = 0; k < 4; k++) { a0[k] = na0[k]; a1[k] = na1[k]; }
            #pragma unroll
            for (int nt = 0; nt < 4; nt++) bv[nt] = nbv[nt];
        }
    }
    #pragma unroll
    for (int G = 0; G < 2; G++) {
        const int r0 = wid * 32 + G * 16 + (lane >> 2), r1 = r0 + 8;
        const int g0 = (r0 < 98) ? r0 : 97, g1 = (r1 < 98) ? r1 : 97;
        const int im0 = g0 / 49, lp0 = g0 % 49;
        const int im1 = g1 / 49, lp1 = g1 % 49;
        #pragma unroll
        for (int nt = 0; nt < 4; nt++) {
            int oc = q * 32 + nt * 8 + t * 2;
            if (r0 < 98) {
                __nv_bfloat16* fb = feat + (size_t)(imgb + im0) * 3136 + oc * 49 + lp0;
                fb[0]  = __float2bfloat16(fmaxf(acc[G][nt][0], 0.0f));
                fb[49] = __float2bfloat16(fmaxf(acc[G][nt][1], 0.0f));
            }
            if (r1 < 98) {
                __nv_bfloat16* fb = feat + (size_t)(imgb + im1) * 3136 + oc * 49 + lp1;
                fb[0]  = __float2bfloat16(fmaxf(acc[G][nt][2], 0.0f));
                fb[49] = __float2bfloat16(fmaxf(acc[G][nt][3], 0.0f));
            }
        }
    }
}

// ---------------------------------------------------------------------------
// FC (bf16 mma): [1024,3136]@[3136,256], split-K 4 -> fp32 partials.
// cp.async double-buffered staging (2 smem buffers).
// smem layout: A0 @0 (30720B), A1 @30720, B0 @61440 (14336B), B1 @75776.
// ---------------------------------------------------------------------------
__global__ void fc_mma(const __nv_bfloat16* __restrict__ feat,
                       const u32* __restrict__ wfu,
                       float* __restrict__ part) {
    extern __shared__ char smc[];
    const int mb = blockIdx.x, nb = blockIdx.y, z = blockIdx.z;
    const int m0b = mb * 128;
    const int lane = threadIdx.x & 31, wid = threadIdx.x >> 5;
    const int t = lane & 3, g = lane >> 2;
    const u32 sbase = smem_u32(smc);

    #define FC_STAGE(IT, BUF) do {                                            \
        const int kbase_ = z * 784 + (IT) * 112;                              \
        const int cbase_ = z * 49 + (IT) * 7;                                 \
        const u32 aoff_ = sbase + (BUF) * 30720u;                             \
        for (int i = threadIdx.x; i < 1792; i += 256) {                       \
            int row_ = i / 14, seg_ = i % 14;                                 \
            cpa16(aoff_ + (u32)(row_ * 120 + seg_ * 8) * 2u,                  \
                  &feat[(size_t)(m0b + row_) * 3136 + kbase_ + seg_ * 8]);    \
        }                                                                     \
        const u32 boff_ = sbase + 61440u + (BUF) * 14336u;                    \
        for (int i = threadIdx.x; i < 896; i += 256) {                        \
            int cn_ = i >> 4, cl_ = cn_ >> 3, ntl_ = cn_ & 7;                 \
            cpa16(boff_ + (u32)i * 16u,                                       \
                  &wfu[((size_t)(cbase_ + cl_) * 32 + nb * 8 + ntl_) * 64     \
                       + (i & 15) * 4]);                                      \
        }                                                                     \
    } while (0)

    float acc[8][4] = {};
    FC_STAGE(0, 0);
    cpa_commit();
    for (int it = 0; it < 7; it++) {
        if (it < 6) {
            FC_STAGE(it + 1, (it + 1) & 1);
            cpa_commit();
            cpa_wait<1>();
        } else {
            cpa_wait<0>();
        }
        __syncthreads();
        const __nv_bfloat16* sA = (const __nv_bfloat16*)(smc + (it & 1) * 30720);
        const u32* sB = (const u32*)(smc + 61440 + (it & 1) * 14336);
        #pragma unroll
        for (int c_l = 0; c_l < 7; c_l++) {
            const int ra = (wid * 16 + g) * 120 + c_l * 16 + 2 * t;
            u32 a[4];
            a[0] = *(const u32*)&sA[ra];
            a[1] = *(const u32*)&sA[ra + 8 * 120];
            a[2] = *(const u32*)&sA[ra + 8];
            a[3] = *(const u32*)&sA[ra + 8 * 120 + 8];
            const u32* wb = sB + c_l * 512 + lane * 2;
            #pragma unroll
            for (int nt = 0; nt < 8; nt++) {
                uint2 bv = *(const uint2*)&wb[nt * 64];
                u32 b[2] = {bv.x, bv.y};
                mmabf(acc[nt], a, b);
            }
        }
        __syncthreads();
    }
    #undef FC_STAGE

    float* pb = part + (size_t)z * 262144;
    const int mr0 = m0b + wid * 16 + g, mr1 = mr0 + 8;
    #pragma unroll
    for (int nt = 0; nt < 8; nt++) {
        int col = nb * 64 + nt * 8 + 2 * t;
        *(float2*)&pb[(size_t)mr0 * 256 + col] = make_float2(acc[nt][0], acc[nt][1]);
        *(float2*)&pb[(size_t)mr1 * 256 + col] = make_float2(acc[nt][2], acc[nt][3]);
    }
}

// ---------------------------------------------------------------------------
// head GEMM bodies (bf16 mma): one 128x64 tile of relu?(A[:,256]@W+b).
// head_bodyP stages A = relu(sum of 4 fc partials + fcb) on the fly.
// ---------------------------------------------------------------------------
__device__ void head_bodyP(const float* __restrict__ part, int rowOff,
                           const float* __restrict__ fcb,
                           const u32* __restrict__ wfu,
                           const float* __restrict__ bias,
                           float* __restrict__ C,
                           int NTg, int mb, int nb) {
    extern __shared__ char smc[];
    __nv_bfloat16* sA = (__nv_bfloat16*)smc;       // 128*136 bf16
    u32* sB = (u32*)(smc + 34816);                  // 4096 u32
    const int m0b = mb * 128;
    const int N = NTg * 8;
    const int lane = threadIdx.x & 31, wid = threadIdx.x >> 5;
    const int t = lane & 3, g = lane >> 2;

    float acc[8][4] = {};
    #pragma unroll
    for (int it = 0; it < 2; it++) {
        const int kbase = it * 128;
        __syncthreads();
        for (int i = threadIdx.x; i < 4096; i += 256) {
            int row = i >> 5, seg = i & 31;
            size_t idx = (size_t)(rowOff + m0b + row) * 256 + kbase + seg * 4;
            float4 v = *(const float4*)&fcb[kbase + seg * 4];
            float4 p0 = *(const float4*)&part[idx];
            float4 p1 = *(const float4*)&part[262144 + idx];
            float4 p2 = *(const float4*)&part[524288 + idx];
            float4 p3 = *(const float4*)&part[786432 + idx];
            v.x = fmaxf(v.x + p0.x + p1.x + p2.x + p3.x, 0.0f);
            v.y = fmaxf(v.y + p0.y + p1.y + p2.y + p3.y, 0.0f);
            v.z = fmaxf(v.z + p0.z + p1.z + p2.z + p3.z, 0.0f);
            v.w = fmaxf(v.w + p0.w + p1.w + p2.w + p3.w, 0.0f);
            u32* d = (u32*)&sA[row * 136 + seg * 4];
            d[0] = packbf(v.x, v.y);
            d[1] = packbf(v.z, v.w);
        }
        for (int i = threadIdx.x; i < 1024; i += 256) {
            int cn = i >> 4, c_l = cn >> 3, ntl = cn & 7;
            ((uint4*)sB)[i] =
                *(const uint4*)&wfu[(((it * 8 + c_l) * NTg) + nb * 8 + ntl) * 64 + (i & 15) * 4];
        }
        __syncthreads();
        #pragma unroll
        for (int c_l = 0; c_l < 8; c_l++) {
            const int ra = (wid * 16 + g) * 136 + c_l * 16 + 2 * t;
            u32 a[4];
            a[0] = *(const u32*)&sA[ra];
            a[1] = *(const u32*)&sA[ra + 8 * 136];
            a[2] = *(const u32*)&sA[ra + 8];
            a[3] = *(const u32*)&sA[ra + 8 * 136 + 8];
            const u32* wb = sB + c_l * 512 + lane * 2;
            #pragma unroll
            for (int nt = 0; nt < 8; nt++) {
                uint2 bv = *(const uint2*)&wb[nt * 64];
                u32 b[2] = {bv.x, bv.y};
                mmabf(acc[nt], a, b);
            }
        }
    }
    const int mr0 = m0b + wid * 16 + g, mr1 = mr0 + 8;
    #pragma unroll
    for (int nt = 0; nt < 8; nt++) {
        int col = nb * 64 + nt * 8 + 2 * t;
        float b0 = bias[col], b1 = bias[col + 1];
        float v00 = fmaxf(acc[nt][0] + b0, 0.0f), v01 = fmaxf(acc[nt][1] + b1, 0.0f);
        float v10 = fmaxf(acc[nt][2] + b0, 0.0f), v11 = fmaxf(acc[nt][3] + b1, 0.0f);
        *(float2*)&C[(size_t)mr0 * N + col] = make_float2(v00, v01);
        *(float2*)&C[(size_t)mr1 * N + col] = make_float2(v10, v11);
    }
}

__device__ void head_body(const float* __restrict__ A,
                          const u32* __restrict__ wfu,
                          const float* __restrict__ bias,
                          float* __restrict__ C,
                          int NTg, int doRelu, int mb, int nb) {
    extern __shared__ char smc[];
    __nv_bfloat16* sA = (__nv_bfloat16*)smc;       // 128*136 bf16
    u32* sB = (u32*)(smc + 34816);                  // 4096 u32
    const int m0b = mb * 128;
    const int N = NTg * 8;
    const int lane = threadIdx.x & 31, wid = threadIdx.x >> 5;
    const int t = lane & 3, g = lane >> 2;

    float acc[8][4] = {};
    #pragma unroll
    for (int it = 0; it < 2; it++) {
        const int kbase = it * 128;
        __syncthreads();
        for (int i = threadIdx.x; i < 4096; i += 256) {
            int row = i >> 5, seg = i & 31;
            float4 v = *(const float4*)&A[(size_t)(m0b + row) * 256 + kbase + seg * 4];
            u32* d = (u32*)&sA[row * 136 + seg * 4];
            d[0] = packbf(v.x, v.y);
            d[1] = packbf(v.z, v.w);
        }
        for (int i = threadIdx.x; i < 1024; i += 256) {
            int cn = i >> 4, c_l = cn >> 3, ntl = cn & 7;
            ((uint4*)sB)[i] =
                *(const uint4*)&wfu[(((it * 8 + c_l) * NTg) + nb * 8 + ntl) * 64 + (i & 15) * 4];
        }
        __syncthreads();
        #pragma unroll
        for (int c_l = 0; c_l < 8; c_l++) {
            const int ra = (wid * 16 + g) * 136 + c_l * 16 + 2 * t;
            u32 a[4];
            a[0] = *(const u32*)&sA[ra];
            a[1] = *(const u32*)&sA[ra + 8 * 136];
            a[2] = *(const u32*)&sA[ra + 8];
            a[3] = *(const u32*)&sA[ra + 8 * 136 + 8];
            const u32* wb = sB + c_l * 512 + lane * 2;
            #pragma unroll
            for (int nt = 0; nt < 8; nt++) {
                uint2 bv = *(const uint2*)&wb[nt * 64];
                u32 b[2] = {bv.x, bv.y};
                mmabf(acc[nt], a, b);
            }
        }
    }
    const int mr0 = m0b + wid * 16 + g, mr1 = mr0 + 8;
    #pragma unroll
    for (int nt = 0; nt < 8; nt++) {
        int col = nb * 64 + nt * 8 + 2 * t;
        float b0 = bias[col], b1 = bias[col + 1];
        float v00 = acc[nt][0] + b0, v01 = acc[nt][1] + b1;
        float v10 = acc[nt][2] + b0, v11 = acc[nt][3] + b1;
        if (doRelu) {
            v00 = fmaxf(v00, 0.0f); v01 = fmaxf(v01, 0.0f);
            v10 = fmaxf(v10, 0.0f); v11 = fmaxf(v11, 0.0f);
        }
        *(float2*)&C[(size_t)mr0 * N + col] = make_float2(v00, v01);
        *(float2*)&C[(size_t)mr1 * N + col] = make_float2(v10, v11);
    }
}

// headA: blocks 0-31 -> h1 = relu(f@e1w+e1b); 32-47 -> hp = relu(f_next@pw1+pb1)
// where f = relu(sum partials + fcb) staged on the fly.
__global__ void headA(const float* __restrict__ part, const float* __restrict__ fcb,
                      const u32* __restrict__ we1, const float* __restrict__ e1b,
                      float* __restrict__ h1,
                      const u32* __restrict__ wp1, const float* __restrict__ pb1,
                      float* __restrict__ hp) {
    int bid = blockIdx.x;
    if (bid < 32) head_bodyP(part, 0, fcb, we1, e1b, h1, 32, bid >> 2, bid & 3);
    else {
        bid -= 32;
        head_bodyP(part, 512, fcb, wp1, pb1, hp, 32, bid >> 2, bid & 3);
    }
}

__global__ void headB(const float* __restrict__ h1,
                      const u32* __restrict__ we2, const float* __restrict__ e2b,
                      float* __restrict__ phi,
                      const float* __restrict__ hp,
                      const float* __restrict__ pw2, const float* __restrict__ pb2,
                      float* __restrict__ cy) {
    int bid = blockIdx.x;
    if (bid < 8) {
        head_body(h1, we2, e2b, phi, 8, 0, bid, 0);
    } else {
        const int gw = (bid - 8) * 8 + (threadIdx.x >> 5);
        const int lane = threadIdx.x & 31;
        float s = 0.0f;
        for (int k = lane; k < 256; k += 32)
            s = fmaf(hp[(size_t)gw * 256 + k], pw2[k], s);
        #pragma unroll
        for (int off = 16; off > 0; off >>= 1) s += __shfl_xor_sync(0xffffffffu, s, off);
        if (lane == 0) cy[gw] = s + pb2[0];
    }
}

// ---------------------------------------------------------------------------
// logits: 4 rows/block (grid 128) + fused final loss (last block).
// ---------------------------------------------------------------------------
__global__ void logits_kernel(const float* __restrict__ phi,
                              const float* __restrict__ cy,
                              float* __restrict__ lse,
                              float* __restrict__ diag,
                              float* __restrict__ out) {
    const int i0 = blockIdx.x * 4;
    __shared__ float sx[4][64];
    __shared__ float red[256];
    __shared__ float red2[256];
    __shared__ float sdiag[4];
    __shared__ int isLast;
    const int tid = threadIdx.x;
    sx[tid >> 6][tid & 63] = phi[(size_t)(i0 + (tid >> 6)) * 64 + (tid & 63)];
    __syncthreads();

    float lg[2][4];
    #pragma unroll
    for (int rep = 0; rep < 2; rep++) {
        const int j = tid + rep * 256;
        const float* y = phi + (size_t)(512 + j) * 64;
        float mx[4] = {0.f, 0.f, 0.f, 0.f}, ss[4] = {0.f, 0.f, 0.f, 0.f};
        #pragma unroll
        for (int k = 0; k < 32; k++) {
            const float yk = y[k];
            #pragma unroll
            for (int r = 0; r < 4; r++) {
                float d = sx[r][k] - yk;
                mx[r] = fmaxf(mx[r], fmaxf(d, 0.0f));
            }
        }
        #pragma unroll
        for (int k = 32; k < 64; k++) {
            const float yk = y[k];
            #pragma unroll
            for (int r = 0; r < 4; r++) {
                float d = sx[r][k] - yk;
                ss[r] = fmaf(d, d, ss[r]);
            }
        }
        const float cyj = cy[j];
        #pragma unroll
        for (int r = 0; r < 4; r++) {
            lg[rep][r] = cyj - (mx[r] + sqrtf(ss[r] + 1e-8f));
            if (j == i0 + r) sdiag[r] = lg[rep][r];
        }
    }
    #pragma unroll
    for (int r = 0; r < 4; r++) {
        __syncthreads();
        red[tid] = fmaxf(lg[0][r], lg[1][r]);
        __syncthreads();
        for (int s = 128; s > 0; s >>= 1) {
            if (tid < s) red[tid] = fmaxf(red[tid], red[tid + s]);
            __syncthreads();
        }
        const float rowmax = red[0];
        __syncthreads();
        red[tid] = expf(lg[0][r] - rowmax) + expf(lg[1][r] - rowmax);
        __syncthreads();
        for (int s = 128; s > 0; s >>= 1) {
            if (tid < s) red[tid] += red[tid + s];
            __syncthreads();
        }
        if (tid == 0) {
            lse[i0 + r] = rowmax + logf(red[0]);
            diag[i0 + r] = sdiag[r];
        }
    }

    __threadfence();
    if (tid == 0) isLast = (atomicAdd(&g_done, 1) == 127) ? 1 : 0;
    __syncthreads();
    if (isLast) {
        __threadfence();
        float s1 = 0.0f, s2 = 0.0f;
        for (int i = tid; i < 512; i += 256) {
            const float l = lse[i];
            s1 += l - diag[i];
            const float u = l + 1e-6f;
            s2 = fmaf(u, u, s2);
        }
        red[tid] = s1; red2[tid] = s2;
        __syncthreads();
        for (int s = 128; s > 0; s >>= 1) {
            if (tid < s) { red[tid] += red[tid + s]; red2[tid] += red2[tid + s]; }
            __syncthreads();
        }
        if (tid == 0) {
            out[0] = red[0] * (1.0f / 512.0f) + 0.1f * red2[0] * (1.0f / 512.0f);
            g_done = 0;
        }
    }
}

// ---------------------------------------------------------------------------
// Host launcher
// ---------------------------------------------------------------------------
extern "C" void kernel_launch(void* const* d_in, const int* in_sizes, int n_in,
                              void* d_out, int out_size) {
    const float* curr = (const float*)d_in[0];
    const float* next = (const float*)d_in[1];
    const float* c1w = (const float*)d_in[2];
    const float* c1b = (const float*)d_in[3];
    const float* c2w = (const float*)d_in[4];
    const float* c2b = (const float*)d_in[5];
    const float* c3w = (const float*)d_in[6];
    const float* c3b = (const float*)d_in[7];
    const float* fcw = (const float*)d_in[8];
    const float* fcb = (const float*)d_in[9];
    const float* e1w = (const float*)d_in[10];
    const float* e1b = (const float*)d_in[11];
    const float* e2w = (const float*)d_in[12];
    const float* e2b = (const float*)d_in[13];
    const float* pw1 = (const float*)d_in[14];
    const float* pb1 = (const float*)d_in[15];
    const float* pw2 = (const float*)d_in[16];
    const float* pb2 = (const float*)d_in[17];

    u32 *p_w1f, *p_w2f, *p_w3f, *p_wfc, *p_we1, *p_we2, *p_wp1;
    __nv_bfloat16 *p_a1, *p_a2n, *p_feat;
    float *p_h1, *p_phi, *p_hp, *p_cy, *p_lse, *p_diag, *p_part;
    cudaGetSymbolAddress((void**)&p_w1f, g_w1f);
    cudaGetSymbolAddress((void**)&p_w2f, g_w2f);
    cudaGetSymbolAddress((void**)&p_w3f, g_w3f);
    cudaGetSymbolAddress((void**)&p_wfc, g_wfc);
    cudaGetSymbolAddress((void**)&p_we1, g_we1);
    cudaGetSymbolAddress((void**)&p_we2, g_we2);
    cudaGetSymbolAddress((void**)&p_wp1, g_wp1);
    cudaGetSymbolAddress((void**)&p_a1, g_a1);
    cudaGetSymbolAddress((void**)&p_a2n, g_a2n);
    cudaGetSymbolAddress((void**)&p_feat, g_feat);
    cudaGetSymbolAddress((void**)&p_h1, g_h1);
    cudaGetSymbolAddress((void**)&p_phi, g_phi);
    cudaGetSymbolAddress((void**)&p_hp, g_hp);
    cudaGetSymbolAddress((void**)&p_cy, g_cy);
    cudaGetSymbolAddress((void**)&p_lse, g_lse);
    cudaGetSymbolAddress((void**)&p_diag, g_diag);
    cudaGetSymbolAddress((void**)&p_part, g_part);

    const int SM1 = 26880;
    const int SM2 = 51200;
    const int SM3 = 23328;
    const int SMF = 90112;   // double-buffered A+B
    const int SMH = 34816 + 4096 * 4;
    cudaFuncSetAttribute(conv1_mma, cudaFuncAttributeMaxDynamicSharedMemorySize, SM1);
    cudaFuncSetAttribute(conv2_mma, cudaFuncAttributeMaxDynamicSharedMemorySize, SM2);
    cudaFuncSetAttribute(conv3_mma, cudaFuncAttributeMaxDynamicSharedMemorySize, SM3);
    cudaFuncSetAttribute(fc_mma, cudaFuncAttributeMaxDynamicSharedMemorySize, SMF);
    cudaFuncSetAttribute(headA, cudaFuncAttributeMaxDynamicSharedMemorySize, SMH);
    cudaFuncSetAttribute(headB, cudaFuncAttributeMaxDynamicSharedMemorySize, SMH);

    prep_all<<<538, 256>>>(c1w, c2w, c3w, fcw, e1w, e2w, pw1,
                           p_w1f, p_w2f, p_w3f, p_wfc, p_we1, p_we2, p_wp1);

    conv1_mma<<<dim3(512, 5), 160, SM1>>>(curr, next, p_w1f, c1b, p_a1);
    conv2_mma<<<dim3(512, 2), 352, SM2>>>(p_a1, p_w2f, c2b, p_a2n);
    conv3_mma<<<dim3(512, 2), 128, SM3>>>(p_a2n, p_w3f, c3b, p_feat);

    fc_mma<<<dim3(8, 4, 4), 256, SMF>>>(p_feat, p_wfc, p_part);

    headA<<<48, 256, SMH>>>(p_part, fcb, p_we1, e1b, p_h1, p_wp1, pb1, p_hp);
    headB<<<72, 256, SMH>>>(p_h1, p_we2, e2b, p_phi, p_hp, pw2, pb2, p_cy);

    logits_kernel<<<128, 256>>>(p_phi, p_cy, p_lse, p_diag, (float*)d_out);
}

// round 13
// speedup vs baseline: 7.9808x; 1.0198x over previous
#include <cuda_runtime.h>
#include <cuda_bf16.h>
#include <math.h>

#define NIMG 1024
typedef unsigned int u32;

// ---------------------------------------------------------------------------
// scratch
// ---------------------------------------------------------------------------
__device__ __align__(128) u32 g_w1f[16 * 4 * 64];
__device__ __align__(128) u32 g_w2f[32 * 8 * 64];
__device__ __align__(128) u32 g_w3f[36 * 8 * 64];
__device__ __align__(128) u32 g_wfc[196 * 32 * 64];
__device__ __align__(128) u32 g_we1[16 * 32 * 64];
__device__ __align__(128) u32 g_we2[16 * 8 * 64];
__device__ __align__(128) u32 g_wp1[16 * 32 * 64];
__device__ __align__(128) __nv_bfloat16 g_a1[(size_t)NIMG * 12800];
__device__ __align__(128) __nv_bfloat16 g_a2n[(size_t)NIMG * 81 * 64];
__device__ __align__(128) __nv_bfloat16 g_feat[(size_t)NIMG * 3136];
__device__ __align__(128) float g_h1[NIMG * 256];
__device__ __align__(128) float g_phi[NIMG * 64];
__device__ __align__(128) float g_hp[512 * 256];
__device__ __align__(128) float g_cy[512];
__device__ __align__(128) float g_lse[512];
__device__ __align__(128) float g_diag[512];
__device__ __align__(128) float g_part[4 * 1024 * 256];
__device__ int g_done = 0;

// ---------------------------------------------------------------------------
// helpers
// ---------------------------------------------------------------------------
__device__ __forceinline__ u32 packbf(float lo, float hi) {
    __nv_bfloat162 h = __float22bfloat162_rn(make_float2(lo, hi));
    return *reinterpret_cast<u32*>(&h);
}
__device__ __forceinline__ void mmabf(float* d, const u32* a, const u32* b) {
    asm volatile(
        "mma.sync.aligned.m16n8k16.row.col.f32.bf16.bf16.f32 "
        "{%0,%1,%2,%3},{%4,%5,%6,%7},{%8,%9},{%0,%1,%2,%3};\n"
        : "+f"(d[0]), "+f"(d[1]), "+f"(d[2]), "+f"(d[3])
        : "r"(a[0]), "r"(a[1]), "r"(a[2]), "r"(a[3]), "r"(b[0]), "r"(b[1]));
}
__device__ __forceinline__ void ldsm4(u32* r, u32 addr) {
    asm volatile("ldmatrix.sync.aligned.m8n8.x4.shared.b16 {%0,%1,%2,%3}, [%4];"
                 : "=r"(r[0]), "=r"(r[1]), "=r"(r[2]), "=r"(r[3]) : "r"(addr));
}
__device__ __forceinline__ u32 smem_u32(const void* p) {
    u32 a;
    asm("{ .reg .u64 t; cvta.to.shared.u64 t, %1; cvt.u32.u64 %0, t; }"
        : "=r"(a) : "l"(p));
    return a;
}
__device__ __forceinline__ void cpa16(u32 saddr, const void* g) {
    asm volatile("cp.async.ca.shared.global [%0], [%1], 16;"
                 :: "r"(saddr), "l"(g));
}
__device__ __forceinline__ void cpa_commit() {
    asm volatile("cp.async.commit_group;");
}
template<int N> __device__ __forceinline__ void cpa_wait() {
    asm volatile("cp.async.wait_group %0;" :: "n"(N));
}

// ---------------------------------------------------------------------------
// unified weight prep (blocks 0..439 scalar, 440..537 tiled fcw)
// ---------------------------------------------------------------------------
__global__ void prep_all(const float* __restrict__ c1w, const float* __restrict__ c2w,
                         const float* __restrict__ c3w, const float* __restrict__ fcw,
                         const float* __restrict__ e1w, const float* __restrict__ e2w,
                         const float* __restrict__ pw1,
                         u32* __restrict__ w1f, u32* __restrict__ w2f,
                         u32* __restrict__ w3f, u32* __restrict__ wfc,
                         u32* __restrict__ we1, u32* __restrict__ we2,
                         u32* __restrict__ wp1) {
    __shared__ float S[32 * 257];
    const int b = blockIdx.x;
    if (b < 440) {
        int gi = b * 256 + threadIdx.x;
        if (gi < 4096) {                               // conv1
            int i = gi;
            int s = i & 1, lane = (i >> 1) & 31;
            int cn = i >> 6, nt = cn & 3, c = cn >> 2;
            int t = lane & 3, g = lane >> 2;
            int n = nt * 8 + g;
            int ic = c >> 2, ky = (c & 3) * 2 + s, kx = 2 * t;
            const float* base = c1w + ((n * 4 + ic) * 8 + ky) * 8 + kx;
            w1f[i] = packbf(base[0], base[1]);
        } else if (gi < 20480) {                       // conv2
            int i = gi - 4096;
            int s = i & 1, lane = (i >> 1) & 31;
            int cn = i >> 6, nt = cn & 7, ic = cn >> 3;
            int t = lane & 3, g = lane >> 2;
            int n = nt * 8 + g;
            int ky = s * 2 + (t >> 1), kx = (t & 1) * 2;
            const float* base = c2w + ((n * 32 + ic) * 4 + ky) * 4 + kx;
            w2f[i] = packbf(base[0], base[1]);
        } else if (gi < 38912) {                       // conv3
            int i = gi - 20480;
            int s = i & 1, lane = (i >> 1) & 31;
            int cn = i >> 6, nt = cn & 7, c = cn >> 3;
            int t = lane & 3, g = lane >> 2;
            int n = nt * 8 + g;
            int p = c >> 2, icc = c & 3;
            int ic = icc * 16 + s * 8 + 2 * t;
            int ky = p / 3, kx = p % 3;
            float lo = c3w[((n * 64 + ic) * 3 + ky) * 3 + kx];
            float hi = c3w[((n * 64 + ic + 1) * 3 + ky) * 3 + kx];
            w3f[i] = packbf(lo, hi);
        } else if (gi < 71680) {                       // e1 (NTg=32)
            int i = gi - 38912;
            int s = i & 1, lane = (i >> 1) & 31;
            int cn = i >> 6, nt = cn & 31, c = cn >> 5;
            int t = lane & 3, g = lane >> 2;
            int n = nt * 8 + g;
            int k0 = c * 16 + s * 8 + 2 * t;
            we1[i] = packbf(e1w[(size_t)k0 * 256 + n], e1w[(size_t)(k0 + 1) * 256 + n]);
        } else if (gi < 79872) {                       // e2 (NTg=8)
            int i = gi - 71680;
            int s = i & 1, lane = (i >> 1) & 31;
            int cn = i >> 6, nt = cn & 7, c = cn >> 3;
            int t = lane & 3, g = lane >> 2;
            int n = nt * 8 + g;
            int k0 = c * 16 + s * 8 + 2 * t;
            we2[i] = packbf(e2w[(size_t)k0 * 64 + n], e2w[(size_t)(k0 + 1) * 64 + n]);
        } else if (gi < 112640) {                      // pw1 (NTg=32)
            int i = gi - 79872;
            int s = i & 1, lane = (i >> 1) & 31;
            int cn = i >> 6, nt = cn & 31, c = cn >> 5;
            int t = lane & 3, g = lane >> 2;
            int n = nt * 8 + g;
            int k0 = c * 16 + s * 8 + 2 * t;
            wp1[i] = packbf(pw1[(size_t)k0 * 256 + n], pw1[(size_t)(k0 + 1) * 256 + n]);
        }
    } else {
        const int bb = b - 440;
        const int kb = bb * 32;
        for (int j = threadIdx.x; j < 2048; j += 256) {
            int krel = j >> 6, n4 = (j & 63) * 4;
            float4 v = *(const float4*)&fcw[(size_t)(kb + krel) * 256 + n4];
            float* row = S + krel * 257 + n4;
            row[0] = v.x; row[1] = v.y; row[2] = v.z; row[3] = v.w;
        }
        __syncthreads();
        for (int j = threadIdx.x; j < 4096; j += 256) {
            int s = j & 1, lane = (j >> 1) & 31;
            int nt = (j >> 6) & 31, cl = j >> 11;
            int t = lane & 3, g = lane >> 2;
            int krel = cl * 16 + s * 8 + 2 * t;
            int n = nt * 8 + g;
            wfc[((size_t)(2 * bb + cl) * 32 + nt) * 64 + lane * 2 + s] =
                packbf(S[krel * 257 + n], S[(krel + 1) * 257 + n]);
        }
    }
}

// ---------------------------------------------------------------------------
// conv1: grid (512 pairs, 5 oy-groups), 160 thr. Scalar A (smem) + gmem B.
// ---------------------------------------------------------------------------
__global__ void __launch_bounds__(160, 7)
conv1_mma(const float* __restrict__ curr,
          const float* __restrict__ next,
          const u32* __restrict__ wfu,
          const float* __restrict__ bias,
          __nv_bfloat16* __restrict__ out) {
    extern __shared__ char smc[];
    __nv_bfloat16* simg = (__nv_bfloat16*)smc;     // 2*6720 bf16
    const int p = blockIdx.x, oyg = blockIdx.y;
    const int iy0 = oyg * 16;
    const float* in0 = curr + (size_t)p * 28224;
    const float* in1 = next + (size_t)p * 28224;
    for (int i = threadIdx.x; i < 3360; i += 160) {
        int e = i * 4;
        int im = e / 6720, e2 = e % 6720;
        int ic = e2 / 1680, rem = e2 % 1680;
        const float* src = im ? in1 : in0;
        float4 v = *(const float4*)&src[ic * 7056 + iy0 * 84 + rem];
        u32* d = (u32*)&simg[e];
        d[0] = packbf(v.x, v.y);
        d[1] = packbf(v.z, v.w);
    }
    __syncthreads();

    const int lane = threadIdx.x & 31, wid = threadIdx.x >> 5;
    const int t = lane & 3;
    const int r0 = wid * 16 + (lane >> 2), r1 = r0 + 8;
    const int b00 = (r0 / 20) * 336 + (r0 % 20) * 4 + 2 * t;
    const int b01 = (r1 / 20) * 336 + (r1 % 20) * 4 + 2 * t;
    const u32* wlane = wfu + lane * 2;

    float acc[2][4][4];
    #pragma unroll
    for (int nt = 0; nt < 4; nt++) {
        int oc = nt * 8 + t * 2;
        float b0 = bias[oc], b1 = bias[oc + 1];
        #pragma unroll
        for (int im = 0; im < 2; im++) {
            acc[im][nt][0] = b0; acc[im][nt][1] = b1;
            acc[im][nt][2] = b0; acc[im][nt][3] = b1;
        }
    }
    u32 a0[4], a1[4];
    uint2 bv[4];
    a0[0] = *(const u32*)&simg[b00];
    a0[1] = *(const u32*)&simg[b01];
    a0[2] = *(const u32*)&simg[84 + b00];
    a0[3] = *(const u32*)&simg[84 + b01];
    a1[0] = *(const u32*)&simg[6720 + b00];
    a1[1] = *(const u32*)&simg[6720 + b01];
    a1[2] = *(const u32*)&simg[6720 + 84 + b00];
    a1[3] = *(const u32*)&simg[6720 + 84 + b01];
    #pragma unroll
    for (int nt = 0; nt < 4; nt++)
        bv[nt] = *(const uint2*)&wlane[nt * 64];

    #pragma unroll
    for (int c = 0; c < 16; c++) {
        u32 na0[4], na1[4];
        uint2 nbv[4];
        if (c < 15) {
            const int o = ((c + 1) >> 2) * 1680 + ((c + 1) & 3) * 168;
            na0[0] = *(const u32*)&simg[o + b00];
            na0[1] = *(const u32*)&simg[o + b01];
            na0[2] = *(const u32*)&simg[o + 84 + b00];
            na0[3] = *(const u32*)&simg[o + 84 + b01];
            na1[0] = *(const u32*)&simg[6720 + o + b00];
            na1[1] = *(const u32*)&simg[6720 + o + b01];
            na1[2] = *(const u32*)&simg[6720 + o + 84 + b00];
            na1[3] = *(const u32*)&simg[6720 + o + 84 + b01];
            #pragma unroll
            for (int nt = 0; nt < 4; nt++)
                nbv[nt] = *(const uint2*)&wlane[((c + 1) * 4 + nt) * 64];
        }
        #pragma unroll
        for (int nt = 0; nt < 4; nt++) {
            u32 b[2] = {bv[nt].x, bv[nt].y};
            mmabf(acc[0][nt], a0, b);
            mmabf(acc[1][nt], a1, b);
        }
        if (c < 15) {
            #pragma unroll
            for (int q = 0; q < 4; q++) { a0[q] = na0[q]; a1[q] = na1[q]; }
            #pragma unroll
            for (int nt = 0; nt < 4; nt++) bv[nt] = nbv[nt];
        }
    }
    #pragma unroll
    for (int im = 0; im < 2; im++) {
        const int img = p + im * 512;
        __nv_bfloat16* ob = out + (size_t)img * 12800 + oyg * 80;
        #pragma unroll
        for (int nt = 0; nt < 4; nt++) {
            int oc = nt * 8 + t * 2;
            __nv_bfloat16* p0 = ob + (size_t)oc * 400;
            p0[r0]       = __float2bfloat16(fmaxf(acc[im][nt][0], 0.0f));
            p0[400 + r0] = __float2bfloat16(fmaxf(acc[im][nt][1], 0.0f));
            p0[r1]       = __float2bfloat16(fmaxf(acc[im][nt][2], 0.0f));
            p0[400 + r1] = __float2bfloat16(fmaxf(acc[im][nt][3], 0.0f));
        }
    }
}

// ---------------------------------------------------------------------------
// conv2: grid (512 pairs, 2 oc-halves), 192 thr (6 warps, M=32/warp).
// Scalar A (smem) + gmem B shared across 2 row-groups. 4 blocks/SM.
// ---------------------------------------------------------------------------
__global__ void __launch_bounds__(192, 4)
conv2_mma(const __nv_bfloat16* __restrict__ a1,
          const u32* __restrict__ wfu,
          const float* __restrict__ bias,
          __nv_bfloat16* __restrict__ out) {
    extern __shared__ char smc[];
    __nv_bfloat16* sin = (__nv_bfloat16*)smc;      // 25600 bf16
    const int p = blockIdx.x, q = blockIdx.y;
    const uint4* src = (const uint4*)(a1 + (size_t)p * 25600);
    for (int i = threadIdx.x; i < 3200; i += 192)
        ((uint4*)sin)[i] = src[i];
    __syncthreads();

    const int lane = threadIdx.x & 31, wid = threadIdx.x >> 5;
    const int t = lane & 3;
    const int toff = (t >> 1) * 20 + (t & 1) * 2;
    const int rb = wid * 32 + (lane >> 2);
    int rr[4] = {rb, rb + 8, rb + 16, rb + 24};
    int AO[4], IM[4], PX[4];
    #pragma unroll
    for (int k = 0; k < 4; k++) {
        int gg = (rr[k] < 162) ? rr[k] : 161;
        IM[k] = gg / 81; PX[k] = gg % 81;
        AO[k] = IM[k] * 12800 + (PX[k] / 9) * 40 + (PX[k] % 9) * 2 + toff;
    }
    const u32* wlane = wfu + (size_t)q * 4 * 64 + lane * 2;

    float acc[2][4][4];
    #pragma unroll
    for (int nt = 0; nt < 4; nt++) {
        int oc = q * 32 + nt * 8 + t * 2;
        float b0 = bias[oc], b1 = bias[oc + 1];
        #pragma unroll
        for (int G = 0; G < 2; G++) {
            acc[G][nt][0] = b0; acc[G][nt][1] = b1;
            acc[G][nt][2] = b0; acc[G][nt][3] = b1;
        }
    }

    u32 aG0[4], aG1[4];
    uint2 bv[4];
    aG0[0] = *(const u32*)&sin[AO[0]];
    aG0[1] = *(const u32*)&sin[AO[1]];
    aG0[2] = *(const u32*)&sin[40 + AO[0]];
    aG0[3] = *(const u32*)&sin[40 + AO[1]];
    aG1[0] = *(const u32*)&sin[AO[2]];
    aG1[1] = *(const u32*)&sin[AO[3]];
    aG1[2] = *(const u32*)&sin[40 + AO[2]];
    aG1[3] = *(const u32*)&sin[40 + AO[3]];
    #pragma unroll
    for (int nt = 0; nt < 4; nt++)
        bv[nt] = *(const uint2*)&wlane[nt * 64];

    #pragma unroll 8
    for (int ic = 0; ic < 32; ic++) {
        u32 na0[4], na1[4];
        uint2 nbv[4];
        if (ic < 31) {
            const int o = (ic + 1) * 400;
            na0[0] = *(const u32*)&sin[o + AO[0]];
            na0[1] = *(const u32*)&sin[o + AO[1]];
            na0[2] = *(const u32*)&sin[o + 40 + AO[0]];
            na0[3] = *(const u32*)&sin[o + 40 + AO[1]];
            na1[0] = *(const u32*)&sin[o + AO[2]];
            na1[1] = *(const u32*)&sin[o + AO[3]];
            na1[2] = *(const u32*)&sin[o + 40 + AO[2]];
            na1[3] = *(const u32*)&sin[o + 40 + AO[3]];
            #pragma unroll
            for (int nt = 0; nt < 4; nt++)
                nbv[nt] = *(const uint2*)&wlane[((ic + 1) * 8 + nt) * 64];
        }
        #pragma unroll
        for (int nt = 0; nt < 4; nt++) {
            u32 b[2] = {bv[nt].x, bv[nt].y};
            mmabf(acc[0][nt], aG0, b);
            mmabf(acc[1][nt], aG1, b);
        }
        if (ic < 31) {
            #pragma unroll
            for (int k = 0; k < 4; k++) { aG0[k] = na0[k]; aG1[k] = na1[k]; }
            #pragma unroll
            for (int nt = 0; nt < 4; nt++) bv[nt] = nbv[nt];
        }
    }
    #pragma unroll
    for (int G = 0; G < 2; G++) {
        #pragma unroll
        for (int nt = 0; nt < 4; nt++) {
            int oc = q * 32 + nt * 8 + t * 2;
            const int k0 = G * 2, k1 = G * 2 + 1;
            if (rr[k0] < 162)
                *(u32*)&out[((size_t)(p * 2 + IM[k0]) * 81 + PX[k0]) * 64 + oc] =
                    packbf(fmaxf(acc[G][nt][0], 0.0f), fmaxf(acc[G][nt][1], 0.0f));
            if (rr[k1] < 162)
                *(u32*)&out[((size_t)(p * 2 + IM[k1]) * 81 + PX[k1]) * 64 + oc] =
                    packbf(fmaxf(acc[G][nt][2], 0.0f), fmaxf(acc[G][nt][3], 0.0f));
        }
    }
}

// ---------------------------------------------------------------------------
// conv3: grid 512 (image pairs), 256 thr (8 warps; warps 0-3 oc 0-31,
// warps 4-7 oc 32-63, M=32/warp). Single A staging per pair.
// ---------------------------------------------------------------------------
__global__ void __launch_bounds__(256, 2)
conv3_mma(const __nv_bfloat16* __restrict__ a2n,
          const u32* __restrict__ wfu,
          const float* __restrict__ bias,
          __nv_bfloat16* __restrict__ feat) {
    extern __shared__ char smc[];
    __nv_bfloat16* sin = (__nv_bfloat16*)smc;      // 2*81*72 bf16
    const int imgb = blockIdx.x * 2;
    for (int i = threadIdx.x; i < 1296; i += 256) {
        int im = i / 648, r = i % 648;
        int px = r >> 3, qq = r & 7;
        *((uint4*)&sin[im * 5832 + px * 72]       + qq) =
        *((const uint4*)&a2n[((size_t)(imgb + im) * 81 + px) * 64] + qq);
    }
    __syncthreads();

    const int lane = threadIdx.x & 31, wid = threadIdx.x >> 5;
    const int wl = wid & 3, q = wid >> 2;
    const int t = lane & 3;
    const u32 sb = smem_u32(smc);
    u32 laG[2];
    #pragma unroll
    for (int G = 0; G < 2; G++) {
        int r = wl * 32 + G * 16 + (lane & 15);
        if (r > 97) r = 97;
        int im = r / 49, lp = r % 49;
        laG[G] = sb + (u32)(im * 11664 + ((lp / 7) * 9 + lp % 7) * 144)
                    + ((lane & 16) ? 16u : 0u);
    }
    const u32* wlane = wfu + (size_t)q * 4 * 64 + lane * 2;

    float acc[2][4][4];
    #pragma unroll
    for (int nt = 0; nt < 4; nt++) {
        int oc = q * 32 + nt * 8 + t * 2;
        float b0 = bias[oc], b1 = bias[oc + 1];
        #pragma unroll
        for (int G = 0; G < 2; G++) {
            acc[G][nt][0] = b0; acc[G][nt][1] = b1;
            acc[G][nt][2] = b0; acc[G][nt][3] = b1;
        }
    }

    u32 a0[4], a1[4];
    uint2 bv[4];
    ldsm4(a0, laG[0]);
    ldsm4(a1, laG[1]);
    #pragma unroll
    for (int nt = 0; nt < 4; nt++)
        bv[nt] = *(const uint2*)&wlane[nt * 64];

    #pragma unroll
    for (int c = 0; c < 36; c++) {
        u32 na0[4], na1[4];
        uint2 nbv[4];
        if (c < 35) {
            const int pp = (c + 1) >> 2, icc = (c + 1) & 3;
            const u32 off = (u32)(((pp / 3) * 9 + (pp % 3)) * 144 + icc * 32);
            ldsm4(na0, laG[0] + off);
            ldsm4(na1, laG[1] + off);
            #pragma unroll
            for (int nt = 0; nt < 4; nt++)
                nbv[nt] = *(const uint2*)&wlane[((c + 1) * 8 + nt) * 64];
        }
        #pragma unroll
        for (int nt = 0; nt < 4; nt++) {
            u32 b[2] = {bv[nt].x, bv[nt].y};
            mmabf(acc[0][nt], a0, b);
            mmabf(acc[1][nt], a1, b);
        }
        if (c < 35) {
            #pragma unroll
            for (int k = 0; k < 4; k++) { a0[k] = na0[k]; a1[k] = na1[k]; }
            #pragma unroll
            for (int nt = 0; nt < 4; nt++) bv[nt] = nbv[nt];
        }
    }
    #pragma unroll
    for (int G = 0; G < 2; G++) {
        const int r0 = wl * 32 + G * 16 + (lane >> 2), r1 = r0 + 8;
        const int g0 = (r0 < 98) ? r0 : 97, g1 = (r1 < 98) ? r1 : 97;
        const int im0 = g0 / 49, lp0 = g0 % 49;
        const int im1 = g1 / 49, lp1 = g1 % 49;
        #pragma unroll
        for (int nt = 0; nt < 4; nt++) {
            int oc = q * 32 + nt * 8 + t * 2;
            if (r0 < 98) {
                __nv_bfloat16* fb = feat + (size_t)(imgb + im0) * 3136 + oc * 49 + lp0;
                fb[0]  = __float2bfloat16(fmaxf(acc[G][nt][0], 0.0f));
                fb[49] = __float2bfloat16(fmaxf(acc[G][nt][1], 0.0f));
            }
            if (r1 < 98) {
                __nv_bfloat16* fb = feat + (size_t)(imgb + im1) * 3136 + oc * 49 + lp1;
                fb[0]  = __float2bfloat16(fmaxf(acc[G][nt][2], 0.0f));
                fb[49] = __float2bfloat16(fmaxf(acc[G][nt][3], 0.0f));
            }
        }
    }
}

// ---------------------------------------------------------------------------
// FC (bf16 mma): [1024,3136]@[3136,256], split-K 4, cp.async double-buffered.
// ---------------------------------------------------------------------------
__global__ void fc_mma(const __nv_bfloat16* __restrict__ feat,
                       const u32* __restrict__ wfu,
                       float* __restrict__ part) {
    extern __shared__ char smc[];
    const int mb = blockIdx.x, nb = blockIdx.y, z = blockIdx.z;
    const int m0b = mb * 128;
    const int lane = threadIdx.x & 31, wid = threadIdx.x >> 5;
    const int t = lane & 3, g = lane >> 2;
    const u32 sbase = smem_u32(smc);

    #define FC_STAGE(IT, BUF) do {                                            \
        const int kbase_ = z * 784 + (IT) * 112;                              \
        const int cbase_ = z * 49 + (IT) * 7;                                 \
        const u32 aoff_ = sbase + (BUF) * 30720u;                             \
        for (int i = threadIdx.x; i < 1792; i += 256) {                       \
            int row_ = i / 14, seg_ = i % 14;                                 \
            cpa16(aoff_ + (u32)(row_ * 120 + seg_ * 8) * 2u,                  \
                  &feat[(size_t)(m0b + row_) * 3136 + kbase_ + seg_ * 8]);    \
        }                                                                     \
        const u32 boff_ = sbase + 61440u + (BUF) * 14336u;                    \
        for (int i = threadIdx.x; i < 896; i += 256) {                        \
            int cn_ = i >> 4, cl_ = cn_ >> 3, ntl_ = cn_ & 7;                 \
            cpa16(boff_ + (u32)i * 16u,                                       \
                  &wfu[((size_t)(cbase_ + cl_) * 32 + nb * 8 + ntl_) * 64     \
                       + (i & 15) * 4]);                                      \
        }                                                                     \
    } while (0)

    float acc[8][4] = {};
    FC_STAGE(0, 0);
    cpa_commit();
    for (int it = 0; it < 7; it++) {
        if (it < 6) {
            FC_STAGE(it + 1, (it + 1) & 1);
            cpa_commit();
            cpa_wait<1>();
        } else {
            cpa_wait<0>();
        }
        __syncthreads();
        const __nv_bfloat16* sA = (const __nv_bfloat16*)(smc + (it & 1) * 30720);
        const u32* sB = (const u32*)(smc + 61440 + (it & 1) * 14336);
        #pragma unroll
        for (int c_l = 0; c_l < 7; c_l++) {
            const int ra = (wid * 16 + g) * 120 + c_l * 16 + 2 * t;
            u32 a[4];
            a[0] = *(const u32*)&sA[ra];
            a[1] = *(const u32*)&sA[ra + 8 * 120];
            a[2] = *(const u32*)&sA[ra + 8];
            a[3] = *(const u32*)&sA[ra + 8 * 120 + 8];
            const u32* wb = sB + c_l * 512 + lane * 2;
            #pragma unroll
            for (int nt = 0; nt < 8; nt++) {
                uint2 bv = *(const uint2*)&wb[nt * 64];
                u32 b[2] = {bv.x, bv.y};
                mmabf(acc[nt], a, b);
            }
        }
        __syncthreads();
    }
    #undef FC_STAGE

    float* pb = part + (size_t)z * 262144;
    const int mr0 = m0b + wid * 16 + g, mr1 = mr0 + 8;
    #pragma unroll
    for (int nt = 0; nt < 8; nt++) {
        int col = nb * 64 + nt * 8 + 2 * t;
        *(float2*)&pb[(size_t)mr0 * 256 + col] = make_float2(acc[nt][0], acc[nt][1]);
        *(float2*)&pb[(size_t)mr1 * 256 + col] = make_float2(acc[nt][2], acc[nt][3]);
    }
}

// ---------------------------------------------------------------------------
// head GEMM bodies
// ---------------------------------------------------------------------------
__device__ void head_bodyP(const float* __restrict__ part, int rowOff,
                           const float* __restrict__ fcb,
                           const u32* __restrict__ wfu,
                           const float* __restrict__ bias,
                           float* __restrict__ C,
                           int NTg, int mb, int nb) {
    extern __shared__ char smc[];
    __nv_bfloat16* sA = (__nv_bfloat16*)smc;
    u32* sB = (u32*)(smc + 34816);
    const int m0b = mb * 128;
    const int N = NTg * 8;
    const int lane = threadIdx.x & 31, wid = threadIdx.x >> 5;
    const int t = lane & 3, g = lane >> 2;

    float acc[8][4] = {};
    #pragma unroll
    for (int it = 0; it < 2; it++) {
        const int kbase = it * 128;
        __syncthreads();
        for (int i = threadIdx.x; i < 4096; i += 256) {
            int row = i >> 5, seg = i & 31;
            size_t idx = (size_t)(rowOff + m0b + row) * 256 + kbase + seg * 4;
            float4 v = *(const float4*)&fcb[kbase + seg * 4];
            float4 p0 = *(const float4*)&part[idx];
            float4 p1 = *(const float4*)&part[262144 + idx];
            float4 p2 = *(const float4*)&part[524288 + idx];
            float4 p3 = *(const float4*)&part[786432 + idx];
            v.x = fmaxf(v.x + p0.x + p1.x + p2.x + p3.x, 0.0f);
            v.y = fmaxf(v.y + p0.y + p1.y + p2.y + p3.y, 0.0f);
            v.z = fmaxf(v.z + p0.z + p1.z + p2.z + p3.z, 0.0f);
            v.w = fmaxf(v.w + p0.w + p1.w + p2.w + p3.w, 0.0f);
            u32* d = (u32*)&sA[row * 136 + seg * 4];
            d[0] = packbf(v.x, v.y);
            d[1] = packbf(v.z, v.w);
        }
        for (int i = threadIdx.x; i < 1024; i += 256) {
            int cn = i >> 4, c_l = cn >> 3, ntl = cn & 7;
            ((uint4*)sB)[i] =
                *(const uint4*)&wfu[(((it * 8 + c_l) * NTg) + nb * 8 + ntl) * 64 + (i & 15) * 4];
        }
        __syncthreads();
        #pragma unroll
        for (int c_l = 0; c_l < 8; c_l++) {
            const int ra = (wid * 16 + g) * 136 + c_l * 16 + 2 * t;
            u32 a[4];
            a[0] = *(const u32*)&sA[ra];
            a[1] = *(const u32*)&sA[ra + 8 * 136];
            a[2] = *(const u32*)&sA[ra + 8];
            a[3] = *(const u32*)&sA[ra + 8 * 136 + 8];
            const u32* wb = sB + c_l * 512 + lane * 2;
            #pragma unroll
            for (int nt = 0; nt < 8; nt++) {
                uint2 bv = *(const uint2*)&wb[nt * 64];
                u32 b[2] = {bv.x, bv.y};
                mmabf(acc[nt], a, b);
            }
        }
    }
    const int mr0 = m0b + wid * 16 + g, mr1 = mr0 + 8;
    #pragma unroll
    for (int nt = 0; nt < 8; nt++) {
        int col = nb * 64 + nt * 8 + 2 * t;
        float b0 = bias[col], b1 = bias[col + 1];
        float v00 = fmaxf(acc[nt][0] + b0, 0.0f), v01 = fmaxf(acc[nt][1] + b1, 0.0f);
        float v10 = fmaxf(acc[nt][2] + b0, 0.0f), v11 = fmaxf(acc[nt][3] + b1, 0.0f);
        *(float2*)&C[(size_t)mr0 * N + col] = make_float2(v00, v01);
        *(float2*)&C[(size_t)mr1 * N + col] = make_float2(v10, v11);
    }
}

__device__ void head_body(const float* __restrict__ A,
                          const u32* __restrict__ wfu,
                          const float* __restrict__ bias,
                          float* __restrict__ C,
                          int NTg, int doRelu, int mb, int nb) {
    extern __shared__ char smc[];
    __nv_bfloat16* sA = (__nv_bfloat16*)smc;
    u32* sB = (u32*)(smc + 34816);
    const int m0b = mb * 128;
    const int N = NTg * 8;
    const int lane = threadIdx.x & 31, wid = threadIdx.x >> 5;
    const int t = lane & 3, g = lane >> 2;

    float acc[8][4] = {};
    #pragma unroll
    for (int it = 0; it < 2; it++) {
        const int kbase = it * 128;
        __syncthreads();
        for (int i = threadIdx.x; i < 4096; i += 256) {
            int row = i >> 5, seg = i & 31;
            float4 v = *(const float4*)&A[(size_t)(m0b + row) * 256 + kbase + seg * 4];
            u32* d = (u32*)&sA[row * 136 + seg * 4];
            d[0] = packbf(v.x, v.y);
            d[1] = packbf(v.z, v.w);
        }
        for (int i = threadIdx.x; i < 1024; i += 256) {
            int cn = i >> 4, c_l = cn >> 3, ntl = cn & 7;
            ((uint4*)sB)[i] =
                *(const uint4*)&wfu[(((it * 8 + c_l) * NTg) + nb * 8 + ntl) * 64 + (i & 15) * 4];
        }
        __syncthreads();
        #pragma unroll
        for (int c_l = 0; c_l < 8; c_l++) {
            const int ra = (wid * 16 + g) * 136 + c_l * 16 + 2 * t;
            u32 a[4];
            a[0] = *(const u32*)&sA[ra];
            a[1] = *(const u32*)&sA[ra + 8 * 136];
            a[2] = *(const u32*)&sA[ra + 8];
            a[3] = *(const u32*)&sA[ra + 8 * 136 + 8];
            const u32* wb = sB + c_l * 512 + lane * 2;
            #pragma unroll
            for (int nt = 0; nt < 8; nt++) {
                uint2 bv = *(const uint2*)&wb[nt * 64];
                u32 b[2] = {bv.x, bv.y};
                mmabf(acc[nt], a, b);
            }
        }
    }
    const int mr0 = m0b + wid * 16 + g, mr1 = mr0 + 8;
    #pragma unroll
    for (int nt = 0; nt < 8; nt++) {
        int col = nb * 64 + nt * 8 + 2 * t;
        float b0 = bias[col], b1 = bias[col + 1];
        float v00 = acc[nt][0] + b0, v01 = acc[nt][1] + b1;
        float v10 = acc[nt][2] + b0, v11 = acc[nt][3] + b1;
        if (doRelu) {
            v00 = fmaxf(v00, 0.0f); v01 = fmaxf(v01, 0.0f);
            v10 = fmaxf(v10, 0.0f); v11 = fmaxf(v11, 0.0f);
        }
        *(float2*)&C[(size_t)mr0 * N + col] = make_float2(v00, v01);
        *(float2*)&C[(size_t)mr1 * N + col] = make_float2(v10, v11);
    }
}

__global__ void headA(const float* __restrict__ part, const float* __restrict__ fcb,
                      const u32* __restrict__ we1, const float* __restrict__ e1b,
                      float* __restrict__ h1,
                      const u32* __restrict__ wp1, const float* __restrict__ pb1,
                      float* __restrict__ hp) {
    int bid = blockIdx.x;
    if (bid < 32) head_bodyP(part, 0, fcb, we1, e1b, h1, 32, bid >> 2, bid & 3);
    else {
        bid -= 32;
        head_bodyP(part, 512, fcb, wp1, pb1, hp, 32, bid >> 2, bid & 3);
    }
}

__global__ void headB(const float* __restrict__ h1,
                      const u32* __restrict__ we2, const float* __restrict__ e2b,
                      float* __restrict__ phi,
                      const float* __restrict__ hp,
                      const float* __restrict__ pw2, const float* __restrict__ pb2,
                      float* __restrict__ cy) {
    int bid = blockIdx.x;
    if (bid < 8) {
        head_body(h1, we2, e2b, phi, 8, 0, bid, 0);
    } else {
        const int gw = (bid - 8) * 8 + (threadIdx.x >> 5);
        const int lane = threadIdx.x & 31;
        float s = 0.0f;
        for (int k = lane; k < 256; k += 32)
            s = fmaf(hp[(size_t)gw * 256 + k], pw2[k], s);
        #pragma unroll
        for (int off = 16; off > 0; off >>= 1) s += __shfl_xor_sync(0xffffffffu, s, off);
        if (lane == 0) cy[gw] = s + pb2[0];
    }
}

// ---------------------------------------------------------------------------
// logits: 4 rows/block (grid 128) + fused final loss (last block).
// ---------------------------------------------------------------------------
__global__ void logits_kernel(const float* __restrict__ phi,
                              const float* __restrict__ cy,
                              float* __restrict__ lse,
                              float* __restrict__ diag,
                              float* __restrict__ out) {
    const int i0 = blockIdx.x * 4;
    __shared__ float sx[4][64];
    __shared__ float red[256];
    __shared__ float red2[256];
    __shared__ float sdiag[4];
    __shared__ int isLast;
    const int tid = threadIdx.x;
    sx[tid >> 6][tid & 63] = phi[(size_t)(i0 + (tid >> 6)) * 64 + (tid & 63)];
    __syncthreads();

    float lg[2][4];
    #pragma unroll
    for (int rep = 0; rep < 2; rep++) {
        const int j = tid + rep * 256;
        const float* y = phi + (size_t)(512 + j) * 64;
        float mx[4] = {0.f, 0.f, 0.f, 0.f}, ss[4] = {0.f, 0.f, 0.f, 0.f};
        #pragma unroll
        for (int k = 0; k < 32; k++) {
            const float yk = y[k];
            #pragma unroll
            for (int r = 0; r < 4; r++) {
                float d = sx[r][k] - yk;
                mx[r] = fmaxf(mx[r], fmaxf(d, 0.0f));
            }
        }
        #pragma unroll
        for (int k = 32; k < 64; k++) {
            const float yk = y[k];
            #pragma unroll
            for (int r = 0; r < 4; r++) {
                float d = sx[r][k] - yk;
                ss[r] = fmaf(d, d, ss[r]);
            }
        }
        const float cyj = cy[j];
        #pragma unroll
        for (int r = 0; r < 4; r++) {
            lg[rep][r] = cyj - (mx[r] + sqrtf(ss[r] + 1e-8f));
            if (j == i0 + r) sdiag[r] = lg[rep][r];
        }
    }
    #pragma unroll
    for (int r = 0; r < 4; r++) {
        __syncthreads();
        red[tid] = fmaxf(lg[0][r], lg[1][r]);
        __syncthreads();
        for (int s = 128; s > 0; s >>= 1) {
            if (tid < s) red[tid] = fmaxf(red[tid], red[tid + s]);
            __syncthreads();
        }
        const float rowmax = red[0];
        __syncthreads();
        red[tid] = expf(lg[0][r] - rowmax) + expf(lg[1][r] - rowmax);
        __syncthreads();
        for (int s = 128; s > 0; s >>= 1) {
            if (tid < s) red[tid] += red[tid + s];
            __syncthreads();
        }
        if (tid == 0) {
            lse[i0 + r] = rowmax + logf(red[0]);
            diag[i0 + r] = sdiag[r];
        }
    }

    __threadfence();
    if (tid == 0) isLast = (atomicAdd(&g_done, 1) == 127) ? 1 : 0;
    __syncthreads();
    if (isLast) {
        __threadfence();
        float s1 = 0.0f, s2 = 0.0f;
        for (int i = tid; i < 512; i += 256) {
            const float l = lse[i];
            s1 += l - diag[i];
            const float u = l + 1e-6f;
            s2 = fmaf(u, u, s2);
        }
        red[tid] = s1; red2[tid] = s2;
        __syncthreads();
        for (int s = 128; s > 0; s >>= 1) {
            if (tid < s) { red[tid] += red[tid + s]; red2[tid] += red2[tid + s]; }
            __syncthreads();
        }
        if (tid == 0) {
            out[0] = red[0] * (1.0f / 512.0f) + 0.1f * red2[0] * (1.0f / 512.0f);
            g_done = 0;
        }
    }
}

// ---------------------------------------------------------------------------
// Host launcher
// ---------------------------------------------------------------------------
extern "C" void kernel_launch(void* const* d_in, const int* in_sizes, int n_in,
                              void* d_out, int out_size) {
    const float* curr = (const float*)d_in[0];
    const float* next = (const float*)d_in[1];
    const float* c1w = (const float*)d_in[2];
    const float* c1b = (const float*)d_in[3];
    const float* c2w = (const float*)d_in[4];
    const float* c2b = (const float*)d_in[5];
    const float* c3w = (const float*)d_in[6];
    const float* c3b = (const float*)d_in[7];
    const float* fcw = (const float*)d_in[8];
    const float* fcb = (const float*)d_in[9];
    const float* e1w = (const float*)d_in[10];
    const float* e1b = (const float*)d_in[11];
    const float* e2w = (const float*)d_in[12];
    const float* e2b = (const float*)d_in[13];
    const float* pw1 = (const float*)d_in[14];
    const float* pb1 = (const float*)d_in[15];
    const float* pw2 = (const float*)d_in[16];
    const float* pb2 = (const float*)d_in[17];

    u32 *p_w1f, *p_w2f, *p_w3f, *p_wfc, *p_we1, *p_we2, *p_wp1;
    __nv_bfloat16 *p_a1, *p_a2n, *p_feat;
    float *p_h1, *p_phi, *p_hp, *p_cy, *p_lse, *p_diag, *p_part;
    cudaGetSymbolAddress((void**)&p_w1f, g_w1f);
    cudaGetSymbolAddress((void**)&p_w2f, g_w2f);
    cudaGetSymbolAddress((void**)&p_w3f, g_w3f);
    cudaGetSymbolAddress((void**)&p_wfc, g_wfc);
    cudaGetSymbolAddress((void**)&p_we1, g_we1);
    cudaGetSymbolAddress((void**)&p_we2, g_we2);
    cudaGetSymbolAddress((void**)&p_wp1, g_wp1);
    cudaGetSymbolAddress((void**)&p_a1, g_a1);
    cudaGetSymbolAddress((void**)&p_a2n, g_a2n);
    cudaGetSymbolAddress((void**)&p_feat, g_feat);
    cudaGetSymbolAddress((void**)&p_h1, g_h1);
    cudaGetSymbolAddress((void**)&p_phi, g_phi);
    cudaGetSymbolAddress((void**)&p_hp, g_hp);
    cudaGetSymbolAddress((void**)&p_cy, g_cy);
    cudaGetSymbolAddress((void**)&p_lse, g_lse);
    cudaGetSymbolAddress((void**)&p_diag, g_diag);
    cudaGetSymbolAddress((void**)&p_part, g_part);

    const int SM1 = 26880;
    const int SM2 = 51200;
    const int SM3 = 23328;
    const int SMF = 90112;
    const int SMH = 34816 + 4096 * 4;
    cudaFuncSetAttribute(conv1_mma, cudaFuncAttributeMaxDynamicSharedMemorySize, SM1);
    cudaFuncSetAttribute(conv2_mma, cudaFuncAttributeMaxDynamicSharedMemorySize, SM2);
    cudaFuncSetAttribute(conv3_mma, cudaFuncAttributeMaxDynamicSharedMemorySize, SM3);
    cudaFuncSetAttribute(fc_mma, cudaFuncAttributeMaxDynamicSharedMemorySize, SMF);
    cudaFuncSetAttribute(headA, cudaFuncAttributeMaxDynamicSharedMemorySize, SMH);
    cudaFuncSetAttribute(headB, cudaFuncAttributeMaxDynamicSharedMemorySize, SMH);

    prep_all<<<538, 256>>>(c1w, c2w, c3w, fcw, e1w, e2w, pw1,
                           p_w1f, p_w2f, p_w3f, p_wfc, p_we1, p_we2, p_wp1);

    conv1_mma<<<dim3(512, 5), 160, SM1>>>(curr, next, p_w1f, c1b, p_a1);
    conv2_mma<<<dim3(512, 2), 192, SM2>>>(p_a1, p_w2f, c2b, p_a2n);
    conv3_mma<<<512, 256, SM3>>>(p_a2n, p_w3f, c3b, p_feat);

    fc_mma<<<dim3(8, 4, 4), 256, SMF>>>(p_feat, p_wfc, p_part);

    headA<<<48, 256, SMH>>>(p_part, fcb, p_we1, e1b, p_h1, p_wp1, pb1, p_hp);
    headB<<<72, 256, SMH>>>(p_h1, p_we2, e2b, p_phi, p_hp, pw2, pb2, p_cy);

    logits_kernel<<<128, 256>>>(p_phi, p_cy, p_lse, p_diag, (float*)d_out);
}